// round 1
// baseline (speedup 1.0000x reference)
#include <cuda_runtime.h>

#define B_ 4
#define S_ 2048
#define H_ 1024
#define NH 16
#define HD 64

// Scratch (no cudaMalloc allowed). g_P holds one batch of per-head scores (268MB),
// reused across batches — launches serialize on the stream so this is safe.
__device__ float g_Q[B_ * S_ * H_];
__device__ float g_K[B_ * S_ * H_];
__device__ float g_V[B_ * S_ * HD];
__device__ float g_AO[B_ * S_ * HD];
__device__ float g_P[(size_t)NH * S_ * S_];

// ---------------------------------------------------------------------------
// C[M,N] = alpha * A(MxK, lda) @ B(NxK, ldb)^T + bias   (both K-contiguous)
// Tiles: 64x64x16, 16x16 threads, 4x4 per thread. Dims assumed divisible.
// Batched via blockIdx.z with element strides sA/sB/sC.
// ---------------------------------------------------------------------------
__global__ void gemm_nt(const float* __restrict__ A, const float* __restrict__ Bm,
                        const float* __restrict__ bias, float* __restrict__ C,
                        int K, int lda, int ldb, int ldc,
                        long sA, long sB, long sC, float alpha)
{
    __shared__ float As[16][65];
    __shared__ float Bs[16][65];
    const int tx = threadIdx.x, ty = threadIdx.y;
    const int tid = ty * 16 + tx;
    const int m0 = blockIdx.y * 64, n0 = blockIdx.x * 64;
    const int rr = tid >> 2;            // 0..63
    const int kq = (tid & 3) << 2;      // 0,4,8,12

    const float* Ap = A + (size_t)blockIdx.z * sA + (size_t)(m0 + rr) * lda + kq;
    const float* Bp = Bm + (size_t)blockIdx.z * sB + (size_t)(n0 + rr) * ldb + kq;
    C += (size_t)blockIdx.z * sC;

    float acc[4][4] = {};
    for (int k0 = 0; k0 < K; k0 += 16) {
#pragma unroll
        for (int j = 0; j < 4; ++j) As[kq + j][rr] = Ap[j];
#pragma unroll
        for (int j = 0; j < 4; ++j) Bs[kq + j][rr] = Bp[j];
        __syncthreads();
#pragma unroll
        for (int kk = 0; kk < 16; ++kk) {
            float a[4], b[4];
#pragma unroll
            for (int i = 0; i < 4; ++i) a[i] = As[kk][ty * 4 + i];
#pragma unroll
            for (int j = 0; j < 4; ++j) b[j] = Bs[kk][tx * 4 + j];
#pragma unroll
            for (int i = 0; i < 4; ++i)
#pragma unroll
                for (int j = 0; j < 4; ++j) acc[i][j] += a[i] * b[j];
        }
        __syncthreads();
        Ap += 16; Bp += 16;
    }
#pragma unroll
    for (int i = 0; i < 4; ++i) {
        const int m = m0 + ty * 4 + i;
#pragma unroll
        for (int j = 0; j < 4; ++j) {
            const int n = n0 + tx * 4 + j;
            float v = acc[i][j] * alpha;
            if (bias) v += bias[n];
            C[(size_t)m * ldc + n] = v;
        }
    }
}

// ---------------------------------------------------------------------------
// C[M,N] = A(MxK, lda) @ B(KxN, ldb)   (B not transposed)
// ---------------------------------------------------------------------------
__global__ void gemm_nn(const float* __restrict__ A, const float* __restrict__ Bm,
                        float* __restrict__ C,
                        int K, int lda, int ldb, int ldc)
{
    __shared__ float As[16][65];
    __shared__ float Bs[16][65];
    const int tx = threadIdx.x, ty = threadIdx.y;
    const int tid = ty * 16 + tx;
    const int m0 = blockIdx.y * 64, n0 = blockIdx.x * 64;
    const int rr = tid >> 2;            // A tile: 0..63
    const int kq = (tid & 3) << 2;
    const int kr = tid >> 4;            // B tile row: 0..15
    const int nq = (tid & 15) << 2;     // B tile col quad

    const float* Ap = A + (size_t)(m0 + rr) * lda + kq;
    const float* Bp = Bm + (size_t)kr * ldb + n0 + nq;

    float acc[4][4] = {};
    for (int k0 = 0; k0 < K; k0 += 16) {
#pragma unroll
        for (int j = 0; j < 4; ++j) As[kq + j][rr] = Ap[j];
#pragma unroll
        for (int j = 0; j < 4; ++j) Bs[kr][nq + j] = Bp[j];
        __syncthreads();
#pragma unroll
        for (int kk = 0; kk < 16; ++kk) {
            float a[4], b[4];
#pragma unroll
            for (int i = 0; i < 4; ++i) a[i] = As[kk][ty * 4 + i];
#pragma unroll
            for (int j = 0; j < 4; ++j) b[j] = Bs[kk][tx * 4 + j];
#pragma unroll
            for (int i = 0; i < 4; ++i)
#pragma unroll
                for (int j = 0; j < 4; ++j) acc[i][j] += a[i] * b[j];
        }
        __syncthreads();
        Ap += 16; Bp += 16 * ldb;
    }
#pragma unroll
    for (int i = 0; i < 4; ++i) {
        const int m = m0 + ty * 4 + i;
#pragma unroll
        for (int j = 0; j < 4; ++j)
            C[(size_t)m * ldc + (n0 + tx * 4 + j)] = acc[i][j];
    }
}

// One block (256 threads) per row of length S_ = 2048 (8 values per thread).
__global__ void softmax_rows(float* __restrict__ P)
{
    float* row = P + (size_t)blockIdx.x * S_;
    const int t = threadIdx.x;
    __shared__ float red[8];

    float v[8];
    float m = -1e30f;
#pragma unroll
    for (int i = 0; i < 8; ++i) { v[i] = row[t + i * 256]; m = fmaxf(m, v[i]); }
#pragma unroll
    for (int o = 16; o > 0; o >>= 1) m = fmaxf(m, __shfl_xor_sync(0xffffffffu, m, o));
    if ((t & 31) == 0) red[t >> 5] = m;
    __syncthreads();
    float bm = red[0];
#pragma unroll
    for (int w = 1; w < 8; ++w) bm = fmaxf(bm, red[w]);

    float s = 0.f;
#pragma unroll
    for (int i = 0; i < 8; ++i) { v[i] = __expf(v[i] - bm); s += v[i]; }
#pragma unroll
    for (int o = 16; o > 0; o >>= 1) s += __shfl_xor_sync(0xffffffffu, s, o);
    __syncthreads();
    if ((t & 31) == 0) red[t >> 5] = s;
    __syncthreads();
    float bs = red[0];
#pragma unroll
    for (int w = 1; w < 8; ++w) bs += red[w];
    const float inv = 1.0f / bs;
#pragma unroll
    for (int i = 0; i < 8; ++i) row[t + i * 256] = v[i] * inv;
}

// avg[i] = mean over 16 heads of P[h][i], i in [0, S_*S_)
__global__ void head_avg(const float* __restrict__ P, float* __restrict__ outp)
{
    const size_t i = (size_t)blockIdx.x * blockDim.x + threadIdx.x;
    float s = 0.f;
#pragma unroll
    for (int h = 0; h < NH; ++h) s += P[(size_t)h * S_ * S_ + i];
    outp[i] = s * (1.0f / NH);
}

extern "C" void kernel_launch(void* const* d_in, const int* in_sizes, int n_in,
                              void* d_out, int out_size)
{
    const float* query  = (const float*)d_in[0];
    const float* key_in = (const float*)d_in[1];
    const float* value  = (const float*)d_in[2];
    const float* Wq = (const float*)d_in[3];
    const float* bq = (const float*)d_in[4];
    const float* Wk = (const float*)d_in[5];
    const float* bk = (const float*)d_in[6];
    const float* Wv = (const float*)d_in[7];
    const float* bv = (const float*)d_in[8];
    const float* Wo = (const float*)d_in[9];
    const float* bo = (const float*)d_in[10];

    float* out = (float*)d_out;                       // [B,S,H]
    float* avg_out = out + (size_t)B_ * S_ * H_;      // [B,S,S]

    float *gQ, *gK, *gV, *gAO, *gP;
    cudaGetSymbolAddress((void**)&gQ, g_Q);
    cudaGetSymbolAddress((void**)&gK, g_K);
    cudaGetSymbolAddress((void**)&gV, g_V);
    cudaGetSymbolAddress((void**)&gAO, g_AO);
    cudaGetSymbolAddress((void**)&gP, g_P);

    const dim3 thr(16, 16);
    const int M = B_ * S_;   // 8192 rows

    // Projections: X @ W^T + b
    gemm_nt<<<dim3(H_ / 64, M / 64, 1), thr>>>(query,  Wq, bq, gQ, H_, H_, H_, H_, 0, 0, 0, 1.f);
    gemm_nt<<<dim3(H_ / 64, M / 64, 1), thr>>>(key_in, Wk, bk, gK, H_, H_, H_, H_, 0, 0, 0, 1.f);
    gemm_nt<<<dim3(HD / 64, M / 64, 1), thr>>>(value,  Wv, bv, gV, H_, H_, H_, HD, 0, 0, 0, 1.f);

    const float scale = 0.125f;  // HD^-0.5
    for (int b = 0; b < B_; ++b) {
        const float* Qb = gQ + (size_t)b * S_ * H_;
        const float* Kb = gK + (size_t)b * S_ * H_;
        float* avg_b = avg_out + (size_t)b * S_ * S_;

        // Per-head scores: P[h] = scale * Q_h @ K_h^T  (batched over z = head)
        gemm_nt<<<dim3(S_ / 64, S_ / 64, NH), thr>>>(Qb, Kb, nullptr, gP,
                                                     HD, H_, H_, S_,
                                                     HD, HD, (long)S_ * S_, scale);
        softmax_rows<<<NH * S_, 256>>>(gP);
        head_avg<<<(S_ * S_) / 256, 256>>>(gP, avg_b);
        // attn_out[b] = avg_attn[b] @ V[b]   (NN, K = S_)
        gemm_nn<<<dim3(HD / 64, S_ / 64, 1), thr>>>(avg_b, gV + (size_t)b * S_ * HD,
                                                    gAO + (size_t)b * S_ * HD,
                                                    S_, S_, HD, HD);
    }

    // output = attn_out @ Wo^T + bo
    gemm_nt<<<dim3(H_ / 64, M / 64, 1), thr>>>(gAO, Wo, bo, out, HD, HD, HD, H_, 0, 0, 0, 1.f);
}

// round 2
// speedup vs baseline: 2.0153x; 2.0153x over previous
#include <cuda_runtime.h>

#define B_ 4
#define S_ 2048
#define H_ 1024
#define NH 16
#define HD 64

// Scratch (no cudaMalloc allowed). g_P holds ALL batches of per-head scores (1.07GB).
__device__ float g_Q[B_ * S_ * H_];
__device__ float g_K[B_ * S_ * H_];
__device__ float g_V[B_ * S_ * HD];
__device__ float g_AO[B_ * S_ * HD];
__device__ float g_P[(size_t)B_ * NH * S_ * S_];

typedef unsigned long long ull;

__device__ __forceinline__ ull pack2(float lo, float hi) {
    ull r; asm("mov.b64 %0, {%1, %2};" : "=l"(r) : "f"(lo), "f"(hi)); return r;
}
__device__ __forceinline__ void unpack2(ull v, float& lo, float& hi) {
    asm("mov.b64 {%0, %1}, %2;" : "=f"(lo), "=f"(hi) : "l"(v));
}
#define FMA2(d, a, b) asm("fma.rn.f32x2 %0, %1, %2, %0;" : "+l"(d) : "l"(a), "l"(b))

// ---------------------------------------------------------------------------
// C = alpha * A @ B^T (+bias).  A: MxK (lda), B: NxK (ldb), both K-contiguous.
// 128x128 tile, Ktile=16, 256 threads, 8x8 per thread using packed f32x2 FMA.
// z-offsets: off = (z>>4)*s?b + (z&15)*s?h   (QK: z = b*16+h; others: z small)
// ---------------------------------------------------------------------------
__global__ void __launch_bounds__(256, 2)
gemm_nt_big(const float* __restrict__ A, const float* __restrict__ Bm,
            const float* __restrict__ bias, float* __restrict__ C,
            int K, int lda, int ldb, int ldc,
            long sAb, long sAh, long sBb, long sBh, long sCb, long sCh,
            float alpha)
{
    __shared__ float As[16][128];
    __shared__ float Bs[16][128];
    const int tid = threadIdx.x;
    const int m0 = blockIdx.y * 128, n0 = blockIdx.x * 128;
    const int zb = blockIdx.z >> 4, zh = blockIdx.z & 15;
    A  += (size_t)zb * sAb + (size_t)zh * sAh;
    Bm += (size_t)zb * sBb + (size_t)zh * sBh;
    C  += (size_t)zb * sCb + (size_t)zh * sCh;

    const int lr = tid >> 2;             // 0..63
    const int lc = (tid & 3) << 2;       // 0,4,8,12 (k offset)
    const float* Ap0 = A + (size_t)(m0 + lr) * lda + lc;
    const float* Ap1 = A + (size_t)(m0 + 64 + lr) * lda + lc;
    const float* Bp0 = Bm + (size_t)(n0 + lr) * ldb + lc;
    const float* Bp1 = Bm + (size_t)(n0 + 64 + lr) * ldb + lc;

    const int tx = tid & 15, ty = tid >> 4;

    ull acc[4][8] = {};   // acc[i][j] = {row 2i, row 2i+1} x col j (within 8x8)

    float4 ra0 = *(const float4*)Ap0;
    float4 ra1 = *(const float4*)Ap1;
    float4 rb0 = *(const float4*)Bp0;
    float4 rb1 = *(const float4*)Bp1;

    for (int k0 = 0; k0 < K; k0 += 16) {
        As[lc + 0][lr] = ra0.x; As[lc + 1][lr] = ra0.y;
        As[lc + 2][lr] = ra0.z; As[lc + 3][lr] = ra0.w;
        As[lc + 0][64 + lr] = ra1.x; As[lc + 1][64 + lr] = ra1.y;
        As[lc + 2][64 + lr] = ra1.z; As[lc + 3][64 + lr] = ra1.w;
        Bs[lc + 0][lr] = rb0.x; Bs[lc + 1][lr] = rb0.y;
        Bs[lc + 2][lr] = rb0.z; Bs[lc + 3][lr] = rb0.w;
        Bs[lc + 0][64 + lr] = rb1.x; Bs[lc + 1][64 + lr] = rb1.y;
        Bs[lc + 2][64 + lr] = rb1.z; Bs[lc + 3][64 + lr] = rb1.w;
        __syncthreads();

        if (k0 + 16 < K) {
            Ap0 += 16; Ap1 += 16; Bp0 += 16; Bp1 += 16;
            ra0 = *(const float4*)Ap0;
            ra1 = *(const float4*)Ap1;
            rb0 = *(const float4*)Bp0;
            rb1 = *(const float4*)Bp1;
        }

#pragma unroll
        for (int kk = 0; kk < 16; ++kk) {
            float4 a0 = *(const float4*)&As[kk][ty * 8];
            float4 a1 = *(const float4*)&As[kk][ty * 8 + 4];
            float4 b0 = *(const float4*)&Bs[kk][tx * 8];
            float4 b1 = *(const float4*)&Bs[kk][tx * 8 + 4];
            ull a2[4], b2[8];
            a2[0] = pack2(a0.x, a0.y); a2[1] = pack2(a0.z, a0.w);
            a2[2] = pack2(a1.x, a1.y); a2[3] = pack2(a1.z, a1.w);
            b2[0] = pack2(b0.x, b0.x); b2[1] = pack2(b0.y, b0.y);
            b2[2] = pack2(b0.z, b0.z); b2[3] = pack2(b0.w, b0.w);
            b2[4] = pack2(b1.x, b1.x); b2[5] = pack2(b1.y, b1.y);
            b2[6] = pack2(b1.z, b1.z); b2[7] = pack2(b1.w, b1.w);
#pragma unroll
            for (int i = 0; i < 4; ++i)
#pragma unroll
                for (int j = 0; j < 8; ++j) FMA2(acc[i][j], a2[i], b2[j]);
        }
        __syncthreads();
    }

    float bsv[8];
#pragma unroll
    for (int j = 0; j < 8; ++j) bsv[j] = bias ? bias[n0 + tx * 8 + j] : 0.0f;

#pragma unroll
    for (int i = 0; i < 4; ++i) {
        float lo[8], hi[8];
#pragma unroll
        for (int j = 0; j < 8; ++j) {
            unpack2(acc[i][j], lo[j], hi[j]);
            lo[j] = lo[j] * alpha + bsv[j];
            hi[j] = hi[j] * alpha + bsv[j];
        }
        float* C0 = C + (size_t)(m0 + ty * 8 + 2 * i) * ldc + n0 + tx * 8;
        float* C1 = C0 + ldc;
        *(float4*)C0       = make_float4(lo[0], lo[1], lo[2], lo[3]);
        *(float4*)(C0 + 4) = make_float4(lo[4], lo[5], lo[6], lo[7]);
        *(float4*)C1       = make_float4(hi[0], hi[1], hi[2], hi[3]);
        *(float4*)(C1 + 4) = make_float4(hi[4], hi[5], hi[6], hi[7]);
    }
}

// ---------------------------------------------------------------------------
// Small-N kernels (N=64): 64x64 tile, 4x4/thread. NT for V-proj, NN for PV.
// ---------------------------------------------------------------------------
__global__ void gemm_nt(const float* __restrict__ A, const float* __restrict__ Bm,
                        const float* __restrict__ bias, float* __restrict__ C,
                        int K, int lda, int ldb, int ldc)
{
    __shared__ float As[16][65];
    __shared__ float Bs[16][65];
    const int tx = threadIdx.x, ty = threadIdx.y;
    const int tid = ty * 16 + tx;
    const int m0 = blockIdx.y * 64, n0 = blockIdx.x * 64;
    const int rr = tid >> 2;
    const int kq = (tid & 3) << 2;

    const float* Ap = A + (size_t)(m0 + rr) * lda + kq;
    const float* Bp = Bm + (size_t)(n0 + rr) * ldb + kq;

    float acc[4][4] = {};
    for (int k0 = 0; k0 < K; k0 += 16) {
#pragma unroll
        for (int j = 0; j < 4; ++j) As[kq + j][rr] = Ap[j];
#pragma unroll
        for (int j = 0; j < 4; ++j) Bs[kq + j][rr] = Bp[j];
        __syncthreads();
#pragma unroll
        for (int kk = 0; kk < 16; ++kk) {
            float a[4], b[4];
#pragma unroll
            for (int i = 0; i < 4; ++i) a[i] = As[kk][ty * 4 + i];
#pragma unroll
            for (int j = 0; j < 4; ++j) b[j] = Bs[kk][tx * 4 + j];
#pragma unroll
            for (int i = 0; i < 4; ++i)
#pragma unroll
                for (int j = 0; j < 4; ++j) acc[i][j] += a[i] * b[j];
        }
        __syncthreads();
        Ap += 16; Bp += 16;
    }
#pragma unroll
    for (int i = 0; i < 4; ++i)
#pragma unroll
        for (int j = 0; j < 4; ++j) {
            const int n = n0 + tx * 4 + j;
            C[(size_t)(m0 + ty * 4 + i) * ldc + n] = acc[i][j] + (bias ? bias[n] : 0.f);
        }
}

__global__ void gemm_nn(const float* __restrict__ A, const float* __restrict__ Bm,
                        float* __restrict__ C,
                        int K, int lda, int ldb, int ldc, long sA, long sB, long sC)
{
    __shared__ float As[16][65];
    __shared__ float Bs[16][65];
    const int tx = threadIdx.x, ty = threadIdx.y;
    const int tid = ty * 16 + tx;
    const int m0 = blockIdx.y * 64, n0 = blockIdx.x * 64;
    const int rr = tid >> 2;
    const int kq = (tid & 3) << 2;
    const int kr = tid >> 4;
    const int nq = (tid & 15) << 2;

    const float* Ap = A + (size_t)blockIdx.z * sA + (size_t)(m0 + rr) * lda + kq;
    const float* Bp = Bm + (size_t)blockIdx.z * sB + (size_t)kr * ldb + n0 + nq;
    C += (size_t)blockIdx.z * sC;

    float acc[4][4] = {};
    for (int k0 = 0; k0 < K; k0 += 16) {
#pragma unroll
        for (int j = 0; j < 4; ++j) As[kq + j][rr] = Ap[j];
#pragma unroll
        for (int j = 0; j < 4; ++j) Bs[kr][nq + j] = Bp[j];
        __syncthreads();
#pragma unroll
        for (int kk = 0; kk < 16; ++kk) {
            float a[4], b[4];
#pragma unroll
            for (int i = 0; i < 4; ++i) a[i] = As[kk][ty * 4 + i];
#pragma unroll
            for (int j = 0; j < 4; ++j) b[j] = Bs[kk][tx * 4 + j];
#pragma unroll
            for (int i = 0; i < 4; ++i)
#pragma unroll
                for (int j = 0; j < 4; ++j) acc[i][j] += a[i] * b[j];
        }
        __syncthreads();
        Ap += 16; Bp += 16 * ldb;
    }
#pragma unroll
    for (int i = 0; i < 4; ++i)
#pragma unroll
        for (int j = 0; j < 4; ++j)
            C[(size_t)(m0 + ty * 4 + i) * ldc + (n0 + tx * 4 + j)] = acc[i][j];
}

// ---------------------------------------------------------------------------
// Fused per-head softmax + head average. One block per (b,q); the per-head
// softmaxed rows are consumed in registers and NEVER written back.
// ---------------------------------------------------------------------------
__global__ void softmax_avg(const float* __restrict__ P, float* __restrict__ avg)
{
    const int t = threadIdx.x;
    const int bq = blockIdx.x;            // b*S + q
    const int b = bq >> 11;               // S_ = 2048
    const int q = bq & (S_ - 1);
    const float* base = P + (size_t)b * NH * S_ * S_ + (size_t)q * S_;
    __shared__ float red[8];

    float acc[8] = {};
    for (int h = 0; h < NH; ++h) {
        const float* row = base + (size_t)h * S_ * S_;
        float v[8];
        float m = -1e30f;
#pragma unroll
        for (int i = 0; i < 8; ++i) { v[i] = row[t + 256 * i]; m = fmaxf(m, v[i]); }
#pragma unroll
        for (int o = 16; o > 0; o >>= 1) m = fmaxf(m, __shfl_xor_sync(0xffffffffu, m, o));
        __syncthreads();
        if ((t & 31) == 0) red[t >> 5] = m;
        __syncthreads();
        m = red[0];
#pragma unroll
        for (int w = 1; w < 8; ++w) m = fmaxf(m, red[w]);

        float s = 0.f;
#pragma unroll
        for (int i = 0; i < 8; ++i) { v[i] = __expf(v[i] - m); s += v[i]; }
#pragma unroll
        for (int o = 16; o > 0; o >>= 1) s += __shfl_xor_sync(0xffffffffu, s, o);
        __syncthreads();
        if ((t & 31) == 0) red[t >> 5] = s;
        __syncthreads();
        s = red[0];
#pragma unroll
        for (int w = 1; w < 8; ++w) s += red[w];
        const float inv = 1.0f / s;
#pragma unroll
        for (int i = 0; i < 8; ++i) acc[i] += v[i] * inv;
    }
    float* o = avg + (size_t)bq * S_;
#pragma unroll
    for (int i = 0; i < 8; ++i) o[t + 256 * i] = acc[i] * (1.0f / NH);
}

extern "C" void kernel_launch(void* const* d_in, const int* in_sizes, int n_in,
                              void* d_out, int out_size)
{
    const float* query  = (const float*)d_in[0];
    const float* key_in = (const float*)d_in[1];
    const float* value  = (const float*)d_in[2];
    const float* Wq = (const float*)d_in[3];
    const float* bq = (const float*)d_in[4];
    const float* Wk = (const float*)d_in[5];
    const float* bk = (const float*)d_in[6];
    const float* Wv = (const float*)d_in[7];
    const float* bv = (const float*)d_in[8];
    const float* Wo = (const float*)d_in[9];
    const float* bo = (const float*)d_in[10];

    float* out = (float*)d_out;                       // [B,S,H]
    float* avg_out = out + (size_t)B_ * S_ * H_;      // [B,S,S]

    float *gQ, *gK, *gV, *gAO, *gP;
    cudaGetSymbolAddress((void**)&gQ, g_Q);
    cudaGetSymbolAddress((void**)&gK, g_K);
    cudaGetSymbolAddress((void**)&gV, g_V);
    cudaGetSymbolAddress((void**)&gAO, g_AO);
    cudaGetSymbolAddress((void**)&gP, g_P);

    const int M = B_ * S_;   // 8192

    // Q, K projections: X @ W^T + b   (128x128 f32x2 kernel)
    gemm_nt_big<<<dim3(H_ / 128, M / 128, 1), 256>>>(query,  Wq, bq, gQ,
        H_, H_, H_, H_, 0, 0, 0, 0, 0, 0, 1.f);
    gemm_nt_big<<<dim3(H_ / 128, M / 128, 1), 256>>>(key_in, Wk, bk, gK,
        H_, H_, H_, H_, 0, 0, 0, 0, 0, 0, 1.f);
    // V projection (N=64)
    gemm_nt<<<dim3(1, M / 64, 1), dim3(16, 16)>>>(value, Wv, bv, gV, H_, H_, H_, HD);

    // Per-head scores for ALL batches/heads: z = b*16 + h
    gemm_nt_big<<<dim3(S_ / 128, S_ / 128, B_ * NH), 256>>>(gQ, gK, nullptr, gP,
        HD, H_, H_, S_,
        (long)S_ * H_, HD,                 // A: batch stride, head stride
        (long)S_ * H_, HD,                 // B: same
        (long)NH * S_ * S_, (long)S_ * S_, // C: per-batch, per-head
        0.125f);

    // Fused softmax over each head-row + average over heads -> avg_out
    softmax_avg<<<B_ * S_, 256>>>(gP, avg_out);

    // attn_out = avg_attn @ V   (batched over B, N=64, K=S)
    gemm_nn<<<dim3(1, S_ / 64, B_), dim3(16, 16)>>>(avg_out, gV, gAO,
        S_, S_, HD, HD, (long)S_ * S_, (long)S_ * HD, (long)S_ * HD);

    // output = attn_out @ Wo^T + bo
    gemm_nt_big<<<dim3(H_ / 128, M / 128, 1), 256>>>(gAO, Wo, bo, out,
        HD, HD, HD, H_, 0, 0, 0, 0, 0, 0, 1.f);
}

// round 4
// speedup vs baseline: 3.4569x; 1.7154x over previous
#include <cuda_runtime.h>
#include <cuda_bf16.h>
#include <cstdint>

#define B_ 4
#define S_ 2048
#define H_ 1024
#define NH 16
#define HD 64

// fp32 scratch
__device__ float g_Q[B_ * S_ * H_];
__device__ float g_K[B_ * S_ * H_];
__device__ float g_V[B_ * S_ * HD];
__device__ float g_AO[B_ * S_ * HD];
__device__ float g_P[(size_t)B_ * NH * S_ * S_];
// bf16 hi/lo split scratch
__device__ __nv_bfloat16 g_hA[B_ * S_ * H_], g_lA[B_ * S_ * H_];
__device__ __nv_bfloat16 g_hW[H_ * H_],      g_lW[H_ * H_];
__device__ __nv_bfloat16 g_hQ[B_ * S_ * H_], g_lQ[B_ * S_ * H_];
__device__ __nv_bfloat16 g_hK[B_ * S_ * H_], g_lK[B_ * S_ * H_];

// ---------------------------------------------------------------------------
// Base-ISA helpers (no 'a'-suffix-gated instructions!)
// ---------------------------------------------------------------------------
__device__ __forceinline__ uint32_t smem_u32(const void* p) {
    uint32_t a;
    asm("{ .reg .u64 t; cvta.to.shared.u64 t, %1; cvt.u32.u64 %0, t; }" : "=r"(a) : "l"(p));
    return a;
}
#define SWZ128(x) ((x) ^ (((x) >> 3) & 0x70))

__device__ __forceinline__ void ldsm4(uint32_t& r0, uint32_t& r1, uint32_t& r2, uint32_t& r3,
                                      uint32_t addr) {
    asm volatile("ldmatrix.sync.aligned.m8n8.x4.shared.b16 {%0,%1,%2,%3}, [%4];"
                 : "=r"(r0), "=r"(r1), "=r"(r2), "=r"(r3) : "r"(addr));
}
__device__ __forceinline__ void mma16816(float* c, const uint32_t* a, const uint32_t* b) {
    asm volatile(
        "mma.sync.aligned.m16n8k16.row.col.f32.bf16.bf16.f32 "
        "{%0,%1,%2,%3}, {%4,%5,%6,%7}, {%8,%9}, {%0,%1,%2,%3};"
        : "+f"(c[0]), "+f"(c[1]), "+f"(c[2]), "+f"(c[3])
        : "r"(a[0]), "r"(a[1]), "r"(a[2]), "r"(a[3]), "r"(b[0]), "r"(b[1]));
}
#define CP16(s, g) asm volatile("cp.async.cg.shared.global [%0], [%1], 16;" :: "r"(s), "l"(g))
#define CP_COMMIT() asm volatile("cp.async.commit_group;" ::: "memory")
#define CP_WAIT(n)  asm volatile("cp.async.wait_group %0;" :: "n"(n) : "memory")

// ---------------------------------------------------------------------------
// fp32 -> bf16 hi/lo split
// ---------------------------------------------------------------------------
__global__ void split_hl(const float* __restrict__ x, __nv_bfloat16* __restrict__ hi,
                         __nv_bfloat16* __restrict__ lo, int n)
{
    int i = blockIdx.x * blockDim.x + threadIdx.x;
    if (i < n) {
        float v = x[i];
        __nv_bfloat16 h = __float2bfloat16(v);
        hi[i] = h;
        lo[i] = __float2bfloat16(v - __bfloat162float(h));
    }
}

// ---------------------------------------------------------------------------
// HMMA bf16x3 GEMM: C = alpha * A @ B^T + bias
// A: MxK fp32-split (hA/lA, lda); B: NxK (hB/lB, ldb); K-contiguous.
// 128x128 block tile, K-chunk 64, double-buffered cp.async smem pipeline.
// 8 warps as 4(m) x 2(n); warp tile 32x64 = 2x8 m16n8k16 atoms.
// 3-term split: D += Ah*Bh + Ah*Bl + Al*Bh   (fp32 accum)
// z: zb = z>>4, zh = z&15 with element strides.
// ---------------------------------------------------------------------------
#define TILE_B 16384                   // 128 rows x 64 bf16 = 16KB
#define BUF_B  (4 * TILE_B)            // hA,lA,hB,lB
#define SM_TOTAL (2 * BUF_B)           // 131072 bytes

__device__ __forceinline__ void cp_tile(const __nv_bfloat16* __restrict__ g, int ld,
                                        uint32_t sdst, int tid, int ko)
{
#pragma unroll
    for (int it = 0; it < 4; ++it) {       // 256 thr * 4 = 1024 x 16B chunks
        int i = tid + it * 256;
        int row = i >> 3, c = i & 7;
        const void* gp = g + (size_t)row * ld + ko + c * 8;
        uint32_t sp = sdst + SWZ128((uint32_t)(row * 128 + c * 16));
        CP16(sp, gp);
    }
}

__global__ void __launch_bounds__(256, 1)
hmma_nt(const __nv_bfloat16* __restrict__ hA, const __nv_bfloat16* __restrict__ lA,
        const __nv_bfloat16* __restrict__ hB, const __nv_bfloat16* __restrict__ lB,
        const float* __restrict__ bias, float* __restrict__ C,
        int K, int lda, int ldb, int ldc,
        long sAb, long sAh, long sBb, long sBh, long sCb, long sCh,
        float alpha)
{
    extern __shared__ char smem[];
    const uint32_t sb = smem_u32(smem);
    const int tid = threadIdx.x, lane = tid & 31, w = tid >> 5;
    const int wm = w >> 1, wn = w & 1;
    const int m0 = blockIdx.y * 128, n0 = blockIdx.x * 128;
    const int zb = blockIdx.z >> 4, zh = blockIdx.z & 15;

    const size_t aoff = (size_t)zb * sAb + (size_t)zh * sAh + (size_t)m0 * lda;
    const size_t boff = (size_t)zb * sBb + (size_t)zh * sBh + (size_t)n0 * ldb;
    hA += aoff; lA += aoff;
    hB += boff; lB += boff;
    C += (size_t)zb * sCb + (size_t)zh * sCh;

    const int nch = K >> 6;

    // prologue: chunk 0 -> buffer 0
    cp_tile(hA, lda, sb + 0 * TILE_B, tid, 0);
    cp_tile(lA, lda, sb + 1 * TILE_B, tid, 0);
    cp_tile(hB, ldb, sb + 2 * TILE_B, tid, 0);
    cp_tile(lB, ldb, sb + 3 * TILE_B, tid, 0);
    CP_COMMIT();

    float acc[2][8][4] = {};

    // per-thread ldmatrix address components (tile-local)
    const int a_row = wm * 32 + (lane & 15);                 // + ma*16
    const uint32_t a_kext = (lane & 16) ? 16u : 0u;          // k-half select
    const int b_row = wn * 64 + ((lane & 16) ? 8 : 0) + (lane & 7);  // + bg*16
    const uint32_t b_kext = (lane & 8) ? 16u : 0u;

    for (int c = 0; c < nch; ++c) {
        const int b = c & 1;
        if (c + 1 < nch) {
            const uint32_t nb = sb + (1 - b) * BUF_B;
            const int ko = (c + 1) << 6;
            cp_tile(hA, lda, nb + 0 * TILE_B, tid, ko);
            cp_tile(lA, lda, nb + 1 * TILE_B, tid, ko);
            cp_tile(hB, ldb, nb + 2 * TILE_B, tid, ko);
            cp_tile(lB, ldb, nb + 3 * TILE_B, tid, ko);
            CP_COMMIT();
            CP_WAIT(1);
        } else {
            CP_WAIT(0);
        }
        __syncthreads();

        const uint32_t base = sb + b * BUF_B;
        const uint32_t aH = base, aL = base + TILE_B;
        const uint32_t bH = base + 2 * TILE_B, bL = base + 3 * TILE_B;

#pragma unroll
        for (int ks = 0; ks < 4; ++ks) {
            uint32_t ah[2][4], al[2][4];
#pragma unroll
            for (int ma = 0; ma < 2; ++ma) {
                const uint32_t off =
                    SWZ128((uint32_t)((a_row + ma * 16) * 128) + (uint32_t)(ks * 32) + a_kext);
                ldsm4(ah[ma][0], ah[ma][1], ah[ma][2], ah[ma][3], aH + off);
                ldsm4(al[ma][0], al[ma][1], al[ma][2], al[ma][3], aL + off);
            }
#pragma unroll
            for (int bg = 0; bg < 4; ++bg) {
                const uint32_t off =
                    SWZ128((uint32_t)((b_row + bg * 16) * 128) + (uint32_t)(ks * 32) + b_kext);
                uint32_t bh[4], bl[4];
                ldsm4(bh[0], bh[1], bh[2], bh[3], bH + off);
                ldsm4(bl[0], bl[1], bl[2], bl[3], bL + off);
#pragma unroll
                for (int na = 0; na < 2; ++na) {
                    const int n = bg * 2 + na;
#pragma unroll
                    for (int ma = 0; ma < 2; ++ma) {
                        mma16816(acc[ma][n], ah[ma], &bh[na * 2]);
                        mma16816(acc[ma][n], ah[ma], &bl[na * 2]);
                        mma16816(acc[ma][n], al[ma], &bh[na * 2]);
                    }
                }
            }
        }
        __syncthreads();
    }

    // epilogue: fragment layout c0,c1 = (row g, cols t2, t2+1); c2,c3 = row g+8
    const int gq = lane >> 2, tig = lane & 3;
#pragma unroll
    for (int ma = 0; ma < 2; ++ma) {
        const int r0 = m0 + wm * 32 + ma * 16 + gq;
#pragma unroll
        for (int n = 0; n < 8; ++n) {
            const int col = n0 + wn * 64 + n * 8 + tig * 2;
            const float b0 = bias ? bias[col] : 0.f;
            const float b1 = bias ? bias[col + 1] : 0.f;
            float2 v0 = make_float2(acc[ma][n][0] * alpha + b0, acc[ma][n][1] * alpha + b1);
            float2 v1 = make_float2(acc[ma][n][2] * alpha + b0, acc[ma][n][3] * alpha + b1);
            *(float2*)(C + (size_t)r0 * ldc + col) = v0;
            *(float2*)(C + (size_t)(r0 + 8) * ldc + col) = v1;
        }
    }
}

// ---------------------------------------------------------------------------
// SIMT small-N kernels (V proj NT, PV NN) + fused softmax/head-avg
// ---------------------------------------------------------------------------
__global__ void gemm_nt(const float* __restrict__ A, const float* __restrict__ Bm,
                        const float* __restrict__ bias, float* __restrict__ C,
                        int K, int lda, int ldb, int ldc)
{
    __shared__ float As[16][65];
    __shared__ float Bs[16][65];
    const int tx = threadIdx.x, ty = threadIdx.y;
    const int tid = ty * 16 + tx;
    const int m0 = blockIdx.y * 64, n0 = blockIdx.x * 64;
    const int rr = tid >> 2;
    const int kq = (tid & 3) << 2;

    const float* Ap = A + (size_t)(m0 + rr) * lda + kq;
    const float* Bp = Bm + (size_t)(n0 + rr) * ldb + kq;

    float acc[4][4] = {};
    for (int k0 = 0; k0 < K; k0 += 16) {
#pragma unroll
        for (int j = 0; j < 4; ++j) As[kq + j][rr] = Ap[j];
#pragma unroll
        for (int j = 0; j < 4; ++j) Bs[kq + j][rr] = Bp[j];
        __syncthreads();
#pragma unroll
        for (int kk = 0; kk < 16; ++kk) {
            float a[4], b[4];
#pragma unroll
            for (int i = 0; i < 4; ++i) a[i] = As[kk][ty * 4 + i];
#pragma unroll
            for (int j = 0; j < 4; ++j) b[j] = Bs[kk][tx * 4 + j];
#pragma unroll
            for (int i = 0; i < 4; ++i)
#pragma unroll
                for (int j = 0; j < 4; ++j) acc[i][j] += a[i] * b[j];
        }
        __syncthreads();
        Ap += 16; Bp += 16;
    }
#pragma unroll
    for (int i = 0; i < 4; ++i)
#pragma unroll
        for (int j = 0; j < 4; ++j) {
            const int n = n0 + tx * 4 + j;
            C[(size_t)(m0 + ty * 4 + i) * ldc + n] = acc[i][j] + (bias ? bias[n] : 0.f);
        }
}

__global__ void gemm_nn(const float* __restrict__ A, const float* __restrict__ Bm,
                        float* __restrict__ C,
                        int K, int lda, int ldb, int ldc, long sA, long sB, long sC)
{
    __shared__ float As[16][65];
    __shared__ float Bs[16][65];
    const int tx = threadIdx.x, ty = threadIdx.y;
    const int tid = ty * 16 + tx;
    const int m0 = blockIdx.y * 64, n0 = blockIdx.x * 64;
    const int rr = tid >> 2;
    const int kq = (tid & 3) << 2;
    const int kr = tid >> 4;
    const int nq = (tid & 15) << 2;

    const float* Ap = A + (size_t)blockIdx.z * sA + (size_t)(m0 + rr) * lda + kq;
    const float* Bp = Bm + (size_t)blockIdx.z * sB + (size_t)kr * ldb + n0 + nq;
    C += (size_t)blockIdx.z * sC;

    float acc[4][4] = {};
    for (int k0 = 0; k0 < K; k0 += 16) {
#pragma unroll
        for (int j = 0; j < 4; ++j) As[kq + j][rr] = Ap[j];
#pragma unroll
        for (int j = 0; j < 4; ++j) Bs[kr][nq + j] = Bp[j];
        __syncthreads();
#pragma unroll
        for (int kk = 0; kk < 16; ++kk) {
            float a[4], b[4];
#pragma unroll
            for (int i = 0; i < 4; ++i) a[i] = As[kk][ty * 4 + i];
#pragma unroll
            for (int j = 0; j < 4; ++j) b[j] = Bs[kk][tx * 4 + j];
#pragma unroll
            for (int i = 0; i < 4; ++i)
#pragma unroll
                for (int j = 0; j < 4; ++j) acc[i][j] += a[i] * b[j];
        }
        __syncthreads();
        Ap += 16; Bp += 16 * ldb;
    }
#pragma unroll
    for (int i = 0; i < 4; ++i)
#pragma unroll
        for (int j = 0; j < 4; ++j)
            C[(size_t)(m0 + ty * 4 + i) * ldc + (n0 + tx * 4 + j)] = acc[i][j];
}

__global__ void softmax_avg(const float* __restrict__ P, float* __restrict__ avg)
{
    const int t = threadIdx.x;
    const int bq = blockIdx.x;
    const int b = bq >> 11;
    const int q = bq & (S_ - 1);
    const float* base = P + (size_t)b * NH * S_ * S_ + (size_t)q * S_;
    __shared__ float red[8];

    float acc[8] = {};
    for (int h = 0; h < NH; ++h) {
        const float* row = base + (size_t)h * S_ * S_;
        float v[8];
        float m = -1e30f;
#pragma unroll
        for (int i = 0; i < 8; ++i) { v[i] = row[t + 256 * i]; m = fmaxf(m, v[i]); }
#pragma unroll
        for (int o = 16; o > 0; o >>= 1) m = fmaxf(m, __shfl_xor_sync(0xffffffffu, m, o));
        __syncthreads();
        if ((t & 31) == 0) red[t >> 5] = m;
        __syncthreads();
        m = red[0];
#pragma unroll
        for (int w = 1; w < 8; ++w) m = fmaxf(m, red[w]);

        float s = 0.f;
#pragma unroll
        for (int i = 0; i < 8; ++i) { v[i] = __expf(v[i] - m); s += v[i]; }
#pragma unroll
        for (int o = 16; o > 0; o >>= 1) s += __shfl_xor_sync(0xffffffffu, s, o);
        __syncthreads();
        if ((t & 31) == 0) red[t >> 5] = s;
        __syncthreads();
        s = red[0];
#pragma unroll
        for (int w = 1; w < 8; ++w) s += red[w];
        const float inv = 1.0f / s;
#pragma unroll
        for (int i = 0; i < 8; ++i) acc[i] += v[i] * inv;
    }
    float* o = avg + (size_t)bq * S_;
#pragma unroll
    for (int i = 0; i < 8; ++i) o[t + 256 * i] = acc[i] * (1.0f / NH);
}

extern "C" void kernel_launch(void* const* d_in, const int* in_sizes, int n_in,
                              void* d_out, int out_size)
{
    const float* query  = (const float*)d_in[0];
    const float* key_in = (const float*)d_in[1];
    const float* value  = (const float*)d_in[2];
    const float* Wq = (const float*)d_in[3];
    const float* bq = (const float*)d_in[4];
    const float* Wk = (const float*)d_in[5];
    const float* bk = (const float*)d_in[6];
    const float* Wv = (const float*)d_in[7];
    const float* bv = (const float*)d_in[8];
    const float* Wo = (const float*)d_in[9];
    const float* bo = (const float*)d_in[10];

    float* out = (float*)d_out;                       // [B,S,H]
    float* avg_out = out + (size_t)B_ * S_ * H_;      // [B,S,S]

    float *gQ, *gK, *gV, *gAO, *gP;
    __nv_bfloat16 *hA, *lA, *hW, *lW, *hQ, *lQ, *hK, *lK;
    cudaGetSymbolAddress((void**)&gQ, g_Q);
    cudaGetSymbolAddress((void**)&gK, g_K);
    cudaGetSymbolAddress((void**)&gV, g_V);
    cudaGetSymbolAddress((void**)&gAO, g_AO);
    cudaGetSymbolAddress((void**)&gP, g_P);
    cudaGetSymbolAddress((void**)&hA, g_hA);
    cudaGetSymbolAddress((void**)&lA, g_lA);
    cudaGetSymbolAddress((void**)&hW, g_hW);
    cudaGetSymbolAddress((void**)&lW, g_lW);
    cudaGetSymbolAddress((void**)&hQ, g_hQ);
    cudaGetSymbolAddress((void**)&lQ, g_lQ);
    cudaGetSymbolAddress((void**)&hK, g_hK);
    cudaGetSymbolAddress((void**)&lK, g_lK);

    cudaFuncSetAttribute(hmma_nt, cudaFuncAttributeMaxDynamicSharedMemorySize, SM_TOTAL);

    const int M = B_ * S_;   // 8192
    const int NXH = B_ * S_ * H_;

    // Q projection
    split_hl<<<NXH / 256, 256>>>(query, hA, lA, NXH);
    split_hl<<<(H_ * H_) / 256, 256>>>(Wq, hW, lW, H_ * H_);
    hmma_nt<<<dim3(H_ / 128, M / 128, 1), 256, SM_TOTAL>>>(hA, lA, hW, lW, bq, gQ,
        H_, H_, H_, H_, 0, 0, 0, 0, 0, 0, 1.f);
    // K projection
    split_hl<<<NXH / 256, 256>>>(key_in, hA, lA, NXH);
    split_hl<<<(H_ * H_) / 256, 256>>>(Wk, hW, lW, H_ * H_);
    hmma_nt<<<dim3(H_ / 128, M / 128, 1), 256, SM_TOTAL>>>(hA, lA, hW, lW, bk, gK,
        H_, H_, H_, H_, 0, 0, 0, 0, 0, 0, 1.f);
    // V projection (fp32 SIMT, N=64)
    gemm_nt<<<dim3(1, M / 64, 1), dim3(16, 16)>>>(value, Wv, bv, gV, H_, H_, H_, HD);

    // Split Q, K for QK^T
    split_hl<<<NXH / 256, 256>>>(gQ, hQ, lQ, NXH);
    split_hl<<<NXH / 256, 256>>>(gK, hK, lK, NXH);

    // Per-head scores: z = b*16 + h, K = 64
    hmma_nt<<<dim3(S_ / 128, S_ / 128, B_ * NH), 256, SM_TOTAL>>>(hQ, lQ, hK, lK,
        nullptr, gP,
        HD, H_, H_, S_,
        (long)S_ * H_, HD, (long)S_ * H_, HD,
        (long)NH * S_ * S_, (long)S_ * S_, 0.125f);

    // Fused softmax + head average
    softmax_avg<<<B_ * S_, 256>>>(gP, avg_out);

    // attn_out = avg_attn @ V (batched over B)
    gemm_nn<<<dim3(1, S_ / 64, B_), dim3(16, 16)>>>(avg_out, gV, gAO,
        S_, S_, HD, HD, (long)S_ * S_, (long)S_ * HD, (long)S_ * HD);

    // O projection: K = 64 on tensor path
    split_hl<<<(B_ * S_ * HD) / 256, 256>>>(gAO, hA, lA, B_ * S_ * HD);
    split_hl<<<(H_ * HD) / 256, 256>>>(Wo, hW, lW, H_ * HD);
    hmma_nt<<<dim3(H_ / 128, M / 128, 1), 256, SM_TOTAL>>>(hA, lA, hW, lW, bo, out,
        HD, HD, HD, H_, 0, 0, 0, 0, 0, 0, 1.f);
}

// round 5
// speedup vs baseline: 4.0669x; 1.1764x over previous
#include <cuda_runtime.h>
#include <cuda_bf16.h>
#include <cuda_fp16.h>
#include <cstdint>

#define B_ 4
#define S_ 2048
#define H_ 1024
#define NH 16
#define HD 64

// scratch
__device__ float g_V[B_ * S_ * HD];
__device__ float g_AO[B_ * S_ * HD];
__device__ __half g_P16[(size_t)B_ * NH * S_ * S_];
__device__ __nv_bfloat16 g_hA[B_ * S_ * H_], g_lA[B_ * S_ * H_];
__device__ __nv_bfloat16 g_hW[H_ * H_],      g_lW[H_ * H_];
__device__ __nv_bfloat16 g_hQ[B_ * S_ * H_], g_lQ[B_ * S_ * H_];
__device__ __nv_bfloat16 g_hK[B_ * S_ * H_], g_lK[B_ * S_ * H_];

// ---------------------------------------------------------------------------
// Base-ISA helpers (sm_103 base target: no 'a'-gated instructions)
// ---------------------------------------------------------------------------
__device__ __forceinline__ uint32_t smem_u32(const void* p) {
    uint32_t a;
    asm("{ .reg .u64 t; cvta.to.shared.u64 t, %1; cvt.u32.u64 %0, t; }" : "=r"(a) : "l"(p));
    return a;
}
#define SWZ128(x) ((x) ^ (((x) >> 3) & 0x70))

__device__ __forceinline__ void ldsm4(uint32_t& r0, uint32_t& r1, uint32_t& r2, uint32_t& r3,
                                      uint32_t addr) {
    asm volatile("ldmatrix.sync.aligned.m8n8.x4.shared.b16 {%0,%1,%2,%3}, [%4];"
                 : "=r"(r0), "=r"(r1), "=r"(r2), "=r"(r3) : "r"(addr));
}
__device__ __forceinline__ void mma16816(float* c, const uint32_t* a, const uint32_t* b) {
    asm volatile(
        "mma.sync.aligned.m16n8k16.row.col.f32.bf16.bf16.f32 "
        "{%0,%1,%2,%3}, {%4,%5,%6,%7}, {%8,%9}, {%0,%1,%2,%3};"
        : "+f"(c[0]), "+f"(c[1]), "+f"(c[2]), "+f"(c[3])
        : "r"(a[0]), "r"(a[1]), "r"(a[2]), "r"(a[3]), "r"(b[0]), "r"(b[1]));
}
#define CP16(s, g) asm volatile("cp.async.cg.shared.global [%0], [%1], 16;" :: "r"(s), "l"(g))
#define CP_COMMIT() asm volatile("cp.async.commit_group;" ::: "memory")
#define CP_WAIT(n)  asm volatile("cp.async.wait_group %0;" :: "n"(n) : "memory")

// ---------------------------------------------------------------------------
// fp32 -> bf16 hi/lo split, 4 elements/thread
// ---------------------------------------------------------------------------
__global__ void split_hl4(const float4* __restrict__ x, uint2* __restrict__ hi,
                          uint2* __restrict__ lo, int n4)
{
    int i = blockIdx.x * blockDim.x + threadIdx.x;
    if (i < n4) {
        float4 v = x[i];
        __nv_bfloat16 h0 = __float2bfloat16(v.x), h1 = __float2bfloat16(v.y);
        __nv_bfloat16 h2 = __float2bfloat16(v.z), h3 = __float2bfloat16(v.w);
        __nv_bfloat16 l0 = __float2bfloat16(v.x - __bfloat162float(h0));
        __nv_bfloat16 l1 = __float2bfloat16(v.y - __bfloat162float(h1));
        __nv_bfloat16 l2 = __float2bfloat16(v.z - __bfloat162float(h2));
        __nv_bfloat16 l3 = __float2bfloat16(v.w - __bfloat162float(h3));
        union { __nv_bfloat162 b2[2]; uint2 u; } ph, pl;
        ph.b2[0].x = h0; ph.b2[0].y = h1; ph.b2[1].x = h2; ph.b2[1].y = h3;
        pl.b2[0].x = l0; pl.b2[0].y = l1; pl.b2[1].x = l2; pl.b2[1].y = l3;
        hi[i] = ph.u;
        lo[i] = pl.u;
    }
}

// ---------------------------------------------------------------------------
// HMMA bf16x3 GEMM: Y = alpha * A @ B^T + bias ; epilogue mode by pointer:
//   C   != 0 -> fp32 out
//   C16 != 0 -> fp16 out
//   else     -> bf16 hi/lo split out (Chi, Clo)
// 128x128 block tile, K-chunk 64, double-buffered cp.async pipeline.
// ---------------------------------------------------------------------------
#define TILE_B 16384                   // 128 rows x 64 bf16
#define BUF_B  (4 * TILE_B)            // hA,lA,hB,lB = 64KB
#define SM_TOTAL (2 * BUF_B)           // 128KB

__device__ __forceinline__ void cp_tile(const __nv_bfloat16* __restrict__ g, int ld,
                                        uint32_t sdst, int tid, int ko)
{
#pragma unroll
    for (int it = 0; it < 4; ++it) {
        int i = tid + it * 256;
        int row = i >> 3, c = i & 7;
        const void* gp = g + (size_t)row * ld + ko + c * 8;
        uint32_t sp = sdst + SWZ128((uint32_t)(row * 128 + c * 16));
        CP16(sp, gp);
    }
}

__global__ void __launch_bounds__(256, 2)
hmma_nt(const __nv_bfloat16* __restrict__ hA, const __nv_bfloat16* __restrict__ lA,
        const __nv_bfloat16* __restrict__ hB, const __nv_bfloat16* __restrict__ lB,
        const float* __restrict__ bias,
        float* __restrict__ C, __half* __restrict__ C16,
        __nv_bfloat16* __restrict__ Chi, __nv_bfloat16* __restrict__ Clo,
        int K, int lda, int ldb, int ldc,
        long sAb, long sAh, long sBb, long sBh, long sCb, long sCh,
        float alpha)
{
    extern __shared__ char smem[];
    const uint32_t sb = smem_u32(smem);
    const int tid = threadIdx.x, lane = tid & 31, w = tid >> 5;
    const int wm = w >> 1, wn = w & 1;
    const int m0 = blockIdx.y * 128, n0 = blockIdx.x * 128;
    const int zb = blockIdx.z >> 4, zh = blockIdx.z & 15;

    const size_t aoff = (size_t)zb * sAb + (size_t)zh * sAh + (size_t)m0 * lda;
    const size_t boff = (size_t)zb * sBb + (size_t)zh * sBh + (size_t)n0 * ldb;
    hA += aoff; lA += aoff;
    hB += boff; lB += boff;
    const size_t coff = (size_t)zb * sCb + (size_t)zh * sCh;

    const int nch = K >> 6;

    cp_tile(hA, lda, sb + 0 * TILE_B, tid, 0);
    cp_tile(lA, lda, sb + 1 * TILE_B, tid, 0);
    cp_tile(hB, ldb, sb + 2 * TILE_B, tid, 0);
    cp_tile(lB, ldb, sb + 3 * TILE_B, tid, 0);
    CP_COMMIT();

    float acc[2][8][4] = {};

    const int a_row = wm * 32 + (lane & 15);
    const uint32_t a_kext = (lane & 16) ? 16u : 0u;
    const int b_row = wn * 64 + ((lane & 16) ? 8 : 0) + (lane & 7);
    const uint32_t b_kext = (lane & 8) ? 16u : 0u;

    for (int c = 0; c < nch; ++c) {
        const int b = c & 1;
        if (c + 1 < nch) {
            const uint32_t nb = sb + (1 - b) * BUF_B;
            const int ko = (c + 1) << 6;
            cp_tile(hA, lda, nb + 0 * TILE_B, tid, ko);
            cp_tile(lA, lda, nb + 1 * TILE_B, tid, ko);
            cp_tile(hB, ldb, nb + 2 * TILE_B, tid, ko);
            cp_tile(lB, ldb, nb + 3 * TILE_B, tid, ko);
            CP_COMMIT();
            CP_WAIT(1);
        } else {
            CP_WAIT(0);
        }
        __syncthreads();

        const uint32_t base = sb + b * BUF_B;
        const uint32_t aH = base, aL = base + TILE_B;
        const uint32_t bH = base + 2 * TILE_B, bL = base + 3 * TILE_B;

#pragma unroll
        for (int ks = 0; ks < 4; ++ks) {
            uint32_t ah[2][4], al[2][4];
#pragma unroll
            for (int ma = 0; ma < 2; ++ma) {
                const uint32_t off =
                    SWZ128((uint32_t)((a_row + ma * 16) * 128) + (uint32_t)(ks * 32) + a_kext);
                ldsm4(ah[ma][0], ah[ma][1], ah[ma][2], ah[ma][3], aH + off);
                ldsm4(al[ma][0], al[ma][1], al[ma][2], al[ma][3], aL + off);
            }
#pragma unroll
            for (int bg = 0; bg < 4; ++bg) {
                const uint32_t off =
                    SWZ128((uint32_t)((b_row + bg * 16) * 128) + (uint32_t)(ks * 32) + b_kext);
                uint32_t bh[4], bl[4];
                ldsm4(bh[0], bh[1], bh[2], bh[3], bH + off);
                ldsm4(bl[0], bl[1], bl[2], bl[3], bL + off);
#pragma unroll
                for (int na = 0; na < 2; ++na) {
                    const int n = bg * 2 + na;
#pragma unroll
                    for (int ma = 0; ma < 2; ++ma) {
                        mma16816(acc[ma][n], ah[ma], &bh[na * 2]);
                        mma16816(acc[ma][n], ah[ma], &bl[na * 2]);
                        mma16816(acc[ma][n], al[ma], &bh[na * 2]);
                    }
                }
            }
        }
        __syncthreads();
    }

    const int gq = lane >> 2, tig = lane & 3;
#pragma unroll
    for (int ma = 0; ma < 2; ++ma) {
        const int r0 = m0 + wm * 32 + ma * 16 + gq;
#pragma unroll
        for (int n = 0; n < 8; ++n) {
            const int col = n0 + wn * 64 + n * 8 + tig * 2;
            const float b0 = bias ? bias[col] : 0.f;
            const float b1 = bias ? bias[col + 1] : 0.f;
            float v00 = acc[ma][n][0] * alpha + b0, v01 = acc[ma][n][1] * alpha + b1;
            float v10 = acc[ma][n][2] * alpha + b0, v11 = acc[ma][n][3] * alpha + b1;
            const size_t i0 = coff + (size_t)r0 * ldc + col;
            const size_t i1 = coff + (size_t)(r0 + 8) * ldc + col;
            if (C) {
                *(float2*)(C + i0) = make_float2(v00, v01);
                *(float2*)(C + i1) = make_float2(v10, v11);
            } else if (C16) {
                *(__half2*)(C16 + i0) = __floats2half2_rn(v00, v01);
                *(__half2*)(C16 + i1) = __floats2half2_rn(v10, v11);
            } else {
                __nv_bfloat162 h, l;
                h.x = __float2bfloat16(v00); h.y = __float2bfloat16(v01);
                l.x = __float2bfloat16(v00 - __bfloat162float(h.x));
                l.y = __float2bfloat16(v01 - __bfloat162float(h.y));
                *(__nv_bfloat162*)(Chi + i0) = h;
                *(__nv_bfloat162*)(Clo + i0) = l;
                h.x = __float2bfloat16(v10); h.y = __float2bfloat16(v11);
                l.x = __float2bfloat16(v10 - __bfloat162float(h.x));
                l.y = __float2bfloat16(v11 - __bfloat162float(h.y));
                *(__nv_bfloat162*)(Chi + i1) = h;
                *(__nv_bfloat162*)(Clo + i1) = l;
            }
        }
    }
}

// ---------------------------------------------------------------------------
// SIMT small-N kernels (V proj NT, PV NN)
// ---------------------------------------------------------------------------
__global__ void gemm_nt(const float* __restrict__ A, const float* __restrict__ Bm,
                        const float* __restrict__ bias, float* __restrict__ C,
                        int K, int lda, int ldb, int ldc)
{
    __shared__ float As[16][65];
    __shared__ float Bs[16][65];
    const int tx = threadIdx.x, ty = threadIdx.y;
    const int tid = ty * 16 + tx;
    const int m0 = blockIdx.y * 64, n0 = blockIdx.x * 64;
    const int rr = tid >> 2;
    const int kq = (tid & 3) << 2;

    const float* Ap = A + (size_t)(m0 + rr) * lda + kq;
    const float* Bp = Bm + (size_t)(n0 + rr) * ldb + kq;

    float acc[4][4] = {};
    for (int k0 = 0; k0 < K; k0 += 16) {
#pragma unroll
        for (int j = 0; j < 4; ++j) As[kq + j][rr] = Ap[j];
#pragma unroll
        for (int j = 0; j < 4; ++j) Bs[kq + j][rr] = Bp[j];
        __syncthreads();
#pragma unroll
        for (int kk = 0; kk < 16; ++kk) {
            float a[4], b[4];
#pragma unroll
            for (int i = 0; i < 4; ++i) a[i] = As[kk][ty * 4 + i];
#pragma unroll
            for (int j = 0; j < 4; ++j) b[j] = Bs[kk][tx * 4 + j];
#pragma unroll
            for (int i = 0; i < 4; ++i)
#pragma unroll
                for (int j = 0; j < 4; ++j) acc[i][j] += a[i] * b[j];
        }
        __syncthreads();
        Ap += 16; Bp += 16;
    }
#pragma unroll
    for (int i = 0; i < 4; ++i)
#pragma unroll
        for (int j = 0; j < 4; ++j) {
            const int n = n0 + tx * 4 + j;
            C[(size_t)(m0 + ty * 4 + i) * ldc + n] = acc[i][j] + (bias ? bias[n] : 0.f);
        }
}

__global__ void gemm_nn(const float* __restrict__ A, const float* __restrict__ Bm,
                        float* __restrict__ C,
                        int K, int lda, int ldb, int ldc, long sA, long sB, long sC)
{
    __shared__ float As[16][65];
    __shared__ float Bs[16][65];
    const int tx = threadIdx.x, ty = threadIdx.y;
    const int tid = ty * 16 + tx;
    const int m0 = blockIdx.y * 64, n0 = blockIdx.x * 64;
    const int rr = tid >> 2;
    const int kq = (tid & 3) << 2;
    const int kr = tid >> 4;
    const int nq = (tid & 15) << 2;

    const float* Ap = A + (size_t)blockIdx.z * sA + (size_t)(m0 + rr) * lda + kq;
    const float* Bp = Bm + (size_t)blockIdx.z * sB + (size_t)kr * ldb + n0 + nq;
    C += (size_t)blockIdx.z * sC;

    float acc[4][4] = {};
    for (int k0 = 0; k0 < K; k0 += 16) {
#pragma unroll
        for (int j = 0; j < 4; ++j) As[kq + j][rr] = Ap[j];
#pragma unroll
        for (int j = 0; j < 4; ++j) Bs[kr][nq + j] = Bp[j];
        __syncthreads();
#pragma unroll
        for (int kk = 0; kk < 16; ++kk) {
            float a[4], b[4];
#pragma unroll
            for (int i = 0; i < 4; ++i) a[i] = As[kk][ty * 4 + i];
#pragma unroll
            for (int j = 0; j < 4; ++j) b[j] = Bs[kk][tx * 4 + j];
#pragma unroll
            for (int i = 0; i < 4; ++i)
#pragma unroll
                for (int j = 0; j < 4; ++j) acc[i][j] += a[i] * b[j];
        }
        __syncthreads();
        Ap += 16; Bp += 16 * ldb;
    }
#pragma unroll
    for (int i = 0; i < 4; ++i)
#pragma unroll
        for (int j = 0; j < 4; ++j)
            C[(size_t)(m0 + ty * 4 + i) * ldc + (n0 + tx * 4 + j)] = acc[i][j];
}

// ---------------------------------------------------------------------------
// Fused softmax + head-average over fp16 scores. One block per (b, q).
// ---------------------------------------------------------------------------
__global__ void softmax_avg(const __half2* __restrict__ P, float* __restrict__ avg)
{
    const int t = threadIdx.x;
    const int bq = blockIdx.x;
    const int b = bq >> 11;
    const int q = bq & (S_ - 1);
    const __half2* base = P + ((size_t)b * NH * S_ * S_ + (size_t)q * S_) / 2;
    const size_t hstride = (size_t)S_ * S_ / 2;
    __shared__ float red[8];

    float accx[4] = {}, accy[4] = {};
    for (int h = 0; h < NH; ++h) {
        const __half2* row = base + (size_t)h * hstride;
        float2 v[4];
        float m = -1e30f;
#pragma unroll
        for (int i = 0; i < 4; ++i) {
            v[i] = __half22float2(row[t + 256 * i]);
            m = fmaxf(m, fmaxf(v[i].x, v[i].y));
        }
#pragma unroll
        for (int o = 16; o > 0; o >>= 1) m = fmaxf(m, __shfl_xor_sync(0xffffffffu, m, o));
        __syncthreads();
        if ((t & 31) == 0) red[t >> 5] = m;
        __syncthreads();
        m = red[0];
#pragma unroll
        for (int w = 1; w < 8; ++w) m = fmaxf(m, red[w]);

        float s = 0.f;
#pragma unroll
        for (int i = 0; i < 4; ++i) {
            v[i].x = __expf(v[i].x - m);
            v[i].y = __expf(v[i].y - m);
            s += v[i].x + v[i].y;
        }
#pragma unroll
        for (int o = 16; o > 0; o >>= 1) s += __shfl_xor_sync(0xffffffffu, s, o);
        __syncthreads();
        if ((t & 31) == 0) red[t >> 5] = s;
        __syncthreads();
        s = red[0];
#pragma unroll
        for (int w = 1; w < 8; ++w) s += red[w];
        const float inv = 1.0f / s;
#pragma unroll
        for (int i = 0; i < 4; ++i) { accx[i] += v[i].x * inv; accy[i] += v[i].y * inv; }
    }
    float* o = avg + (size_t)bq * S_;
#pragma unroll
    for (int i = 0; i < 4; ++i)
        *(float2*)(o + 2 * (t + 256 * i)) =
            make_float2(accx[i] * (1.0f / NH), accy[i] * (1.0f / NH));
}

extern "C" void kernel_launch(void* const* d_in, const int* in_sizes, int n_in,
                              void* d_out, int out_size)
{
    const float* query  = (const float*)d_in[0];
    const float* key_in = (const float*)d_in[1];
    const float* value  = (const float*)d_in[2];
    const float* Wq = (const float*)d_in[3];
    const float* bq = (const float*)d_in[4];
    const float* Wk = (const float*)d_in[5];
    const float* bk = (const float*)d_in[6];
    const float* Wv = (const float*)d_in[7];
    const float* bv = (const float*)d_in[8];
    const float* Wo = (const float*)d_in[9];
    const float* bo = (const float*)d_in[10];

    float* out = (float*)d_out;
    float* avg_out = out + (size_t)B_ * S_ * H_;

    float *gV, *gAO;
    __half* gP16;
    __nv_bfloat16 *hA, *lA, *hW, *lW, *hQ, *lQ, *hK, *lK;
    cudaGetSymbolAddress((void**)&gV, g_V);
    cudaGetSymbolAddress((void**)&gAO, g_AO);
    cudaGetSymbolAddress((void**)&gP16, g_P16);
    cudaGetSymbolAddress((void**)&hA, g_hA);
    cudaGetSymbolAddress((void**)&lA, g_lA);
    cudaGetSymbolAddress((void**)&hW, g_hW);
    cudaGetSymbolAddress((void**)&lW, g_lW);
    cudaGetSymbolAddress((void**)&hQ, g_hQ);
    cudaGetSymbolAddress((void**)&lQ, g_lQ);
    cudaGetSymbolAddress((void**)&hK, g_hK);
    cudaGetSymbolAddress((void**)&lK, g_lK);

    cudaFuncSetAttribute(hmma_nt, cudaFuncAttributeMaxDynamicSharedMemorySize, SM_TOTAL);

    const int M = B_ * S_;          // 8192
    const int NXH = B_ * S_ * H_;   // 8M

    // Q projection -> split bf16 out
    split_hl4<<<NXH / 1024, 256>>>((const float4*)query, (uint2*)hA, (uint2*)lA, NXH / 4);
    split_hl4<<<(H_ * H_) / 1024, 256>>>((const float4*)Wq, (uint2*)hW, (uint2*)lW, H_ * H_ / 4);
    hmma_nt<<<dim3(H_ / 128, M / 128, 1), 256, SM_TOTAL>>>(hA, lA, hW, lW, bq,
        nullptr, nullptr, hQ, lQ, H_, H_, H_, H_, 0, 0, 0, 0, 0, 0, 1.f);
    // K projection -> split bf16 out
    split_hl4<<<NXH / 1024, 256>>>((const float4*)key_in, (uint2*)hA, (uint2*)lA, NXH / 4);
    split_hl4<<<(H_ * H_) / 1024, 256>>>((const float4*)Wk, (uint2*)hW, (uint2*)lW, H_ * H_ / 4);
    hmma_nt<<<dim3(H_ / 128, M / 128, 1), 256, SM_TOTAL>>>(hA, lA, hW, lW, bk,
        nullptr, nullptr, hK, lK, H_, H_, H_, H_, 0, 0, 0, 0, 0, 0, 1.f);
    // V projection (fp32 SIMT, N=64)
    gemm_nt<<<dim3(1, M / 64, 1), dim3(16, 16)>>>(value, Wv, bv, gV, H_, H_, H_, HD);

    // Per-head scores -> fp16 P.  K=64 (1 chunk): 64KB smem -> 2 CTA/SM.
    hmma_nt<<<dim3(S_ / 128, S_ / 128, B_ * NH), 256, BUF_B>>>(hQ, lQ, hK, lK,
        nullptr, nullptr, gP16, nullptr, nullptr,
        HD, H_, H_, S_,
        (long)S_ * H_, HD, (long)S_ * H_, HD,
        (long)NH * S_ * S_, (long)S_ * S_, 0.125f);

    // Fused softmax + head average (fp16 in, fp32 out)
    softmax_avg<<<B_ * S_, 256>>>((const __half2*)gP16, avg_out);

    // attn_out = avg_attn @ V (batched over B)
    gemm_nn<<<dim3(1, S_ / 64, B_), dim3(16, 16)>>>(avg_out, gV, gAO,
        S_, S_, HD, HD, (long)S_ * S_, (long)S_ * HD, (long)S_ * HD);

    // O projection (K=64, 1 chunk -> 64KB smem)
    split_hl4<<<(B_ * S_ * HD) / 1024, 256>>>((const float4*)gAO, (uint2*)hA, (uint2*)lA,
                                              B_ * S_ * HD / 4);
    split_hl4<<<(H_ * HD) / 1024, 256>>>((const float4*)Wo, (uint2*)hW, (uint2*)lW, H_ * HD / 4);
    hmma_nt<<<dim3(H_ / 128, M / 128, 1), 256, BUF_B>>>(hA, lA, hW, lW, bo,
        out, nullptr, nullptr, nullptr, HD, HD, HD, H_, 0, 0, 0, 0, 0, 0, 1.f);
}

// round 6
// speedup vs baseline: 4.1428x; 1.0187x over previous
#include <cuda_runtime.h>
#include <cuda_bf16.h>
#include <cuda_fp16.h>
#include <cstdint>

#define B_ 4
#define S_ 2048
#define H_ 1024
#define NH 16
#define HD 64

// scratch
__device__ float g_V[B_ * S_ * HD];
__device__ float g_AO[B_ * S_ * HD];
__device__ __half g_P16[(size_t)B_ * NH * S_ * S_];
__device__ __half g_A16[B_ * S_ * H_];      // converted input (query/key)
__device__ __half g_W16[H_ * H_];           // converted weight
__device__ __half g_Q16[B_ * S_ * H_];
__device__ __half g_K16[B_ * S_ * H_];
__device__ __nv_bfloat16 g_hA[B_ * S_ * HD], g_lA[B_ * S_ * HD];   // AO split
__device__ __nv_bfloat16 g_hW[H_ * HD],      g_lW[H_ * HD];        // Wo split

// ---------------------------------------------------------------------------
// Base-ISA helpers
// ---------------------------------------------------------------------------
__device__ __forceinline__ uint32_t smem_u32(const void* p) {
    uint32_t a;
    asm("{ .reg .u64 t; cvta.to.shared.u64 t, %1; cvt.u32.u64 %0, t; }" : "=r"(a) : "l"(p));
    return a;
}
#define SWZ128(x) ((x) ^ (((x) >> 3) & 0x70))

__device__ __forceinline__ void ldsm4(uint32_t& r0, uint32_t& r1, uint32_t& r2, uint32_t& r3,
                                      uint32_t addr) {
    asm volatile("ldmatrix.sync.aligned.m8n8.x4.shared.b16 {%0,%1,%2,%3}, [%4];"
                 : "=r"(r0), "=r"(r1), "=r"(r2), "=r"(r3) : "r"(addr));
}
__device__ __forceinline__ void mma_bf16(float* c, const uint32_t* a, const uint32_t* b) {
    asm volatile(
        "mma.sync.aligned.m16n8k16.row.col.f32.bf16.bf16.f32 "
        "{%0,%1,%2,%3}, {%4,%5,%6,%7}, {%8,%9}, {%0,%1,%2,%3};"
        : "+f"(c[0]), "+f"(c[1]), "+f"(c[2]), "+f"(c[3])
        : "r"(a[0]), "r"(a[1]), "r"(a[2]), "r"(a[3]), "r"(b[0]), "r"(b[1]));
}
__device__ __forceinline__ void mma_f16(float* c, const uint32_t* a, const uint32_t* b) {
    asm volatile(
        "mma.sync.aligned.m16n8k16.row.col.f32.f16.f16.f32 "
        "{%0,%1,%2,%3}, {%4,%5,%6,%7}, {%8,%9}, {%0,%1,%2,%3};"
        : "+f"(c[0]), "+f"(c[1]), "+f"(c[2]), "+f"(c[3])
        : "r"(a[0]), "r"(a[1]), "r"(a[2]), "r"(a[3]), "r"(b[0]), "r"(b[1]));
}
#define CP16(s, g) asm volatile("cp.async.cg.shared.global [%0], [%1], 16;" :: "r"(s), "l"(g))
#define CP_COMMIT() asm volatile("cp.async.commit_group;" ::: "memory")
#define CP_WAIT(n)  asm volatile("cp.async.wait_group %0;" :: "n"(n) : "memory")

// ---------------------------------------------------------------------------
// conversion kernels
// ---------------------------------------------------------------------------
__global__ void cvt_f16_4(const float4* __restrict__ x, uint2* __restrict__ y, int n4)
{
    int i = blockIdx.x * blockDim.x + threadIdx.x;
    if (i < n4) {
        float4 v = x[i];
        union { __half2 h2[2]; uint2 u; } p;
        p.h2[0] = __floats2half2_rn(v.x, v.y);
        p.h2[1] = __floats2half2_rn(v.z, v.w);
        y[i] = p.u;
    }
}

__global__ void split_hl4(const float4* __restrict__ x, uint2* __restrict__ hi,
                          uint2* __restrict__ lo, int n4)
{
    int i = blockIdx.x * blockDim.x + threadIdx.x;
    if (i < n4) {
        float4 v = x[i];
        __nv_bfloat16 h0 = __float2bfloat16(v.x), h1 = __float2bfloat16(v.y);
        __nv_bfloat16 h2 = __float2bfloat16(v.z), h3 = __float2bfloat16(v.w);
        __nv_bfloat16 l0 = __float2bfloat16(v.x - __bfloat162float(h0));
        __nv_bfloat16 l1 = __float2bfloat16(v.y - __bfloat162float(h1));
        __nv_bfloat16 l2 = __float2bfloat16(v.z - __bfloat162float(h2));
        __nv_bfloat16 l3 = __float2bfloat16(v.w - __bfloat162float(h3));
        union { __nv_bfloat162 b2[2]; uint2 u; } ph, pl;
        ph.b2[0].x = h0; ph.b2[0].y = h1; ph.b2[1].x = h2; ph.b2[1].y = h3;
        pl.b2[0].x = l0; pl.b2[0].y = l1; pl.b2[1].x = l2; pl.b2[1].y = l3;
        hi[i] = ph.u;
        lo[i] = pl.u;
    }
}

// ---------------------------------------------------------------------------
// shared GEMM machinery: 128x128 tile, K-chunk 64, cp.async double buffer.
// 8 warps 4(m) x 2(n), warp tile 32x64.
// ---------------------------------------------------------------------------
#define TILE_B 16384                   // 128 rows x 64 b16 elems

__device__ __forceinline__ void cp_tile(const void* __restrict__ g, int ld_elems,
                                        uint32_t sdst, int tid, int ko)
{
    const __half* gh = (const __half*)g;
#pragma unroll
    for (int it = 0; it < 4; ++it) {
        int i = tid + it * 256;
        int row = i >> 3, c = i & 7;
        const void* gp = gh + (size_t)row * ld_elems + ko + c * 8;
        uint32_t sp = sdst + SWZ128((uint32_t)(row * 128 + c * 16));
        CP16(sp, gp);
    }
}

// ---------------------------------------------------------------------------
// single-term fp16 GEMM: Y = alpha * A @ B^T (+bias); out fp32 (C) or fp16 (C16)
// ---------------------------------------------------------------------------
#define BUF2 (2 * TILE_B)              // A+B per stage = 32KB

__global__ void __launch_bounds__(256, 3)
hmma_f16_nt(const __half* __restrict__ A, const __half* __restrict__ Bm,
            const float* __restrict__ bias,
            float* __restrict__ C, __half* __restrict__ C16,
            int K, int lda, int ldb, int ldc,
            long sAb, long sAh, long sBb, long sBh, long sCb, long sCh,
            float alpha)
{
    extern __shared__ char smem[];
    const uint32_t sb = smem_u32(smem);
    const int tid = threadIdx.x, lane = tid & 31, w = tid >> 5;
    const int wm = w >> 1, wn = w & 1;
    const int m0 = blockIdx.y * 128, n0 = blockIdx.x * 128;
    const int zb = blockIdx.z >> 4, zh = blockIdx.z & 15;

    A  += (size_t)zb * sAb + (size_t)zh * sAh + (size_t)m0 * lda;
    Bm += (size_t)zb * sBb + (size_t)zh * sBh + (size_t)n0 * ldb;
    const size_t coff = (size_t)zb * sCb + (size_t)zh * sCh;

    const int nch = K >> 6;

    cp_tile(A, lda, sb, tid, 0);
    cp_tile(Bm, ldb, sb + TILE_B, tid, 0);
    CP_COMMIT();

    float acc[2][8][4] = {};

    const int a_row = wm * 32 + (lane & 15);
    const uint32_t a_kext = (lane & 16) ? 16u : 0u;
    const int b_row = wn * 64 + ((lane & 16) ? 8 : 0) + (lane & 7);
    const uint32_t b_kext = (lane & 8) ? 16u : 0u;

    for (int c = 0; c < nch; ++c) {
        const int b = c & 1;
        if (c + 1 < nch) {
            const uint32_t nb = sb + (1 - b) * BUF2;
            const int ko = (c + 1) << 6;
            cp_tile(A, lda, nb, tid, ko);
            cp_tile(Bm, ldb, nb + TILE_B, tid, ko);
            CP_COMMIT();
            CP_WAIT(1);
        } else {
            CP_WAIT(0);
        }
        __syncthreads();

        const uint32_t aS = sb + b * BUF2, bS = aS + TILE_B;

#pragma unroll
        for (int ks = 0; ks < 4; ++ks) {
            uint32_t ah[2][4];
#pragma unroll
            for (int ma = 0; ma < 2; ++ma) {
                const uint32_t off =
                    SWZ128((uint32_t)((a_row + ma * 16) * 128) + (uint32_t)(ks * 32) + a_kext);
                ldsm4(ah[ma][0], ah[ma][1], ah[ma][2], ah[ma][3], aS + off);
            }
#pragma unroll
            for (int bg = 0; bg < 4; ++bg) {
                const uint32_t off =
                    SWZ128((uint32_t)((b_row + bg * 16) * 128) + (uint32_t)(ks * 32) + b_kext);
                uint32_t bh[4];
                ldsm4(bh[0], bh[1], bh[2], bh[3], bS + off);
#pragma unroll
                for (int na = 0; na < 2; ++na)
#pragma unroll
                    for (int ma = 0; ma < 2; ++ma)
                        mma_f16(acc[ma][bg * 2 + na], ah[ma], &bh[na * 2]);
            }
        }
        __syncthreads();
    }

    const int gq = lane >> 2, tig = lane & 3;
#pragma unroll
    for (int ma = 0; ma < 2; ++ma) {
        const int r0 = m0 + wm * 32 + ma * 16 + gq;
#pragma unroll
        for (int n = 0; n < 8; ++n) {
            const int col = n0 + wn * 64 + n * 8 + tig * 2;
            const float b0 = bias ? bias[col] : 0.f;
            const float b1 = bias ? bias[col + 1] : 0.f;
            float v00 = acc[ma][n][0] * alpha + b0, v01 = acc[ma][n][1] * alpha + b1;
            float v10 = acc[ma][n][2] * alpha + b0, v11 = acc[ma][n][3] * alpha + b1;
            const size_t i0 = coff + (size_t)r0 * ldc + col;
            const size_t i1 = coff + (size_t)(r0 + 8) * ldc + col;
            if (C) {
                *(float2*)(C + i0) = make_float2(v00, v01);
                *(float2*)(C + i1) = make_float2(v10, v11);
            } else {
                *(__half2*)(C16 + i0) = __floats2half2_rn(v00, v01);
                *(__half2*)(C16 + i1) = __floats2half2_rn(v10, v11);
            }
        }
    }
}

// ---------------------------------------------------------------------------
// bf16x3 split GEMM (O projection): C = A @ B^T + bias, fp32 out
// ---------------------------------------------------------------------------
#define BUF4 (4 * TILE_B)

__global__ void __launch_bounds__(256, 2)
hmma_bf16x3_nt(const __nv_bfloat16* __restrict__ hA, const __nv_bfloat16* __restrict__ lA,
               const __nv_bfloat16* __restrict__ hB, const __nv_bfloat16* __restrict__ lB,
               const float* __restrict__ bias, float* __restrict__ C,
               int K, int lda, int ldb, int ldc)
{
    extern __shared__ char smem[];
    const uint32_t sb = smem_u32(smem);
    const int tid = threadIdx.x, lane = tid & 31, w = tid >> 5;
    const int wm = w >> 1, wn = w & 1;
    const int m0 = blockIdx.y * 128, n0 = blockIdx.x * 128;

    hA += (size_t)m0 * lda; lA += (size_t)m0 * lda;
    hB += (size_t)n0 * ldb; lB += (size_t)n0 * ldb;

    const int nch = K >> 6;

    cp_tile(hA, lda, sb + 0 * TILE_B, tid, 0);
    cp_tile(lA, lda, sb + 1 * TILE_B, tid, 0);
    cp_tile(hB, ldb, sb + 2 * TILE_B, tid, 0);
    cp_tile(lB, ldb, sb + 3 * TILE_B, tid, 0);
    CP_COMMIT();

    float acc[2][8][4] = {};

    const int a_row = wm * 32 + (lane & 15);
    const uint32_t a_kext = (lane & 16) ? 16u : 0u;
    const int b_row = wn * 64 + ((lane & 16) ? 8 : 0) + (lane & 7);
    const uint32_t b_kext = (lane & 8) ? 16u : 0u;

    for (int c = 0; c < nch; ++c) {
        const int b = c & 1;
        if (c + 1 < nch) {
            const uint32_t nb = sb + (1 - b) * BUF4;
            const int ko = (c + 1) << 6;
            cp_tile(hA, lda, nb + 0 * TILE_B, tid, ko);
            cp_tile(lA, lda, nb + 1 * TILE_B, tid, ko);
            cp_tile(hB, ldb, nb + 2 * TILE_B, tid, ko);
            cp_tile(lB, ldb, nb + 3 * TILE_B, tid, ko);
            CP_COMMIT();
            CP_WAIT(1);
        } else {
            CP_WAIT(0);
        }
        __syncthreads();

        const uint32_t base = sb + b * BUF4;
        const uint32_t aH = base, aL = base + TILE_B;
        const uint32_t bH = base + 2 * TILE_B, bL = base + 3 * TILE_B;

#pragma unroll
        for (int ks = 0; ks < 4; ++ks) {
            uint32_t ah[2][4], al[2][4];
#pragma unroll
            for (int ma = 0; ma < 2; ++ma) {
                const uint32_t off =
                    SWZ128((uint32_t)((a_row + ma * 16) * 128) + (uint32_t)(ks * 32) + a_kext);
                ldsm4(ah[ma][0], ah[ma][1], ah[ma][2], ah[ma][3], aH + off);
                ldsm4(al[ma][0], al[ma][1], al[ma][2], al[ma][3], aL + off);
            }
#pragma unroll
            for (int bg = 0; bg < 4; ++bg) {
                const uint32_t off =
                    SWZ128((uint32_t)((b_row + bg * 16) * 128) + (uint32_t)(ks * 32) + b_kext);
                uint32_t bh[4], bl[4];
                ldsm4(bh[0], bh[1], bh[2], bh[3], bH + off);
                ldsm4(bl[0], bl[1], bl[2], bl[3], bL + off);
#pragma unroll
                for (int na = 0; na < 2; ++na) {
                    const int n = bg * 2 + na;
#pragma unroll
                    for (int ma = 0; ma < 2; ++ma) {
                        mma_bf16(acc[ma][n], ah[ma], &bh[na * 2]);
                        mma_bf16(acc[ma][n], ah[ma], &bl[na * 2]);
                        mma_bf16(acc[ma][n], al[ma], &bh[na * 2]);
                    }
                }
            }
        }
        __syncthreads();
    }

    const int gq = lane >> 2, tig = lane & 3;
#pragma unroll
    for (int ma = 0; ma < 2; ++ma) {
        const int r0 = m0 + wm * 32 + ma * 16 + gq;
#pragma unroll
        for (int n = 0; n < 8; ++n) {
            const int col = n0 + wn * 64 + n * 8 + tig * 2;
            const float b0 = bias ? bias[col] : 0.f;
            const float b1 = bias ? bias[col + 1] : 0.f;
            *(float2*)(C + (size_t)r0 * ldc + col) =
                make_float2(acc[ma][n][0] + b0, acc[ma][n][1] + b1);
            *(float2*)(C + (size_t)(r0 + 8) * ldc + col) =
                make_float2(acc[ma][n][2] + b0, acc[ma][n][3] + b1);
        }
    }
}

// ---------------------------------------------------------------------------
// SIMT small-N kernels (V proj NT, PV NN)
// ---------------------------------------------------------------------------
__global__ void gemm_nt(const float* __restrict__ A, const float* __restrict__ Bm,
                        const float* __restrict__ bias, float* __restrict__ C,
                        int K, int lda, int ldb, int ldc)
{
    __shared__ float As[16][65];
    __shared__ float Bs[16][65];
    const int tx = threadIdx.x, ty = threadIdx.y;
    const int tid = ty * 16 + tx;
    const int m0 = blockIdx.y * 64, n0 = blockIdx.x * 64;
    const int rr = tid >> 2;
    const int kq = (tid & 3) << 2;

    const float* Ap = A + (size_t)(m0 + rr) * lda + kq;
    const float* Bp = Bm + (size_t)(n0 + rr) * ldb + kq;

    float acc[4][4] = {};
    for (int k0 = 0; k0 < K; k0 += 16) {
#pragma unroll
        for (int j = 0; j < 4; ++j) As[kq + j][rr] = Ap[j];
#pragma unroll
        for (int j = 0; j < 4; ++j) Bs[kq + j][rr] = Bp[j];
        __syncthreads();
#pragma unroll
        for (int kk = 0; kk < 16; ++kk) {
            float a[4], b[4];
#pragma unroll
            for (int i = 0; i < 4; ++i) a[i] = As[kk][ty * 4 + i];
#pragma unroll
            for (int j = 0; j < 4; ++j) b[j] = Bs[kk][tx * 4 + j];
#pragma unroll
            for (int i = 0; i < 4; ++i)
#pragma unroll
                for (int j = 0; j < 4; ++j) acc[i][j] += a[i] * b[j];
        }
        __syncthreads();
        Ap += 16; Bp += 16;
    }
#pragma unroll
    for (int i = 0; i < 4; ++i)
#pragma unroll
        for (int j = 0; j < 4; ++j) {
            const int n = n0 + tx * 4 + j;
            C[(size_t)(m0 + ty * 4 + i) * ldc + n] = acc[i][j] + (bias ? bias[n] : 0.f);
        }
}

__global__ void gemm_nn(const float* __restrict__ A, const float* __restrict__ Bm,
                        float* __restrict__ C,
                        int K, int lda, int ldb, int ldc, long sA, long sB, long sC)
{
    __shared__ float As[16][65];
    __shared__ float Bs[16][65];
    const int tx = threadIdx.x, ty = threadIdx.y;
    const int tid = ty * 16 + tx;
    const int m0 = blockIdx.y * 64, n0 = blockIdx.x * 64;
    const int rr = tid >> 2;
    const int kq = (tid & 3) << 2;
    const int kr = tid >> 4;
    const int nq = (tid & 15) << 2;

    const float* Ap = A + (size_t)blockIdx.z * sA + (size_t)(m0 + rr) * lda + kq;
    const float* Bp = Bm + (size_t)blockIdx.z * sB + (size_t)kr * ldb + n0 + nq;
    C += (size_t)blockIdx.z * sC;

    float acc[4][4] = {};
    for (int k0 = 0; k0 < K; k0 += 16) {
#pragma unroll
        for (int j = 0; j < 4; ++j) As[kq + j][rr] = Ap[j];
#pragma unroll
        for (int j = 0; j < 4; ++j) Bs[kr][nq + j] = Bp[j];
        __syncthreads();
#pragma unroll
        for (int kk = 0; kk < 16; ++kk) {
            float a[4], b[4];
#pragma unroll
            for (int i = 0; i < 4; ++i) a[i] = As[kk][ty * 4 + i];
#pragma unroll
            for (int j = 0; j < 4; ++j) b[j] = Bs[kk][tx * 4 + j];
#pragma unroll
            for (int i = 0; i < 4; ++i)
#pragma unroll
                for (int j = 0; j < 4; ++j) acc[i][j] += a[i] * b[j];
        }
        __syncthreads();
        Ap += 16; Bp += 16 * ldb;
    }
#pragma unroll
    for (int i = 0; i < 4; ++i)
#pragma unroll
        for (int j = 0; j < 4; ++j)
            C[(size_t)(m0 + ty * 4 + i) * ldc + (n0 + tx * 4 + j)] = acc[i][j];
}

// ---------------------------------------------------------------------------
// Fused softmax + head-average over fp16 scores. One block per (b, q).
// ---------------------------------------------------------------------------
__global__ void softmax_avg(const __half2* __restrict__ P, float* __restrict__ avg)
{
    const int t = threadIdx.x;
    const int bq = blockIdx.x;
    const int b = bq >> 11;
    const int q = bq & (S_ - 1);
    const __half2* base = P + ((size_t)b * NH * S_ * S_ + (size_t)q * S_) / 2;
    const size_t hstride = (size_t)S_ * S_ / 2;
    __shared__ float red[8];

    float accx[4] = {}, accy[4] = {};
    for (int h = 0; h < NH; ++h) {
        const __half2* row = base + (size_t)h * hstride;
        float2 v[4];
        float m = -1e30f;
#pragma unroll
        for (int i = 0; i < 4; ++i) {
            v[i] = __half22float2(row[t + 256 * i]);
            m = fmaxf(m, fmaxf(v[i].x, v[i].y));
        }
#pragma unroll
        for (int o = 16; o > 0; o >>= 1) m = fmaxf(m, __shfl_xor_sync(0xffffffffu, m, o));
        __syncthreads();
        if ((t & 31) == 0) red[t >> 5] = m;
        __syncthreads();
        m = red[0];
#pragma unroll
        for (int w = 1; w < 8; ++w) m = fmaxf(m, red[w]);

        float s = 0.f;
#pragma unroll
        for (int i = 0; i < 4; ++i) {
            v[i].x = __expf(v[i].x - m);
            v[i].y = __expf(v[i].y - m);
            s += v[i].x + v[i].y;
        }
#pragma unroll
        for (int o = 16; o > 0; o >>= 1) s += __shfl_xor_sync(0xffffffffu, s, o);
        __syncthreads();
        if ((t & 31) == 0) red[t >> 5] = s;
        __syncthreads();
        s = red[0];
#pragma unroll
        for (int w = 1; w < 8; ++w) s += red[w];
        const float inv = 1.0f / s;
#pragma unroll
        for (int i = 0; i < 4; ++i) { accx[i] += v[i].x * inv; accy[i] += v[i].y * inv; }
    }
    float* o = avg + (size_t)bq * S_;
#pragma unroll
    for (int i = 0; i < 4; ++i)
        *(float2*)(o + 2 * (t + 256 * i)) =
            make_float2(accx[i] * (1.0f / NH), accy[i] * (1.0f / NH));
}

extern "C" void kernel_launch(void* const* d_in, const int* in_sizes, int n_in,
                              void* d_out, int out_size)
{
    const float* query  = (const float*)d_in[0];
    const float* key_in = (const float*)d_in[1];
    const float* value  = (const float*)d_in[2];
    const float* Wq = (const float*)d_in[3];
    const float* bq = (const float*)d_in[4];
    const float* Wk = (const float*)d_in[5];
    const float* bk = (const float*)d_in[6];
    const float* Wv = (const float*)d_in[7];
    const float* bv = (const float*)d_in[8];
    const float* Wo = (const float*)d_in[9];
    const float* bo = (const float*)d_in[10];

    float* out = (float*)d_out;
    float* avg_out = out + (size_t)B_ * S_ * H_;

    float *gV, *gAO;
    __half *gP16, *gA16, *gW16, *gQ16, *gK16;
    __nv_bfloat16 *hA, *lA, *hW, *lW;
    cudaGetSymbolAddress((void**)&gV, g_V);
    cudaGetSymbolAddress((void**)&gAO, g_AO);
    cudaGetSymbolAddress((void**)&gP16, g_P16);
    cudaGetSymbolAddress((void**)&gA16, g_A16);
    cudaGetSymbolAddress((void**)&gW16, g_W16);
    cudaGetSymbolAddress((void**)&gQ16, g_Q16);
    cudaGetSymbolAddress((void**)&gK16, g_K16);
    cudaGetSymbolAddress((void**)&hA, g_hA);
    cudaGetSymbolAddress((void**)&lA, g_lA);
    cudaGetSymbolAddress((void**)&hW, g_hW);
    cudaGetSymbolAddress((void**)&lW, g_lW);

    cudaFuncSetAttribute(hmma_f16_nt, cudaFuncAttributeMaxDynamicSharedMemorySize, 2 * BUF2);
    cudaFuncSetAttribute(hmma_bf16x3_nt, cudaFuncAttributeMaxDynamicSharedMemorySize, 2 * BUF4);

    const int M = B_ * S_;          // 8192
    const int NXH = B_ * S_ * H_;   // 8M

    // Q projection (fp16 single-term)
    cvt_f16_4<<<NXH / 1024, 256>>>((const float4*)query, (uint2*)gA16, NXH / 4);
    cvt_f16_4<<<(H_ * H_) / 1024, 256>>>((const float4*)Wq, (uint2*)gW16, H_ * H_ / 4);
    hmma_f16_nt<<<dim3(H_ / 128, M / 128, 1), 256, 2 * BUF2>>>(gA16, gW16, bq,
        nullptr, gQ16, H_, H_, H_, H_, 0, 0, 0, 0, 0, 0, 1.f);
    // K projection
    cvt_f16_4<<<NXH / 1024, 256>>>((const float4*)key_in, (uint2*)gA16, NXH / 4);
    cvt_f16_4<<<(H_ * H_) / 1024, 256>>>((const float4*)Wk, (uint2*)gW16, H_ * H_ / 4);
    hmma_f16_nt<<<dim3(H_ / 128, M / 128, 1), 256, 2 * BUF2>>>(gA16, gW16, bk,
        nullptr, gK16, H_, H_, H_, H_, 0, 0, 0, 0, 0, 0, 1.f);
    // V projection (fp32 SIMT, N=64)
    gemm_nt<<<dim3(1, M / 64, 1), dim3(16, 16)>>>(value, Wv, bv, gV, H_, H_, H_, HD);

    // Per-head scores (fp16 single-term), K=64 single chunk -> 32KB smem
    hmma_f16_nt<<<dim3(S_ / 128, S_ / 128, B_ * NH), 256, BUF2>>>(gQ16, gK16,
        nullptr, nullptr, gP16,
        HD, H_, H_, S_,
        (long)S_ * H_, HD, (long)S_ * H_, HD,
        (long)NH * S_ * S_, (long)S_ * S_, 0.125f);

    // Fused softmax + head average
    softmax_avg<<<B_ * S_, 256>>>((const __half2*)gP16, avg_out);

    // attn_out = avg_attn @ V (batched over B)
    gemm_nn<<<dim3(1, S_ / 64, B_), dim3(16, 16)>>>(avg_out, gV, gAO,
        S_, S_, HD, HD, (long)S_ * S_, (long)S_ * HD, (long)S_ * HD);

    // O projection (bf16x3, K=64 -> 64KB smem single stage)
    split_hl4<<<(B_ * S_ * HD) / 1024, 256>>>((const float4*)gAO, (uint2*)hA, (uint2*)lA,
                                              B_ * S_ * HD / 4);
    split_hl4<<<(H_ * HD) / 1024, 256>>>((const float4*)Wo, (uint2*)hW, (uint2*)lW, H_ * HD / 4);
    hmma_bf16x3_nt<<<dim3(H_ / 128, M / 128, 1), 256, BUF4>>>(hA, lA, hW, lW, bo,
        out, HD, HD, HD, H_);
}

// round 7
// speedup vs baseline: 5.4391x; 1.3129x over previous
#include <cuda_runtime.h>
#include <cuda_bf16.h>
#include <cuda_fp16.h>
#include <cstdint>

#define B_ 4
#define S_ 2048
#define H_ 1024
#define NH 16
#define HD 64

// scratch
__device__ float g_V[B_ * S_ * HD];
__device__ float g_AO[B_ * S_ * HD];
__device__ float g_iL[B_ * NH * S_];        // 1/(16 * sum_k exp(s))
__device__ __half g_A16[B_ * S_ * H_];
__device__ __half g_W16[H_ * H_];
__device__ __half g_Q16[B_ * S_ * H_];
__device__ __half g_K16[B_ * S_ * H_];
__device__ __nv_bfloat16 g_hA[B_ * S_ * HD], g_lA[B_ * S_ * HD];
__device__ __nv_bfloat16 g_hW[H_ * HD],      g_lW[H_ * HD];

// ---------------------------------------------------------------------------
// Base-ISA helpers
// ---------------------------------------------------------------------------
__device__ __forceinline__ uint32_t smem_u32(const void* p) {
    uint32_t a;
    asm("{ .reg .u64 t; cvta.to.shared.u64 t, %1; cvt.u32.u64 %0, t; }" : "=r"(a) : "l"(p));
    return a;
}
#define SWZ128(x) ((x) ^ (((x) >> 3) & 0x70))

__device__ __forceinline__ void ldsm4(uint32_t& r0, uint32_t& r1, uint32_t& r2, uint32_t& r3,
                                      uint32_t addr) {
    asm volatile("ldmatrix.sync.aligned.m8n8.x4.shared.b16 {%0,%1,%2,%3}, [%4];"
                 : "=r"(r0), "=r"(r1), "=r"(r2), "=r"(r3) : "r"(addr));
}
__device__ __forceinline__ void mma_bf16(float* c, const uint32_t* a, const uint32_t* b) {
    asm volatile(
        "mma.sync.aligned.m16n8k16.row.col.f32.bf16.bf16.f32 "
        "{%0,%1,%2,%3}, {%4,%5,%6,%7}, {%8,%9}, {%0,%1,%2,%3};"
        : "+f"(c[0]), "+f"(c[1]), "+f"(c[2]), "+f"(c[3])
        : "r"(a[0]), "r"(a[1]), "r"(a[2]), "r"(a[3]), "r"(b[0]), "r"(b[1]));
}
__device__ __forceinline__ void mma_f16(float* c, const uint32_t* a, const uint32_t* b) {
    asm volatile(
        "mma.sync.aligned.m16n8k16.row.col.f32.f16.f16.f32 "
        "{%0,%1,%2,%3}, {%4,%5,%6,%7}, {%8,%9}, {%0,%1,%2,%3};"
        : "+f"(c[0]), "+f"(c[1]), "+f"(c[2]), "+f"(c[3])
        : "r"(a[0]), "r"(a[1]), "r"(a[2]), "r"(a[3]), "r"(b[0]), "r"(b[1]));
}
#define CP16(s, g) asm volatile("cp.async.cg.shared.global [%0], [%1], 16;" :: "r"(s), "l"(g))
#define CP_COMMIT() asm volatile("cp.async.commit_group;" ::: "memory")
#define CP_WAIT(n)  asm volatile("cp.async.wait_group %0;" :: "n"(n) : "memory")

#define TILE_B 16384                   // 128 rows x 64 b16 elems
#define BUF2 (2 * TILE_B)
#define BUF4 (4 * TILE_B)

__device__ __forceinline__ void cp_tile(const void* __restrict__ g, int ld_elems,
                                        uint32_t sdst, int tid)
{
    const __half* gh = (const __half*)g;
#pragma unroll
    for (int it = 0; it < 4; ++it) {
        int i = tid + it * 256;
        int row = i >> 3, c = i & 7;
        const void* gp = gh + (size_t)row * ld_elems + c * 8;
        uint32_t sp = sdst + SWZ128((uint32_t)(row * 128 + c * 16));
        CP16(sp, gp);
    }
}

// One 128x128x64 fp16 MMA tile: acc += A(128x64 smem) @ B(128x64 smem)^T
__device__ __forceinline__ void mma_tile_f16(float acc[2][8][4], uint32_t aS, uint32_t bS,
                                             int a_row, uint32_t a_kext,
                                             int b_row, uint32_t b_kext)
{
#pragma unroll
    for (int ks = 0; ks < 4; ++ks) {
        uint32_t ah[2][4];
#pragma unroll
        for (int ma = 0; ma < 2; ++ma) {
            const uint32_t off =
                SWZ128((uint32_t)((a_row + ma * 16) * 128) + (uint32_t)(ks * 32) + a_kext);
            ldsm4(ah[ma][0], ah[ma][1], ah[ma][2], ah[ma][3], aS + off);
        }
#pragma unroll
        for (int bg = 0; bg < 4; ++bg) {
            const uint32_t off =
                SWZ128((uint32_t)((b_row + bg * 16) * 128) + (uint32_t)(ks * 32) + b_kext);
            uint32_t bh[4];
            ldsm4(bh[0], bh[1], bh[2], bh[3], bS + off);
#pragma unroll
            for (int na = 0; na < 2; ++na)
#pragma unroll
                for (int ma = 0; ma < 2; ++ma)
                    mma_f16(acc[ma][bg * 2 + na], ah[ma], &bh[na * 2]);
        }
    }
}

// ---------------------------------------------------------------------------
// conversion kernels
// ---------------------------------------------------------------------------
__global__ void cvt_f16_4(const float4* __restrict__ x, uint2* __restrict__ y, int n4)
{
    int i = blockIdx.x * blockDim.x + threadIdx.x;
    if (i < n4) {
        float4 v = x[i];
        union { __half2 h2[2]; uint2 u; } p;
        p.h2[0] = __floats2half2_rn(v.x, v.y);
        p.h2[1] = __floats2half2_rn(v.z, v.w);
        y[i] = p.u;
    }
}

__global__ void split_hl4(const float4* __restrict__ x, uint2* __restrict__ hi,
                          uint2* __restrict__ lo, int n4)
{
    int i = blockIdx.x * blockDim.x + threadIdx.x;
    if (i < n4) {
        float4 v = x[i];
        __nv_bfloat16 h0 = __float2bfloat16(v.x), h1 = __float2bfloat16(v.y);
        __nv_bfloat16 h2 = __float2bfloat16(v.z), h3 = __float2bfloat16(v.w);
        __nv_bfloat16 l0 = __float2bfloat16(v.x - __bfloat162float(h0));
        __nv_bfloat16 l1 = __float2bfloat16(v.y - __bfloat162float(h1));
        __nv_bfloat16 l2 = __float2bfloat16(v.z - __bfloat162float(h2));
        __nv_bfloat16 l3 = __float2bfloat16(v.w - __bfloat162float(h3));
        union { __nv_bfloat162 b2[2]; uint2 u; } ph, pl;
        ph.b2[0].x = h0; ph.b2[0].y = h1; ph.b2[1].x = h2; ph.b2[1].y = h3;
        pl.b2[0].x = l0; pl.b2[0].y = l1; pl.b2[1].x = l2; pl.b2[1].y = l3;
        hi[i] = ph.u;
        lo[i] = pl.u;
    }
}

// ---------------------------------------------------------------------------
// single-term fp16 GEMM for Q/K projections: Y = A @ B^T + bias, fp16 out
// ---------------------------------------------------------------------------
__global__ void __launch_bounds__(256, 3)
hmma_f16_nt(const __half* __restrict__ A, const __half* __restrict__ Bm,
            const float* __restrict__ bias, __half* __restrict__ C16,
            int K, int lda, int ldb, int ldc)
{
    extern __shared__ char smem[];
    const uint32_t sb = smem_u32(smem);
    const int tid = threadIdx.x, lane = tid & 31, w = tid >> 5;
    const int wm = w >> 1, wn = w & 1;
    const int m0 = blockIdx.y * 128, n0 = blockIdx.x * 128;

    A  += (size_t)m0 * lda;
    Bm += (size_t)n0 * ldb;

    const int nch = K >> 6;

    cp_tile(A, lda, sb, tid);
    cp_tile(Bm, ldb, sb + TILE_B, tid);
    CP_COMMIT();

    float acc[2][8][4] = {};

    const int a_row = wm * 32 + (lane & 15);
    const uint32_t a_kext = (lane & 16) ? 16u : 0u;
    const int b_row = wn * 64 + ((lane & 16) ? 8 : 0) + (lane & 7);
    const uint32_t b_kext = (lane & 8) ? 16u : 0u;

    for (int c = 0; c < nch; ++c) {
        const int b = c & 1;
        if (c + 1 < nch) {
            const uint32_t nb = sb + (1 - b) * BUF2;
            const int ko = (c + 1) << 6;
            cp_tile(A + ko, lda, nb, tid);
            cp_tile(Bm + ko, ldb, nb + TILE_B, tid);
            CP_COMMIT();
            CP_WAIT(1);
        } else {
            CP_WAIT(0);
        }
        __syncthreads();
        const uint32_t aS = sb + b * BUF2;
        mma_tile_f16(acc, aS, aS + TILE_B, a_row, a_kext, b_row, b_kext);
        __syncthreads();
    }

    const int gq = lane >> 2, tig = lane & 3;
#pragma unroll
    for (int ma = 0; ma < 2; ++ma) {
        const int r0 = m0 + wm * 32 + ma * 16 + gq;
#pragma unroll
        for (int n = 0; n < 8; ++n) {
            const int col = n0 + wn * 64 + n * 8 + tig * 2;
            const float b0 = bias[col], b1 = bias[col + 1];
            *(__half2*)(C16 + (size_t)r0 * ldc + col) =
                __floats2half2_rn(acc[ma][n][0] + b0, acc[ma][n][1] + b1);
            *(__half2*)(C16 + (size_t)(r0 + 8) * ldc + col) =
                __floats2half2_rn(acc[ma][n][2] + b0, acc[ma][n][3] + b1);
        }
    }
}

// ---------------------------------------------------------------------------
// Pass A: per (b,h,q-tile) row sums of exp(s/8), s = Q K^T per head.
// Stores 1/(16 * L). smem: Q 16KB + K dbuf 32KB = 48KB.
// ---------------------------------------------------------------------------
__global__ void __launch_bounds__(256, 2)
qk_rowsum(const __half* __restrict__ Q, const __half* __restrict__ Kt,
          float* __restrict__ iL)
{
    extern __shared__ char smem[];
    const uint32_t sb = smem_u32(smem);
    const int tid = threadIdx.x, lane = tid & 31, w = tid >> 5;
    const int wm = w >> 1, wn = w & 1;
    const int qt = blockIdx.x, h = blockIdx.y, b = blockIdx.z;

    const __half* Qb = Q + (size_t)b * S_ * H_ + (size_t)qt * 128 * H_ + h * HD;
    const __half* Kb = Kt + (size_t)b * S_ * H_ + h * HD;

    cp_tile(Qb, H_, sb, tid);
    cp_tile(Kb, H_, sb + TILE_B, tid);
    CP_COMMIT();

    const int a_row = wm * 32 + (lane & 15);
    const uint32_t a_kext = (lane & 16) ? 16u : 0u;
    const int b_row = wn * 64 + ((lane & 16) ? 8 : 0) + (lane & 7);
    const uint32_t b_kext = (lane & 8) ? 16u : 0u;

    float lsum[2][2] = {};

    for (int kt = 0; kt < 16; ++kt) {
        const int bb = kt & 1;
        if (kt + 1 < 16) {
            cp_tile(Kb + (size_t)(kt + 1) * 128 * H_, H_, sb + TILE_B + (1 - bb) * TILE_B, tid);
            CP_COMMIT();
            CP_WAIT(1);
        } else {
            CP_WAIT(0);
        }
        __syncthreads();

        float acc[2][8][4] = {};
        mma_tile_f16(acc, sb, sb + TILE_B + bb * TILE_B, a_row, a_kext, b_row, b_kext);

#pragma unroll
        for (int ma = 0; ma < 2; ++ma)
#pragma unroll
            for (int n = 0; n < 8; ++n) {
                lsum[ma][0] += __expf(0.125f * acc[ma][n][0]) + __expf(0.125f * acc[ma][n][1]);
                lsum[ma][1] += __expf(0.125f * acc[ma][n][2]) + __expf(0.125f * acc[ma][n][3]);
            }
        __syncthreads();
    }

    // reduce across the 4-lane quad sharing a row
#pragma unroll
    for (int o = 1; o <= 2; o <<= 1)
#pragma unroll
        for (int ma = 0; ma < 2; ++ma)
#pragma unroll
            for (int hh = 0; hh < 2; ++hh)
                lsum[ma][hh] += __shfl_xor_sync(0xffffffffu, lsum[ma][hh], o);

    __shared__ float Ls[128];
    if (tid < 128) Ls[tid] = 0.f;
    __syncthreads();
    if ((lane & 3) == 0) {
        const int gq = lane >> 2;
#pragma unroll
        for (int ma = 0; ma < 2; ++ma) {
            atomicAdd(&Ls[wm * 32 + ma * 16 + gq], lsum[ma][0]);
            atomicAdd(&Ls[wm * 32 + ma * 16 + gq + 8], lsum[ma][1]);
        }
    }
    __syncthreads();
    if (tid < 128)
        iL[((size_t)b * NH + h) * S_ + qt * 128 + tid] = 1.0f / (16.0f * Ls[tid]);
}

// ---------------------------------------------------------------------------
// Pass B: per (b,q-tile,k-tile), recompute scores for all 16 heads and emit
// the head-averaged softmax tile. smem: 2 x (Q+K) = 64KB.
// ---------------------------------------------------------------------------
__global__ void __launch_bounds__(256, 1)
attn_avg(const __half* __restrict__ Q, const __half* __restrict__ Kt,
         const float* __restrict__ iL, float* __restrict__ avg)
{
    extern __shared__ char smem[];
    const uint32_t sb = smem_u32(smem);
    const int tid = threadIdx.x, lane = tid & 31, w = tid >> 5;
    const int wm = w >> 1, wn = w & 1;
    const int kt = blockIdx.x, qt = blockIdx.y, b = blockIdx.z;

    const __half* Qb = Q + (size_t)b * S_ * H_ + (size_t)qt * 128 * H_;
    const __half* Kb = Kt + (size_t)b * S_ * H_ + (size_t)kt * 128 * H_;

    cp_tile(Qb, H_, sb, tid);
    cp_tile(Kb, H_, sb + TILE_B, tid);
    CP_COMMIT();

    const int a_row = wm * 32 + (lane & 15);
    const uint32_t a_kext = (lane & 16) ? 16u : 0u;
    const int b_row = wn * 64 + ((lane & 16) ? 8 : 0) + (lane & 7);
    const uint32_t b_kext = (lane & 8) ? 16u : 0u;
    const int gq = lane >> 2;

    float avgf[2][8][4] = {};

    for (int h = 0; h < NH; ++h) {
        const int bb = h & 1;
        if (h + 1 < NH) {
            const uint32_t nb = sb + (1 - bb) * BUF2;
            cp_tile(Qb + (h + 1) * HD, H_, nb, tid);
            cp_tile(Kb + (h + 1) * HD, H_, nb + TILE_B, tid);
            CP_COMMIT();
            CP_WAIT(1);
        } else {
            CP_WAIT(0);
        }
        __syncthreads();

        float acc[2][8][4] = {};
        const uint32_t aS = sb + bb * BUF2;
        mma_tile_f16(acc, aS, aS + TILE_B, a_row, a_kext, b_row, b_kext);

        const float* Lh = iL + ((size_t)b * NH + h) * S_ + qt * 128;
#pragma unroll
        for (int ma = 0; ma < 2; ++ma) {
            const float l0 = Lh[wm * 32 + ma * 16 + gq];
            const float l1 = Lh[wm * 32 + ma * 16 + gq + 8];
#pragma unroll
            for (int n = 0; n < 8; ++n) {
                avgf[ma][n][0] += __expf(0.125f * acc[ma][n][0]) * l0;
                avgf[ma][n][1] += __expf(0.125f * acc[ma][n][1]) * l0;
                avgf[ma][n][2] += __expf(0.125f * acc[ma][n][2]) * l1;
                avgf[ma][n][3] += __expf(0.125f * acc[ma][n][3]) * l1;
            }
        }
        __syncthreads();
    }

    float* out = avg + (size_t)b * S_ * S_;
    const int tig = lane & 3;
#pragma unroll
    for (int ma = 0; ma < 2; ++ma) {
        const int r0 = qt * 128 + wm * 32 + ma * 16 + gq;
#pragma unroll
        for (int n = 0; n < 8; ++n) {
            const int col = kt * 128 + wn * 64 + n * 8 + tig * 2;
            *(float2*)(out + (size_t)r0 * S_ + col) = make_float2(avgf[ma][n][0], avgf[ma][n][1]);
            *(float2*)(out + (size_t)(r0 + 8) * S_ + col) = make_float2(avgf[ma][n][2], avgf[ma][n][3]);
        }
    }
}

// ---------------------------------------------------------------------------
// bf16x3 split GEMM (O projection)
// ---------------------------------------------------------------------------
__global__ void __launch_bounds__(256, 2)
hmma_bf16x3_nt(const __nv_bfloat16* __restrict__ hA, const __nv_bfloat16* __restrict__ lA,
               const __nv_bfloat16* __restrict__ hB, const __nv_bfloat16* __restrict__ lB,
               const float* __restrict__ bias, float* __restrict__ C,
               int K, int lda, int ldb, int ldc)
{
    extern __shared__ char smem[];
    const uint32_t sb = smem_u32(smem);
    const int tid = threadIdx.x, lane = tid & 31, w = tid >> 5;
    const int wm = w >> 1, wn = w & 1;
    const int m0 = blockIdx.y * 128, n0 = blockIdx.x * 128;

    hA += (size_t)m0 * lda; lA += (size_t)m0 * lda;
    hB += (size_t)n0 * ldb; lB += (size_t)n0 * ldb;

    cp_tile(hA, lda, sb + 0 * TILE_B, tid);
    cp_tile(lA, lda, sb + 1 * TILE_B, tid);
    cp_tile(hB, ldb, sb + 2 * TILE_B, tid);
    cp_tile(lB, ldb, sb + 3 * TILE_B, tid);
    CP_COMMIT();
    CP_WAIT(0);
    __syncthreads();

    float acc[2][8][4] = {};

    const int a_row = wm * 32 + (lane & 15);
    const uint32_t a_kext = (lane & 16) ? 16u : 0u;
    const int b_row = wn * 64 + ((lane & 16) ? 8 : 0) + (lane & 7);
    const uint32_t b_kext = (lane & 8) ? 16u : 0u;

    const uint32_t aH = sb, aL = sb + TILE_B, bH = sb + 2 * TILE_B, bL = sb + 3 * TILE_B;

#pragma unroll
    for (int ks = 0; ks < 4; ++ks) {
        uint32_t ah[2][4], al[2][4];
#pragma unroll
        for (int ma = 0; ma < 2; ++ma) {
            const uint32_t off =
                SWZ128((uint32_t)((a_row + ma * 16) * 128) + (uint32_t)(ks * 32) + a_kext);
            ldsm4(ah[ma][0], ah[ma][1], ah[ma][2], ah[ma][3], aH + off);
            ldsm4(al[ma][0], al[ma][1], al[ma][2], al[ma][3], aL + off);
        }
#pragma unroll
        for (int bg = 0; bg < 4; ++bg) {
            const uint32_t off =
                SWZ128((uint32_t)((b_row + bg * 16) * 128) + (uint32_t)(ks * 32) + b_kext);
            uint32_t bh[4], bl[4];
            ldsm4(bh[0], bh[1], bh[2], bh[3], bH + off);
            ldsm4(bl[0], bl[1], bl[2], bl[3], bL + off);
#pragma unroll
            for (int na = 0; na < 2; ++na) {
                const int n = bg * 2 + na;
#pragma unroll
                for (int ma = 0; ma < 2; ++ma) {
                    mma_bf16(acc[ma][n], ah[ma], &bh[na * 2]);
                    mma_bf16(acc[ma][n], ah[ma], &bl[na * 2]);
                    mma_bf16(acc[ma][n], al[ma], &bh[na * 2]);
                }
            }
        }
    }

    const int gq = lane >> 2, tig = lane & 3;
#pragma unroll
    for (int ma = 0; ma < 2; ++ma) {
        const int r0 = m0 + wm * 32 + ma * 16 + gq;
#pragma unroll
        for (int n = 0; n < 8; ++n) {
            const int col = n0 + wn * 64 + n * 8 + tig * 2;
            const float b0 = bias[col], b1 = bias[col + 1];
            *(float2*)(C + (size_t)r0 * ldc + col) =
                make_float2(acc[ma][n][0] + b0, acc[ma][n][1] + b1);
            *(float2*)(C + (size_t)(r0 + 8) * ldc + col) =
                make_float2(acc[ma][n][2] + b0, acc[ma][n][3] + b1);
        }
    }
}

// ---------------------------------------------------------------------------
// SIMT small-N kernels (V proj NT, PV NN)
// ---------------------------------------------------------------------------
__global__ void gemm_nt(const float* __restrict__ A, const float* __restrict__ Bm,
                        const float* __restrict__ bias, float* __restrict__ C,
                        int K, int lda, int ldb, int ldc)
{
    __shared__ float As[16][65];
    __shared__ float Bs[16][65];
    const int tx = threadIdx.x, ty = threadIdx.y;
    const int tid = ty * 16 + tx;
    const int m0 = blockIdx.y * 64, n0 = blockIdx.x * 64;
    const int rr = tid >> 2;
    const int kq = (tid & 3) << 2;

    const float* Ap = A + (size_t)(m0 + rr) * lda + kq;
    const float* Bp = Bm + (size_t)(n0 + rr) * ldb + kq;

    float acc[4][4] = {};
    for (int k0 = 0; k0 < K; k0 += 16) {
#pragma unroll
        for (int j = 0; j < 4; ++j) As[kq + j][rr] = Ap[j];
#pragma unroll
        for (int j = 0; j < 4; ++j) Bs[kq + j][rr] = Bp[j];
        __syncthreads();
#pragma unroll
        for (int kk = 0; kk < 16; ++kk) {
            float a[4], b[4];
#pragma unroll
            for (int i = 0; i < 4; ++i) a[i] = As[kk][ty * 4 + i];
#pragma unroll
            for (int j = 0; j < 4; ++j) b[j] = Bs[kk][tx * 4 + j];
#pragma unroll
            for (int i = 0; i < 4; ++i)
#pragma unroll
                for (int j = 0; j < 4; ++j) acc[i][j] += a[i] * b[j];
        }
        __syncthreads();
        Ap += 16; Bp += 16;
    }
#pragma unroll
    for (int i = 0; i < 4; ++i)
#pragma unroll
        for (int j = 0; j < 4; ++j) {
            const int n = n0 + tx * 4 + j;
            C[(size_t)(m0 + ty * 4 + i) * ldc + n] = acc[i][j] + (bias ? bias[n] : 0.f);
        }
}

__global__ void gemm_nn(const float* __restrict__ A, const float* __restrict__ Bm,
                        float* __restrict__ C,
                        int K, int lda, int ldb, int ldc, long sA, long sB, long sC)
{
    __shared__ float As[16][65];
    __shared__ float Bs[16][65];
    const int tx = threadIdx.x, ty = threadIdx.y;
    const int tid = ty * 16 + tx;
    const int m0 = blockIdx.y * 64, n0 = blockIdx.x * 64;
    const int rr = tid >> 2;
    const int kq = (tid & 3) << 2;
    const int kr = tid >> 4;
    const int nq = (tid & 15) << 2;

    const float* Ap = A + (size_t)blockIdx.z * sA + (size_t)(m0 + rr) * lda + kq;
    const float* Bp = Bm + (size_t)blockIdx.z * sB + (size_t)kr * ldb + n0 + nq;
    C += (size_t)blockIdx.z * sC;

    float acc[4][4] = {};
    for (int k0 = 0; k0 < K; k0 += 16) {
#pragma unroll
        for (int j = 0; j < 4; ++j) As[kq + j][rr] = Ap[j];
#pragma unroll
        for (int j = 0; j < 4; ++j) Bs[kr][nq + j] = Bp[j];
        __syncthreads();
#pragma unroll
        for (int kk = 0; kk < 16; ++kk) {
            float a[4], b[4];
#pragma unroll
            for (int i = 0; i < 4; ++i) a[i] = As[kk][ty * 4 + i];
#pragma unroll
            for (int j = 0; j < 4; ++j) b[j] = Bs[kk][tx * 4 + j];
#pragma unroll
            for (int i = 0; i < 4; ++i)
#pragma unroll
                for (int j = 0; j < 4; ++j) acc[i][j] += a[i] * b[j];
        }
        __syncthreads();
        Ap += 16; Bp += 16 * ldb;
    }
#pragma unroll
    for (int i = 0; i < 4; ++i)
#pragma unroll
        for (int j = 0; j < 4; ++j)
            C[(size_t)(m0 + ty * 4 + i) * ldc + (n0 + tx * 4 + j)] = acc[i][j];
}

extern "C" void kernel_launch(void* const* d_in, const int* in_sizes, int n_in,
                              void* d_out, int out_size)
{
    const float* query  = (const float*)d_in[0];
    const float* key_in = (const float*)d_in[1];
    const float* value  = (const float*)d_in[2];
    const float* Wq = (const float*)d_in[3];
    const float* bq = (const float*)d_in[4];
    const float* Wk = (const float*)d_in[5];
    const float* bk = (const float*)d_in[6];
    const float* Wv = (const float*)d_in[7];
    const float* bv = (const float*)d_in[8];
    const float* Wo = (const float*)d_in[9];
    const float* bo = (const float*)d_in[10];

    float* out = (float*)d_out;
    float* avg_out = out + (size_t)B_ * S_ * H_;

    float *gV, *gAO, *giL;
    __half *gA16, *gW16, *gQ16, *gK16;
    __nv_bfloat16 *hA, *lA, *hW, *lW;
    cudaGetSymbolAddress((void**)&gV, g_V);
    cudaGetSymbolAddress((void**)&gAO, g_AO);
    cudaGetSymbolAddress((void**)&giL, g_iL);
    cudaGetSymbolAddress((void**)&gA16, g_A16);
    cudaGetSymbolAddress((void**)&gW16, g_W16);
    cudaGetSymbolAddress((void**)&gQ16, g_Q16);
    cudaGetSymbolAddress((void**)&gK16, g_K16);
    cudaGetSymbolAddress((void**)&hA, g_hA);
    cudaGetSymbolAddress((void**)&lA, g_lA);
    cudaGetSymbolAddress((void**)&hW, g_hW);
    cudaGetSymbolAddress((void**)&lW, g_lW);

    cudaFuncSetAttribute(hmma_f16_nt, cudaFuncAttributeMaxDynamicSharedMemorySize, 2 * BUF2);
    cudaFuncSetAttribute(hmma_bf16x3_nt, cudaFuncAttributeMaxDynamicSharedMemorySize, BUF4);
    cudaFuncSetAttribute(qk_rowsum, cudaFuncAttributeMaxDynamicSharedMemorySize, 3 * TILE_B);
    cudaFuncSetAttribute(attn_avg, cudaFuncAttributeMaxDynamicSharedMemorySize, 2 * BUF2);

    const int M = B_ * S_;          // 8192
    const int NXH = B_ * S_ * H_;   // 8M

    // Q projection (fp16 single-term)
    cvt_f16_4<<<NXH / 1024, 256>>>((const float4*)query, (uint2*)gA16, NXH / 4);
    cvt_f16_4<<<(H_ * H_) / 1024, 256>>>((const float4*)Wq, (uint2*)gW16, H_ * H_ / 4);
    hmma_f16_nt<<<dim3(H_ / 128, M / 128, 1), 256, 2 * BUF2>>>(gA16, gW16, bq, gQ16,
                                                               H_, H_, H_, H_);
    // K projection
    cvt_f16_4<<<NXH / 1024, 256>>>((const float4*)key_in, (uint2*)gA16, NXH / 4);
    cvt_f16_4<<<(H_ * H_) / 1024, 256>>>((const float4*)Wk, (uint2*)gW16, H_ * H_ / 4);
    hmma_f16_nt<<<dim3(H_ / 128, M / 128, 1), 256, 2 * BUF2>>>(gA16, gW16, bk, gK16,
                                                               H_, H_, H_, H_);
    // V projection (fp32 SIMT, N=64)
    gemm_nt<<<dim3(1, M / 64, 1), dim3(16, 16)>>>(value, Wv, bv, gV, H_, H_, H_, HD);

    // Pass A: softmax denominators (no P materialization)
    qk_rowsum<<<dim3(S_ / 128, NH, B_), 256, 3 * TILE_B>>>(gQ16, gK16, giL);

    // Pass B: recompute scores, emit head-averaged softmax directly
    attn_avg<<<dim3(S_ / 128, S_ / 128, B_), 256, 2 * BUF2>>>(gQ16, gK16, giL, avg_out);

    // attn_out = avg_attn @ V (batched over B)
    gemm_nn<<<dim3(1, S_ / 64, B_), dim3(16, 16)>>>(avg_out, gV, gAO,
        S_, S_, HD, HD, (long)S_ * S_, (long)S_ * HD, (long)S_ * HD);

    // O projection (bf16x3)
    split_hl4<<<(B_ * S_ * HD) / 1024, 256>>>((const float4*)gAO, (uint2*)hA, (uint2*)lA,
                                              B_ * S_ * HD / 4);
    split_hl4<<<(H_ * HD) / 1024, 256>>>((const float4*)Wo, (uint2*)hW, (uint2*)lW, H_ * HD / 4);
    hmma_bf16x3_nt<<<dim3(H_ / 128, M / 128, 1), 256, BUF4>>>(hA, lA, hW, lW, bo,
        out, HD, HD, HD, H_);
}

// round 8
// speedup vs baseline: 6.6274x; 1.2185x over previous
#include <cuda_runtime.h>
#include <cuda_bf16.h>
#include <cuda_fp16.h>
#include <cstdint>

#define B_ 4
#define S_ 2048
#define H_ 1024
#define NH 16
#define HD 64

// scratch
__device__ float g_V[B_ * S_ * HD];
__device__ float g_AO[B_ * S_ * HD];
__device__ float g_iL[B_ * NH * S_];
__device__ __half g_VT16[B_ * HD * S_];     // V transposed: [b][d][s]
__device__ __half g_A16[B_ * S_ * H_];
__device__ __half g_W16[H_ * H_];
__device__ __half g_Q16[B_ * S_ * H_];
__device__ __half g_K16[B_ * S_ * H_];
__device__ __nv_bfloat16 g_hA[B_ * S_ * HD], g_lA[B_ * S_ * HD];
__device__ __nv_bfloat16 g_hW[H_ * HD],      g_lW[H_ * HD];

// ---------------------------------------------------------------------------
// Base-ISA helpers
// ---------------------------------------------------------------------------
__device__ __forceinline__ uint32_t smem_u32(const void* p) {
    uint32_t a;
    asm("{ .reg .u64 t; cvta.to.shared.u64 t, %1; cvt.u32.u64 %0, t; }" : "=r"(a) : "l"(p));
    return a;
}
#define SWZ128(x) ((x) ^ (((x) >> 3) & 0x70))

__device__ __forceinline__ void ldsm4(uint32_t& r0, uint32_t& r1, uint32_t& r2, uint32_t& r3,
                                      uint32_t addr) {
    asm volatile("ldmatrix.sync.aligned.m8n8.x4.shared.b16 {%0,%1,%2,%3}, [%4];"
                 : "=r"(r0), "=r"(r1), "=r"(r2), "=r"(r3) : "r"(addr));
}
__device__ __forceinline__ void mma_bf16(float* c, const uint32_t* a, const uint32_t* b) {
    asm volatile(
        "mma.sync.aligned.m16n8k16.row.col.f32.bf16.bf16.f32 "
        "{%0,%1,%2,%3}, {%4,%5,%6,%7}, {%8,%9}, {%0,%1,%2,%3};"
        : "+f"(c[0]), "+f"(c[1]), "+f"(c[2]), "+f"(c[3])
        : "r"(a[0]), "r"(a[1]), "r"(a[2]), "r"(a[3]), "r"(b[0]), "r"(b[1]));
}
__device__ __forceinline__ void mma_f16(float* c, const uint32_t* a, const uint32_t* b) {
    asm volatile(
        "mma.sync.aligned.m16n8k16.row.col.f32.f16.f16.f32 "
        "{%0,%1,%2,%3}, {%4,%5,%6,%7}, {%8,%9}, {%0,%1,%2,%3};"
        : "+f"(c[0]), "+f"(c[1]), "+f"(c[2]), "+f"(c[3])
        : "r"(a[0]), "r"(a[1]), "r"(a[2]), "r"(a[3]), "r"(b[0]), "r"(b[1]));
}
#define CP16(s, g) asm volatile("cp.async.cg.shared.global [%0], [%1], 16;" :: "r"(s), "l"(g))
#define CP_COMMIT() asm volatile("cp.async.commit_group;" ::: "memory")
#define CP_WAIT(n)  asm volatile("cp.async.wait_group %0;" :: "n"(n) : "memory")

#define TILE_B 16384
#define BUF2 (2 * TILE_B)
#define BUF4 (4 * TILE_B)

__device__ __forceinline__ void cp_tile(const void* __restrict__ g, int ld_elems,
                                        uint32_t sdst, int tid)
{
    const __half* gh = (const __half*)g;
#pragma unroll
    for (int it = 0; it < 4; ++it) {
        int i = tid + it * 256;
        int row = i >> 3, c = i & 7;
        const void* gp = gh + (size_t)row * ld_elems + c * 8;
        uint32_t sp = sdst + SWZ128((uint32_t)(row * 128 + c * 16));
        CP16(sp, gp);
    }
}

__device__ __forceinline__ void mma_tile_f16(float acc[2][8][4], uint32_t aS, uint32_t bS,
                                             int a_row, uint32_t a_kext,
                                             int b_row, uint32_t b_kext)
{
#pragma unroll
    for (int ks = 0; ks < 4; ++ks) {
        uint32_t ah[2][4];
#pragma unroll
        for (int ma = 0; ma < 2; ++ma) {
            const uint32_t off =
                SWZ128((uint32_t)((a_row + ma * 16) * 128) + (uint32_t)(ks * 32) + a_kext);
            ldsm4(ah[ma][0], ah[ma][1], ah[ma][2], ah[ma][3], aS + off);
        }
#pragma unroll
        for (int bg = 0; bg < 4; ++bg) {
            const uint32_t off =
                SWZ128((uint32_t)((b_row + bg * 16) * 128) + (uint32_t)(ks * 32) + b_kext);
            uint32_t bh[4];
            ldsm4(bh[0], bh[1], bh[2], bh[3], bS + off);
#pragma unroll
            for (int na = 0; na < 2; ++na)
#pragma unroll
                for (int ma = 0; ma < 2; ++ma)
                    mma_f16(acc[ma][bg * 2 + na], ah[ma], &bh[na * 2]);
        }
    }
}

// ---------------------------------------------------------------------------
// small utility kernels
// ---------------------------------------------------------------------------
__global__ void cvt_f16_4(const float4* __restrict__ x, uint2* __restrict__ y, int n4)
{
    int i = blockIdx.x * blockDim.x + threadIdx.x;
    if (i < n4) {
        float4 v = x[i];
        union { __half2 h2[2]; uint2 u; } p;
        p.h2[0] = __floats2half2_rn(v.x, v.y);
        p.h2[1] = __floats2half2_rn(v.z, v.w);
        y[i] = p.u;
    }
}

__global__ void split_hl4(const float4* __restrict__ x, uint2* __restrict__ hi,
                          uint2* __restrict__ lo, int n4)
{
    int i = blockIdx.x * blockDim.x + threadIdx.x;
    if (i < n4) {
        float4 v = x[i];
        __nv_bfloat16 h0 = __float2bfloat16(v.x), h1 = __float2bfloat16(v.y);
        __nv_bfloat16 h2 = __float2bfloat16(v.z), h3 = __float2bfloat16(v.w);
        __nv_bfloat16 l0 = __float2bfloat16(v.x - __bfloat162float(h0));
        __nv_bfloat16 l1 = __float2bfloat16(v.y - __bfloat162float(h1));
        __nv_bfloat16 l2 = __float2bfloat16(v.z - __bfloat162float(h2));
        __nv_bfloat16 l3 = __float2bfloat16(v.w - __bfloat162float(h3));
        union { __nv_bfloat162 b2[2]; uint2 u; } ph, pl;
        ph.b2[0].x = h0; ph.b2[0].y = h1; ph.b2[1].x = h2; ph.b2[1].y = h3;
        pl.b2[0].x = l0; pl.b2[0].y = l1; pl.b2[1].x = l2; pl.b2[1].y = l3;
        hi[i] = ph.u;
        lo[i] = pl.u;
    }
}

__global__ void zero_f(float* __restrict__ p, int n)
{
    int i = blockIdx.x * blockDim.x + threadIdx.x;
    if (i < n) p[i] = 0.f;
}

// V [b][s][64] fp32 -> VT [b][d][s] fp16 ; one block per 64x64 tile
__global__ void vt_cvt(const float* __restrict__ V, __half* __restrict__ VT)
{
    __shared__ float ts[64][65];
    const int s0 = blockIdx.x * 64, b = blockIdx.y;
    const int tid = threadIdx.x;
#pragma unroll
    for (int j = 0; j < 16; ++j) {
        int idx = tid + j * 256;
        int sl = idx >> 6, d = idx & 63;
        ts[sl][d] = V[((size_t)b * S_ + s0 + sl) * HD + d];
    }
    __syncthreads();
#pragma unroll
    for (int j = 0; j < 16; ++j) {
        int idx = tid + j * 256;
        int d = idx >> 6, sl = idx & 63;
        VT[((size_t)b * HD + d) * S_ + s0 + sl] = __float2half(ts[sl][d]);
    }
}

// ---------------------------------------------------------------------------
// fp16 GEMM for Q/K projections
// ---------------------------------------------------------------------------
__global__ void __launch_bounds__(256, 3)
hmma_f16_nt(const __half* __restrict__ A, const __half* __restrict__ Bm,
            const float* __restrict__ bias, __half* __restrict__ C16,
            int K, int lda, int ldb, int ldc)
{
    extern __shared__ char smem[];
    const uint32_t sb = smem_u32(smem);
    const int tid = threadIdx.x, lane = tid & 31, w = tid >> 5;
    const int wm = w >> 1, wn = w & 1;
    const int m0 = blockIdx.y * 128, n0 = blockIdx.x * 128;

    A  += (size_t)m0 * lda;
    Bm += (size_t)n0 * ldb;

    const int nch = K >> 6;

    cp_tile(A, lda, sb, tid);
    cp_tile(Bm, ldb, sb + TILE_B, tid);
    CP_COMMIT();

    float acc[2][8][4] = {};

    const int a_row = wm * 32 + (lane & 15);
    const uint32_t a_kext = (lane & 16) ? 16u : 0u;
    const int b_row = wn * 64 + ((lane & 16) ? 8 : 0) + (lane & 7);
    const uint32_t b_kext = (lane & 8) ? 16u : 0u;

    for (int c = 0; c < nch; ++c) {
        const int b = c & 1;
        if (c + 1 < nch) {
            const uint32_t nb = sb + (1 - b) * BUF2;
            const int ko = (c + 1) << 6;
            cp_tile(A + ko, lda, nb, tid);
            cp_tile(Bm + ko, ldb, nb + TILE_B, tid);
            CP_COMMIT();
            CP_WAIT(1);
        } else {
            CP_WAIT(0);
        }
        __syncthreads();
        const uint32_t aS = sb + b * BUF2;
        mma_tile_f16(acc, aS, aS + TILE_B, a_row, a_kext, b_row, b_kext);
        __syncthreads();
    }

    const int gq = lane >> 2, tig = lane & 3;
#pragma unroll
    for (int ma = 0; ma < 2; ++ma) {
        const int r0 = m0 + wm * 32 + ma * 16 + gq;
#pragma unroll
        for (int n = 0; n < 8; ++n) {
            const int col = n0 + wn * 64 + n * 8 + tig * 2;
            const float b0 = bias[col], b1 = bias[col + 1];
            *(__half2*)(C16 + (size_t)r0 * ldc + col) =
                __floats2half2_rn(acc[ma][n][0] + b0, acc[ma][n][1] + b1);
            *(__half2*)(C16 + (size_t)(r0 + 8) * ldc + col) =
                __floats2half2_rn(acc[ma][n][2] + b0, acc[ma][n][3] + b1);
        }
    }
}

// ---------------------------------------------------------------------------
// Pass A: per-(b,h,q) denominators
// ---------------------------------------------------------------------------
__global__ void __launch_bounds__(256, 2)
qk_rowsum(const __half* __restrict__ Q, const __half* __restrict__ Kt,
          float* __restrict__ iL)
{
    extern __shared__ char smem[];
    const uint32_t sb = smem_u32(smem);
    const int tid = threadIdx.x, lane = tid & 31, w = tid >> 5;
    const int wm = w >> 1, wn = w & 1;
    const int qt = blockIdx.x, h = blockIdx.y, b = blockIdx.z;

    const __half* Qb = Q + (size_t)b * S_ * H_ + (size_t)qt * 128 * H_ + h * HD;
    const __half* Kb = Kt + (size_t)b * S_ * H_ + h * HD;

    cp_tile(Qb, H_, sb, tid);
    cp_tile(Kb, H_, sb + TILE_B, tid);
    CP_COMMIT();

    const int a_row = wm * 32 + (lane & 15);
    const uint32_t a_kext = (lane & 16) ? 16u : 0u;
    const int b_row = wn * 64 + ((lane & 16) ? 8 : 0) + (lane & 7);
    const uint32_t b_kext = (lane & 8) ? 16u : 0u;

    float lsum[2][2] = {};

    for (int kt = 0; kt < 16; ++kt) {
        const int bb = kt & 1;
        if (kt + 1 < 16) {
            cp_tile(Kb + (size_t)(kt + 1) * 128 * H_, H_, sb + TILE_B + (1 - bb) * TILE_B, tid);
            CP_COMMIT();
            CP_WAIT(1);
        } else {
            CP_WAIT(0);
        }
        __syncthreads();

        float acc[2][8][4] = {};
        mma_tile_f16(acc, sb, sb + TILE_B + bb * TILE_B, a_row, a_kext, b_row, b_kext);

#pragma unroll
        for (int ma = 0; ma < 2; ++ma)
#pragma unroll
            for (int n = 0; n < 8; ++n) {
                lsum[ma][0] += __expf(0.125f * acc[ma][n][0]) + __expf(0.125f * acc[ma][n][1]);
                lsum[ma][1] += __expf(0.125f * acc[ma][n][2]) + __expf(0.125f * acc[ma][n][3]);
            }
        __syncthreads();
    }

#pragma unroll
    for (int o = 1; o <= 2; o <<= 1)
#pragma unroll
        for (int ma = 0; ma < 2; ++ma)
#pragma unroll
            for (int hh = 0; hh < 2; ++hh)
                lsum[ma][hh] += __shfl_xor_sync(0xffffffffu, lsum[ma][hh], o);

    __shared__ float Ls[128];
    if (tid < 128) Ls[tid] = 0.f;
    __syncthreads();
    if ((lane & 3) == 0) {
        const int gq = lane >> 2;
#pragma unroll
        for (int ma = 0; ma < 2; ++ma) {
            atomicAdd(&Ls[wm * 32 + ma * 16 + gq], lsum[ma][0]);
            atomicAdd(&Ls[wm * 32 + ma * 16 + gq + 8], lsum[ma][1]);
        }
    }
    __syncthreads();
    if (tid < 128)
        iL[((size_t)b * NH + h) * S_ + qt * 128 + tid] = 1.0f / (16.0f * Ls[tid]);
}

// ---------------------------------------------------------------------------
// Pass B: recompute scores for 16 heads, emit head-averaged softmax tile,
// then fuse PV: attn_out partial = avg_tile(fp16) @ V_tile -> atomicAdd.
// smem: Q/K dbuf 64KB @0 | P chunks 2x16KB @65536 | VT chunks 2x8KB @98304
// ---------------------------------------------------------------------------
#define SM_P  (2 * BUF2)
#define SM_VT (SM_P + 2 * 16384)
#define SM_AA (SM_VT + 2 * 8192)       // 114688

__global__ void __launch_bounds__(256, 1)
attn_avg(const __half* __restrict__ Q, const __half* __restrict__ Kt,
         const __half* __restrict__ VT, const float* __restrict__ iL,
         float* __restrict__ avg, float* __restrict__ AO)
{
    extern __shared__ char smem[];
    const uint32_t sb = smem_u32(smem);
    const int tid = threadIdx.x, lane = tid & 31, w = tid >> 5;
    const int wm = w >> 1, wn = w & 1;
    const int kt = blockIdx.x, qt = blockIdx.y, b = blockIdx.z;

    const __half* Qb = Q + (size_t)b * S_ * H_ + (size_t)qt * 128 * H_;
    const __half* Kb = Kt + (size_t)b * S_ * H_ + (size_t)kt * 128 * H_;

    cp_tile(Qb, H_, sb, tid);
    cp_tile(Kb, H_, sb + TILE_B, tid);
    CP_COMMIT();

    const int a_row = wm * 32 + (lane & 15);
    const uint32_t a_kext = (lane & 16) ? 16u : 0u;
    const int b_row = wn * 64 + ((lane & 16) ? 8 : 0) + (lane & 7);
    const uint32_t b_kext = (lane & 8) ? 16u : 0u;
    const int gq = lane >> 2, tig = lane & 3;

    float avgf[2][8][4] = {};

    for (int h = 0; h < NH; ++h) {
        const int bb = h & 1;
        if (h + 1 < NH) {
            const uint32_t nb = sb + (1 - bb) * BUF2;
            cp_tile(Qb + (h + 1) * HD, H_, nb, tid);
            cp_tile(Kb + (h + 1) * HD, H_, nb + TILE_B, tid);
            CP_COMMIT();
            CP_WAIT(1);
        } else {
            CP_WAIT(0);
        }
        __syncthreads();

        float acc[2][8][4] = {};
        const uint32_t aS = sb + bb * BUF2;
        mma_tile_f16(acc, aS, aS + TILE_B, a_row, a_kext, b_row, b_kext);

        const float* Lh = iL + ((size_t)b * NH + h) * S_ + qt * 128;
#pragma unroll
        for (int ma = 0; ma < 2; ++ma) {
            const float l0 = Lh[wm * 32 + ma * 16 + gq];
            const float l1 = Lh[wm * 32 + ma * 16 + gq + 8];
#pragma unroll
            for (int n = 0; n < 8; ++n) {
                avgf[ma][n][0] += __expf(0.125f * acc[ma][n][0]) * l0;
                avgf[ma][n][1] += __expf(0.125f * acc[ma][n][1]) * l0;
                avgf[ma][n][2] += __expf(0.125f * acc[ma][n][2]) * l1;
                avgf[ma][n][3] += __expf(0.125f * acc[ma][n][3]) * l1;
            }
        }
        __syncthreads();
    }

    // write avg tile (mandatory output) + stage fp16 copy into P smem chunks
    float* outp = avg + (size_t)b * S_ * S_;
#pragma unroll
    for (int ma = 0; ma < 2; ++ma) {
        const int rl = wm * 32 + ma * 16 + gq;
        const int r0 = qt * 128 + rl;
#pragma unroll
        for (int n = 0; n < 8; ++n) {
            const int col = wn * 64 + n * 8 + tig * 2;
            *(float2*)(outp + (size_t)r0 * S_ + kt * 128 + col) =
                make_float2(avgf[ma][n][0], avgf[ma][n][1]);
            *(float2*)(outp + (size_t)(r0 + 8) * S_ + kt * 128 + col) =
                make_float2(avgf[ma][n][2], avgf[ma][n][3]);
            const uint32_t pbase = sb + SM_P + (col >> 6) * 16384;
            const uint32_t cc = (col & 63) * 2;
            __half2 p0 = __floats2half2_rn(avgf[ma][n][0], avgf[ma][n][1]);
            __half2 p1 = __floats2half2_rn(avgf[ma][n][2], avgf[ma][n][3]);
            *(__half2*)(smem + (pbase - sb) + SWZ128((uint32_t)(rl * 128) + cc)) = p0;
            *(__half2*)(smem + (pbase - sb) + SWZ128((uint32_t)((rl + 8) * 128) + cc)) = p1;
        }
    }

    // load VT tile: d 0..63, k = kt*128 + chunk*64 + 0..63
    {
        const __half* Vb = VT + (size_t)b * HD * S_ + (size_t)kt * 128;
#pragma unroll
        for (int cck = 0; cck < 2; ++cck) {
#pragma unroll
            for (int it = 0; it < 2; ++it) {
                int i = tid + it * 256;
                int d = i >> 3, c8 = i & 7;
                uint4 v = *(const uint4*)(Vb + (size_t)d * S_ + cck * 64 + c8 * 8);
                *(uint4*)(smem + SM_VT + cck * 8192 + SWZ128((uint32_t)(d * 128 + c8 * 16))) = v;
            }
        }
    }
    __syncthreads();

    // PV: [128q x 64d] += P[128q x 128k] @ VT[64d x 128k]^T
    float apv[2][4][4] = {};
    const int pv_brow = wn * 32 + ((lane & 16) ? 8 : 0) + (lane & 7);
#pragma unroll
    for (int c = 0; c < 2; ++c) {
        const uint32_t pS = sb + SM_P + c * 16384;
        const uint32_t vS = sb + SM_VT + c * 8192;
#pragma unroll
        for (int ks = 0; ks < 4; ++ks) {
            uint32_t ah[2][4];
#pragma unroll
            for (int ma = 0; ma < 2; ++ma) {
                const uint32_t off =
                    SWZ128((uint32_t)((a_row + ma * 16) * 128) + (uint32_t)(ks * 32) + a_kext);
                ldsm4(ah[ma][0], ah[ma][1], ah[ma][2], ah[ma][3], pS + off);
            }
#pragma unroll
            for (int bg = 0; bg < 2; ++bg) {
                const uint32_t off =
                    SWZ128((uint32_t)((pv_brow + bg * 16) * 128) + (uint32_t)(ks * 32) + b_kext);
                uint32_t bh[4];
                ldsm4(bh[0], bh[1], bh[2], bh[3], vS + off);
#pragma unroll
                for (int na = 0; na < 2; ++na)
#pragma unroll
                    for (int ma = 0; ma < 2; ++ma)
                        mma_f16(apv[ma][bg * 2 + na], ah[ma], &bh[na * 2]);
            }
        }
    }

    // accumulate partial attn_out
#pragma unroll
    for (int ma = 0; ma < 2; ++ma) {
        const int r0 = qt * 128 + wm * 32 + ma * 16 + gq;
#pragma unroll
        for (int nI = 0; nI < 4; ++nI) {
            const int d = wn * 32 + nI * 8 + tig * 2;
            float* a0 = AO + ((size_t)b * S_ + r0) * HD + d;
            float* a1 = AO + ((size_t)b * S_ + r0 + 8) * HD + d;
            atomicAdd(a0, apv[ma][nI][0]);
            atomicAdd(a0 + 1, apv[ma][nI][1]);
            atomicAdd(a1, apv[ma][nI][2]);
            atomicAdd(a1 + 1, apv[ma][nI][3]);
        }
    }
}

// ---------------------------------------------------------------------------
// bf16x3 split GEMM (O projection, K=64 single chunk)
// ---------------------------------------------------------------------------
__global__ void __launch_bounds__(256, 2)
hmma_bf16x3_nt(const __nv_bfloat16* __restrict__ hA, const __nv_bfloat16* __restrict__ lA,
               const __nv_bfloat16* __restrict__ hB, const __nv_bfloat16* __restrict__ lB,
               const float* __restrict__ bias, float* __restrict__ C,
               int K, int lda, int ldb, int ldc)
{
    extern __shared__ char smem[];
    const uint32_t sb = smem_u32(smem);
    const int tid = threadIdx.x, lane = tid & 31, w = tid >> 5;
    const int wm = w >> 1, wn = w & 1;
    const int m0 = blockIdx.y * 128, n0 = blockIdx.x * 128;

    hA += (size_t)m0 * lda; lA += (size_t)m0 * lda;
    hB += (size_t)n0 * ldb; lB += (size_t)n0 * ldb;

    cp_tile(hA, lda, sb + 0 * TILE_B, tid);
    cp_tile(lA, lda, sb + 1 * TILE_B, tid);
    cp_tile(hB, ldb, sb + 2 * TILE_B, tid);
    cp_tile(lB, ldb, sb + 3 * TILE_B, tid);
    CP_COMMIT();
    CP_WAIT(0);
    __syncthreads();

    float acc[2][8][4] = {};

    const int a_row = wm * 32 + (lane & 15);
    const uint32_t a_kext = (lane & 16) ? 16u : 0u;
    const int b_row = wn * 64 + ((lane & 16) ? 8 : 0) + (lane & 7);
    const uint32_t b_kext = (lane & 8) ? 16u : 0u;

    const uint32_t aH = sb, aL = sb + TILE_B, bH = sb + 2 * TILE_B, bL = sb + 3 * TILE_B;

#pragma unroll
    for (int ks = 0; ks < 4; ++ks) {
        uint32_t ah[2][4], al[2][4];
#pragma unroll
        for (int ma = 0; ma < 2; ++ma) {
            const uint32_t off =
                SWZ128((uint32_t)((a_row + ma * 16) * 128) + (uint32_t)(ks * 32) + a_kext);
            ldsm4(ah[ma][0], ah[ma][1], ah[ma][2], ah[ma][3], aH + off);
            ldsm4(al[ma][0], al[ma][1], al[ma][2], al[ma][3], aL + off);
        }
#pragma unroll
        for (int bg = 0; bg < 4; ++bg) {
            const uint32_t off =
                SWZ128((uint32_t)((b_row + bg * 16) * 128) + (uint32_t)(ks * 32) + b_kext);
            uint32_t bh[4], bl[4];
            ldsm4(bh[0], bh[1], bh[2], bh[3], bH + off);
            ldsm4(bl[0], bl[1], bl[2], bl[3], bL + off);
#pragma unroll
            for (int na = 0; na < 2; ++na) {
                const int n = bg * 2 + na;
#pragma unroll
                for (int ma = 0; ma < 2; ++ma) {
                    mma_bf16(acc[ma][n], ah[ma], &bh[na * 2]);
                    mma_bf16(acc[ma][n], ah[ma], &bl[na * 2]);
                    mma_bf16(acc[ma][n], al[ma], &bh[na * 2]);
                }
            }
        }
    }

    const int gq = lane >> 2, tig = lane & 3;
#pragma unroll
    for (int ma = 0; ma < 2; ++ma) {
        const int r0 = m0 + wm * 32 + ma * 16 + gq;
#pragma unroll
        for (int n = 0; n < 8; ++n) {
            const int col = n0 + wn * 64 + n * 8 + tig * 2;
            const float b0 = bias[col], b1 = bias[col + 1];
            *(float2*)(C + (size_t)r0 * ldc + col) =
                make_float2(acc[ma][n][0] + b0, acc[ma][n][1] + b1);
            *(float2*)(C + (size_t)(r0 + 8) * ldc + col) =
                make_float2(acc[ma][n][2] + b0, acc[ma][n][3] + b1);
        }
    }
}

// ---------------------------------------------------------------------------
// SIMT V projection (fp32, N=64)
// ---------------------------------------------------------------------------
__global__ void gemm_nt(const float* __restrict__ A, const float* __restrict__ Bm,
                        const float* __restrict__ bias, float* __restrict__ C,
                        int K, int lda, int ldb, int ldc)
{
    __shared__ float As[16][65];
    __shared__ float Bs[16][65];
    const int tx = threadIdx.x, ty = threadIdx.y;
    const int tid = ty * 16 + tx;
    const int m0 = blockIdx.y * 64, n0 = blockIdx.x * 64;
    const int rr = tid >> 2;
    const int kq = (tid & 3) << 2;

    const float* Ap = A + (size_t)(m0 + rr) * lda + kq;
    const float* Bp = Bm + (size_t)(n0 + rr) * ldb + kq;

    float acc[4][4] = {};
    for (int k0 = 0; k0 < K; k0 += 16) {
#pragma unroll
        for (int j = 0; j < 4; ++j) As[kq + j][rr] = Ap[j];
#pragma unroll
        for (int j = 0; j < 4; ++j) Bs[kq + j][rr] = Bp[j];
        __syncthreads();
#pragma unroll
        for (int kk = 0; kk < 16; ++kk) {
            float a[4], b[4];
#pragma unroll
            for (int i = 0; i < 4; ++i) a[i] = As[kk][ty * 4 + i];
#pragma unroll
            for (int j = 0; j < 4; ++j) b[j] = Bs[kk][tx * 4 + j];
#pragma unroll
            for (int i = 0; i < 4; ++i)
#pragma unroll
                for (int j = 0; j < 4; ++j) acc[i][j] += a[i] * b[j];
        }
        __syncthreads();
        Ap += 16; Bp += 16;
    }
#pragma unroll
    for (int i = 0; i < 4; ++i)
#pragma unroll
        for (int j = 0; j < 4; ++j) {
            const int n = n0 + tx * 4 + j;
            C[(size_t)(m0 + ty * 4 + i) * ldc + n] = acc[i][j] + (bias ? bias[n] : 0.f);
        }
}

extern "C" void kernel_launch(void* const* d_in, const int* in_sizes, int n_in,
                              void* d_out, int out_size)
{
    const float* query  = (const float*)d_in[0];
    const float* key_in = (const float*)d_in[1];
    const float* value  = (const float*)d_in[2];
    const float* Wq = (const float*)d_in[3];
    const float* bq = (const float*)d_in[4];
    const float* Wk = (const float*)d_in[5];
    const float* bk = (const float*)d_in[6];
    const float* Wv = (const float*)d_in[7];
    const float* bv = (const float*)d_in[8];
    const float* Wo = (const float*)d_in[9];
    const float* bo = (const float*)d_in[10];

    float* out = (float*)d_out;
    float* avg_out = out + (size_t)B_ * S_ * H_;

    float *gV, *gAO, *giL;
    __half *gA16, *gW16, *gQ16, *gK16, *gVT16;
    __nv_bfloat16 *hA, *lA, *hW, *lW;
    cudaGetSymbolAddress((void**)&gV, g_V);
    cudaGetSymbolAddress((void**)&gAO, g_AO);
    cudaGetSymbolAddress((void**)&giL, g_iL);
    cudaGetSymbolAddress((void**)&gA16, g_A16);
    cudaGetSymbolAddress((void**)&gW16, g_W16);
    cudaGetSymbolAddress((void**)&gQ16, g_Q16);
    cudaGetSymbolAddress((void**)&gK16, g_K16);
    cudaGetSymbolAddress((void**)&gVT16, g_VT16);
    cudaGetSymbolAddress((void**)&hA, g_hA);
    cudaGetSymbolAddress((void**)&lA, g_lA);
    cudaGetSymbolAddress((void**)&hW, g_hW);
    cudaGetSymbolAddress((void**)&lW, g_lW);

    cudaFuncSetAttribute(hmma_f16_nt, cudaFuncAttributeMaxDynamicSharedMemorySize, 2 * BUF2);
    cudaFuncSetAttribute(hmma_bf16x3_nt, cudaFuncAttributeMaxDynamicSharedMemorySize, BUF4);
    cudaFuncSetAttribute(qk_rowsum, cudaFuncAttributeMaxDynamicSharedMemorySize, 3 * TILE_B);
    cudaFuncSetAttribute(attn_avg, cudaFuncAttributeMaxDynamicSharedMemorySize, SM_AA);

    const int M = B_ * S_;          // 8192
    const int NXH = B_ * S_ * H_;   // 8M

    // zero attn_out accumulator (graph-replay safe)
    zero_f<<<(B_ * S_ * HD) / 256, 256>>>(gAO, B_ * S_ * HD);

    // Q projection (fp16)
    cvt_f16_4<<<NXH / 1024, 256>>>((const float4*)query, (uint2*)gA16, NXH / 4);
    cvt_f16_4<<<(H_ * H_) / 1024, 256>>>((const float4*)Wq, (uint2*)gW16, H_ * H_ / 4);
    hmma_f16_nt<<<dim3(H_ / 128, M / 128, 1), 256, 2 * BUF2>>>(gA16, gW16, bq, gQ16,
                                                               H_, H_, H_, H_);
    // K projection
    cvt_f16_4<<<NXH / 1024, 256>>>((const float4*)key_in, (uint2*)gA16, NXH / 4);
    cvt_f16_4<<<(H_ * H_) / 1024, 256>>>((const float4*)Wk, (uint2*)gW16, H_ * H_ / 4);
    hmma_f16_nt<<<dim3(H_ / 128, M / 128, 1), 256, 2 * BUF2>>>(gA16, gW16, bk, gK16,
                                                               H_, H_, H_, H_);
    // V projection (fp32 SIMT) + transpose/convert
    gemm_nt<<<dim3(1, M / 64, 1), dim3(16, 16)>>>(value, Wv, bv, gV, H_, H_, H_, HD);
    vt_cvt<<<dim3(S_ / 64, B_), 256>>>(gV, gVT16);

    // Pass A: softmax denominators
    qk_rowsum<<<dim3(S_ / 128, NH, B_), 256, 3 * TILE_B>>>(gQ16, gK16, giL);

    // Pass B: head-averaged softmax + fused PV accumulation
    attn_avg<<<dim3(S_ / 128, S_ / 128, B_), 256, SM_AA>>>(gQ16, gK16, gVT16, giL,
                                                           avg_out, gAO);

    // O projection (bf16x3)
    split_hl4<<<(B_ * S_ * HD) / 1024, 256>>>((const float4*)gAO, (uint2*)hA, (uint2*)lA,
                                              B_ * S_ * HD / 4);
    split_hl4<<<(H_ * HD) / 1024, 256>>>((const float4*)Wo, (uint2*)hW, (uint2*)lW, H_ * HD / 4);
    hmma_bf16x3_nt<<<dim3(H_ / 128, M / 128, 1), 256, BUF4>>>(hA, lA, hW, lW, bo,
        out, HD, HD, HD, H_);
}

// round 10
// speedup vs baseline: 8.6557x; 1.3060x over previous
#include <cuda_runtime.h>
#include <cuda_bf16.h>
#include <cuda_fp16.h>
#include <cstdint>

#define B_ 4
#define S_ 2048
#define H_ 1024
#define NH 16
#define HD 64

#define TAB 18432            // packed tile: 128 rows x 144B pitch (64 fp16 cols)
#define VTB 17408            // VT tile: 64 rows x 272B pitch (128 fp16 cols)

// scratch
__device__ float g_V[B_ * S_ * HD];
__device__ float g_AO[B_ * S_ * HD];
__device__ float g_iL[B_ * NH * S_];
__device__ __align__(16) char g_Ap[64 * 16 * TAB];   // packed activations (query/key reuse)
__device__ __align__(16) char g_Wp[8 * 16 * TAB];    // packed weights
__device__ __align__(16) char g_Qp[64 * 16 * TAB];   // packed Q (tile rt = b*16+qt, chunk = head)
__device__ __align__(16) char g_Kp[64 * 16 * TAB];   // packed K
__device__ __align__(16) char g_VTp[64 * VTB];       // packed V^T tiles (b*16+kt)
__device__ __nv_bfloat16 g_hA[B_ * S_ * HD], g_lA[B_ * S_ * HD];
__device__ __nv_bfloat16 g_hW[H_ * HD],      g_lW[H_ * HD];

// ---------------------------------------------------------------------------
// helpers
// ---------------------------------------------------------------------------
__device__ __forceinline__ uint32_t smem_u32(const void* p) {
    uint32_t a;
    asm("{ .reg .u64 t; cvta.to.shared.u64 t, %1; cvt.u32.u64 %0, t; }" : "=r"(a) : "l"(p));
    return a;
}
#define SWZ128(x) ((x) ^ (((x) >> 3) & 0x70))

__device__ __forceinline__ void ldsm4(uint32_t& r0, uint32_t& r1, uint32_t& r2, uint32_t& r3,
                                      uint32_t addr) {
    asm volatile("ldmatrix.sync.aligned.m8n8.x4.shared.b16 {%0,%1,%2,%3}, [%4];"
                 : "=r"(r0), "=r"(r1), "=r"(r2), "=r"(r3) : "r"(addr));
}
__device__ __forceinline__ void mma_bf16(float* c, const uint32_t* a, const uint32_t* b) {
    asm volatile(
        "mma.sync.aligned.m16n8k16.row.col.f32.bf16.bf16.f32 "
        "{%0,%1,%2,%3}, {%4,%5,%6,%7}, {%8,%9}, {%0,%1,%2,%3};"
        : "+f"(c[0]), "+f"(c[1]), "+f"(c[2]), "+f"(c[3])
        : "r"(a[0]), "r"(a[1]), "r"(a[2]), "r"(a[3]), "r"(b[0]), "r"(b[1]));
}
__device__ __forceinline__ void mma_f16(float* c, const uint32_t* a, const uint32_t* b) {
    asm volatile(
        "mma.sync.aligned.m16n8k16.row.col.f32.f16.f16.f32 "
        "{%0,%1,%2,%3}, {%4,%5,%6,%7}, {%8,%9}, {%0,%1,%2,%3};"
        : "+f"(c[0]), "+f"(c[1]), "+f"(c[2]), "+f"(c[3])
        : "r"(a[0]), "r"(a[1]), "r"(a[2]), "r"(a[3]), "r"(b[0]), "r"(b[1]));
}
#define CP16(s, g) asm volatile("cp.async.cg.shared.global [%0], [%1], 16;" :: "r"(s), "l"(g))
#define CP_COMMIT() asm volatile("cp.async.commit_group;" ::: "memory")
#define CP_WAIT(n)  asm volatile("cp.async.wait_group %0;" :: "n"(n) : "memory")

// --- TMA bulk-copy + mbarrier (base sm_90 PTX; NOT 'a'-gated) ---
__device__ __forceinline__ void bulk_cp(uint32_t sdst, const void* gsrc, uint32_t bytes,
                                        uint32_t mbar) {
    asm volatile(
        "cp.async.bulk.shared::cta.global.mbarrier::complete_tx::bytes [%0], [%1], %2, [%3];"
        :: "r"(sdst), "l"(gsrc), "r"(bytes), "r"(mbar) : "memory");
}
#define MBAR_INIT(a, n) \
    asm volatile("mbarrier.init.shared.b64 [%0], %1;" :: "r"(a), "r"((uint32_t)(n)) : "memory")
#define MBAR_EXPECT(a, bytes) \
    asm volatile("mbarrier.arrive.expect_tx.shared.b64 _, [%0], %1;" \
                 :: "r"(a), "r"((uint32_t)(bytes)) : "memory")
__device__ __forceinline__ void mbar_wait(uint32_t mbar, int parity) {
    asm volatile(
        "{\n\t.reg .pred P;\n\t"
        "LAB_%=:\n\t"
        "mbarrier.try_wait.parity.acquire.cta.shared::cta.b64 P, [%0], %1;\n\t"
        "@!P bra LAB_%=;\n\t}"
        :: "r"(mbar), "r"((uint32_t)parity) : "memory");
}

// LDGSTS staging (kept for O-projection only)
__device__ __forceinline__ void cp_tile(const void* __restrict__ g, int ld_elems,
                                        uint32_t sdst, int tid)
{
    const __half* gh = (const __half*)g;
#pragma unroll
    for (int it = 0; it < 4; ++it) {
        int i = tid + it * 256;
        int row = i >> 3, c = i & 7;
        const void* gp = gh + (size_t)row * ld_elems + c * 8;
        uint32_t sp = sdst + SWZ128((uint32_t)(row * 128 + c * 16));
        CP16(sp, gp);
    }
}

// 128x128x64 fp16 MMA on two pitch-144 tiles
__device__ __forceinline__ void mma_tile144(float acc[2][8][4], uint32_t aS, uint32_t bS,
                                            int a_row, uint32_t a_kext,
                                            int b_row, uint32_t b_kext)
{
#pragma unroll
    for (int ks = 0; ks < 4; ++ks) {
        uint32_t ah[2][4];
#pragma unroll
        for (int ma = 0; ma < 2; ++ma) {
            const uint32_t off = (uint32_t)((a_row + ma * 16) * 144 + ks * 32) + a_kext;
            ldsm4(ah[ma][0], ah[ma][1], ah[ma][2], ah[ma][3], aS + off);
        }
#pragma unroll
        for (int bg = 0; bg < 4; ++bg) {
            const uint32_t off = (uint32_t)((b_row + bg * 16) * 144 + ks * 32) + b_kext;
            uint32_t bh[4];
            ldsm4(bh[0], bh[1], bh[2], bh[3], bS + off);
#pragma unroll
            for (int na = 0; na < 2; ++na)
#pragma unroll
                for (int ma = 0; ma < 2; ++ma)
                    mma_f16(acc[ma][bg * 2 + na], ah[ma], &bh[na * 2]);
        }
    }
}

// ---------------------------------------------------------------------------
// utility kernels
// ---------------------------------------------------------------------------
// fp32 [rows x 1024] -> packed fp16 tiles (rt, chunk) 128x64 @ pitch 144
__global__ void cvt_pack(const float4* __restrict__ x, char* __restrict__ out, int n4)
{
    int i = blockIdx.x * blockDim.x + threadIdx.x;
    if (i >= n4) return;
    float4 v = x[i];
    union { __half2 h2[2]; uint2 u; } p;
    p.h2[0] = __floats2half2_rn(v.x, v.y);
    p.h2[1] = __floats2half2_rn(v.z, v.w);
    int row = i >> 8;              // 1024 cols / 4
    int col = (i & 255) << 2;
    int rt = row >> 7, r = row & 127, c = col >> 6, k = col & 63;
    *(uint2*)(out + (size_t)(rt * 16 + c) * TAB + r * 144 + k * 2) = p.u;
}

__global__ void split_hl4(const float4* __restrict__ x, uint2* __restrict__ hi,
                          uint2* __restrict__ lo, int n4)
{
    int i = blockIdx.x * blockDim.x + threadIdx.x;
    if (i < n4) {
        float4 v = x[i];
        __nv_bfloat16 h0 = __float2bfloat16(v.x), h1 = __float2bfloat16(v.y);
        __nv_bfloat16 h2 = __float2bfloat16(v.z), h3 = __float2bfloat16(v.w);
        __nv_bfloat16 l0 = __float2bfloat16(v.x - __bfloat162float(h0));
        __nv_bfloat16 l1 = __float2bfloat16(v.y - __bfloat162float(h1));
        __nv_bfloat16 l2 = __float2bfloat16(v.z - __bfloat162float(h2));
        __nv_bfloat16 l3 = __float2bfloat16(v.w - __bfloat162float(h3));
        union { __nv_bfloat162 b2[2]; uint2 u; } ph, pl;
        ph.b2[0].x = h0; ph.b2[0].y = h1; ph.b2[1].x = h2; ph.b2[1].y = h3;
        pl.b2[0].x = l0; pl.b2[0].y = l1; pl.b2[1].x = l2; pl.b2[1].y = l3;
        hi[i] = ph.u;
        lo[i] = pl.u;
    }
}

__global__ void zero_f(float* __restrict__ p, int n)
{
    int i = blockIdx.x * blockDim.x + threadIdx.x;
    if (i < n) p[i] = 0.f;
}

// V [b][s][64] fp32 -> packed VT tiles (b*16+kt): 64 d-rows x 128 s-cols @ pitch 272
__global__ void vt_cvt_p(const float* __restrict__ V, char* __restrict__ VTp)
{
    __shared__ float ts[64][65];
    const int s0 = blockIdx.x * 64, b = blockIdx.y;
    const int tid = threadIdx.x;
#pragma unroll
    for (int j = 0; j < 16; ++j) {
        int idx = tid + j * 256;
        int sl = idx >> 6, d = idx & 63;
        ts[sl][d] = V[((size_t)b * S_ + s0 + sl) * HD + d];
    }
    __syncthreads();
    const int kt = s0 >> 7, sc0 = s0 & 127;
#pragma unroll
    for (int j = 0; j < 16; ++j) {
        int idx = tid + j * 256;
        int d = idx >> 6, sl = idx & 63;
        *(__half*)(VTp + (size_t)(b * 16 + kt) * VTB + d * 272 + (sc0 + sl) * 2) =
            __float2half(ts[sl][d]);
    }
}

// ---------------------------------------------------------------------------
// fp16 projection GEMM on packed tiles, TMA-bulk staged.
// grid (8 n-tiles, 64 m-tiles). Output written PACKED (tile = m-tile, chunk = col/64).
// ---------------------------------------------------------------------------
__global__ void __launch_bounds__(256, 2)
proj_f16(const char* __restrict__ Ap, const char* __restrict__ Wp,
         const float* __restrict__ bias, char* __restrict__ Cp)
{
    extern __shared__ char smem[];
    __shared__ uint64_t mb[2];
    const uint32_t sb = smem_u32(smem);
    const int tid = threadIdx.x, lane = tid & 31, w = tid >> 5;
    const int wm = w >> 1, wn = w & 1;
    const int nx = blockIdx.x, my = blockIdx.y;

    const uint32_t mbar0 = smem_u32(&mb[0]), mbar1 = smem_u32(&mb[1]);
    if (tid == 0) { MBAR_INIT(mbar0, 1); MBAR_INIT(mbar1, 1); }
    __syncthreads();

    const char* Asrc = Ap + (size_t)my * 16 * TAB;
    const char* Wsrc = Wp + (size_t)nx * 16 * TAB;

    if (tid == 0) {
        MBAR_EXPECT(mbar0, 2 * TAB);
        bulk_cp(sb, Asrc, TAB, mbar0);
        bulk_cp(sb + TAB, Wsrc, TAB, mbar0);
    }

    float acc[2][8][4] = {};
    const int a_row = wm * 32 + (lane & 15);
    const uint32_t a_kext = (lane & 16) ? 16u : 0u;
    const int b_row = wn * 64 + ((lane & 16) ? 8 : 0) + (lane & 7);
    const uint32_t b_kext = (lane & 8) ? 16u : 0u;
    int ph0 = 0, ph1 = 0;

    for (int c = 0; c < 16; ++c) {
        const int b = c & 1;
        if (c + 1 < 16 && tid == 0) {
            const uint32_t nb = sb + (1 - b) * 2 * TAB;
            const uint32_t m = b ? mbar0 : mbar1;
            MBAR_EXPECT(m, 2 * TAB);
            bulk_cp(nb, Asrc + (size_t)(c + 1) * TAB, TAB, m);
            bulk_cp(nb + TAB, Wsrc + (size_t)(c + 1) * TAB, TAB, m);
        }
        if (b == 0) { mbar_wait(mbar0, ph0); ph0 ^= 1; }
        else        { mbar_wait(mbar1, ph1); ph1 ^= 1; }
        const uint32_t aS = sb + b * 2 * TAB;
        mma_tile144(acc, aS, aS + TAB, a_row, a_kext, b_row, b_kext);
        __syncthreads();
    }

    const int gq = lane >> 2, tig = lane & 3;
#pragma unroll
    for (int ma = 0; ma < 2; ++ma) {
        const int rl = wm * 32 + ma * 16 + gq;
#pragma unroll
        for (int n = 0; n < 8; ++n) {
            const int col = nx * 128 + wn * 64 + n * 8 + tig * 2;
            const float b0 = bias[col], b1 = bias[col + 1];
            const size_t tb = (size_t)(my * 16 + (col >> 6)) * TAB + (col & 63) * 2;
            *(__half2*)(Cp + tb + rl * 144) =
                __floats2half2_rn(acc[ma][n][0] + b0, acc[ma][n][1] + b1);
            *(__half2*)(Cp + tb + (rl + 8) * 144) =
                __floats2half2_rn(acc[ma][n][2] + b0, acc[ma][n][3] + b1);
        }
    }
}

// ---------------------------------------------------------------------------
// Pass A: per-(b,h,q) softmax denominators. TMA-bulk staged packed tiles.
// smem: Q 18432 | K0 18432 | K1 18432
// ---------------------------------------------------------------------------
__global__ void __launch_bounds__(256, 2)
qk_rowsum_p(const char* __restrict__ Qp, const char* __restrict__ Kp, float* __restrict__ iL)
{
    extern __shared__ char smem[];
    __shared__ uint64_t mb[2];
    const uint32_t sb = smem_u32(smem);
    const int tid = threadIdx.x, lane = tid & 31, w = tid >> 5;
    const int wm = w >> 1, wn = w & 1;
    const int qt = blockIdx.x, h = blockIdx.y, b = blockIdx.z;

    const uint32_t mbar0 = smem_u32(&mb[0]), mbar1 = smem_u32(&mb[1]);
    if (tid == 0) { MBAR_INIT(mbar0, 1); MBAR_INIT(mbar1, 1); }
    __syncthreads();

    const char* Qsrc = Qp + ((size_t)(b * 16 + qt) * 16 + h) * TAB;
    if (tid == 0) {
        MBAR_EXPECT(mbar0, 2 * TAB);
        bulk_cp(sb, Qsrc, TAB, mbar0);
        bulk_cp(sb + TAB, Kp + ((size_t)(b * 16 + 0) * 16 + h) * TAB, TAB, mbar0);
    }

    const int a_row = wm * 32 + (lane & 15);
    const uint32_t a_kext = (lane & 16) ? 16u : 0u;
    const int b_row = wn * 64 + ((lane & 16) ? 8 : 0) + (lane & 7);
    const uint32_t b_kext = (lane & 8) ? 16u : 0u;

    float lsum[2][2] = {};
    int ph0 = 0, ph1 = 0;

    for (int kt = 0; kt < 16; ++kt) {
        const int bb = kt & 1;
        if (kt + 1 < 16 && tid == 0) {
            const uint32_t m = bb ? mbar0 : mbar1;
            MBAR_EXPECT(m, TAB);
            bulk_cp(sb + TAB + (1 - bb) * TAB,
                    Kp + ((size_t)(b * 16 + kt + 1) * 16 + h) * TAB, TAB, m);
        }
        if (bb == 0) { mbar_wait(mbar0, ph0); ph0 ^= 1; }
        else         { mbar_wait(mbar1, ph1); ph1 ^= 1; }

        float acc[2][8][4] = {};
        mma_tile144(acc, sb, sb + TAB + bb * TAB, a_row, a_kext, b_row, b_kext);

#pragma unroll
        for (int ma = 0; ma < 2; ++ma)
#pragma unroll
            for (int n = 0; n < 8; ++n) {
                lsum[ma][0] += __expf(0.125f * acc[ma][n][0]) + __expf(0.125f * acc[ma][n][1]);
                lsum[ma][1] += __expf(0.125f * acc[ma][n][2]) + __expf(0.125f * acc[ma][n][3]);
            }
        __syncthreads();
    }

#pragma unroll
    for (int o = 1; o <= 2; o <<= 1)
#pragma unroll
        for (int ma = 0; ma < 2; ++ma)
#pragma unroll
            for (int hh = 0; hh < 2; ++hh)
                lsum[ma][hh] += __shfl_xor_sync(0xffffffffu, lsum[ma][hh], o);

    __shared__ float Ls[128];
    if (tid < 128) Ls[tid] = 0.f;
    __syncthreads();
    if ((lane & 3) == 0) {
        const int gq = lane >> 2;
#pragma unroll
        for (int ma = 0; ma < 2; ++ma) {
            atomicAdd(&Ls[wm * 32 + ma * 16 + gq], lsum[ma][0]);
            atomicAdd(&Ls[wm * 32 + ma * 16 + gq + 8], lsum[ma][1]);
        }
    }
    __syncthreads();
    if (tid < 128)
        iL[((size_t)b * NH + h) * S_ + qt * 128 + tid] = 1.0f / (16.0f * Ls[tid]);
}

// ---------------------------------------------------------------------------
// Pass B: head-averaged softmax + fused PV. TMA-bulk staged.
// smem: Qb0|Kb0|Qb1|Kb1 (4*18432) | P 128x272 @73728 | VT 64x272 @108544
// ---------------------------------------------------------------------------
#define P_OFF  73728
#define VT_OFF 108544
#define ATT_SM 125952

__global__ void __launch_bounds__(256, 1)
attn_avg_p(const char* __restrict__ Qp, const char* __restrict__ Kp,
           const char* __restrict__ VTp, const float* __restrict__ iL,
           float* __restrict__ avg, float* __restrict__ AO)
{
    extern __shared__ char smem[];
    __shared__ uint64_t mb[3];
    const uint32_t sb = smem_u32(smem);
    const int tid = threadIdx.x, lane = tid & 31, w = tid >> 5;
    const int wm = w >> 1, wn = w & 1;
    const int kt = blockIdx.x, qt = blockIdx.y, b = blockIdx.z;

    const uint32_t mbar0 = smem_u32(&mb[0]), mbar1 = smem_u32(&mb[1]), mbar2 = smem_u32(&mb[2]);
    if (tid == 0) { MBAR_INIT(mbar0, 1); MBAR_INIT(mbar1, 1); MBAR_INIT(mbar2, 1); }
    __syncthreads();

    const char* Qsrc = Qp + (size_t)(b * 16 + qt) * 16 * TAB;
    const char* Ksrc = Kp + (size_t)(b * 16 + kt) * 16 * TAB;

    if (tid == 0) {
        MBAR_EXPECT(mbar2, VTB);
        bulk_cp(sb + VT_OFF, VTp + (size_t)(b * 16 + kt) * VTB, VTB, mbar2);
        MBAR_EXPECT(mbar0, 2 * TAB);
        bulk_cp(sb, Qsrc, TAB, mbar0);
        bulk_cp(sb + TAB, Ksrc, TAB, mbar0);
    }

    const int a_row = wm * 32 + (lane & 15);
    const uint32_t a_kext = (lane & 16) ? 16u : 0u;
    const int b_row = wn * 64 + ((lane & 16) ? 8 : 0) + (lane & 7);
    const uint32_t b_kext = (lane & 8) ? 16u : 0u;
    const int gq = lane >> 2, tig = lane & 3;

    float avgf[2][8][4] = {};
    int ph0 = 0, ph1 = 0;

    for (int h = 0; h < NH; ++h) {
        const int bb = h & 1;
        if (h + 1 < NH && tid == 0) {
            const uint32_t nb = sb + (1 - bb) * 2 * TAB;
            const uint32_t m = bb ? mbar0 : mbar1;
            MBAR_EXPECT(m, 2 * TAB);
            bulk_cp(nb, Qsrc + (size_t)(h + 1) * TAB, TAB, m);
            bulk_cp(nb + TAB, Ksrc + (size_t)(h + 1) * TAB, TAB, m);
        }
        if (bb == 0) { mbar_wait(mbar0, ph0); ph0 ^= 1; }
        else         { mbar_wait(mbar1, ph1); ph1 ^= 1; }

        float acc[2][8][4] = {};
        const uint32_t aS = sb + bb * 2 * TAB;
        mma_tile144(acc, aS, aS + TAB, a_row, a_kext, b_row, b_kext);

        const float* Lh = iL + ((size_t)b * NH + h) * S_ + qt * 128;
#pragma unroll
        for (int ma = 0; ma < 2; ++ma) {
            const float l0 = Lh[wm * 32 + ma * 16 + gq];
            const float l1 = Lh[wm * 32 + ma * 16 + gq + 8];
#pragma unroll
            for (int n = 0; n < 8; ++n) {
                avgf[ma][n][0] += __expf(0.125f * acc[ma][n][0]) * l0;
                avgf[ma][n][1] += __expf(0.125f * acc[ma][n][1]) * l0;
                avgf[ma][n][2] += __expf(0.125f * acc[ma][n][2]) * l1;
                avgf[ma][n][3] += __expf(0.125f * acc[ma][n][3]) * l1;
            }
        }
        __syncthreads();
    }

    // write avg tile (output) + stage fp16 copy into P (pitch 272)
    float* outp = avg + (size_t)b * S_ * S_;
#pragma unroll
    for (int ma = 0; ma < 2; ++ma) {
        const int rl = wm * 32 + ma * 16 + gq;
        const int r0 = qt * 128 + rl;
#pragma unroll
        for (int n = 0; n < 8; ++n) {
            const int col = wn * 64 + n * 8 + tig * 2;
            *(float2*)(outp + (size_t)r0 * S_ + kt * 128 + col) =
                make_float2(avgf[ma][n][0], avgf[ma][n][1]);
            *(float2*)(outp + (size_t)(r0 + 8) * S_ + kt * 128 + col) =
                make_float2(avgf[ma][n][2], avgf[ma][n][3]);
            *(__half2*)(smem + P_OFF + rl * 272 + col * 2) =
                __floats2half2_rn(avgf[ma][n][0], avgf[ma][n][1]);
            *(__half2*)(smem + P_OFF + (rl + 8) * 272 + col * 2) =
                __floats2half2_rn(avgf[ma][n][2], avgf[ma][n][3]);
        }
    }
    mbar_wait(mbar2, 0);
    __syncthreads();

    // PV: [128q x 64d] += P[128q x 128k] @ VT[64d x 128k]^T
    float apv[2][4][4] = {};
    const int pv_brow = wn * 32 + ((lane & 16) ? 8 : 0) + (lane & 7);
    const uint32_t pS = sb + P_OFF, vS = sb + VT_OFF;
#pragma unroll
    for (int ks = 0; ks < 8; ++ks) {
        uint32_t ah[2][4];
#pragma unroll
        for (int ma = 0; ma < 2; ++ma) {
            const uint32_t off = (uint32_t)((a_row + ma * 16) * 272 + ks * 32) + a_kext;
            ldsm4(ah[ma][0], ah[ma][1], ah[ma][2], ah[ma][3], pS + off);
        }
#pragma unroll
        for (int bg = 0; bg < 2; ++bg) {
            const uint32_t off = (uint32_t)((pv_brow + bg * 16) * 272 + ks * 32) + b_kext;
            uint32_t bh[4];
            ldsm4(bh[0], bh[1], bh[2], bh[3], vS + off);
#pragma unroll
            for (int na = 0; na < 2; ++na)
#pragma unroll
                for (int ma = 0; ma < 2; ++ma)
                    mma_f16(apv[ma][bg * 2 + na], ah[ma], &bh[na * 2]);
        }
    }

#pragma unroll
    for (int ma = 0; ma < 2; ++ma) {
        const int r0 = qt * 128 + wm * 32 + ma * 16 + gq;
#pragma unroll
        for (int nI = 0; nI < 4; ++nI) {
            const int d = wn * 32 + nI * 8 + tig * 2;
            float* a0 = AO + ((size_t)b * S_ + r0) * HD + d;
            float* a1 = AO + ((size_t)b * S_ + r0 + 8) * HD + d;
            atomicAdd(a0, apv[ma][nI][0]);
            atomicAdd(a0 + 1, apv[ma][nI][1]);
            atomicAdd(a1, apv[ma][nI][2]);
            atomicAdd(a1 + 1, apv[ma][nI][3]);
        }
    }
}

// ---------------------------------------------------------------------------
// bf16x3 split GEMM (O projection, K=64, LDGSTS path kept)
// ---------------------------------------------------------------------------
#define TILE_B 16384
#define BUF4 (4 * TILE_B)

__global__ void __launch_bounds__(256, 2)
hmma_bf16x3_nt(const __nv_bfloat16* __restrict__ hA, const __nv_bfloat16* __restrict__ lA,
               const __nv_bfloat16* __restrict__ hB, const __nv_bfloat16* __restrict__ lB,
               const float* __restrict__ bias, float* __restrict__ C,
               int K, int lda, int ldb, int ldc)
{
    extern __shared__ char smem[];
    const uint32_t sb = smem_u32(smem);
    const int tid = threadIdx.x, lane = tid & 31, w = tid >> 5;
    const int wm = w >> 1, wn = w & 1;
    const int m0 = blockIdx.y * 128, n0 = blockIdx.x * 128;

    hA += (size_t)m0 * lda; lA += (size_t)m0 * lda;
    hB += (size_t)n0 * ldb; lB += (size_t)n0 * ldb;

    cp_tile(hA, lda, sb + 0 * TILE_B, tid);
    cp_tile(lA, lda, sb + 1 * TILE_B, tid);
    cp_tile(hB, ldb, sb + 2 * TILE_B, tid);
    cp_tile(lB, ldb, sb + 3 * TILE_B, tid);
    CP_COMMIT();
    CP_WAIT(0);
    __syncthreads();

    float acc[2][8][4] = {};

    const int a_row = wm * 32 + (lane & 15);
    const uint32_t a_kext = (lane & 16) ? 16u : 0u;
    const int b_row = wn * 64 + ((lane & 16) ? 8 : 0) + (lane & 7);
    const uint32_t b_kext = (lane & 8) ? 16u : 0u;

    const uint32_t aH = sb, aL = sb + TILE_B, bH = sb + 2 * TILE_B, bL = sb + 3 * TILE_B;

#pragma unroll
    for (int ks = 0; ks < 4; ++ks) {
        uint32_t ah[2][4], al[2][4];
#pragma unroll
        for (int ma = 0; ma < 2; ++ma) {
            const uint32_t off =
                SWZ128((uint32_t)((a_row + ma * 16) * 128) + (uint32_t)(ks * 32) + a_kext);
            ldsm4(ah[ma][0], ah[ma][1], ah[ma][2], ah[ma][3], aH + off);
            ldsm4(al[ma][0], al[ma][1], al[ma][2], al[ma][3], aL + off);
        }
#pragma unroll
        for (int bg = 0; bg < 4; ++bg) {
            const uint32_t off =
                SWZ128((uint32_t)((b_row + bg * 16) * 128) + (uint32_t)(ks * 32) + b_kext);
            uint32_t bh[4], bl[4];
            ldsm4(bh[0], bh[1], bh[2], bh[3], bH + off);
            ldsm4(bl[0], bl[1], bl[2], bl[3], bL + off);
#pragma unroll
            for (int na = 0; na < 2; ++na) {
                const int n = bg * 2 + na;
#pragma unroll
                for (int ma = 0; ma < 2; ++ma) {
                    mma_bf16(acc[ma][n], ah[ma], &bh[na * 2]);
                    mma_bf16(acc[ma][n], ah[ma], &bl[na * 2]);
                    mma_bf16(acc[ma][n], al[ma], &bh[na * 2]);
                }
            }
        }
    }

    const int gq = lane >> 2, tig = lane & 3;
#pragma unroll
    for (int ma = 0; ma < 2; ++ma) {
        const int r0 = m0 + wm * 32 + ma * 16 + gq;
#pragma unroll
        for (int n = 0; n < 8; ++n) {
            const int col = n0 + wn * 64 + n * 8 + tig * 2;
            const float b0 = bias[col], b1 = bias[col + 1];
            *(float2*)(C + (size_t)r0 * ldc + col) =
                make_float2(acc[ma][n][0] + b0, acc[ma][n][1] + b1);
            *(float2*)(C + (size_t)(r0 + 8) * ldc + col) =
                make_float2(acc[ma][n][2] + b0, acc[ma][n][3] + b1);
        }
    }
}

// ---------------------------------------------------------------------------
// SIMT V projection (fp32, N=64)
// ---------------------------------------------------------------------------
__global__ void gemm_nt(const float* __restrict__ A, const float* __restrict__ Bm,
                        const float* __restrict__ bias, float* __restrict__ C,
                        int K, int lda, int ldb, int ldc)
{
    __shared__ float As[16][65];
    __shared__ float Bs[16][65];
    const int tx = threadIdx.x, ty = threadIdx.y;
    const int tid = ty * 16 + tx;
    const int m0 = blockIdx.y * 64, n0 = blockIdx.x * 64;
    const int rr = tid >> 2;
    const int kq = (tid & 3) << 2;

    const float* Ap = A + (size_t)(m0 + rr) * lda + kq;
    const float* Bp = Bm + (size_t)(n0 + rr) * ldb + kq;

    float acc[4][4] = {};
    for (int k0 = 0; k0 < K; k0 += 16) {
#pragma unroll
        for (int j = 0; j < 4; ++j) As[kq + j][rr] = Ap[j];
#pragma unroll
        for (int j = 0; j < 4; ++j) Bs[kq + j][rr] = Bp[j];
        __syncthreads();
#pragma unroll
        for (int kk = 0; kk < 16; ++kk) {
            float a[4], b[4];
#pragma unroll
            for (int i = 0; i < 4; ++i) a[i] = As[kk][ty * 4 + i];
#pragma unroll
            for (int j = 0; j < 4; ++j) b[j] = Bs[kk][tx * 4 + j];
#pragma unroll
            for (int i = 0; i < 4; ++i)
#pragma unroll
                for (int j = 0; j < 4; ++j) acc[i][j] += a[i] * b[j];
        }
        __syncthreads();
        Ap += 16; Bp += 16;
    }
#pragma unroll
    for (int i = 0; i < 4; ++i)
#pragma unroll
        for (int j = 0; j < 4; ++j) {
            const int n = n0 + tx * 4 + j;
            C[(size_t)(m0 + ty * 4 + i) * ldc + n] = acc[i][j] + (bias ? bias[n] : 0.f);
        }
}

extern "C" void kernel_launch(void* const* d_in, const int* in_sizes, int n_in,
                              void* d_out, int out_size)
{
    const float* query  = (const float*)d_in[0];
    const float* key_in = (const float*)d_in[1];
    const float* value  = (const float*)d_in[2];
    const float* Wq = (const float*)d_in[3];
    const float* bq = (const float*)d_in[4];
    const float* Wk = (const float*)d_in[5];
    const float* bk = (const float*)d_in[6];
    const float* Wv = (const float*)d_in[7];
    const float* bv = (const float*)d_in[8];
    const float* Wo = (const float*)d_in[9];
    const float* bo = (const float*)d_in[10];

    float* out = (float*)d_out;
    float* avg_out = out + (size_t)B_ * S_ * H_;

    float *gV, *gAO, *giL;
    char *gApc, *gWpc, *gQpc, *gKpc, *gVTpc;
    __nv_bfloat16 *hA, *lA, *hW, *lW;
    cudaGetSymbolAddress((void**)&gV, g_V);
    cudaGetSymbolAddress((void**)&gAO, g_AO);
    cudaGetSymbolAddress((void**)&giL, g_iL);
    cudaGetSymbolAddress((void**)&gApc, g_Ap);
    cudaGetSymbolAddress((void**)&gWpc, g_Wp);
    cudaGetSymbolAddress((void**)&gQpc, g_Qp);
    cudaGetSymbolAddress((void**)&gKpc, g_Kp);
    cudaGetSymbolAddress((void**)&gVTpc, g_VTp);
    cudaGetSymbolAddress((void**)&hA, g_hA);
    cudaGetSymbolAddress((void**)&lA, g_lA);
    cudaGetSymbolAddress((void**)&hW, g_hW);
    cudaGetSymbolAddress((void**)&lW, g_lW);

    cudaFuncSetAttribute(proj_f16, cudaFuncAttributeMaxDynamicSharedMemorySize, 4 * TAB);
    cudaFuncSetAttribute(qk_rowsum_p, cudaFuncAttributeMaxDynamicSharedMemorySize, 3 * TAB);
    cudaFuncSetAttribute(attn_avg_p, cudaFuncAttributeMaxDynamicSharedMemorySize, ATT_SM);
    cudaFuncSetAttribute(hmma_bf16x3_nt, cudaFuncAttributeMaxDynamicSharedMemorySize, BUF4);

    const int M = B_ * S_;          // 8192
    const int NXH = B_ * S_ * H_;   // 8M

    zero_f<<<(B_ * S_ * HD) / 256, 256>>>(gAO, B_ * S_ * HD);

    // Q projection
    cvt_pack<<<NXH / 1024, 256>>>((const float4*)query, gApc, NXH / 4);
    cvt_pack<<<(H_ * H_) / 1024, 256>>>((const float4*)Wq, gWpc, H_ * H_ / 4);
    proj_f16<<<dim3(8, 64), 256, 4 * TAB>>>(gApc, gWpc, bq, gQpc);
    // K projection
    cvt_pack<<<NXH / 1024, 256>>>((const float4*)key_in, gApc, NXH / 4);
    cvt_pack<<<(H_ * H_) / 1024, 256>>>((const float4*)Wk, gWpc, H_ * H_ / 4);
    proj_f16<<<dim3(8, 64), 256, 4 * TAB>>>(gApc, gWpc, bk, gKpc);
    // V projection + packed transpose
    gemm_nt<<<dim3(1, M / 64, 1), dim3(16, 16)>>>(value, Wv, bv, gV, H_, H_, H_, HD);
    vt_cvt_p<<<dim3(S_ / 64, B_), 256>>>(gV, gVTpc);

    // Pass A: softmax denominators
    qk_rowsum_p<<<dim3(S_ / 128, NH, B_), 256, 3 * TAB>>>(gQpc, gKpc, giL);

    // Pass B: head-averaged softmax + fused PV
    attn_avg_p<<<dim3(S_ / 128, S_ / 128, B_), 256, ATT_SM>>>(gQpc, gKpc, gVTpc, giL,
                                                              avg_out, gAO);

    // O projection (bf16x3)
    split_hl4<<<(B_ * S_ * HD) / 1024, 256>>>((const float4*)gAO, (uint2*)hA, (uint2*)lA,
                                              B_ * S_ * HD / 4);
    split_hl4<<<(H_ * HD) / 1024, 256>>>((const float4*)Wo, (uint2*)hW, (uint2*)lW, H_ * HD / 4);
    hmma_bf16x3_nt<<<dim3(H_ / 128, M / 128, 1), 256, BUF4>>>(hA, lA, hW, lW, bo,
        out, HD, HD, HD, H_);
}

// round 11
// speedup vs baseline: 10.2184x; 1.1805x over previous
#include <cuda_runtime.h>
#include <cuda_bf16.h>
#include <cuda_fp16.h>
#include <cstdint>

#define B_ 4
#define S_ 2048
#define H_ 1024
#define NH 16
#define HD 64

#define TAB 18432            // packed tile: 128 rows x 144B pitch (64 fp16 cols)
#define VTB 17408            // VT tile: 64 rows x 272B pitch (128 fp16 cols)

// scratch
__device__ float g_AO[B_ * S_ * HD];
__device__ float g_iL[B_ * NH * S_];
__device__ __align__(16) char g_Ap[64 * 16 * TAB];   // packed activations (value/query/key reuse)
__device__ __align__(16) char g_Wp[8 * 16 * TAB];    // packed weights (Wq/Wk reuse)
__device__ __align__(16) char g_Wvp[16 * TAB];       // packed Wv (rows 64..127 zero)
__device__ __align__(16) char g_Qp[64 * 16 * TAB];   // packed Q (tile = b*16+qt, chunk = head)
__device__ __align__(16) char g_Kp[64 * 16 * TAB];   // packed K
__device__ __align__(16) char g_VTp[64 * VTB];       // packed V^T tiles (b*16+kt)
__device__ __nv_bfloat16 g_hA[B_ * S_ * HD], g_lA[B_ * S_ * HD];
__device__ __nv_bfloat16 g_hW[H_ * HD],      g_lW[H_ * HD];

// ---------------------------------------------------------------------------
// helpers
// ---------------------------------------------------------------------------
__device__ __forceinline__ uint32_t smem_u32(const void* p) {
    uint32_t a;
    asm("{ .reg .u64 t; cvta.to.shared.u64 t, %1; cvt.u32.u64 %0, t; }" : "=r"(a) : "l"(p));
    return a;
}
#define SWZ128(x) ((x) ^ (((x) >> 3) & 0x70))

__device__ __forceinline__ void ldsm4(uint32_t& r0, uint32_t& r1, uint32_t& r2, uint32_t& r3,
                                      uint32_t addr) {
    asm volatile("ldmatrix.sync.aligned.m8n8.x4.shared.b16 {%0,%1,%2,%3}, [%4];"
                 : "=r"(r0), "=r"(r1), "=r"(r2), "=r"(r3) : "r"(addr));
}
__device__ __forceinline__ void mma_bf16(float* c, const uint32_t* a, const uint32_t* b) {
    asm volatile(
        "mma.sync.aligned.m16n8k16.row.col.f32.bf16.bf16.f32 "
        "{%0,%1,%2,%3}, {%4,%5,%6,%7}, {%8,%9}, {%0,%1,%2,%3};"
        : "+f"(c[0]), "+f"(c[1]), "+f"(c[2]), "+f"(c[3])
        : "r"(a[0]), "r"(a[1]), "r"(a[2]), "r"(a[3]), "r"(b[0]), "r"(b[1]));
}
__device__ __forceinline__ void mma_f16(float* c, const uint32_t* a, const uint32_t* b) {
    asm volatile(
        "mma.sync.aligned.m16n8k16.row.col.f32.f16.f16.f32 "
        "{%0,%1,%2,%3}, {%4,%5,%6,%7}, {%8,%9}, {%0,%1,%2,%3};"
        : "+f"(c[0]), "+f"(c[1]), "+f"(c[2]), "+f"(c[3])
        : "r"(a[0]), "r"(a[1]), "r"(a[2]), "r"(a[3]), "r"(b[0]), "r"(b[1]));
}
#define CP16(s, g) asm volatile("cp.async.cg.shared.global [%0], [%1], 16;" :: "r"(s), "l"(g))
#define CP_COMMIT() asm volatile("cp.async.commit_group;" ::: "memory")
#define CP_WAIT(n)  asm volatile("cp.async.wait_group %0;" :: "n"(n) : "memory")

// --- TMA bulk-copy + mbarrier (base sm_90 PTX) ---
__device__ __forceinline__ void bulk_cp(uint32_t sdst, const void* gsrc, uint32_t bytes,
                                        uint32_t mbar) {
    asm volatile(
        "cp.async.bulk.shared::cta.global.mbarrier::complete_tx::bytes [%0], [%1], %2, [%3];"
        :: "r"(sdst), "l"(gsrc), "r"(bytes), "r"(mbar) : "memory");
}
#define MBAR_INIT(a, n) \
    asm volatile("mbarrier.init.shared.b64 [%0], %1;" :: "r"(a), "r"((uint32_t)(n)) : "memory")
#define MBAR_EXPECT(a, bytes) \
    asm volatile("mbarrier.arrive.expect_tx.shared.b64 _, [%0], %1;" \
                 :: "r"(a), "r"((uint32_t)(bytes)) : "memory")
__device__ __forceinline__ void mbar_wait(uint32_t mbar, int parity) {
    asm volatile(
        "{\n\t.reg .pred P;\n\t"
        "LAB_%=:\n\t"
        "mbarrier.try_wait.parity.acquire.cta.shared::cta.b64 P, [%0], %1;\n\t"
        "@!P bra LAB_%=;\n\t}"
        :: "r"(mbar), "r"((uint32_t)parity) : "memory");
}

// LDGSTS staging (O-projection only)
__device__ __forceinline__ void cp_tile(const void* __restrict__ g, int ld_elems,
                                        uint32_t sdst, int tid)
{
    const __half* gh = (const __half*)g;
#pragma unroll
    for (int it = 0; it < 4; ++it) {
        int i = tid + it * 256;
        int row = i >> 3, c = i & 7;
        const void* gp = gh + (size_t)row * ld_elems + c * 8;
        uint32_t sp = sdst + SWZ128((uint32_t)(row * 128 + c * 16));
        CP16(sp, gp);
    }
}

// 128x128x64 fp16 MMA on two pitch-144 tiles
__device__ __forceinline__ void mma_tile144(float acc[2][8][4], uint32_t aS, uint32_t bS,
                                            int a_row, uint32_t a_kext,
                                            int b_row, uint32_t b_kext)
{
#pragma unroll
    for (int ks = 0; ks < 4; ++ks) {
        uint32_t ah[2][4];
#pragma unroll
        for (int ma = 0; ma < 2; ++ma) {
            const uint32_t off = (uint32_t)((a_row + ma * 16) * 144 + ks * 32) + a_kext;
            ldsm4(ah[ma][0], ah[ma][1], ah[ma][2], ah[ma][3], aS + off);
        }
#pragma unroll
        for (int bg = 0; bg < 4; ++bg) {
            const uint32_t off = (uint32_t)((b_row + bg * 16) * 144 + ks * 32) + b_kext;
            uint32_t bh[4];
            ldsm4(bh[0], bh[1], bh[2], bh[3], bS + off);
#pragma unroll
            for (int na = 0; na < 2; ++na)
#pragma unroll
                for (int ma = 0; ma < 2; ++ma)
                    mma_f16(acc[ma][bg * 2 + na], ah[ma], &bh[na * 2]);
        }
    }
}

// ---------------------------------------------------------------------------
// utility kernels
// ---------------------------------------------------------------------------
// fp32 [rows x 1024] -> packed fp16 tiles (rt, chunk) 128x64 @ pitch 144
__global__ void cvt_pack(const float4* __restrict__ x, char* __restrict__ out, int n4)
{
    int i = blockIdx.x * blockDim.x + threadIdx.x;
    if (i >= n4) return;
    float4 v = x[i];
    union { __half2 h2[2]; uint2 u; } p;
    p.h2[0] = __floats2half2_rn(v.x, v.y);
    p.h2[1] = __floats2half2_rn(v.z, v.w);
    int row = i >> 8;
    int col = (i & 255) << 2;
    int rt = row >> 7, r = row & 127, c = col >> 6, k = col & 63;
    *(uint2*)(out + (size_t)(rt * 16 + c) * TAB + r * 144 + k * 2) = p.u;
}

// Wv [64 x 1024] fp32 -> packed tiles (chunk) rows 0..63 @ pitch 144
__global__ void cvt_pack_w64(const float4* __restrict__ x, char* __restrict__ out, int n4)
{
    int i = blockIdx.x * blockDim.x + threadIdx.x;
    if (i >= n4) return;
    float4 v = x[i];
    union { __half2 h2[2]; uint2 u; } p;
    p.h2[0] = __floats2half2_rn(v.x, v.y);
    p.h2[1] = __floats2half2_rn(v.z, v.w);
    int row = i >> 8;              // 0..63
    int col = (i & 255) << 2;
    int c = col >> 6, k = col & 63;
    *(uint2*)(out + (size_t)c * TAB + row * 144 + k * 2) = p.u;
}

__global__ void split_hl4(const float4* __restrict__ x, uint2* __restrict__ hi,
                          uint2* __restrict__ lo, int n4)
{
    int i = blockIdx.x * blockDim.x + threadIdx.x;
    if (i < n4) {
        float4 v = x[i];
        __nv_bfloat16 h0 = __float2bfloat16(v.x), h1 = __float2bfloat16(v.y);
        __nv_bfloat16 h2 = __float2bfloat16(v.z), h3 = __float2bfloat16(v.w);
        __nv_bfloat16 l0 = __float2bfloat16(v.x - __bfloat162float(h0));
        __nv_bfloat16 l1 = __float2bfloat16(v.y - __bfloat162float(h1));
        __nv_bfloat16 l2 = __float2bfloat16(v.z - __bfloat162float(h2));
        __nv_bfloat16 l3 = __float2bfloat16(v.w - __bfloat162float(h3));
        union { __nv_bfloat162 b2[2]; uint2 u; } ph, pl;
        ph.b2[0].x = h0; ph.b2[0].y = h1; ph.b2[1].x = h2; ph.b2[1].y = h3;
        pl.b2[0].x = l0; pl.b2[0].y = l1; pl.b2[1].x = l2; pl.b2[1].y = l3;
        hi[i] = ph.u;
        lo[i] = pl.u;
    }
}

__global__ void zero_f(float* __restrict__ p, int n)
{
    int i = blockIdx.x * blockDim.x + threadIdx.x;
    if (i < n) p[i] = 0.f;
}

// ---------------------------------------------------------------------------
// fp16 projection GEMM on packed tiles, TMA-bulk staged. Output packed.
// ---------------------------------------------------------------------------
__global__ void __launch_bounds__(256, 2)
proj_f16(const char* __restrict__ Ap, const char* __restrict__ Wp,
         const float* __restrict__ bias, char* __restrict__ Cp)
{
    extern __shared__ char smem[];
    __shared__ uint64_t mb[2];
    const uint32_t sb = smem_u32(smem);
    const int tid = threadIdx.x, lane = tid & 31, w = tid >> 5;
    const int wm = w >> 1, wn = w & 1;
    const int nx = blockIdx.x, my = blockIdx.y;

    const uint32_t mbar0 = smem_u32(&mb[0]), mbar1 = smem_u32(&mb[1]);
    if (tid == 0) { MBAR_INIT(mbar0, 1); MBAR_INIT(mbar1, 1); }
    __syncthreads();

    const char* Asrc = Ap + (size_t)my * 16 * TAB;
    const char* Wsrc = Wp + (size_t)nx * 16 * TAB;

    if (tid == 0) {
        MBAR_EXPECT(mbar0, 2 * TAB);
        bulk_cp(sb, Asrc, TAB, mbar0);
        bulk_cp(sb + TAB, Wsrc, TAB, mbar0);
    }

    float acc[2][8][4] = {};
    const int a_row = wm * 32 + (lane & 15);
    const uint32_t a_kext = (lane & 16) ? 16u : 0u;
    const int b_row = wn * 64 + ((lane & 16) ? 8 : 0) + (lane & 7);
    const uint32_t b_kext = (lane & 8) ? 16u : 0u;
    int ph0 = 0, ph1 = 0;

    for (int c = 0; c < 16; ++c) {
        const int b = c & 1;
        if (c + 1 < 16 && tid == 0) {
            const uint32_t nb = sb + (1 - b) * 2 * TAB;
            const uint32_t m = b ? mbar0 : mbar1;
            MBAR_EXPECT(m, 2 * TAB);
            bulk_cp(nb, Asrc + (size_t)(c + 1) * TAB, TAB, m);
            bulk_cp(nb + TAB, Wsrc + (size_t)(c + 1) * TAB, TAB, m);
        }
        if (b == 0) { mbar_wait(mbar0, ph0); ph0 ^= 1; }
        else        { mbar_wait(mbar1, ph1); ph1 ^= 1; }
        const uint32_t aS = sb + b * 2 * TAB;
        mma_tile144(acc, aS, aS + TAB, a_row, a_kext, b_row, b_kext);
        __syncthreads();
    }

    const int gq = lane >> 2, tig = lane & 3;
#pragma unroll
    for (int ma = 0; ma < 2; ++ma) {
        const int rl = wm * 32 + ma * 16 + gq;
#pragma unroll
        for (int n = 0; n < 8; ++n) {
            const int col = nx * 128 + wn * 64 + n * 8 + tig * 2;
            const float b0 = bias[col], b1 = bias[col + 1];
            const size_t tb = (size_t)(my * 16 + (col >> 6)) * TAB + (col & 63) * 2;
            *(__half2*)(Cp + tb + rl * 144) =
                __floats2half2_rn(acc[ma][n][0] + b0, acc[ma][n][1] + b1);
            *(__half2*)(Cp + tb + (rl + 8) * 144) =
                __floats2half2_rn(acc[ma][n][2] + b0, acc[ma][n][3] + b1);
        }
    }
}

// ---------------------------------------------------------------------------
// V projection on HMMA, writing transposed packed VT directly.
// B tile = padded Wv (rows 64..127 zero, never stored).
// ---------------------------------------------------------------------------
__global__ void __launch_bounds__(256, 2)
proj_v(const char* __restrict__ Ap, const char* __restrict__ Wvp,
       const float* __restrict__ bias, char* __restrict__ VTp)
{
    extern __shared__ char smem[];
    __shared__ uint64_t mb[2];
    const uint32_t sb = smem_u32(smem);
    const int tid = threadIdx.x, lane = tid & 31, w = tid >> 5;
    const int wm = w >> 1, wn = w & 1;
    const int my = blockIdx.x;

    const uint32_t mbar0 = smem_u32(&mb[0]), mbar1 = smem_u32(&mb[1]);
    if (tid == 0) { MBAR_INIT(mbar0, 1); MBAR_INIT(mbar1, 1); }
    __syncthreads();

    const char* Asrc = Ap + (size_t)my * 16 * TAB;

    if (tid == 0) {
        MBAR_EXPECT(mbar0, 2 * TAB);
        bulk_cp(sb, Asrc, TAB, mbar0);
        bulk_cp(sb + TAB, Wvp, TAB, mbar0);
    }

    float acc[2][8][4] = {};
    const int a_row = wm * 32 + (lane & 15);
    const uint32_t a_kext = (lane & 16) ? 16u : 0u;
    const int b_row = wn * 64 + ((lane & 16) ? 8 : 0) + (lane & 7);
    const uint32_t b_kext = (lane & 8) ? 16u : 0u;
    int ph0 = 0, ph1 = 0;

    for (int c = 0; c < 16; ++c) {
        const int b = c & 1;
        if (c + 1 < 16 && tid == 0) {
            const uint32_t nb = sb + (1 - b) * 2 * TAB;
            const uint32_t m = b ? mbar0 : mbar1;
            MBAR_EXPECT(m, 2 * TAB);
            bulk_cp(nb, Asrc + (size_t)(c + 1) * TAB, TAB, m);
            bulk_cp(nb + TAB, Wvp + (size_t)(c + 1) * TAB, TAB, m);
        }
        if (b == 0) { mbar_wait(mbar0, ph0); ph0 ^= 1; }
        else        { mbar_wait(mbar1, ph1); ph1 ^= 1; }
        const uint32_t aS = sb + b * 2 * TAB;
        mma_tile144(acc, aS, aS + TAB, a_row, a_kext, b_row, b_kext);
        __syncthreads();
    }

    if (wn == 0) {   // only cols 0..63 are real
        const int gq = lane >> 2, tig = lane & 3;
        char* Vt = VTp + (size_t)my * VTB;
#pragma unroll
        for (int ma = 0; ma < 2; ++ma) {
            const int rl = wm * 32 + ma * 16 + gq;
#pragma unroll
            for (int n = 0; n < 8; ++n) {
                const int d = n * 8 + tig * 2;
                const float b0 = bias[d], b1 = bias[d + 1];
                *(__half*)(Vt + d * 272 + rl * 2)           = __float2half(acc[ma][n][0] + b0);
                *(__half*)(Vt + (d + 1) * 272 + rl * 2)     = __float2half(acc[ma][n][1] + b1);
                *(__half*)(Vt + d * 272 + (rl + 8) * 2)     = __float2half(acc[ma][n][2] + b0);
                *(__half*)(Vt + (d + 1) * 272 + (rl + 8) * 2) = __float2half(acc[ma][n][3] + b1);
            }
        }
    }
}

// ---------------------------------------------------------------------------
// Pass A: per-(b,h,q) softmax denominators. TMA-bulk staged packed tiles.
// ---------------------------------------------------------------------------
__global__ void __launch_bounds__(256, 2)
qk_rowsum_p(const char* __restrict__ Qp, const char* __restrict__ Kp, float* __restrict__ iL)
{
    extern __shared__ char smem[];
    __shared__ uint64_t mb[2];
    const uint32_t sb = smem_u32(smem);
    const int tid = threadIdx.x, lane = tid & 31, w = tid >> 5;
    const int wm = w >> 1, wn = w & 1;
    const int qt = blockIdx.x, h = blockIdx.y, b = blockIdx.z;

    const uint32_t mbar0 = smem_u32(&mb[0]), mbar1 = smem_u32(&mb[1]);
    if (tid == 0) { MBAR_INIT(mbar0, 1); MBAR_INIT(mbar1, 1); }
    __syncthreads();

    const char* Qsrc = Qp + ((size_t)(b * 16 + qt) * 16 + h) * TAB;
    if (tid == 0) {
        MBAR_EXPECT(mbar0, 2 * TAB);
        bulk_cp(sb, Qsrc, TAB, mbar0);
        bulk_cp(sb + TAB, Kp + ((size_t)(b * 16 + 0) * 16 + h) * TAB, TAB, mbar0);
    }

    const int a_row = wm * 32 + (lane & 15);
    const uint32_t a_kext = (lane & 16) ? 16u : 0u;
    const int b_row = wn * 64 + ((lane & 16) ? 8 : 0) + (lane & 7);
    const uint32_t b_kext = (lane & 8) ? 16u : 0u;

    float lsum[2][2] = {};
    int ph0 = 0, ph1 = 0;

    for (int kt = 0; kt < 16; ++kt) {
        const int bb = kt & 1;
        if (kt + 1 < 16 && tid == 0) {
            const uint32_t m = bb ? mbar0 : mbar1;
            MBAR_EXPECT(m, TAB);
            bulk_cp(sb + TAB + (1 - bb) * TAB,
                    Kp + ((size_t)(b * 16 + kt + 1) * 16 + h) * TAB, TAB, m);
        }
        if (bb == 0) { mbar_wait(mbar0, ph0); ph0 ^= 1; }
        else         { mbar_wait(mbar1, ph1); ph1 ^= 1; }

        float acc[2][8][4] = {};
        mma_tile144(acc, sb, sb + TAB + bb * TAB, a_row, a_kext, b_row, b_kext);

#pragma unroll
        for (int ma = 0; ma < 2; ++ma)
#pragma unroll
            for (int n = 0; n < 8; ++n) {
                lsum[ma][0] += __expf(0.125f * acc[ma][n][0]) + __expf(0.125f * acc[ma][n][1]);
                lsum[ma][1] += __expf(0.125f * acc[ma][n][2]) + __expf(0.125f * acc[ma][n][3]);
            }
        __syncthreads();
    }

#pragma unroll
    for (int o = 1; o <= 2; o <<= 1)
#pragma unroll
        for (int ma = 0; ma < 2; ++ma)
#pragma unroll
            for (int hh = 0; hh < 2; ++hh)
                lsum[ma][hh] += __shfl_xor_sync(0xffffffffu, lsum[ma][hh], o);

    __shared__ float Ls[128];
    if (tid < 128) Ls[tid] = 0.f;
    __syncthreads();
    if ((lane & 3) == 0) {
        const int gq = lane >> 2;
#pragma unroll
        for (int ma = 0; ma < 2; ++ma) {
            atomicAdd(&Ls[wm * 32 + ma * 16 + gq], lsum[ma][0]);
            atomicAdd(&Ls[wm * 32 + ma * 16 + gq + 8], lsum[ma][1]);
        }
    }
    __syncthreads();
    if (tid < 128)
        iL[((size_t)b * NH + h) * S_ + qt * 128 + tid] = 1.0f / (16.0f * Ls[tid]);
}

// ---------------------------------------------------------------------------
// Pass B: head-averaged softmax + fused PV. smem = 4*TAB only (73728):
// Q/K double buffer during head loop; afterwards the SAME region is reused:
// P (128x272 = 34816) at offset 0 (buf0, dead after h=14),
// VT (64x272 = 17408) at offset 36864 (buf1, loaded after the loop).
// -> occupancy 2.
// ---------------------------------------------------------------------------
#define ATT_SM (4 * TAB)

__global__ void __launch_bounds__(256, 2)
attn_avg_p(const char* __restrict__ Qp, const char* __restrict__ Kp,
           const char* __restrict__ VTp, const float* __restrict__ iL,
           float* __restrict__ avg, float* __restrict__ AO)
{
    extern __shared__ char smem[];
    __shared__ uint64_t mb[3];
    const uint32_t sb = smem_u32(smem);
    const int tid = threadIdx.x, lane = tid & 31, w = tid >> 5;
    const int wm = w >> 1, wn = w & 1;
    const int kt = blockIdx.x, qt = blockIdx.y, b = blockIdx.z;

    const uint32_t mbar0 = smem_u32(&mb[0]), mbar1 = smem_u32(&mb[1]), mbar2 = smem_u32(&mb[2]);
    if (tid == 0) { MBAR_INIT(mbar0, 1); MBAR_INIT(mbar1, 1); MBAR_INIT(mbar2, 1); }
    __syncthreads();

    const char* Qsrc = Qp + (size_t)(b * 16 + qt) * 16 * TAB;
    const char* Ksrc = Kp + (size_t)(b * 16 + kt) * 16 * TAB;

    if (tid == 0) {
        MBAR_EXPECT(mbar0, 2 * TAB);
        bulk_cp(sb, Qsrc, TAB, mbar0);
        bulk_cp(sb + TAB, Ksrc, TAB, mbar0);
    }

    const int a_row = wm * 32 + (lane & 15);
    const uint32_t a_kext = (lane & 16) ? 16u : 0u;
    const int b_row = wn * 64 + ((lane & 16) ? 8 : 0) + (lane & 7);
    const uint32_t b_kext = (lane & 8) ? 16u : 0u;
    const int gq = lane >> 2, tig = lane & 3;

    float avgf[2][8][4] = {};
    int ph0 = 0, ph1 = 0;

    for (int h = 0; h < NH; ++h) {
        const int bb = h & 1;
        if (h + 1 < NH && tid == 0) {
            const uint32_t nb = sb + (1 - bb) * 2 * TAB;
            const uint32_t m = bb ? mbar0 : mbar1;
            MBAR_EXPECT(m, 2 * TAB);
            bulk_cp(nb, Qsrc + (size_t)(h + 1) * TAB, TAB, m);
            bulk_cp(nb + TAB, Ksrc + (size_t)(h + 1) * TAB, TAB, m);
        }
        if (bb == 0) { mbar_wait(mbar0, ph0); ph0 ^= 1; }
        else         { mbar_wait(mbar1, ph1); ph1 ^= 1; }

        float acc[2][8][4] = {};
        const uint32_t aS = sb + bb * 2 * TAB;
        mma_tile144(acc, aS, aS + TAB, a_row, a_kext, b_row, b_kext);

        const float* Lh = iL + ((size_t)b * NH + h) * S_ + qt * 128;
#pragma unroll
        for (int ma = 0; ma < 2; ++ma) {
            const float l0 = Lh[wm * 32 + ma * 16 + gq];
            const float l1 = Lh[wm * 32 + ma * 16 + gq + 8];
#pragma unroll
            for (int n = 0; n < 8; ++n) {
                avgf[ma][n][0] += __expf(0.125f * acc[ma][n][0]) * l0;
                avgf[ma][n][1] += __expf(0.125f * acc[ma][n][1]) * l0;
                avgf[ma][n][2] += __expf(0.125f * acc[ma][n][2]) * l1;
                avgf[ma][n][3] += __expf(0.125f * acc[ma][n][3]) * l1;
            }
        }
        __syncthreads();
    }

    // All Q/K buffers dead now. Load VT into buf1 region; stage P into buf0 region.
    if (tid == 0) {
        MBAR_EXPECT(mbar2, VTB);
        bulk_cp(sb + 2 * TAB, VTp + (size_t)(b * 16 + kt) * VTB, VTB, mbar2);
    }

    float* outp = avg + (size_t)b * S_ * S_;
#pragma unroll
    for (int ma = 0; ma < 2; ++ma) {
        const int rl = wm * 32 + ma * 16 + gq;
        const int r0 = qt * 128 + rl;
#pragma unroll
        for (int n = 0; n < 8; ++n) {
            const int col = wn * 64 + n * 8 + tig * 2;
            *(float2*)(outp + (size_t)r0 * S_ + kt * 128 + col) =
                make_float2(avgf[ma][n][0], avgf[ma][n][1]);
            *(float2*)(outp + (size_t)(r0 + 8) * S_ + kt * 128 + col) =
                make_float2(avgf[ma][n][2], avgf[ma][n][3]);
            *(__half2*)(smem + rl * 272 + col * 2) =
                __floats2half2_rn(avgf[ma][n][0], avgf[ma][n][1]);
            *(__half2*)(smem + (rl + 8) * 272 + col * 2) =
                __floats2half2_rn(avgf[ma][n][2], avgf[ma][n][3]);
        }
    }
    mbar_wait(mbar2, 0);
    __syncthreads();

    // PV: [128q x 64d] += P[128q x 128k] @ VT[64d x 128k]^T
    float apv[2][4][4] = {};
    const int pv_brow = wn * 32 + ((lane & 16) ? 8 : 0) + (lane & 7);
    const uint32_t pS = sb, vS = sb + 2 * TAB;
#pragma unroll
    for (int ks = 0; ks < 8; ++ks) {
        uint32_t ah[2][4];
#pragma unroll
        for (int ma = 0; ma < 2; ++ma) {
            const uint32_t off = (uint32_t)((a_row + ma * 16) * 272 + ks * 32) + a_kext;
            ldsm4(ah[ma][0], ah[ma][1], ah[ma][2], ah[ma][3], pS + off);
        }
#pragma unroll
        for (int bg = 0; bg < 2; ++bg) {
            const uint32_t off = (uint32_t)((pv_brow + bg * 16) * 272 + ks * 32) + b_kext;
            uint32_t bh[4];
            ldsm4(bh[0], bh[1], bh[2], bh[3], vS + off);
#pragma unroll
            for (int na = 0; na < 2; ++na)
#pragma unroll
                for (int ma = 0; ma < 2; ++ma)
                    mma_f16(apv[ma][bg * 2 + na], ah[ma], &bh[na * 2]);
        }
    }

#pragma unroll
    for (int ma = 0; ma < 2; ++ma) {
        const int r0 = qt * 128 + wm * 32 + ma * 16 + gq;
#pragma unroll
        for (int nI = 0; nI < 4; ++nI) {
            const int d = wn * 32 + nI * 8 + tig * 2;
            float* a0 = AO + ((size_t)b * S_ + r0) * HD + d;
            float* a1 = AO + ((size_t)b * S_ + r0 + 8) * HD + d;
            atomicAdd(a0, apv[ma][nI][0]);
            atomicAdd(a0 + 1, apv[ma][nI][1]);
            atomicAdd(a1, apv[ma][nI][2]);
            atomicAdd(a1 + 1, apv[ma][nI][3]);
        }
    }
}

// ---------------------------------------------------------------------------
// bf16x3 split GEMM (O projection, K=64, LDGSTS path)
// ---------------------------------------------------------------------------
#define TILE_B 16384
#define BUF4 (4 * TILE_B)

__global__ void __launch_bounds__(256, 2)
hmma_bf16x3_nt(const __nv_bfloat16* __restrict__ hA, const __nv_bfloat16* __restrict__ lA,
               const __nv_bfloat16* __restrict__ hB, const __nv_bfloat16* __restrict__ lB,
               const float* __restrict__ bias, float* __restrict__ C,
               int K, int lda, int ldb, int ldc)
{
    extern __shared__ char smem[];
    const uint32_t sb = smem_u32(smem);
    const int tid = threadIdx.x, lane = tid & 31, w = tid >> 5;
    const int wm = w >> 1, wn = w & 1;
    const int m0 = blockIdx.y * 128, n0 = blockIdx.x * 128;

    hA += (size_t)m0 * lda; lA += (size_t)m0 * lda;
    hB += (size_t)n0 * ldb; lB += (size_t)n0 * ldb;

    cp_tile(hA, lda, sb + 0 * TILE_B, tid);
    cp_tile(lA, lda, sb + 1 * TILE_B, tid);
    cp_tile(hB, ldb, sb + 2 * TILE_B, tid);
    cp_tile(lB, ldb, sb + 3 * TILE_B, tid);
    CP_COMMIT();
    CP_WAIT(0);
    __syncthreads();

    float acc[2][8][4] = {};

    const int a_row = wm * 32 + (lane & 15);
    const uint32_t a_kext = (lane & 16) ? 16u : 0u;
    const int b_row = wn * 64 + ((lane & 16) ? 8 : 0) + (lane & 7);
    const uint32_t b_kext = (lane & 8) ? 16u : 0u;

    const uint32_t aH = sb, aL = sb + TILE_B, bH = sb + 2 * TILE_B, bL = sb + 3 * TILE_B;

#pragma unroll
    for (int ks = 0; ks < 4; ++ks) {
        uint32_t ah[2][4], al[2][4];
#pragma unroll
        for (int ma = 0; ma < 2; ++ma) {
            const uint32_t off =
                SWZ128((uint32_t)((a_row + ma * 16) * 128) + (uint32_t)(ks * 32) + a_kext);
            ldsm4(ah[ma][0], ah[ma][1], ah[ma][2], ah[ma][3], aH + off);
            ldsm4(al[ma][0], al[ma][1], al[ma][2], al[ma][3], aL + off);
        }
#pragma unroll
        for (int bg = 0; bg < 4; ++bg) {
            const uint32_t off =
                SWZ128((uint32_t)((b_row + bg * 16) * 128) + (uint32_t)(ks * 32) + b_kext);
            uint32_t bh[4], bl[4];
            ldsm4(bh[0], bh[1], bh[2], bh[3], bH + off);
            ldsm4(bl[0], bl[1], bl[2], bl[3], bL + off);
#pragma unroll
            for (int na = 0; na < 2; ++na) {
                const int n = bg * 2 + na;
#pragma unroll
                for (int ma = 0; ma < 2; ++ma) {
                    mma_bf16(acc[ma][n], ah[ma], &bh[na * 2]);
                    mma_bf16(acc[ma][n], ah[ma], &bl[na * 2]);
                    mma_bf16(acc[ma][n], al[ma], &bh[na * 2]);
                }
            }
        }
    }

    const int gq = lane >> 2, tig = lane & 3;
#pragma unroll
    for (int ma = 0; ma < 2; ++ma) {
        const int r0 = m0 + wm * 32 + ma * 16 + gq;
#pragma unroll
        for (int n = 0; n < 8; ++n) {
            const int col = n0 + wn * 64 + n * 8 + tig * 2;
            const float b0 = bias[col], b1 = bias[col + 1];
            *(float2*)(C + (size_t)r0 * ldc + col) =
                make_float2(acc[ma][n][0] + b0, acc[ma][n][1] + b1);
            *(float2*)(C + (size_t)(r0 + 8) * ldc + col) =
                make_float2(acc[ma][n][2] + b0, acc[ma][n][3] + b1);
        }
    }
}

extern "C" void kernel_launch(void* const* d_in, const int* in_sizes, int n_in,
                              void* d_out, int out_size)
{
    const float* query  = (const float*)d_in[0];
    const float* key_in = (const float*)d_in[1];
    const float* value  = (const float*)d_in[2];
    const float* Wq = (const float*)d_in[3];
    const float* bq = (const float*)d_in[4];
    const float* Wk = (const float*)d_in[5];
    const float* bk = (const float*)d_in[6];
    const float* Wv = (const float*)d_in[7];
    const float* bv = (const float*)d_in[8];
    const float* Wo = (const float*)d_in[9];
    const float* bo = (const float*)d_in[10];

    float* out = (float*)d_out;
    float* avg_out = out + (size_t)B_ * S_ * H_;

    float *gAO, *giL;
    char *gApc, *gWpc, *gWvpc, *gQpc, *gKpc, *gVTpc;
    __nv_bfloat16 *hA, *lA, *hW, *lW;
    cudaGetSymbolAddress((void**)&gAO, g_AO);
    cudaGetSymbolAddress((void**)&giL, g_iL);
    cudaGetSymbolAddress((void**)&gApc, g_Ap);
    cudaGetSymbolAddress((void**)&gWpc, g_Wp);
    cudaGetSymbolAddress((void**)&gWvpc, g_Wvp);
    cudaGetSymbolAddress((void**)&gQpc, g_Qp);
    cudaGetSymbolAddress((void**)&gKpc, g_Kp);
    cudaGetSymbolAddress((void**)&gVTpc, g_VTp);
    cudaGetSymbolAddress((void**)&hA, g_hA);
    cudaGetSymbolAddress((void**)&lA, g_lA);
    cudaGetSymbolAddress((void**)&hW, g_hW);
    cudaGetSymbolAddress((void**)&lW, g_lW);

    cudaFuncSetAttribute(proj_f16, cudaFuncAttributeMaxDynamicSharedMemorySize, 4 * TAB);
    cudaFuncSetAttribute(proj_v, cudaFuncAttributeMaxDynamicSharedMemorySize, 4 * TAB);
    cudaFuncSetAttribute(qk_rowsum_p, cudaFuncAttributeMaxDynamicSharedMemorySize, 3 * TAB);
    cudaFuncSetAttribute(attn_avg_p, cudaFuncAttributeMaxDynamicSharedMemorySize, ATT_SM);
    cudaFuncSetAttribute(hmma_bf16x3_nt, cudaFuncAttributeMaxDynamicSharedMemorySize, BUF4);

    const int M = B_ * S_;          // 8192
    const int NXH = B_ * S_ * H_;   // 8M

    zero_f<<<(B_ * S_ * HD) / 256, 256>>>(gAO, B_ * S_ * HD);
    zero_f<<<(16 * TAB / 4) / 256, 256>>>((float*)gWvpc, 16 * TAB / 4);

    // V projection (fp16 HMMA -> packed VT directly)
    cvt_pack<<<NXH / 1024, 256>>>((const float4*)value, gApc, NXH / 4);
    cvt_pack_w64<<<(HD * H_) / 1024, 256>>>((const float4*)Wv, gWvpc, HD * H_ / 4);
    proj_v<<<64, 256, 4 * TAB>>>(gApc, gWvpc, bv, gVTpc);

    // Q projection
    cvt_pack<<<NXH / 1024, 256>>>((const float4*)query, gApc, NXH / 4);
    cvt_pack<<<(H_ * H_) / 1024, 256>>>((const float4*)Wq, gWpc, H_ * H_ / 4);
    proj_f16<<<dim3(8, 64), 256, 4 * TAB>>>(gApc, gWpc, bq, gQpc);
    // K projection
    cvt_pack<<<NXH / 1024, 256>>>((const float4*)key_in, gApc, NXH / 4);
    cvt_pack<<<(H_ * H_) / 1024, 256>>>((const float4*)Wk, gWpc, H_ * H_ / 4);
    proj_f16<<<dim3(8, 64), 256, 4 * TAB>>>(gApc, gWpc, bk, gKpc);

    // Pass A: softmax denominators
    qk_rowsum_p<<<dim3(S_ / 128, NH, B_), 256, 3 * TAB>>>(gQpc, gKpc, giL);

    // Pass B: head-averaged softmax + fused PV (occupancy 2)
    attn_avg_p<<<dim3(S_ / 128, S_ / 128, B_), 256, ATT_SM>>>(gQpc, gKpc, gVTpc, giL,
                                                              avg_out, gAO);

    // O projection (bf16x3)
    split_hl4<<<(B_ * S_ * HD) / 1024, 256>>>((const float4*)gAO, (uint2*)hA, (uint2*)lA,
                                              B_ * S_ * HD / 4);
    split_hl4<<<(H_ * HD) / 1024, 256>>>((const float4*)Wo, (uint2*)hW, (uint2*)lW, H_ * HD / 4);
    hmma_bf16x3_nt<<<dim3(H_ / 128, M / 128, 1), 256, BUF4>>>(hA, lA, hW, lW, bo,
        out, HD, HD, HD, H_);
}

// round 12
// speedup vs baseline: 10.2538x; 1.0035x over previous
#include <cuda_runtime.h>
#include <cuda_bf16.h>
#include <cuda_fp16.h>
#include <cstdint>

#define B_ 4
#define S_ 2048
#define H_ 1024
#define NH 16
#define HD 64

#define TAB 18432            // packed tile: 128 rows x 144B pitch (64 fp16 cols)
#define VTB 17408            // VT tile: 64 rows x 272B pitch (128 fp16 cols)

// Q is pre-scaled by 0.125*log2(e) so softmax weight = exp2(score)
#define QSCALE 0.180336879f

// scratch
__device__ float g_AO[B_ * S_ * HD];
__device__ float g_iL[B_ * NH * S_];
__device__ __align__(16) char g_Ap[64 * 16 * TAB];
__device__ __align__(16) char g_Wp[8 * 16 * TAB];
__device__ __align__(16) char g_Wvp[16 * TAB];
__device__ __align__(16) char g_Qp[64 * 16 * TAB];
__device__ __align__(16) char g_Kp[64 * 16 * TAB];
__device__ __align__(16) char g_VTp[64 * VTB];
__device__ __nv_bfloat16 g_hA[B_ * S_ * HD], g_lA[B_ * S_ * HD];
__device__ __nv_bfloat16 g_hW[H_ * HD],      g_lW[H_ * HD];

// ---------------------------------------------------------------------------
// helpers
// ---------------------------------------------------------------------------
__device__ __forceinline__ uint32_t smem_u32(const void* p) {
    uint32_t a;
    asm("{ .reg .u64 t; cvta.to.shared.u64 t, %1; cvt.u32.u64 %0, t; }" : "=r"(a) : "l"(p));
    return a;
}
#define SWZ128(x) ((x) ^ (((x) >> 3) & 0x70))

__device__ __forceinline__ void ldsm4(uint32_t& r0, uint32_t& r1, uint32_t& r2, uint32_t& r3,
                                      uint32_t addr) {
    asm volatile("ldmatrix.sync.aligned.m8n8.x4.shared.b16 {%0,%1,%2,%3}, [%4];"
                 : "=r"(r0), "=r"(r1), "=r"(r2), "=r"(r3) : "r"(addr));
}
__device__ __forceinline__ void mma_bf16(float* c, const uint32_t* a, const uint32_t* b) {
    asm volatile(
        "mma.sync.aligned.m16n8k16.row.col.f32.bf16.bf16.f32 "
        "{%0,%1,%2,%3}, {%4,%5,%6,%7}, {%8,%9}, {%0,%1,%2,%3};"
        : "+f"(c[0]), "+f"(c[1]), "+f"(c[2]), "+f"(c[3])
        : "r"(a[0]), "r"(a[1]), "r"(a[2]), "r"(a[3]), "r"(b[0]), "r"(b[1]));
}
__device__ __forceinline__ void mma_f16(float* c, const uint32_t* a, const uint32_t* b) {
    asm volatile(
        "mma.sync.aligned.m16n8k16.row.col.f32.f16.f16.f32 "
        "{%0,%1,%2,%3}, {%4,%5,%6,%7}, {%8,%9}, {%0,%1,%2,%3};"
        : "+f"(c[0]), "+f"(c[1]), "+f"(c[2]), "+f"(c[3])
        : "r"(a[0]), "r"(a[1]), "r"(a[2]), "r"(a[3]), "r"(b[0]), "r"(b[1]));
}
#define CP16(s, g) asm volatile("cp.async.cg.shared.global [%0], [%1], 16;" :: "r"(s), "l"(g))
#define CP_COMMIT() asm volatile("cp.async.commit_group;" ::: "memory")
#define CP_WAIT(n)  asm volatile("cp.async.wait_group %0;" :: "n"(n) : "memory")

// --- TMA bulk-copy + mbarrier (base sm_90 PTX) ---
__device__ __forceinline__ void bulk_cp(uint32_t sdst, const void* gsrc, uint32_t bytes,
                                        uint32_t mbar) {
    asm volatile(
        "cp.async.bulk.shared::cta.global.mbarrier::complete_tx::bytes [%0], [%1], %2, [%3];"
        :: "r"(sdst), "l"(gsrc), "r"(bytes), "r"(mbar) : "memory");
}
#define MBAR_INIT(a, n) \
    asm volatile("mbarrier.init.shared.b64 [%0], %1;" :: "r"(a), "r"((uint32_t)(n)) : "memory")
#define MBAR_EXPECT(a, bytes) \
    asm volatile("mbarrier.arrive.expect_tx.shared.b64 _, [%0], %1;" \
                 :: "r"(a), "r"((uint32_t)(bytes)) : "memory")
__device__ __forceinline__ void mbar_wait(uint32_t mbar, int parity) {
    asm volatile(
        "{\n\t.reg .pred P;\n\t"
        "LAB_%=:\n\t"
        "mbarrier.try_wait.parity.acquire.cta.shared::cta.b64 P, [%0], %1;\n\t"
        "@!P bra LAB_%=;\n\t}"
        :: "r"(mbar), "r"((uint32_t)parity) : "memory");
}

// LDGSTS staging (O-projection only)
__device__ __forceinline__ void cp_tile(const void* __restrict__ g, int ld_elems,
                                        uint32_t sdst, int tid)
{
    const __half* gh = (const __half*)g;
#pragma unroll
    for (int it = 0; it < 4; ++it) {
        int i = tid + it * 256;
        int row = i >> 3, c = i & 7;
        const void* gp = gh + (size_t)row * ld_elems + c * 8;
        uint32_t sp = sdst + SWZ128((uint32_t)(row * 128 + c * 16));
        CP16(sp, gp);
    }
}

// 128x128x64 fp16 MMA on two pitch-144 tiles
__device__ __forceinline__ void mma_tile144(float acc[2][8][4], uint32_t aS, uint32_t bS,
                                            int a_row, uint32_t a_kext,
                                            int b_row, uint32_t b_kext)
{
#pragma unroll
    for (int ks = 0; ks < 4; ++ks) {
        uint32_t ah[2][4];
#pragma unroll
        for (int ma = 0; ma < 2; ++ma) {
            const uint32_t off = (uint32_t)((a_row + ma * 16) * 144 + ks * 32) + a_kext;
            ldsm4(ah[ma][0], ah[ma][1], ah[ma][2], ah[ma][3], aS + off);
        }
#pragma unroll
        for (int bg = 0; bg < 4; ++bg) {
            const uint32_t off = (uint32_t)((b_row + bg * 16) * 144 + ks * 32) + b_kext;
            uint32_t bh[4];
            ldsm4(bh[0], bh[1], bh[2], bh[3], bS + off);
#pragma unroll
            for (int na = 0; na < 2; ++na)
#pragma unroll
                for (int ma = 0; ma < 2; ++ma)
                    mma_f16(acc[ma][bg * 2 + na], ah[ma], &bh[na * 2]);
        }
    }
}

// ---------------------------------------------------------------------------
// utility kernels
// ---------------------------------------------------------------------------
__global__ void cvt_pack(const float4* __restrict__ x, char* __restrict__ out, int n4)
{
    int i = blockIdx.x * blockDim.x + threadIdx.x;
    if (i >= n4) return;
    float4 v = x[i];
    union { __half2 h2[2]; uint2 u; } p;
    p.h2[0] = __floats2half2_rn(v.x, v.y);
    p.h2[1] = __floats2half2_rn(v.z, v.w);
    int row = i >> 8;
    int col = (i & 255) << 2;
    int rt = row >> 7, r = row & 127, c = col >> 6, k = col & 63;
    *(uint2*)(out + (size_t)(rt * 16 + c) * TAB + r * 144 + k * 2) = p.u;
}

__global__ void cvt_pack_w64(const float4* __restrict__ x, char* __restrict__ out, int n4)
{
    int i = blockIdx.x * blockDim.x + threadIdx.x;
    if (i >= n4) return;
    float4 v = x[i];
    union { __half2 h2[2]; uint2 u; } p;
    p.h2[0] = __floats2half2_rn(v.x, v.y);
    p.h2[1] = __floats2half2_rn(v.z, v.w);
    int row = i >> 8;
    int col = (i & 255) << 2;
    int c = col >> 6, k = col & 63;
    *(uint2*)(out + (size_t)c * TAB + row * 144 + k * 2) = p.u;
}

__global__ void split_hl4(const float4* __restrict__ x, uint2* __restrict__ hi,
                          uint2* __restrict__ lo, int n4)
{
    int i = blockIdx.x * blockDim.x + threadIdx.x;
    if (i < n4) {
        float4 v = x[i];
        __nv_bfloat16 h0 = __float2bfloat16(v.x), h1 = __float2bfloat16(v.y);
        __nv_bfloat16 h2 = __float2bfloat16(v.z), h3 = __float2bfloat16(v.w);
        __nv_bfloat16 l0 = __float2bfloat16(v.x - __bfloat162float(h0));
        __nv_bfloat16 l1 = __float2bfloat16(v.y - __bfloat162float(h1));
        __nv_bfloat16 l2 = __float2bfloat16(v.z - __bfloat162float(h2));
        __nv_bfloat16 l3 = __float2bfloat16(v.w - __bfloat162float(h3));
        union { __nv_bfloat162 b2[2]; uint2 u; } ph, pl;
        ph.b2[0].x = h0; ph.b2[0].y = h1; ph.b2[1].x = h2; ph.b2[1].y = h3;
        pl.b2[0].x = l0; pl.b2[0].y = l1; pl.b2[1].x = l2; pl.b2[1].y = l3;
        hi[i] = ph.u;
        lo[i] = pl.u;
    }
}

__global__ void zero_f(float* __restrict__ p, int n)
{
    int i = blockIdx.x * blockDim.x + threadIdx.x;
    if (i < n) p[i] = 0.f;
}

// ---------------------------------------------------------------------------
// fp16 projection GEMM on packed tiles, TMA-bulk staged. Output packed.
// cs: output scale (folds 0.125*log2e into Q).
// ---------------------------------------------------------------------------
__global__ void __launch_bounds__(256, 2)
proj_f16(const char* __restrict__ Ap, const char* __restrict__ Wp,
         const float* __restrict__ bias, char* __restrict__ Cp, float cs)
{
    extern __shared__ char smem[];
    __shared__ uint64_t mb[2];
    const uint32_t sb = smem_u32(smem);
    const int tid = threadIdx.x, lane = tid & 31, w = tid >> 5;
    const int wm = w >> 1, wn = w & 1;
    const int nx = blockIdx.x, my = blockIdx.y;

    const uint32_t mbar0 = smem_u32(&mb[0]), mbar1 = smem_u32(&mb[1]);
    if (tid == 0) { MBAR_INIT(mbar0, 1); MBAR_INIT(mbar1, 1); }
    __syncthreads();

    const char* Asrc = Ap + (size_t)my * 16 * TAB;
    const char* Wsrc = Wp + (size_t)nx * 16 * TAB;

    if (tid == 0) {
        MBAR_EXPECT(mbar0, 2 * TAB);
        bulk_cp(sb, Asrc, TAB, mbar0);
        bulk_cp(sb + TAB, Wsrc, TAB, mbar0);
    }

    float acc[2][8][4] = {};
    const int a_row = wm * 32 + (lane & 15);
    const uint32_t a_kext = (lane & 16) ? 16u : 0u;
    const int b_row = wn * 64 + ((lane & 16) ? 8 : 0) + (lane & 7);
    const uint32_t b_kext = (lane & 8) ? 16u : 0u;
    int ph0 = 0, ph1 = 0;

    for (int c = 0; c < 16; ++c) {
        const int b = c & 1;
        if (c + 1 < 16 && tid == 0) {
            const uint32_t nb = sb + (1 - b) * 2 * TAB;
            const uint32_t m = b ? mbar0 : mbar1;
            MBAR_EXPECT(m, 2 * TAB);
            bulk_cp(nb, Asrc + (size_t)(c + 1) * TAB, TAB, m);
            bulk_cp(nb + TAB, Wsrc + (size_t)(c + 1) * TAB, TAB, m);
        }
        if (b == 0) { mbar_wait(mbar0, ph0); ph0 ^= 1; }
        else        { mbar_wait(mbar1, ph1); ph1 ^= 1; }
        const uint32_t aS = sb + b * 2 * TAB;
        mma_tile144(acc, aS, aS + TAB, a_row, a_kext, b_row, b_kext);
        __syncthreads();
    }

    const int gq = lane >> 2, tig = lane & 3;
#pragma unroll
    for (int ma = 0; ma < 2; ++ma) {
        const int rl = wm * 32 + ma * 16 + gq;
#pragma unroll
        for (int n = 0; n < 8; ++n) {
            const int col = nx * 128 + wn * 64 + n * 8 + tig * 2;
            const float b0 = bias[col], b1 = bias[col + 1];
            const size_t tb = (size_t)(my * 16 + (col >> 6)) * TAB + (col & 63) * 2;
            *(__half2*)(Cp + tb + rl * 144) =
                __floats2half2_rn((acc[ma][n][0] + b0) * cs, (acc[ma][n][1] + b1) * cs);
            *(__half2*)(Cp + tb + (rl + 8) * 144) =
                __floats2half2_rn((acc[ma][n][2] + b0) * cs, (acc[ma][n][3] + b1) * cs);
        }
    }
}

// ---------------------------------------------------------------------------
// V projection on HMMA, writing transposed packed VT directly.
// ---------------------------------------------------------------------------
__global__ void __launch_bounds__(256, 2)
proj_v(const char* __restrict__ Ap, const char* __restrict__ Wvp,
       const float* __restrict__ bias, char* __restrict__ VTp)
{
    extern __shared__ char smem[];
    __shared__ uint64_t mb[2];
    const uint32_t sb = smem_u32(smem);
    const int tid = threadIdx.x, lane = tid & 31, w = tid >> 5;
    const int wm = w >> 1, wn = w & 1;
    const int my = blockIdx.x;

    const uint32_t mbar0 = smem_u32(&mb[0]), mbar1 = smem_u32(&mb[1]);
    if (tid == 0) { MBAR_INIT(mbar0, 1); MBAR_INIT(mbar1, 1); }
    __syncthreads();

    const char* Asrc = Ap + (size_t)my * 16 * TAB;

    if (tid == 0) {
        MBAR_EXPECT(mbar0, 2 * TAB);
        bulk_cp(sb, Asrc, TAB, mbar0);
        bulk_cp(sb + TAB, Wvp, TAB, mbar0);
    }

    float acc[2][8][4] = {};
    const int a_row = wm * 32 + (lane & 15);
    const uint32_t a_kext = (lane & 16) ? 16u : 0u;
    const int b_row = wn * 64 + ((lane & 16) ? 8 : 0) + (lane & 7);
    const uint32_t b_kext = (lane & 8) ? 16u : 0u;
    int ph0 = 0, ph1 = 0;

    for (int c = 0; c < 16; ++c) {
        const int b = c & 1;
        if (c + 1 < 16 && tid == 0) {
            const uint32_t nb = sb + (1 - b) * 2 * TAB;
            const uint32_t m = b ? mbar0 : mbar1;
            MBAR_EXPECT(m, 2 * TAB);
            bulk_cp(nb, Asrc + (size_t)(c + 1) * TAB, TAB, m);
            bulk_cp(nb + TAB, Wvp + (size_t)(c + 1) * TAB, TAB, m);
        }
        if (b == 0) { mbar_wait(mbar0, ph0); ph0 ^= 1; }
        else        { mbar_wait(mbar1, ph1); ph1 ^= 1; }
        const uint32_t aS = sb + b * 2 * TAB;
        mma_tile144(acc, aS, aS + TAB, a_row, a_kext, b_row, b_kext);
        __syncthreads();
    }

    if (wn == 0) {
        const int gq = lane >> 2, tig = lane & 3;
        char* Vt = VTp + (size_t)my * VTB;
#pragma unroll
        for (int ma = 0; ma < 2; ++ma) {
            const int rl = wm * 32 + ma * 16 + gq;
#pragma unroll
            for (int n = 0; n < 8; ++n) {
                const int d = n * 8 + tig * 2;
                const float b0 = bias[d], b1 = bias[d + 1];
                *(__half*)(Vt + d * 272 + rl * 2)             = __float2half(acc[ma][n][0] + b0);
                *(__half*)(Vt + (d + 1) * 272 + rl * 2)       = __float2half(acc[ma][n][1] + b1);
                *(__half*)(Vt + d * 272 + (rl + 8) * 2)       = __float2half(acc[ma][n][2] + b0);
                *(__half*)(Vt + (d + 1) * 272 + (rl + 8) * 2) = __float2half(acc[ma][n][3] + b1);
            }
        }
    }
}

// ---------------------------------------------------------------------------
// Pass A: per-(b,h,q) softmax denominators. weight = exp2(score') via h2exp2.
// ---------------------------------------------------------------------------
__global__ void __launch_bounds__(256, 2)
qk_rowsum_p(const char* __restrict__ Qp, const char* __restrict__ Kp, float* __restrict__ iL)
{
    extern __shared__ char smem[];
    __shared__ uint64_t mb[2];
    const uint32_t sb = smem_u32(smem);
    const int tid = threadIdx.x, lane = tid & 31, w = tid >> 5;
    const int wm = w >> 1, wn = w & 1;
    const int qt = blockIdx.x, h = blockIdx.y, b = blockIdx.z;

    const uint32_t mbar0 = smem_u32(&mb[0]), mbar1 = smem_u32(&mb[1]);
    if (tid == 0) { MBAR_INIT(mbar0, 1); MBAR_INIT(mbar1, 1); }
    __syncthreads();

    const char* Qsrc = Qp + ((size_t)(b * 16 + qt) * 16 + h) * TAB;
    if (tid == 0) {
        MBAR_EXPECT(mbar0, 2 * TAB);
        bulk_cp(sb, Qsrc, TAB, mbar0);
        bulk_cp(sb + TAB, Kp + ((size_t)(b * 16 + 0) * 16 + h) * TAB, TAB, mbar0);
    }

    const int a_row = wm * 32 + (lane & 15);
    const uint32_t a_kext = (lane & 16) ? 16u : 0u;
    const int b_row = wn * 64 + ((lane & 16) ? 8 : 0) + (lane & 7);
    const uint32_t b_kext = (lane & 8) ? 16u : 0u;

    float lsum[2][2] = {};
    int ph0 = 0, ph1 = 0;

    for (int kt = 0; kt < 16; ++kt) {
        const int bb = kt & 1;
        if (kt + 1 < 16 && tid == 0) {
            const uint32_t m = bb ? mbar0 : mbar1;
            MBAR_EXPECT(m, TAB);
            bulk_cp(sb + TAB + (1 - bb) * TAB,
                    Kp + ((size_t)(b * 16 + kt + 1) * 16 + h) * TAB, TAB, m);
        }
        if (bb == 0) { mbar_wait(mbar0, ph0); ph0 ^= 1; }
        else         { mbar_wait(mbar1, ph1); ph1 ^= 1; }

        float acc[2][8][4] = {};
        mma_tile144(acc, sb, sb + TAB + bb * TAB, a_row, a_kext, b_row, b_kext);

#pragma unroll
        for (int ma = 0; ma < 2; ++ma)
#pragma unroll
            for (int n = 0; n < 8; ++n) {
                float2 e0 = __half22float2(h2exp2(__floats2half2_rn(acc[ma][n][0], acc[ma][n][1])));
                float2 e1 = __half22float2(h2exp2(__floats2half2_rn(acc[ma][n][2], acc[ma][n][3])));
                lsum[ma][0] += e0.x + e0.y;
                lsum[ma][1] += e1.x + e1.y;
            }
        __syncthreads();
    }

#pragma unroll
    for (int o = 1; o <= 2; o <<= 1)
#pragma unroll
        for (int ma = 0; ma < 2; ++ma)
#pragma unroll
            for (int hh = 0; hh < 2; ++hh)
                lsum[ma][hh] += __shfl_xor_sync(0xffffffffu, lsum[ma][hh], o);

    __shared__ float Ls[128];
    if (tid < 128) Ls[tid] = 0.f;
    __syncthreads();
    if ((lane & 3) == 0) {
        const int gq = lane >> 2;
#pragma unroll
        for (int ma = 0; ma < 2; ++ma) {
            atomicAdd(&Ls[wm * 32 + ma * 16 + gq], lsum[ma][0]);
            atomicAdd(&Ls[wm * 32 + ma * 16 + gq + 8], lsum[ma][1]);
        }
    }
    __syncthreads();
    if (tid < 128)
        iL[((size_t)b * NH + h) * S_ + qt * 128 + tid] = 1.0f / (16.0f * Ls[tid]);
}

// ---------------------------------------------------------------------------
// Pass B: head-averaged softmax + fused PV. smem overlay -> occupancy 2.
// ---------------------------------------------------------------------------
#define ATT_SM (4 * TAB)

__global__ void __launch_bounds__(256, 2)
attn_avg_p(const char* __restrict__ Qp, const char* __restrict__ Kp,
           const char* __restrict__ VTp, const float* __restrict__ iL,
           float* __restrict__ avg, float* __restrict__ AO)
{
    extern __shared__ char smem[];
    __shared__ uint64_t mb[3];
    const uint32_t sb = smem_u32(smem);
    const int tid = threadIdx.x, lane = tid & 31, w = tid >> 5;
    const int wm = w >> 1, wn = w & 1;
    const int kt = blockIdx.x, qt = blockIdx.y, b = blockIdx.z;

    const uint32_t mbar0 = smem_u32(&mb[0]), mbar1 = smem_u32(&mb[1]), mbar2 = smem_u32(&mb[2]);
    if (tid == 0) { MBAR_INIT(mbar0, 1); MBAR_INIT(mbar1, 1); MBAR_INIT(mbar2, 1); }
    __syncthreads();

    const char* Qsrc = Qp + (size_t)(b * 16 + qt) * 16 * TAB;
    const char* Ksrc = Kp + (size_t)(b * 16 + kt) * 16 * TAB;

    if (tid == 0) {
        MBAR_EXPECT(mbar0, 2 * TAB);
        bulk_cp(sb, Qsrc, TAB, mbar0);
        bulk_cp(sb + TAB, Ksrc, TAB, mbar0);
    }

    const int a_row = wm * 32 + (lane & 15);
    const uint32_t a_kext = (lane & 16) ? 16u : 0u;
    const int b_row = wn * 64 + ((lane & 16) ? 8 : 0) + (lane & 7);
    const uint32_t b_kext = (lane & 8) ? 16u : 0u;
    const int gq = lane >> 2, tig = lane & 3;

    float avgf[2][8][4] = {};
    int ph0 = 0, ph1 = 0;

    for (int h = 0; h < NH; ++h) {
        const int bb = h & 1;
        if (h + 1 < NH && tid == 0) {
            const uint32_t nb = sb + (1 - bb) * 2 * TAB;
            const uint32_t m = bb ? mbar0 : mbar1;
            MBAR_EXPECT(m, 2 * TAB);
            bulk_cp(nb, Qsrc + (size_t)(h + 1) * TAB, TAB, m);
            bulk_cp(nb + TAB, Ksrc + (size_t)(h + 1) * TAB, TAB, m);
        }
        if (bb == 0) { mbar_wait(mbar0, ph0); ph0 ^= 1; }
        else         { mbar_wait(mbar1, ph1); ph1 ^= 1; }

        float acc[2][8][4] = {};
        const uint32_t aS = sb + bb * 2 * TAB;
        mma_tile144(acc, aS, aS + TAB, a_row, a_kext, b_row, b_kext);

        const float* Lh = iL + ((size_t)b * NH + h) * S_ + qt * 128;
#pragma unroll
        for (int ma = 0; ma < 2; ++ma) {
            const float l0 = Lh[wm * 32 + ma * 16 + gq];
            const float l1 = Lh[wm * 32 + ma * 16 + gq + 8];
#pragma unroll
            for (int n = 0; n < 8; ++n) {
                float2 e0 = __half22float2(h2exp2(__floats2half2_rn(acc[ma][n][0], acc[ma][n][1])));
                float2 e1 = __half22float2(h2exp2(__floats2half2_rn(acc[ma][n][2], acc[ma][n][3])));
                avgf[ma][n][0] += e0.x * l0;
                avgf[ma][n][1] += e0.y * l0;
                avgf[ma][n][2] += e1.x * l1;
                avgf[ma][n][3] += e1.y * l1;
            }
        }
        __syncthreads();
    }

    // Q/K buffers dead. Load VT into buf1 region; stage P into buf0 region.
    if (tid == 0) {
        MBAR_EXPECT(mbar2, VTB);
        bulk_cp(sb + 2 * TAB, VTp + (size_t)(b * 16 + kt) * VTB, VTB, mbar2);
    }

    float* outp = avg + (size_t)b * S_ * S_;
#pragma unroll
    for (int ma = 0; ma < 2; ++ma) {
        const int rl = wm * 32 + ma * 16 + gq;
        const int r0 = qt * 128 + rl;
#pragma unroll
        for (int n = 0; n < 8; ++n) {
            const int col = wn * 64 + n * 8 + tig * 2;
            *(float2*)(outp + (size_t)r0 * S_ + kt * 128 + col) =
                make_float2(avgf[ma][n][0], avgf[ma][n][1]);
            *(float2*)(outp + (size_t)(r0 + 8) * S_ + kt * 128 + col) =
                make_float2(avgf[ma][n][2], avgf[ma][n][3]);
            *(__half2*)(smem + rl * 272 + col * 2) =
                __floats2half2_rn(avgf[ma][n][0], avgf[ma][n][1]);
            *(__half2*)(smem + (rl + 8) * 272 + col * 2) =
                __floats2half2_rn(avgf[ma][n][2], avgf[ma][n][3]);
        }
    }
    mbar_wait(mbar2, 0);
    __syncthreads();

    // PV: [128q x 64d] += P[128q x 128k] @ VT[64d x 128k]^T
    float apv[2][4][4] = {};
    const int pv_brow = wn * 32 + ((lane & 16) ? 8 : 0) + (lane & 7);
    const uint32_t pS = sb, vS = sb + 2 * TAB;
#pragma unroll
    for (int ks = 0; ks < 8; ++ks) {
        uint32_t ah[2][4];
#pragma unroll
        for (int ma = 0; ma < 2; ++ma) {
            const uint32_t off = (uint32_t)((a_row + ma * 16) * 272 + ks * 32) + a_kext;
            ldsm4(ah[ma][0], ah[ma][1], ah[ma][2], ah[ma][3], pS + off);
        }
#pragma unroll
        for (int bg = 0; bg < 2; ++bg) {
            const uint32_t off = (uint32_t)((pv_brow + bg * 16) * 272 + ks * 32) + b_kext;
            uint32_t bh[4];
            ldsm4(bh[0], bh[1], bh[2], bh[3], vS + off);
#pragma unroll
            for (int na = 0; na < 2; ++na)
#pragma unroll
                for (int ma = 0; ma < 2; ++ma)
                    mma_f16(apv[ma][bg * 2 + na], ah[ma], &bh[na * 2]);
        }
    }

#pragma unroll
    for (int ma = 0; ma < 2; ++ma) {
        const int r0 = qt * 128 + wm * 32 + ma * 16 + gq;
#pragma unroll
        for (int nI = 0; nI < 4; ++nI) {
            const int d = wn * 32 + nI * 8 + tig * 2;
            float* a0 = AO + ((size_t)b * S_ + r0) * HD + d;
            float* a1 = AO + ((size_t)b * S_ + r0 + 8) * HD + d;
            atomicAdd(a0, apv[ma][nI][0]);
            atomicAdd(a0 + 1, apv[ma][nI][1]);
            atomicAdd(a1, apv[ma][nI][2]);
            atomicAdd(a1 + 1, apv[ma][nI][3]);
        }
    }
}

// ---------------------------------------------------------------------------
// bf16x3 split GEMM (O projection, K=64, LDGSTS path)
// ---------------------------------------------------------------------------
#define TILE_B 16384
#define BUF4 (4 * TILE_B)

__global__ void __launch_bounds__(256, 2)
hmma_bf16x3_nt(const __nv_bfloat16* __restrict__ hA, const __nv_bfloat16* __restrict__ lA,
               const __nv_bfloat16* __restrict__ hB, const __nv_bfloat16* __restrict__ lB,
               const float* __restrict__ bias, float* __restrict__ C,
               int K, int lda, int ldb, int ldc)
{
    extern __shared__ char smem[];
    const uint32_t sb = smem_u32(smem);
    const int tid = threadIdx.x, lane = tid & 31, w = tid >> 5;
    const int wm = w >> 1, wn = w & 1;
    const int m0 = blockIdx.y * 128, n0 = blockIdx.x * 128;

    hA += (size_t)m0 * lda; lA += (size_t)m0 * lda;
    hB += (size_t)n0 * ldb; lB += (size_t)n0 * ldb;

    cp_tile(hA, lda, sb + 0 * TILE_B, tid);
    cp_tile(lA, lda, sb + 1 * TILE_B, tid);
    cp_tile(hB, ldb, sb + 2 * TILE_B, tid);
    cp_tile(lB, ldb, sb + 3 * TILE_B, tid);
    CP_COMMIT();
    CP_WAIT(0);
    __syncthreads();

    float acc[2][8][4] = {};

    const int a_row = wm * 32 + (lane & 15);
    const uint32_t a_kext = (lane & 16) ? 16u : 0u;
    const int b_row = wn * 64 + ((lane & 16) ? 8 : 0) + (lane & 7);
    const uint32_t b_kext = (lane & 8) ? 16u : 0u;

    const uint32_t aH = sb, aL = sb + TILE_B, bH = sb + 2 * TILE_B, bL = sb + 3 * TILE_B;

#pragma unroll
    for (int ks = 0; ks < 4; ++ks) {
        uint32_t ah[2][4], al[2][4];
#pragma unroll
        for (int ma = 0; ma < 2; ++ma) {
            const uint32_t off =
                SWZ128((uint32_t)((a_row + ma * 16) * 128) + (uint32_t)(ks * 32) + a_kext);
            ldsm4(ah[ma][0], ah[ma][1], ah[ma][2], ah[ma][3], aH + off);
            ldsm4(al[ma][0], al[ma][1], al[ma][2], al[ma][3], aL + off);
        }
#pragma unroll
        for (int bg = 0; bg < 4; ++bg) {
            const uint32_t off =
                SWZ128((uint32_t)((b_row + bg * 16) * 128) + (uint32_t)(ks * 32) + b_kext);
            uint32_t bh[4], bl[4];
            ldsm4(bh[0], bh[1], bh[2], bh[3], bH + off);
            ldsm4(bl[0], bl[1], bl[2], bl[3], bL + off);
#pragma unroll
            for (int na = 0; na < 2; ++na) {
                const int n = bg * 2 + na;
#pragma unroll
                for (int ma = 0; ma < 2; ++ma) {
                    mma_bf16(acc[ma][n], ah[ma], &bh[na * 2]);
                    mma_bf16(acc[ma][n], ah[ma], &bl[na * 2]);
                    mma_bf16(acc[ma][n], al[ma], &bh[na * 2]);
                }
            }
        }
    }

    const int gq = lane >> 2, tig = lane & 3;
#pragma unroll
    for (int ma = 0; ma < 2; ++ma) {
        const int r0 = m0 + wm * 32 + ma * 16 + gq;
#pragma unroll
        for (int n = 0; n < 8; ++n) {
            const int col = n0 + wn * 64 + n * 8 + tig * 2;
            const float b0 = bias[col], b1 = bias[col + 1];
            *(float2*)(C + (size_t)r0 * ldc + col) =
                make_float2(acc[ma][n][0] + b0, acc[ma][n][1] + b1);
            *(float2*)(C + (size_t)(r0 + 8) * ldc + col) =
                make_float2(acc[ma][n][2] + b0, acc[ma][n][3] + b1);
        }
    }
}

extern "C" void kernel_launch(void* const* d_in, const int* in_sizes, int n_in,
                              void* d_out, int out_size)
{
    const float* query  = (const float*)d_in[0];
    const float* key_in = (const float*)d_in[1];
    const float* value  = (const float*)d_in[2];
    const float* Wq = (const float*)d_in[3];
    const float* bq = (const float*)d_in[4];
    const float* Wk = (const float*)d_in[5];
    const float* bk = (const float*)d_in[6];
    const float* Wv = (const float*)d_in[7];
    const float* bv = (const float*)d_in[8];
    const float* Wo = (const float*)d_in[9];
    const float* bo = (const float*)d_in[10];

    float* out = (float*)d_out;
    float* avg_out = out + (size_t)B_ * S_ * H_;

    float *gAO, *giL;
    char *gApc, *gWpc, *gWvpc, *gQpc, *gKpc, *gVTpc;
    __nv_bfloat16 *hA, *lA, *hW, *lW;
    cudaGetSymbolAddress((void**)&gAO, g_AO);
    cudaGetSymbolAddress((void**)&giL, g_iL);
    cudaGetSymbolAddress((void**)&gApc, g_Ap);
    cudaGetSymbolAddress((void**)&gWpc, g_Wp);
    cudaGetSymbolAddress((void**)&gWvpc, g_Wvp);
    cudaGetSymbolAddress((void**)&gQpc, g_Qp);
    cudaGetSymbolAddress((void**)&gKpc, g_Kp);
    cudaGetSymbolAddress((void**)&gVTpc, g_VTp);
    cudaGetSymbolAddress((void**)&hA, g_hA);
    cudaGetSymbolAddress((void**)&lA, g_lA);
    cudaGetSymbolAddress((void**)&hW, g_hW);
    cudaGetSymbolAddress((void**)&lW, g_lW);

    cudaFuncSetAttribute(proj_f16, cudaFuncAttributeMaxDynamicSharedMemorySize, 4 * TAB);
    cudaFuncSetAttribute(proj_v, cudaFuncAttributeMaxDynamicSharedMemorySize, 4 * TAB);
    cudaFuncSetAttribute(qk_rowsum_p, cudaFuncAttributeMaxDynamicSharedMemorySize, 3 * TAB);
    cudaFuncSetAttribute(attn_avg_p, cudaFuncAttributeMaxDynamicSharedMemorySize, ATT_SM);
    cudaFuncSetAttribute(hmma_bf16x3_nt, cudaFuncAttributeMaxDynamicSharedMemorySize, BUF4);

    const int M = B_ * S_;          // 8192
    const int NXH = B_ * S_ * H_;   // 8M

    zero_f<<<(B_ * S_ * HD) / 256, 256>>>(gAO, B_ * S_ * HD);
    zero_f<<<(16 * TAB / 4) / 256, 256>>>((float*)gWvpc, 16 * TAB / 4);

    // V projection (fp16 HMMA -> packed VT directly)
    cvt_pack<<<NXH / 1024, 256>>>((const float4*)value, gApc, NXH / 4);
    cvt_pack_w64<<<(HD * H_) / 1024, 256>>>((const float4*)Wv, gWvpc, HD * H_ / 4);
    proj_v<<<64, 256, 4 * TAB>>>(gApc, gWvpc, bv, gVTpc);

    // Q projection (scaled by 0.125*log2e: weights = exp2(score'))
    cvt_pack<<<NXH / 1024, 256>>>((const float4*)query, gApc, NXH / 4);
    cvt_pack<<<(H_ * H_) / 1024, 256>>>((const float4*)Wq, gWpc, H_ * H_ / 4);
    proj_f16<<<dim3(8, 64), 256, 4 * TAB>>>(gApc, gWpc, bq, gQpc, QSCALE);
    // K projection (unscaled)
    cvt_pack<<<NXH / 1024, 256>>>((const float4*)key_in, gApc, NXH / 4);
    cvt_pack<<<(H_ * H_) / 1024, 256>>>((const float4*)Wk, gWpc, H_ * H_ / 4);
    proj_f16<<<dim3(8, 64), 256, 4 * TAB>>>(gApc, gWpc, bk, gKpc, 1.0f);

    // Pass A: softmax denominators
    qk_rowsum_p<<<dim3(S_ / 128, NH, B_), 256, 3 * TAB>>>(gQpc, gKpc, giL);

    // Pass B: head-averaged softmax + fused PV (occupancy 2)
    attn_avg_p<<<dim3(S_ / 128, S_ / 128, B_), 256, ATT_SM>>>(gQpc, gKpc, gVTpc, giL,
                                                              avg_out, gAO);

    // O projection (bf16x3)
    split_hl4<<<(B_ * S_ * HD) / 1024, 256>>>((const float4*)gAO, (uint2*)hA, (uint2*)lA,
                                              B_ * S_ * HD / 4);
    split_hl4<<<(H_ * HD) / 1024, 256>>>((const float4*)Wo, (uint2*)hW, (uint2*)lW, H_ * HD / 4);
    hmma_bf16x3_nt<<<dim3(H_ / 128, M / 128, 1), 256, BUF4>>>(hA, lA, hW, lW, bo,
        out, HD, HD, HD, H_);
}

// round 13
// speedup vs baseline: 11.0469x; 1.0773x over previous
#include <cuda_runtime.h>
#include <cuda_bf16.h>
#include <cuda_fp16.h>
#include <cstdint>

#define B_ 4
#define S_ 2048
#define H_ 1024
#define NH 16
#define HD 64

#define TAB 18432            // packed tile: 128 rows x 144B pitch (64 fp16 cols)
#define VTB 17408            // VT tile: 64 rows x 272B pitch (128 fp16 cols)

// Q is pre-scaled by 0.125*log2(e) so softmax weight = exp2(score)
#define QSCALE 0.180336879f

// scratch
__device__ float g_AO[B_ * S_ * HD];
__device__ float g_iL[B_ * NH * S_];
__device__ __align__(16) char g_Ap[64 * 16 * TAB];
__device__ __align__(16) char g_Wp[8 * 16 * TAB];
__device__ __align__(16) char g_Wvp[16 * TAB];
__device__ __align__(16) char g_Qp[64 * 16 * TAB];
__device__ __align__(16) char g_Kp[64 * 16 * TAB];
__device__ __align__(16) char g_VTp[64 * VTB];
__device__ __nv_bfloat16 g_hA[B_ * S_ * HD], g_lA[B_ * S_ * HD];
__device__ __nv_bfloat16 g_hW[H_ * HD],      g_lW[H_ * HD];

// ---------------------------------------------------------------------------
// helpers
// ---------------------------------------------------------------------------
__device__ __forceinline__ uint32_t smem_u32(const void* p) {
    uint32_t a;
    asm("{ .reg .u64 t; cvta.to.shared.u64 t, %1; cvt.u32.u64 %0, t; }" : "=r"(a) : "l"(p));
    return a;
}
#define SWZ128(x) ((x) ^ (((x) >> 3) & 0x70))

__device__ __forceinline__ float ex2(float x) {
    float y; asm("ex2.approx.f32 %0, %1;" : "=f"(y) : "f"(x)); return y;
}

__device__ __forceinline__ void ldsm4(uint32_t& r0, uint32_t& r1, uint32_t& r2, uint32_t& r3,
                                      uint32_t addr) {
    asm volatile("ldmatrix.sync.aligned.m8n8.x4.shared.b16 {%0,%1,%2,%3}, [%4];"
                 : "=r"(r0), "=r"(r1), "=r"(r2), "=r"(r3) : "r"(addr));
}
__device__ __forceinline__ void mma_bf16(float* c, const uint32_t* a, const uint32_t* b) {
    asm volatile(
        "mma.sync.aligned.m16n8k16.row.col.f32.bf16.bf16.f32 "
        "{%0,%1,%2,%3}, {%4,%5,%6,%7}, {%8,%9}, {%0,%1,%2,%3};"
        : "+f"(c[0]), "+f"(c[1]), "+f"(c[2]), "+f"(c[3])
        : "r"(a[0]), "r"(a[1]), "r"(a[2]), "r"(a[3]), "r"(b[0]), "r"(b[1]));
}
__device__ __forceinline__ void mma_f16(float* c, const uint32_t* a, const uint32_t* b) {
    asm volatile(
        "mma.sync.aligned.m16n8k16.row.col.f32.f16.f16.f32 "
        "{%0,%1,%2,%3}, {%4,%5,%6,%7}, {%8,%9}, {%0,%1,%2,%3};"
        : "+f"(c[0]), "+f"(c[1]), "+f"(c[2]), "+f"(c[3])
        : "r"(a[0]), "r"(a[1]), "r"(a[2]), "r"(a[3]), "r"(b[0]), "r"(b[1]));
}
#define CP16(s, g) asm volatile("cp.async.cg.shared.global [%0], [%1], 16;" :: "r"(s), "l"(g))
#define CP_COMMIT() asm volatile("cp.async.commit_group;" ::: "memory")
#define CP_WAIT(n)  asm volatile("cp.async.wait_group %0;" :: "n"(n) : "memory")

// --- TMA bulk-copy + mbarrier (base sm_90 PTX) ---
__device__ __forceinline__ void bulk_cp(uint32_t sdst, const void* gsrc, uint32_t bytes,
                                        uint32_t mbar) {
    asm volatile(
        "cp.async.bulk.shared::cta.global.mbarrier::complete_tx::bytes [%0], [%1], %2, [%3];"
        :: "r"(sdst), "l"(gsrc), "r"(bytes), "r"(mbar) : "memory");
}
#define MBAR_INIT(a, n) \
    asm volatile("mbarrier.init.shared.b64 [%0], %1;" :: "r"(a), "r"((uint32_t)(n)) : "memory")
#define MBAR_EXPECT(a, bytes) \
    asm volatile("mbarrier.arrive.expect_tx.shared.b64 _, [%0], %1;" \
                 :: "r"(a), "r"((uint32_t)(bytes)) : "memory")
__device__ __forceinline__ void mbar_wait(uint32_t mbar, int parity) {
    asm volatile(
        "{\n\t.reg .pred P;\n\t"
        "LAB_%=:\n\t"
        "mbarrier.try_wait.parity.acquire.cta.shared::cta.b64 P, [%0], %1;\n\t"
        "@!P bra LAB_%=;\n\t}"
        :: "r"(mbar), "r"((uint32_t)parity) : "memory");
}

// LDGSTS staging (O-projection only)
__device__ __forceinline__ void cp_tile(const void* __restrict__ g, int ld_elems,
                                        uint32_t sdst, int tid)
{
    const __half* gh = (const __half*)g;
#pragma unroll
    for (int it = 0; it < 4; ++it) {
        int i = tid + it * 256;
        int row = i >> 3, c = i & 7;
        const void* gp = gh + (size_t)row * ld_elems + c * 8;
        uint32_t sp = sdst + SWZ128((uint32_t)(row * 128 + c * 16));
        CP16(sp, gp);
    }
}

// 128x128x64 fp16 MMA on two pitch-144 tiles
__device__ __forceinline__ void mma_tile144(float acc[2][8][4], uint32_t aS, uint32_t bS,
                                            int a_row, uint32_t a_kext,
                                            int b_row, uint32_t b_kext)
{
#pragma unroll
    for (int ks = 0; ks < 4; ++ks) {
        uint32_t ah[2][4];
#pragma unroll
        for (int ma = 0; ma < 2; ++ma) {
            const uint32_t off = (uint32_t)((a_row + ma * 16) * 144 + ks * 32) + a_kext;
            ldsm4(ah[ma][0], ah[ma][1], ah[ma][2], ah[ma][3], aS + off);
        }
#pragma unroll
        for (int bg = 0; bg < 4; ++bg) {
            const uint32_t off = (uint32_t)((b_row + bg * 16) * 144 + ks * 32) + b_kext;
            uint32_t bh[4];
            ldsm4(bh[0], bh[1], bh[2], bh[3], bS + off);
#pragma unroll
            for (int na = 0; na < 2; ++na)
#pragma unroll
                for (int ma = 0; ma < 2; ++ma)
                    mma_f16(acc[ma][bg * 2 + na], ah[ma], &bh[na * 2]);
        }
    }
}

// ---------------------------------------------------------------------------
// utility kernels
// ---------------------------------------------------------------------------
__global__ void cvt_pack(const float4* __restrict__ x, char* __restrict__ out, int n4)
{
    int i = blockIdx.x * blockDim.x + threadIdx.x;
    if (i >= n4) return;
    float4 v = x[i];
    union { __half2 h2[2]; uint2 u; } p;
    p.h2[0] = __floats2half2_rn(v.x, v.y);
    p.h2[1] = __floats2half2_rn(v.z, v.w);
    int row = i >> 8;
    int col = (i & 255) << 2;
    int rt = row >> 7, r = row & 127, c = col >> 6, k = col & 63;
    *(uint2*)(out + (size_t)(rt * 16 + c) * TAB + r * 144 + k * 2) = p.u;
}

__global__ void cvt_pack_w64(const float4* __restrict__ x, char* __restrict__ out, int n4)
{
    int i = blockIdx.x * blockDim.x + threadIdx.x;
    if (i >= n4) return;
    float4 v = x[i];
    union { __half2 h2[2]; uint2 u; } p;
    p.h2[0] = __floats2half2_rn(v.x, v.y);
    p.h2[1] = __floats2half2_rn(v.z, v.w);
    int row = i >> 8;
    int col = (i & 255) << 2;
    int c = col >> 6, k = col & 63;
    *(uint2*)(out + (size_t)c * TAB + row * 144 + k * 2) = p.u;
}

__global__ void split_hl4(const float4* __restrict__ x, uint2* __restrict__ hi,
                          uint2* __restrict__ lo, int n4)
{
    int i = blockIdx.x * blockDim.x + threadIdx.x;
    if (i < n4) {
        float4 v = x[i];
        __nv_bfloat16 h0 = __float2bfloat16(v.x), h1 = __float2bfloat16(v.y);
        __nv_bfloat16 h2 = __float2bfloat16(v.z), h3 = __float2bfloat16(v.w);
        __nv_bfloat16 l0 = __float2bfloat16(v.x - __bfloat162float(h0));
        __nv_bfloat16 l1 = __float2bfloat16(v.y - __bfloat162float(h1));
        __nv_bfloat16 l2 = __float2bfloat16(v.z - __bfloat162float(h2));
        __nv_bfloat16 l3 = __float2bfloat16(v.w - __bfloat162float(h3));
        union { __nv_bfloat162 b2[2]; uint2 u; } ph, pl;
        ph.b2[0].x = h0; ph.b2[0].y = h1; ph.b2[1].x = h2; ph.b2[1].y = h3;
        pl.b2[0].x = l0; pl.b2[0].y = l1; pl.b2[1].x = l2; pl.b2[1].y = l3;
        hi[i] = ph.u;
        lo[i] = pl.u;
    }
}

__global__ void zero_f(float* __restrict__ p, int n)
{
    int i = blockIdx.x * blockDim.x + threadIdx.x;
    if (i < n) p[i] = 0.f;
}

// ---------------------------------------------------------------------------
// fp16 projection GEMM on packed tiles, TMA-bulk staged. Output packed.
// ---------------------------------------------------------------------------
__global__ void __launch_bounds__(256, 2)
proj_f16(const char* __restrict__ Ap, const char* __restrict__ Wp,
         const float* __restrict__ bias, char* __restrict__ Cp, float cs)
{
    extern __shared__ char smem[];
    __shared__ uint64_t mb[2];
    const uint32_t sb = smem_u32(smem);
    const int tid = threadIdx.x, lane = tid & 31, w = tid >> 5;
    const int wm = w >> 1, wn = w & 1;
    const int nx = blockIdx.x, my = blockIdx.y;

    const uint32_t mbar0 = smem_u32(&mb[0]), mbar1 = smem_u32(&mb[1]);
    if (tid == 0) { MBAR_INIT(mbar0, 1); MBAR_INIT(mbar1, 1); }
    __syncthreads();

    const char* Asrc = Ap + (size_t)my * 16 * TAB;
    const char* Wsrc = Wp + (size_t)nx * 16 * TAB;

    if (tid == 0) {
        MBAR_EXPECT(mbar0, 2 * TAB);
        bulk_cp(sb, Asrc, TAB, mbar0);
        bulk_cp(sb + TAB, Wsrc, TAB, mbar0);
    }

    float acc[2][8][4] = {};
    const int a_row = wm * 32 + (lane & 15);
    const uint32_t a_kext = (lane & 16) ? 16u : 0u;
    const int b_row = wn * 64 + ((lane & 16) ? 8 : 0) + (lane & 7);
    const uint32_t b_kext = (lane & 8) ? 16u : 0u;
    int ph0 = 0, ph1 = 0;

    for (int c = 0; c < 16; ++c) {
        const int b = c & 1;
        if (c + 1 < 16 && tid == 0) {
            const uint32_t nb = sb + (1 - b) * 2 * TAB;
            const uint32_t m = b ? mbar0 : mbar1;
            MBAR_EXPECT(m, 2 * TAB);
            bulk_cp(nb, Asrc + (size_t)(c + 1) * TAB, TAB, m);
            bulk_cp(nb + TAB, Wsrc + (size_t)(c + 1) * TAB, TAB, m);
        }
        if (b == 0) { mbar_wait(mbar0, ph0); ph0 ^= 1; }
        else        { mbar_wait(mbar1, ph1); ph1 ^= 1; }
        const uint32_t aS = sb + b * 2 * TAB;
        mma_tile144(acc, aS, aS + TAB, a_row, a_kext, b_row, b_kext);
        __syncthreads();
    }

    const int gq = lane >> 2, tig = lane & 3;
#pragma unroll
    for (int ma = 0; ma < 2; ++ma) {
        const int rl = wm * 32 + ma * 16 + gq;
#pragma unroll
        for (int n = 0; n < 8; ++n) {
            const int col = nx * 128 + wn * 64 + n * 8 + tig * 2;
            const float b0 = bias[col], b1 = bias[col + 1];
            const size_t tb = (size_t)(my * 16 + (col >> 6)) * TAB + (col & 63) * 2;
            *(__half2*)(Cp + tb + rl * 144) =
                __floats2half2_rn((acc[ma][n][0] + b0) * cs, (acc[ma][n][1] + b1) * cs);
            *(__half2*)(Cp + tb + (rl + 8) * 144) =
                __floats2half2_rn((acc[ma][n][2] + b0) * cs, (acc[ma][n][3] + b1) * cs);
        }
    }
}

// ---------------------------------------------------------------------------
// V projection on HMMA, writing transposed packed VT directly.
// ---------------------------------------------------------------------------
__global__ void __launch_bounds__(256, 2)
proj_v(const char* __restrict__ Ap, const char* __restrict__ Wvp,
       const float* __restrict__ bias, char* __restrict__ VTp)
{
    extern __shared__ char smem[];
    __shared__ uint64_t mb[2];
    const uint32_t sb = smem_u32(smem);
    const int tid = threadIdx.x, lane = tid & 31, w = tid >> 5;
    const int wm = w >> 1, wn = w & 1;
    const int my = blockIdx.x;

    const uint32_t mbar0 = smem_u32(&mb[0]), mbar1 = smem_u32(&mb[1]);
    if (tid == 0) { MBAR_INIT(mbar0, 1); MBAR_INIT(mbar1, 1); }
    __syncthreads();

    const char* Asrc = Ap + (size_t)my * 16 * TAB;

    if (tid == 0) {
        MBAR_EXPECT(mbar0, 2 * TAB);
        bulk_cp(sb, Asrc, TAB, mbar0);
        bulk_cp(sb + TAB, Wvp, TAB, mbar0);
    }

    float acc[2][8][4] = {};
    const int a_row = wm * 32 + (lane & 15);
    const uint32_t a_kext = (lane & 16) ? 16u : 0u;
    const int b_row = wn * 64 + ((lane & 16) ? 8 : 0) + (lane & 7);
    const uint32_t b_kext = (lane & 8) ? 16u : 0u;
    int ph0 = 0, ph1 = 0;

    for (int c = 0; c < 16; ++c) {
        const int b = c & 1;
        if (c + 1 < 16 && tid == 0) {
            const uint32_t nb = sb + (1 - b) * 2 * TAB;
            const uint32_t m = b ? mbar0 : mbar1;
            MBAR_EXPECT(m, 2 * TAB);
            bulk_cp(nb, Asrc + (size_t)(c + 1) * TAB, TAB, m);
            bulk_cp(nb + TAB, Wvp + (size_t)(c + 1) * TAB, TAB, m);
        }
        if (b == 0) { mbar_wait(mbar0, ph0); ph0 ^= 1; }
        else        { mbar_wait(mbar1, ph1); ph1 ^= 1; }
        const uint32_t aS = sb + b * 2 * TAB;
        mma_tile144(acc, aS, aS + TAB, a_row, a_kext, b_row, b_kext);
        __syncthreads();
    }

    if (wn == 0) {
        const int gq = lane >> 2, tig = lane & 3;
        char* Vt = VTp + (size_t)my * VTB;
#pragma unroll
        for (int ma = 0; ma < 2; ++ma) {
            const int rl = wm * 32 + ma * 16 + gq;
#pragma unroll
            for (int n = 0; n < 8; ++n) {
                const int d = n * 8 + tig * 2;
                const float b0 = bias[d], b1 = bias[d + 1];
                *(__half*)(Vt + d * 272 + rl * 2)             = __float2half(acc[ma][n][0] + b0);
                *(__half*)(Vt + (d + 1) * 272 + rl * 2)       = __float2half(acc[ma][n][1] + b1);
                *(__half*)(Vt + d * 272 + (rl + 8) * 2)       = __float2half(acc[ma][n][2] + b0);
                *(__half*)(Vt + (d + 1) * 272 + (rl + 8) * 2) = __float2half(acc[ma][n][3] + b1);
            }
        }
    }
}

// ---------------------------------------------------------------------------
// Pass A: per-(b,h,q) softmax denominators. weight = exp2(score') via ex2.f32.
// ---------------------------------------------------------------------------
__global__ void __launch_bounds__(256, 2)
qk_rowsum_p(const char* __restrict__ Qp, const char* __restrict__ Kp, float* __restrict__ iL)
{
    extern __shared__ char smem[];
    __shared__ uint64_t mb[2];
    const uint32_t sb = smem_u32(smem);
    const int tid = threadIdx.x, lane = tid & 31, w = tid >> 5;
    const int wm = w >> 1, wn = w & 1;
    const int qt = blockIdx.x, h = blockIdx.y, b = blockIdx.z;

    const uint32_t mbar0 = smem_u32(&mb[0]), mbar1 = smem_u32(&mb[1]);
    if (tid == 0) { MBAR_INIT(mbar0, 1); MBAR_INIT(mbar1, 1); }
    __syncthreads();

    const char* Qsrc = Qp + ((size_t)(b * 16 + qt) * 16 + h) * TAB;
    if (tid == 0) {
        MBAR_EXPECT(mbar0, 2 * TAB);
        bulk_cp(sb, Qsrc, TAB, mbar0);
        bulk_cp(sb + TAB, Kp + ((size_t)(b * 16 + 0) * 16 + h) * TAB, TAB, mbar0);
    }

    const int a_row = wm * 32 + (lane & 15);
    const uint32_t a_kext = (lane & 16) ? 16u : 0u;
    const int b_row = wn * 64 + ((lane & 16) ? 8 : 0) + (lane & 7);
    const uint32_t b_kext = (lane & 8) ? 16u : 0u;

    float lsum[2][2] = {};
    int ph0 = 0, ph1 = 0;

    for (int kt = 0; kt < 16; ++kt) {
        const int bb = kt & 1;
        if (kt + 1 < 16 && tid == 0) {
            const uint32_t m = bb ? mbar0 : mbar1;
            MBAR_EXPECT(m, TAB);
            bulk_cp(sb + TAB + (1 - bb) * TAB,
                    Kp + ((size_t)(b * 16 + kt + 1) * 16 + h) * TAB, TAB, m);
        }
        if (bb == 0) { mbar_wait(mbar0, ph0); ph0 ^= 1; }
        else         { mbar_wait(mbar1, ph1); ph1 ^= 1; }

        float acc[2][8][4] = {};
        mma_tile144(acc, sb, sb + TAB + bb * TAB, a_row, a_kext, b_row, b_kext);

#pragma unroll
        for (int ma = 0; ma < 2; ++ma)
#pragma unroll
            for (int n = 0; n < 8; ++n) {
                lsum[ma][0] += ex2(acc[ma][n][0]) + ex2(acc[ma][n][1]);
                lsum[ma][1] += ex2(acc[ma][n][2]) + ex2(acc[ma][n][3]);
            }
        __syncthreads();
    }

#pragma unroll
    for (int o = 1; o <= 2; o <<= 1)
#pragma unroll
        for (int ma = 0; ma < 2; ++ma)
#pragma unroll
            for (int hh = 0; hh < 2; ++hh)
                lsum[ma][hh] += __shfl_xor_sync(0xffffffffu, lsum[ma][hh], o);

    __shared__ float Ls[128];
    if (tid < 128) Ls[tid] = 0.f;
    __syncthreads();
    if ((lane & 3) == 0) {
        const int gq = lane >> 2;
#pragma unroll
        for (int ma = 0; ma < 2; ++ma) {
            atomicAdd(&Ls[wm * 32 + ma * 16 + gq], lsum[ma][0]);
            atomicAdd(&Ls[wm * 32 + ma * 16 + gq + 8], lsum[ma][1]);
        }
    }
    __syncthreads();
    if (tid < 128)
        iL[((size_t)b * NH + h) * S_ + qt * 128 + tid] = 1.0f / (16.0f * Ls[tid]);
}

// ---------------------------------------------------------------------------
// Pass B: head-averaged softmax + fused PV. smem overlay -> occupancy 2.
// ---------------------------------------------------------------------------
#define ATT_SM (4 * TAB)

__global__ void __launch_bounds__(256, 2)
attn_avg_p(const char* __restrict__ Qp, const char* __restrict__ Kp,
           const char* __restrict__ VTp, const float* __restrict__ iL,
           float* __restrict__ avg, float* __restrict__ AO)
{
    extern __shared__ char smem[];
    __shared__ uint64_t mb[3];
    const uint32_t sb = smem_u32(smem);
    const int tid = threadIdx.x, lane = tid & 31, w = tid >> 5;
    const int wm = w >> 1, wn = w & 1;
    const int kt = blockIdx.x, qt = blockIdx.y, b = blockIdx.z;

    const uint32_t mbar0 = smem_u32(&mb[0]), mbar1 = smem_u32(&mb[1]), mbar2 = smem_u32(&mb[2]);
    if (tid == 0) { MBAR_INIT(mbar0, 1); MBAR_INIT(mbar1, 1); MBAR_INIT(mbar2, 1); }
    __syncthreads();

    const char* Qsrc = Qp + (size_t)(b * 16 + qt) * 16 * TAB;
    const char* Ksrc = Kp + (size_t)(b * 16 + kt) * 16 * TAB;

    if (tid == 0) {
        MBAR_EXPECT(mbar0, 2 * TAB);
        bulk_cp(sb, Qsrc, TAB, mbar0);
        bulk_cp(sb + TAB, Ksrc, TAB, mbar0);
    }

    const int a_row = wm * 32 + (lane & 15);
    const uint32_t a_kext = (lane & 16) ? 16u : 0u;
    const int b_row = wn * 64 + ((lane & 16) ? 8 : 0) + (lane & 7);
    const uint32_t b_kext = (lane & 8) ? 16u : 0u;
    const int gq = lane >> 2, tig = lane & 3;

    float avgf[2][8][4] = {};
    int ph0 = 0, ph1 = 0;

    for (int h = 0; h < NH; ++h) {
        const int bb = h & 1;
        if (h + 1 < NH && tid == 0) {
            const uint32_t nb = sb + (1 - bb) * 2 * TAB;
            const uint32_t m = bb ? mbar0 : mbar1;
            MBAR_EXPECT(m, 2 * TAB);
            bulk_cp(nb, Qsrc + (size_t)(h + 1) * TAB, TAB, m);
            bulk_cp(nb + TAB, Ksrc + (size_t)(h + 1) * TAB, TAB, m);
        }
        if (bb == 0) { mbar_wait(mbar0, ph0); ph0 ^= 1; }
        else         { mbar_wait(mbar1, ph1); ph1 ^= 1; }

        float acc[2][8][4] = {};
        const uint32_t aS = sb + bb * 2 * TAB;
        mma_tile144(acc, aS, aS + TAB, a_row, a_kext, b_row, b_kext);

        const float* Lh = iL + ((size_t)b * NH + h) * S_ + qt * 128;
#pragma unroll
        for (int ma = 0; ma < 2; ++ma) {
            const float l0 = Lh[wm * 32 + ma * 16 + gq];
            const float l1 = Lh[wm * 32 + ma * 16 + gq + 8];
#pragma unroll
            for (int n = 0; n < 8; ++n) {
                avgf[ma][n][0] += ex2(acc[ma][n][0]) * l0;
                avgf[ma][n][1] += ex2(acc[ma][n][1]) * l0;
                avgf[ma][n][2] += ex2(acc[ma][n][2]) * l1;
                avgf[ma][n][3] += ex2(acc[ma][n][3]) * l1;
            }
        }
        __syncthreads();
    }

    // Q/K buffers dead. Load VT into buf1 region; stage P into buf0 region.
    if (tid == 0) {
        MBAR_EXPECT(mbar2, VTB);
        bulk_cp(sb + 2 * TAB, VTp + (size_t)(b * 16 + kt) * VTB, VTB, mbar2);
    }

    float* outp = avg + (size_t)b * S_ * S_;
#pragma unroll
    for (int ma = 0; ma < 2; ++ma) {
        const int rl = wm * 32 + ma * 16 + gq;
        const int r0 = qt * 128 + rl;
#pragma unroll
        for (int n = 0; n < 8; ++n) {
            const int col = wn * 64 + n * 8 + tig * 2;
            *(float2*)(outp + (size_t)r0 * S_ + kt * 128 + col) =
                make_float2(avgf[ma][n][0], avgf[ma][n][1]);
            *(float2*)(outp + (size_t)(r0 + 8) * S_ + kt * 128 + col) =
                make_float2(avgf[ma][n][2], avgf[ma][n][3]);
            *(__half2*)(smem + rl * 272 + col * 2) =
                __floats2half2_rn(avgf[ma][n][0], avgf[ma][n][1]);
            *(__half2*)(smem + (rl + 8) * 272 + col * 2) =
                __floats2half2_rn(avgf[ma][n][2], avgf[ma][n][3]);
        }
    }
    mbar_wait(mbar2, 0);
    __syncthreads();

    // PV: [128q x 64d] += P[128q x 128k] @ VT[64d x 128k]^T
    float apv[2][4][4] = {};
    const int pv_brow = wn * 32 + ((lane & 16) ? 8 : 0) + (lane & 7);
    const uint32_t pS = sb, vS = sb + 2 * TAB;
#pragma unroll
    for (int ks = 0; ks < 8; ++ks) {
        uint32_t ah[2][4];
#pragma unroll
        for (int ma = 0; ma < 2; ++ma) {
            const uint32_t off = (uint32_t)((a_row + ma * 16) * 272 + ks * 32) + a_kext;
            ldsm4(ah[ma][0], ah[ma][1], ah[ma][2], ah[ma][3], pS + off);
        }
#pragma unroll
        for (int bg = 0; bg < 2; ++bg) {
            const uint32_t off = (uint32_t)((pv_brow + bg * 16) * 272 + ks * 32) + b_kext;
            uint32_t bh[4];
            ldsm4(bh[0], bh[1], bh[2], bh[3], vS + off);
#pragma unroll
            for (int na = 0; na < 2; ++na)
#pragma unroll
                for (int ma = 0; ma < 2; ++ma)
                    mma_f16(apv[ma][bg * 2 + na], ah[ma], &bh[na * 2]);
        }
    }

#pragma unroll
    for (int ma = 0; ma < 2; ++ma) {
        const int r0 = qt * 128 + wm * 32 + ma * 16 + gq;
#pragma unroll
        for (int nI = 0; nI < 4; ++nI) {
            const int d = wn * 32 + nI * 8 + tig * 2;
            float* a0 = AO + ((size_t)b * S_ + r0) * HD + d;
            float* a1 = AO + ((size_t)b * S_ + r0 + 8) * HD + d;
            atomicAdd(a0, apv[ma][nI][0]);
            atomicAdd(a0 + 1, apv[ma][nI][1]);
            atomicAdd(a1, apv[ma][nI][2]);
            atomicAdd(a1 + 1, apv[ma][nI][3]);
        }
    }
}

// ---------------------------------------------------------------------------
// bf16x3 split GEMM (O projection, K=64, LDGSTS path)
// ---------------------------------------------------------------------------
#define TILE_B 16384
#define BUF4 (4 * TILE_B)

__global__ void __launch_bounds__(256, 2)
hmma_bf16x3_nt(const __nv_bfloat16* __restrict__ hA, const __nv_bfloat16* __restrict__ lA,
               const __nv_bfloat16* __restrict__ hB, const __nv_bfloat16* __restrict__ lB,
               const float* __restrict__ bias, float* __restrict__ C,
               int K, int lda, int ldb, int ldc)
{
    extern __shared__ char smem[];
    const uint32_t sb = smem_u32(smem);
    const int tid = threadIdx.x, lane = tid & 31, w = tid >> 5;
    const int wm = w >> 1, wn = w & 1;
    const int m0 = blockIdx.y * 128, n0 = blockIdx.x * 128;

    hA += (size_t)m0 * lda; lA += (size_t)m0 * lda;
    hB += (size_t)n0 * ldb; lB += (size_t)n0 * ldb;

    cp_tile(hA, lda, sb + 0 * TILE_B, tid);
    cp_tile(lA, lda, sb + 1 * TILE_B, tid);
    cp_tile(hB, ldb, sb + 2 * TILE_B, tid);
    cp_tile(lB, ldb, sb + 3 * TILE_B, tid);
    CP_COMMIT();
    CP_WAIT(0);
    __syncthreads();

    float acc[2][8][4] = {};

    const int a_row = wm * 32 + (lane & 15);
    const uint32_t a_kext = (lane & 16) ? 16u : 0u;
    const int b_row = wn * 64 + ((lane & 16) ? 8 : 0) + (lane & 7);
    const uint32_t b_kext = (lane & 8) ? 16u : 0u;

    const uint32_t aH = sb, aL = sb + TILE_B, bH = sb + 2 * TILE_B, bL = sb + 3 * TILE_B;

#pragma unroll
    for (int ks = 0; ks < 4; ++ks) {
        uint32_t ah[2][4], al[2][4];
#pragma unroll
        for (int ma = 0; ma < 2; ++ma) {
            const uint32_t off =
                SWZ128((uint32_t)((a_row + ma * 16) * 128) + (uint32_t)(ks * 32) + a_kext);
            ldsm4(ah[ma][0], ah[ma][1], ah[ma][2], ah[ma][3], aH + off);
            ldsm4(al[ma][0], al[ma][1], al[ma][2], al[ma][3], aL + off);
        }
#pragma unroll
        for (int bg = 0; bg < 4; ++bg) {
            const uint32_t off =
                SWZ128((uint32_t)((b_row + bg * 16) * 128) + (uint32_t)(ks * 32) + b_kext);
            uint32_t bh[4], bl[4];
            ldsm4(bh[0], bh[1], bh[2], bh[3], bH + off);
            ldsm4(bl[0], bl[1], bl[2], bl[3], bL + off);
#pragma unroll
            for (int na = 0; na < 2; ++na) {
                const int n = bg * 2 + na;
#pragma unroll
                for (int ma = 0; ma < 2; ++ma) {
                    mma_bf16(acc[ma][n], ah[ma], &bh[na * 2]);
                    mma_bf16(acc[ma][n], ah[ma], &bl[na * 2]);
                    mma_bf16(acc[ma][n], al[ma], &bh[na * 2]);
                }
            }
        }
    }

    const int gq = lane >> 2, tig = lane & 3;
#pragma unroll
    for (int ma = 0; ma < 2; ++ma) {
        const int r0 = m0 + wm * 32 + ma * 16 + gq;
#pragma unroll
        for (int n = 0; n < 8; ++n) {
            const int col = n0 + wn * 64 + n * 8 + tig * 2;
            const float b0 = bias[col], b1 = bias[col + 1];
            *(float2*)(C + (size_t)r0 * ldc + col) =
                make_float2(acc[ma][n][0] + b0, acc[ma][n][1] + b1);
            *(float2*)(C + (size_t)(r0 + 8) * ldc + col) =
                make_float2(acc[ma][n][2] + b0, acc[ma][n][3] + b1);
        }
    }
}

extern "C" void kernel_launch(void* const* d_in, const int* in_sizes, int n_in,
                              void* d_out, int out_size)
{
    const float* query  = (const float*)d_in[0];
    const float* key_in = (const float*)d_in[1];
    const float* value  = (const float*)d_in[2];
    const float* Wq = (const float*)d_in[3];
    const float* bq = (const float*)d_in[4];
    const float* Wk = (const float*)d_in[5];
    const float* bk = (const float*)d_in[6];
    const float* Wv = (const float*)d_in[7];
    const float* bv = (const float*)d_in[8];
    const float* Wo = (const float*)d_in[9];
    const float* bo = (const float*)d_in[10];

    float* out = (float*)d_out;
    float* avg_out = out + (size_t)B_ * S_ * H_;

    float *gAO, *giL;
    char *gApc, *gWpc, *gWvpc, *gQpc, *gKpc, *gVTpc;
    __nv_bfloat16 *hA, *lA, *hW, *lW;
    cudaGetSymbolAddress((void**)&gAO, g_AO);
    cudaGetSymbolAddress((void**)&giL, g_iL);
    cudaGetSymbolAddress((void**)&gApc, g_Ap);
    cudaGetSymbolAddress((void**)&gWpc, g_Wp);
    cudaGetSymbolAddress((void**)&gWvpc, g_Wvp);
    cudaGetSymbolAddress((void**)&gQpc, g_Qp);
    cudaGetSymbolAddress((void**)&gKpc, g_Kp);
    cudaGetSymbolAddress((void**)&gVTpc, g_VTp);
    cudaGetSymbolAddress((void**)&hA, g_hA);
    cudaGetSymbolAddress((void**)&lA, g_lA);
    cudaGetSymbolAddress((void**)&hW, g_hW);
    cudaGetSymbolAddress((void**)&lW, g_lW);

    cudaFuncSetAttribute(proj_f16, cudaFuncAttributeMaxDynamicSharedMemorySize, 4 * TAB);
    cudaFuncSetAttribute(proj_v, cudaFuncAttributeMaxDynamicSharedMemorySize, 4 * TAB);
    cudaFuncSetAttribute(qk_rowsum_p, cudaFuncAttributeMaxDynamicSharedMemorySize, 3 * TAB);
    cudaFuncSetAttribute(attn_avg_p, cudaFuncAttributeMaxDynamicSharedMemorySize, ATT_SM);
    cudaFuncSetAttribute(hmma_bf16x3_nt, cudaFuncAttributeMaxDynamicSharedMemorySize, BUF4);

    const int M = B_ * S_;          // 8192
    const int NXH = B_ * S_ * H_;   // 8M

    zero_f<<<(B_ * S_ * HD) / 256, 256>>>(gAO, B_ * S_ * HD);
    zero_f<<<(16 * TAB / 4) / 256, 256>>>((float*)gWvpc, 16 * TAB / 4);

    // V projection (fp16 HMMA -> packed VT directly)
    cvt_pack<<<NXH / 1024, 256>>>((const float4*)value, gApc, NXH / 4);
    cvt_pack_w64<<<(HD * H_) / 1024, 256>>>((const float4*)Wv, gWvpc, HD * H_ / 4);
    proj_v<<<64, 256, 4 * TAB>>>(gApc, gWvpc, bv, gVTpc);

    // Q projection (scaled by 0.125*log2e: weights = exp2(score'))
    cvt_pack<<<NXH / 1024, 256>>>((const float4*)query, gApc, NXH / 4);
    cvt_pack<<<(H_ * H_) / 1024, 256>>>((const float4*)Wq, gWpc, H_ * H_ / 4);
    proj_f16<<<dim3(8, 64), 256, 4 * TAB>>>(gApc, gWpc, bq, gQpc, QSCALE);
    // K projection (unscaled)
    cvt_pack<<<NXH / 1024, 256>>>((const float4*)key_in, gApc, NXH / 4);
    cvt_pack<<<(H_ * H_) / 1024, 256>>>((const float4*)Wk, gWpc, H_ * H_ / 4);
    proj_f16<<<dim3(8, 64), 256, 4 * TAB>>>(gApc, gWpc, bk, gKpc, 1.0f);

    // Pass A: softmax denominators
    qk_rowsum_p<<<dim3(S_ / 128, NH, B_), 256, 3 * TAB>>>(gQpc, gKpc, giL);

    // Pass B: head-averaged softmax + fused PV (occupancy 2)
    attn_avg_p<<<dim3(S_ / 128, S_ / 128, B_), 256, ATT_SM>>>(gQpc, gKpc, gVTpc, giL,
                                                              avg_out, gAO);

    // O projection (bf16x3)
    split_hl4<<<(B_ * S_ * HD) / 1024, 256>>>((const float4*)gAO, (uint2*)hA, (uint2*)lA,
                                              B_ * S_ * HD / 4);
    split_hl4<<<(H_ * HD) / 1024, 256>>>((const float4*)Wo, (uint2*)hW, (uint2*)lW, H_ * HD / 4);
    hmma_bf16x3_nt<<<dim3(H_ / 128, M / 128, 1), 256, BUF4>>>(hA, lA, hW, lW, bo,
        out, HD, HD, HD, H_);
}

// round 14
// speedup vs baseline: 11.4648x; 1.0378x over previous
#include <cuda_runtime.h>
#include <cuda_bf16.h>
#include <cuda_fp16.h>
#include <cstdint>

#define B_ 4
#define S_ 2048
#define H_ 1024
#define NH 16
#define HD 64

#define TAB 18432            // packed tile: 128 rows x 144B pitch (64 fp16 cols)
#define VTB 17408            // VT tile: 64 rows x 272B pitch (128 fp16 cols)
#define ASLICE ((size_t)64 * 16 * TAB)

// Q is pre-scaled by 0.125*log2(e) so softmax weight = exp2(score)
#define QSCALE 0.180336879f

// scratch
__device__ float g_AO[B_ * S_ * HD];
__device__ float g_iL[B_ * NH * S_];
__device__ __align__(16) char g_Ap[3 * 64 * 16 * TAB];   // slices: 0=value,1=query,2=key
__device__ __align__(16) char g_Wp[16 * 16 * TAB];       // slices 0-7: Wq, 8-15: Wk
__device__ __align__(16) char g_Wvp[16 * TAB];           // packed Wv (rows 64..127 zero)
__device__ __align__(16) char g_Qp[64 * 16 * TAB];
__device__ __align__(16) char g_Kp[64 * 16 * TAB];
__device__ __align__(16) char g_VTp[64 * VTB];
__device__ __nv_bfloat16 g_hA[B_ * S_ * HD], g_lA[B_ * S_ * HD];
__device__ __nv_bfloat16 g_hW[H_ * HD],      g_lW[H_ * HD];

// ---------------------------------------------------------------------------
// helpers
// ---------------------------------------------------------------------------
__device__ __forceinline__ uint32_t smem_u32(const void* p) {
    uint32_t a;
    asm("{ .reg .u64 t; cvta.to.shared.u64 t, %1; cvt.u32.u64 %0, t; }" : "=r"(a) : "l"(p));
    return a;
}
#define SWZ128(x) ((x) ^ (((x) >> 3) & 0x70))

__device__ __forceinline__ float ex2(float x) {
    float y; asm("ex2.approx.f32 %0, %1;" : "=f"(y) : "f"(x)); return y;
}

__device__ __forceinline__ void ldsm4(uint32_t& r0, uint32_t& r1, uint32_t& r2, uint32_t& r3,
                                      uint32_t addr) {
    asm volatile("ldmatrix.sync.aligned.m8n8.x4.shared.b16 {%0,%1,%2,%3}, [%4];"
                 : "=r"(r0), "=r"(r1), "=r"(r2), "=r"(r3) : "r"(addr));
}
__device__ __forceinline__ void mma_bf16(float* c, const uint32_t* a, const uint32_t* b) {
    asm volatile(
        "mma.sync.aligned.m16n8k16.row.col.f32.bf16.bf16.f32 "
        "{%0,%1,%2,%3}, {%4,%5,%6,%7}, {%8,%9}, {%0,%1,%2,%3};"
        : "+f"(c[0]), "+f"(c[1]), "+f"(c[2]), "+f"(c[3])
        : "r"(a[0]), "r"(a[1]), "r"(a[2]), "r"(a[3]), "r"(b[0]), "r"(b[1]));
}
__device__ __forceinline__ void mma_f16(float* c, const uint32_t* a, const uint32_t* b) {
    asm volatile(
        "mma.sync.aligned.m16n8k16.row.col.f32.f16.f16.f32 "
        "{%0,%1,%2,%3}, {%4,%5,%6,%7}, {%8,%9}, {%0,%1,%2,%3};"
        : "+f"(c[0]), "+f"(c[1]), "+f"(c[2]), "+f"(c[3])
        : "r"(a[0]), "r"(a[1]), "r"(a[2]), "r"(a[3]), "r"(b[0]), "r"(b[1]));
}
#define CP16(s, g) asm volatile("cp.async.cg.shared.global [%0], [%1], 16;" :: "r"(s), "l"(g))
#define CP_COMMIT() asm volatile("cp.async.commit_group;" ::: "memory")
#define CP_WAIT(n)  asm volatile("cp.async.wait_group %0;" :: "n"(n) : "memory")

// --- TMA bulk-copy + mbarrier (base sm_90 PTX) ---
__device__ __forceinline__ void bulk_cp(uint32_t sdst, const void* gsrc, uint32_t bytes,
                                        uint32_t mbar) {
    asm volatile(
        "cp.async.bulk.shared::cta.global.mbarrier::complete_tx::bytes [%0], [%1], %2, [%3];"
        :: "r"(sdst), "l"(gsrc), "r"(bytes), "r"(mbar) : "memory");
}
#define MBAR_INIT(a, n) \
    asm volatile("mbarrier.init.shared.b64 [%0], %1;" :: "r"(a), "r"((uint32_t)(n)) : "memory")
#define MBAR_EXPECT(a, bytes) \
    asm volatile("mbarrier.arrive.expect_tx.shared.b64 _, [%0], %1;" \
                 :: "r"(a), "r"((uint32_t)(bytes)) : "memory")
__device__ __forceinline__ void mbar_wait(uint32_t mbar, int parity) {
    asm volatile(
        "{\n\t.reg .pred P;\n\t"
        "LAB_%=:\n\t"
        "mbarrier.try_wait.parity.acquire.cta.shared::cta.b64 P, [%0], %1;\n\t"
        "@!P bra LAB_%=;\n\t}"
        :: "r"(mbar), "r"((uint32_t)parity) : "memory");
}

// LDGSTS staging (O-projection only)
__device__ __forceinline__ void cp_tile(const void* __restrict__ g, int ld_elems,
                                        uint32_t sdst, int tid)
{
    const __half* gh = (const __half*)g;
#pragma unroll
    for (int it = 0; it < 4; ++it) {
        int i = tid + it * 256;
        int row = i >> 3, c = i & 7;
        const void* gp = gh + (size_t)row * ld_elems + c * 8;
        uint32_t sp = sdst + SWZ128((uint32_t)(row * 128 + c * 16));
        CP16(sp, gp);
    }
}

// 128x128x64 fp16 MMA on two pitch-144 tiles
__device__ __forceinline__ void mma_tile144(float acc[2][8][4], uint32_t aS, uint32_t bS,
                                            int a_row, uint32_t a_kext,
                                            int b_row, uint32_t b_kext)
{
#pragma unroll
    for (int ks = 0; ks < 4; ++ks) {
        uint32_t ah[2][4];
#pragma unroll
        for (int ma = 0; ma < 2; ++ma) {
            const uint32_t off = (uint32_t)((a_row + ma * 16) * 144 + ks * 32) + a_kext;
            ldsm4(ah[ma][0], ah[ma][1], ah[ma][2], ah[ma][3], aS + off);
        }
#pragma unroll
        for (int bg = 0; bg < 4; ++bg) {
            const uint32_t off = (uint32_t)((b_row + bg * 16) * 144 + ks * 32) + b_kext;
            uint32_t bh[4];
            ldsm4(bh[0], bh[1], bh[2], bh[3], bS + off);
#pragma unroll
            for (int na = 0; na < 2; ++na)
#pragma unroll
                for (int ma = 0; ma < 2; ++ma)
                    mma_f16(acc[ma][bg * 2 + na], ah[ma], &bh[na * 2]);
        }
    }
}

// ---------------------------------------------------------------------------
// utility kernels
// ---------------------------------------------------------------------------
// pack three activation tensors (value/query/key) in one launch; z selects.
__global__ void cvt_pack3(const float4* __restrict__ x0, const float4* __restrict__ x1,
                          const float4* __restrict__ x2, char* __restrict__ out, int n4)
{
    int i = blockIdx.x * blockDim.x + threadIdx.x;
    if (i >= n4) return;
    const int z = blockIdx.y;
    const float4* x = (z == 0) ? x0 : ((z == 1) ? x1 : x2);
    float4 v = x[i];
    union { __half2 h2[2]; uint2 u; } p;
    p.h2[0] = __floats2half2_rn(v.x, v.y);
    p.h2[1] = __floats2half2_rn(v.z, v.w);
    int row = i >> 8;
    int col = (i & 255) << 2;
    int rt = row >> 7, r = row & 127, c = col >> 6, k = col & 63;
    *(uint2*)(out + (size_t)z * ASLICE + (size_t)(rt * 16 + c) * TAB + r * 144 + k * 2) = p.u;
}

// pack Wq (z=0) and Wk (z=1) into g_Wp slices
__global__ void cvt_pack_w2(const float4* __restrict__ x0, const float4* __restrict__ x1,
                            char* __restrict__ out, int n4)
{
    int i = blockIdx.x * blockDim.x + threadIdx.x;
    if (i >= n4) return;
    const int z = blockIdx.y;
    const float4* x = z ? x1 : x0;
    float4 v = x[i];
    union { __half2 h2[2]; uint2 u; } p;
    p.h2[0] = __floats2half2_rn(v.x, v.y);
    p.h2[1] = __floats2half2_rn(v.z, v.w);
    int row = i >> 8;
    int col = (i & 255) << 2;
    int rt = row >> 7, r = row & 127, c = col >> 6, k = col & 63;
    *(uint2*)(out + (size_t)((z * 8 + rt) * 16 + c) * TAB + r * 144 + k * 2) = p.u;
}

// Wv [64 x 1024] -> packed rows 0..63
__global__ void cvt_pack_w64(const float4* __restrict__ x, char* __restrict__ out, int n4)
{
    int i = blockIdx.x * blockDim.x + threadIdx.x;
    if (i >= n4) return;
    float4 v = x[i];
    union { __half2 h2[2]; uint2 u; } p;
    p.h2[0] = __floats2half2_rn(v.x, v.y);
    p.h2[1] = __floats2half2_rn(v.z, v.w);
    int row = i >> 8;
    int col = (i & 255) << 2;
    int c = col >> 6, k = col & 63;
    *(uint2*)(out + (size_t)c * TAB + row * 144 + k * 2) = p.u;
}

__global__ void split_hl4(const float4* __restrict__ x, uint2* __restrict__ hi,
                          uint2* __restrict__ lo, int n4)
{
    int i = blockIdx.x * blockDim.x + threadIdx.x;
    if (i < n4) {
        float4 v = x[i];
        __nv_bfloat16 h0 = __float2bfloat16(v.x), h1 = __float2bfloat16(v.y);
        __nv_bfloat16 h2 = __float2bfloat16(v.z), h3 = __float2bfloat16(v.w);
        __nv_bfloat16 l0 = __float2bfloat16(v.x - __bfloat162float(h0));
        __nv_bfloat16 l1 = __float2bfloat16(v.y - __bfloat162float(h1));
        __nv_bfloat16 l2 = __float2bfloat16(v.z - __bfloat162float(h2));
        __nv_bfloat16 l3 = __float2bfloat16(v.w - __bfloat162float(h3));
        union { __nv_bfloat162 b2[2]; uint2 u; } ph, pl;
        ph.b2[0].x = h0; ph.b2[0].y = h1; ph.b2[1].x = h2; ph.b2[1].y = h3;
        pl.b2[0].x = l0; pl.b2[0].y = l1; pl.b2[1].x = l2; pl.b2[1].y = l3;
        hi[i] = ph.u;
        lo[i] = pl.u;
    }
}

__global__ void zero_f(float* __restrict__ p, int n)
{
    int i = blockIdx.x * blockDim.x + threadIdx.x;
    if (i < n) p[i] = 0.f;
}

// ---------------------------------------------------------------------------
// Merged projection kernel: grid (17, 64).
//  nx 0..7  : Q projection  (A slice 1, W = Wp[nx],    out packed Qp, cs=QSCALE)
//  nx 8..15 : K projection  (A slice 2, W = Wp[nx],    out packed Kp, cs=1)
//  nx == 16 : V projection  (A slice 0, W = Wvp,       out transposed VTp)
// ---------------------------------------------------------------------------
__global__ void __launch_bounds__(256, 2)
proj_all(const char* __restrict__ Ap, const char* __restrict__ Wp,
         const char* __restrict__ Wvp,
         const float* __restrict__ bq, const float* __restrict__ bk,
         const float* __restrict__ bv,
         char* __restrict__ Qp, char* __restrict__ Kp, char* __restrict__ VTp)
{
    extern __shared__ char smem[];
    __shared__ uint64_t mb[2];
    const uint32_t sb = smem_u32(smem);
    const int tid = threadIdx.x, lane = tid & 31, w = tid >> 5;
    const int wm = w >> 1, wn = w & 1;
    const int nx = blockIdx.x, my = blockIdx.y;
    const bool isV = (nx == 16);

    const uint32_t mbar0 = smem_u32(&mb[0]), mbar1 = smem_u32(&mb[1]);
    if (tid == 0) { MBAR_INIT(mbar0, 1); MBAR_INIT(mbar1, 1); }
    __syncthreads();

    const int slice = isV ? 0 : (nx < 8 ? 1 : 2);
    const char* Asrc = Ap + (size_t)slice * ASLICE + (size_t)my * 16 * TAB;
    const char* Wsrc = isV ? Wvp : (Wp + (size_t)nx * 16 * TAB);

    if (tid == 0) {
        MBAR_EXPECT(mbar0, 2 * TAB);
        bulk_cp(sb, Asrc, TAB, mbar0);
        bulk_cp(sb + TAB, Wsrc, TAB, mbar0);
    }

    float acc[2][8][4] = {};
    const int a_row = wm * 32 + (lane & 15);
    const uint32_t a_kext = (lane & 16) ? 16u : 0u;
    const int b_row = wn * 64 + ((lane & 16) ? 8 : 0) + (lane & 7);
    const uint32_t b_kext = (lane & 8) ? 16u : 0u;
    int ph0 = 0, ph1 = 0;

    for (int c = 0; c < 16; ++c) {
        const int b = c & 1;
        if (c + 1 < 16 && tid == 0) {
            const uint32_t nb = sb + (1 - b) * 2 * TAB;
            const uint32_t m = b ? mbar0 : mbar1;
            MBAR_EXPECT(m, 2 * TAB);
            bulk_cp(nb, Asrc + (size_t)(c + 1) * TAB, TAB, m);
            bulk_cp(nb + TAB, Wsrc + (size_t)(c + 1) * TAB, TAB, m);
        }
        if (b == 0) { mbar_wait(mbar0, ph0); ph0 ^= 1; }
        else        { mbar_wait(mbar1, ph1); ph1 ^= 1; }
        const uint32_t aS = sb + b * 2 * TAB;
        mma_tile144(acc, aS, aS + TAB, a_row, a_kext, b_row, b_kext);
        __syncthreads();
    }

    const int gq = lane >> 2, tig = lane & 3;
    if (isV) {
        if (wn == 0) {
            char* Vt = VTp + (size_t)my * VTB;
#pragma unroll
            for (int ma = 0; ma < 2; ++ma) {
                const int rl = wm * 32 + ma * 16 + gq;
#pragma unroll
                for (int n = 0; n < 8; ++n) {
                    const int d = n * 8 + tig * 2;
                    const float b0 = bv[d], b1 = bv[d + 1];
                    *(__half*)(Vt + d * 272 + rl * 2)             = __float2half(acc[ma][n][0] + b0);
                    *(__half*)(Vt + (d + 1) * 272 + rl * 2)       = __float2half(acc[ma][n][1] + b1);
                    *(__half*)(Vt + d * 272 + (rl + 8) * 2)       = __float2half(acc[ma][n][2] + b0);
                    *(__half*)(Vt + (d + 1) * 272 + (rl + 8) * 2) = __float2half(acc[ma][n][3] + b1);
                }
            }
        }
    } else {
        const float* bias = (nx < 8) ? bq : bk;
        const float cs = (nx < 8) ? QSCALE : 1.0f;
        char* Cp = (nx < 8) ? Qp : Kp;
        const int nxl = nx & 7;
#pragma unroll
        for (int ma = 0; ma < 2; ++ma) {
            const int rl = wm * 32 + ma * 16 + gq;
#pragma unroll
            for (int n = 0; n < 8; ++n) {
                const int col = nxl * 128 + wn * 64 + n * 8 + tig * 2;
                const float b0 = bias[col], b1 = bias[col + 1];
                const size_t tb = (size_t)(my * 16 + (col >> 6)) * TAB + (col & 63) * 2;
                *(__half2*)(Cp + tb + rl * 144) =
                    __floats2half2_rn((acc[ma][n][0] + b0) * cs, (acc[ma][n][1] + b1) * cs);
                *(__half2*)(Cp + tb + (rl + 8) * 144) =
                    __floats2half2_rn((acc[ma][n][2] + b0) * cs, (acc[ma][n][3] + b1) * cs);
            }
        }
    }
}

// ---------------------------------------------------------------------------
// Pass A: per-(b,h,q) softmax denominators. weight = exp2(score') via ex2.f32.
// ---------------------------------------------------------------------------
__global__ void __launch_bounds__(256, 2)
qk_rowsum_p(const char* __restrict__ Qp, const char* __restrict__ Kp, float* __restrict__ iL)
{
    extern __shared__ char smem[];
    __shared__ uint64_t mb[2];
    const uint32_t sb = smem_u32(smem);
    const int tid = threadIdx.x, lane = tid & 31, w = tid >> 5;
    const int wm = w >> 1, wn = w & 1;
    const int qt = blockIdx.x, h = blockIdx.y, b = blockIdx.z;

    const uint32_t mbar0 = smem_u32(&mb[0]), mbar1 = smem_u32(&mb[1]);
    if (tid == 0) { MBAR_INIT(mbar0, 1); MBAR_INIT(mbar1, 1); }
    __syncthreads();

    const char* Qsrc = Qp + ((size_t)(b * 16 + qt) * 16 + h) * TAB;
    if (tid == 0) {
        MBAR_EXPECT(mbar0, 2 * TAB);
        bulk_cp(sb, Qsrc, TAB, mbar0);
        bulk_cp(sb + TAB, Kp + ((size_t)(b * 16 + 0) * 16 + h) * TAB, TAB, mbar0);
    }

    const int a_row = wm * 32 + (lane & 15);
    const uint32_t a_kext = (lane & 16) ? 16u : 0u;
    const int b_row = wn * 64 + ((lane & 16) ? 8 : 0) + (lane & 7);
    const uint32_t b_kext = (lane & 8) ? 16u : 0u;

    float lsum[2][2] = {};
    int ph0 = 0, ph1 = 0;

    for (int kt = 0; kt < 16; ++kt) {
        const int bb = kt & 1;
        if (kt + 1 < 16 && tid == 0) {
            const uint32_t m = bb ? mbar0 : mbar1;
            MBAR_EXPECT(m, TAB);
            bulk_cp(sb + TAB + (1 - bb) * TAB,
                    Kp + ((size_t)(b * 16 + kt + 1) * 16 + h) * TAB, TAB, m);
        }
        if (bb == 0) { mbar_wait(mbar0, ph0); ph0 ^= 1; }
        else         { mbar_wait(mbar1, ph1); ph1 ^= 1; }

        float acc[2][8][4] = {};
        mma_tile144(acc, sb, sb + TAB + bb * TAB, a_row, a_kext, b_row, b_kext);

#pragma unroll
        for (int ma = 0; ma < 2; ++ma)
#pragma unroll
            for (int n = 0; n < 8; ++n) {
                lsum[ma][0] += ex2(acc[ma][n][0]) + ex2(acc[ma][n][1]);
                lsum[ma][1] += ex2(acc[ma][n][2]) + ex2(acc[ma][n][3]);
            }
        __syncthreads();
    }

#pragma unroll
    for (int o = 1; o <= 2; o <<= 1)
#pragma unroll
        for (int ma = 0; ma < 2; ++ma)
#pragma unroll
            for (int hh = 0; hh < 2; ++hh)
                lsum[ma][hh] += __shfl_xor_sync(0xffffffffu, lsum[ma][hh], o);

    __shared__ float Ls[128];
    if (tid < 128) Ls[tid] = 0.f;
    __syncthreads();
    if ((lane & 3) == 0) {
        const int gq = lane >> 2;
#pragma unroll
        for (int ma = 0; ma < 2; ++ma) {
            atomicAdd(&Ls[wm * 32 + ma * 16 + gq], lsum[ma][0]);
            atomicAdd(&Ls[wm * 32 + ma * 16 + gq + 8], lsum[ma][1]);
        }
    }
    __syncthreads();
    if (tid < 128)
        iL[((size_t)b * NH + h) * S_ + qt * 128 + tid] = 1.0f / (16.0f * Ls[tid]);
}

// ---------------------------------------------------------------------------
// Pass B: head-averaged softmax + fused PV. smem overlay -> occupancy 2.
// ---------------------------------------------------------------------------
#define ATT_SM (4 * TAB)

__global__ void __launch_bounds__(256, 2)
attn_avg_p(const char* __restrict__ Qp, const char* __restrict__ Kp,
           const char* __restrict__ VTp, const float* __restrict__ iL,
           float* __restrict__ avg, float* __restrict__ AO)
{
    extern __shared__ char smem[];
    __shared__ uint64_t mb[3];
    const uint32_t sb = smem_u32(smem);
    const int tid = threadIdx.x, lane = tid & 31, w = tid >> 5;
    const int wm = w >> 1, wn = w & 1;
    const int kt = blockIdx.x, qt = blockIdx.y, b = blockIdx.z;

    const uint32_t mbar0 = smem_u32(&mb[0]), mbar1 = smem_u32(&mb[1]), mbar2 = smem_u32(&mb[2]);
    if (tid == 0) { MBAR_INIT(mbar0, 1); MBAR_INIT(mbar1, 1); MBAR_INIT(mbar2, 1); }
    __syncthreads();

    const char* Qsrc = Qp + (size_t)(b * 16 + qt) * 16 * TAB;
    const char* Ksrc = Kp + (size_t)(b * 16 + kt) * 16 * TAB;

    if (tid == 0) {
        MBAR_EXPECT(mbar0, 2 * TAB);
        bulk_cp(sb, Qsrc, TAB, mbar0);
        bulk_cp(sb + TAB, Ksrc, TAB, mbar0);
    }

    const int a_row = wm * 32 + (lane & 15);
    const uint32_t a_kext = (lane & 16) ? 16u : 0u;
    const int b_row = wn * 64 + ((lane & 16) ? 8 : 0) + (lane & 7);
    const uint32_t b_kext = (lane & 8) ? 16u : 0u;
    const int gq = lane >> 2, tig = lane & 3;

    float avgf[2][8][4] = {};
    int ph0 = 0, ph1 = 0;

    for (int h = 0; h < NH; ++h) {
        const int bb = h & 1;
        if (h + 1 < NH && tid == 0) {
            const uint32_t nb = sb + (1 - bb) * 2 * TAB;
            const uint32_t m = bb ? mbar0 : mbar1;
            MBAR_EXPECT(m, 2 * TAB);
            bulk_cp(nb, Qsrc + (size_t)(h + 1) * TAB, TAB, m);
            bulk_cp(nb + TAB, Ksrc + (size_t)(h + 1) * TAB, TAB, m);
        }
        if (bb == 0) { mbar_wait(mbar0, ph0); ph0 ^= 1; }
        else         { mbar_wait(mbar1, ph1); ph1 ^= 1; }

        float acc[2][8][4] = {};
        const uint32_t aS = sb + bb * 2 * TAB;
        mma_tile144(acc, aS, aS + TAB, a_row, a_kext, b_row, b_kext);

        const float* Lh = iL + ((size_t)b * NH + h) * S_ + qt * 128;
#pragma unroll
        for (int ma = 0; ma < 2; ++ma) {
            const float l0 = Lh[wm * 32 + ma * 16 + gq];
            const float l1 = Lh[wm * 32 + ma * 16 + gq + 8];
#pragma unroll
            for (int n = 0; n < 8; ++n) {
                avgf[ma][n][0] += ex2(acc[ma][n][0]) * l0;
                avgf[ma][n][1] += ex2(acc[ma][n][1]) * l0;
                avgf[ma][n][2] += ex2(acc[ma][n][2]) * l1;
                avgf[ma][n][3] += ex2(acc[ma][n][3]) * l1;
            }
        }
        __syncthreads();
    }

    // Q/K buffers dead. Load VT into buf1 region; stage P into buf0 region.
    if (tid == 0) {
        MBAR_EXPECT(mbar2, VTB);
        bulk_cp(sb + 2 * TAB, VTp + (size_t)(b * 16 + kt) * VTB, VTB, mbar2);
    }

    float* outp = avg + (size_t)b * S_ * S_;
#pragma unroll
    for (int ma = 0; ma < 2; ++ma) {
        const int rl = wm * 32 + ma * 16 + gq;
        const int r0 = qt * 128 + rl;
#pragma unroll
        for (int n = 0; n < 8; ++n) {
            const int col = wn * 64 + n * 8 + tig * 2;
            *(float2*)(outp + (size_t)r0 * S_ + kt * 128 + col) =
                make_float2(avgf[ma][n][0], avgf[ma][n][1]);
            *(float2*)(outp + (size_t)(r0 + 8) * S_ + kt * 128 + col) =
                make_float2(avgf[ma][n][2], avgf[ma][n][3]);
            *(__half2*)(smem + rl * 272 + col * 2) =
                __floats2half2_rn(avgf[ma][n][0], avgf[ma][n][1]);
            *(__half2*)(smem + (rl + 8) * 272 + col * 2) =
                __floats2half2_rn(avgf[ma][n][2], avgf[ma][n][3]);
        }
    }
    mbar_wait(mbar2, 0);
    __syncthreads();

    // PV: [128q x 64d] += P[128q x 128k] @ VT[64d x 128k]^T
    float apv[2][4][4] = {};
    const int pv_brow = wn * 32 + ((lane & 16) ? 8 : 0) + (lane & 7);
    const uint32_t pS = sb, vS = sb + 2 * TAB;
#pragma unroll
    for (int ks = 0; ks < 8; ++ks) {
        uint32_t ah[2][4];
#pragma unroll
        for (int ma = 0; ma < 2; ++ma) {
            const uint32_t off = (uint32_t)((a_row + ma * 16) * 272 + ks * 32) + a_kext;
            ldsm4(ah[ma][0], ah[ma][1], ah[ma][2], ah[ma][3], pS + off);
        }
#pragma unroll
        for (int bg = 0; bg < 2; ++bg) {
            const uint32_t off = (uint32_t)((pv_brow + bg * 16) * 272 + ks * 32) + b_kext;
            uint32_t bh[4];
            ldsm4(bh[0], bh[1], bh[2], bh[3], vS + off);
#pragma unroll
            for (int na = 0; na < 2; ++na)
#pragma unroll
                for (int ma = 0; ma < 2; ++ma)
                    mma_f16(apv[ma][bg * 2 + na], ah[ma], &bh[na * 2]);
        }
    }

#pragma unroll
    for (int ma = 0; ma < 2; ++ma) {
        const int r0 = qt * 128 + wm * 32 + ma * 16 + gq;
#pragma unroll
        for (int nI = 0; nI < 4; ++nI) {
            const int d = wn * 32 + nI * 8 + tig * 2;
            float* a0 = AO + ((size_t)b * S_ + r0) * HD + d;
            float* a1 = AO + ((size_t)b * S_ + r0 + 8) * HD + d;
            atomicAdd(a0, apv[ma][nI][0]);
            atomicAdd(a0 + 1, apv[ma][nI][1]);
            atomicAdd(a1, apv[ma][nI][2]);
            atomicAdd(a1 + 1, apv[ma][nI][3]);
        }
    }
}

// ---------------------------------------------------------------------------
// bf16x3 split GEMM (O projection, K=64, LDGSTS path)
// ---------------------------------------------------------------------------
#define TILE_B 16384
#define BUF4 (4 * TILE_B)

__global__ void __launch_bounds__(256, 2)
hmma_bf16x3_nt(const __nv_bfloat16* __restrict__ hA, const __nv_bfloat16* __restrict__ lA,
               const __nv_bfloat16* __restrict__ hB, const __nv_bfloat16* __restrict__ lB,
               const float* __restrict__ bias, float* __restrict__ C,
               int K, int lda, int ldb, int ldc)
{
    extern __shared__ char smem[];
    const uint32_t sb = smem_u32(smem);
    const int tid = threadIdx.x, lane = tid & 31, w = tid >> 5;
    const int wm = w >> 1, wn = w & 1;
    const int m0 = blockIdx.y * 128, n0 = blockIdx.x * 128;

    hA += (size_t)m0 * lda; lA += (size_t)m0 * lda;
    hB += (size_t)n0 * ldb; lB += (size_t)n0 * ldb;

    cp_tile(hA, lda, sb + 0 * TILE_B, tid);
    cp_tile(lA, lda, sb + 1 * TILE_B, tid);
    cp_tile(hB, ldb, sb + 2 * TILE_B, tid);
    cp_tile(lB, ldb, sb + 3 * TILE_B, tid);
    CP_COMMIT();
    CP_WAIT(0);
    __syncthreads();

    float acc[2][8][4] = {};

    const int a_row = wm * 32 + (lane & 15);
    const uint32_t a_kext = (lane & 16) ? 16u : 0u;
    const int b_row = wn * 64 + ((lane & 16) ? 8 : 0) + (lane & 7);
    const uint32_t b_kext = (lane & 8) ? 16u : 0u;

    const uint32_t aH = sb, aL = sb + TILE_B, bH = sb + 2 * TILE_B, bL = sb + 3 * TILE_B;

#pragma unroll
    for (int ks = 0; ks < 4; ++ks) {
        uint32_t ah[2][4], al[2][4];
#pragma unroll
        for (int ma = 0; ma < 2; ++ma) {
            const uint32_t off =
                SWZ128((uint32_t)((a_row + ma * 16) * 128) + (uint32_t)(ks * 32) + a_kext);
            ldsm4(ah[ma][0], ah[ma][1], ah[ma][2], ah[ma][3], aH + off);
            ldsm4(al[ma][0], al[ma][1], al[ma][2], al[ma][3], aL + off);
        }
#pragma unroll
        for (int bg = 0; bg < 4; ++bg) {
            const uint32_t off =
                SWZ128((uint32_t)((b_row + bg * 16) * 128) + (uint32_t)(ks * 32) + b_kext);
            uint32_t bh[4], bl[4];
            ldsm4(bh[0], bh[1], bh[2], bh[3], bH + off);
            ldsm4(bl[0], bl[1], bl[2], bl[3], bL + off);
#pragma unroll
            for (int na = 0; na < 2; ++na) {
                const int n = bg * 2 + na;
#pragma unroll
                for (int ma = 0; ma < 2; ++ma) {
                    mma_bf16(acc[ma][n], ah[ma], &bh[na * 2]);
                    mma_bf16(acc[ma][n], ah[ma], &bl[na * 2]);
                    mma_bf16(acc[ma][n], al[ma], &bh[na * 2]);
                }
            }
        }
    }

    const int gq = lane >> 2, tig = lane & 3;
#pragma unroll
    for (int ma = 0; ma < 2; ++ma) {
        const int r0 = m0 + wm * 32 + ma * 16 + gq;
#pragma unroll
        for (int n = 0; n < 8; ++n) {
            const int col = n0 + wn * 64 + n * 8 + tig * 2;
            const float b0 = bias[col], b1 = bias[col + 1];
            *(float2*)(C + (size_t)r0 * ldc + col) =
                make_float2(acc[ma][n][0] + b0, acc[ma][n][1] + b1);
            *(float2*)(C + (size_t)(r0 + 8) * ldc + col) =
                make_float2(acc[ma][n][2] + b0, acc[ma][n][3] + b1);
        }
    }
}

extern "C" void kernel_launch(void* const* d_in, const int* in_sizes, int n_in,
                              void* d_out, int out_size)
{
    const float* query  = (const float*)d_in[0];
    const float* key_in = (const float*)d_in[1];
    const float* value  = (const float*)d_in[2];
    const float* Wq = (const float*)d_in[3];
    const float* bq = (const float*)d_in[4];
    const float* Wk = (const float*)d_in[5];
    const float* bk = (const float*)d_in[6];
    const float* Wv = (const float*)d_in[7];
    const float* bv = (const float*)d_in[8];
    const float* Wo = (const float*)d_in[9];
    const float* bo = (const float*)d_in[10];

    float* out = (float*)d_out;
    float* avg_out = out + (size_t)B_ * S_ * H_;

    float *gAO, *giL;
    char *gApc, *gWpc, *gWvpc, *gQpc, *gKpc, *gVTpc;
    __nv_bfloat16 *hA, *lA, *hW, *lW;
    cudaGetSymbolAddress((void**)&gAO, g_AO);
    cudaGetSymbolAddress((void**)&giL, g_iL);
    cudaGetSymbolAddress((void**)&gApc, g_Ap);
    cudaGetSymbolAddress((void**)&gWpc, g_Wp);
    cudaGetSymbolAddress((void**)&gWvpc, g_Wvp);
    cudaGetSymbolAddress((void**)&gQpc, g_Qp);
    cudaGetSymbolAddress((void**)&gKpc, g_Kp);
    cudaGetSymbolAddress((void**)&gVTpc, g_VTp);
    cudaGetSymbolAddress((void**)&hA, g_hA);
    cudaGetSymbolAddress((void**)&lA, g_lA);
    cudaGetSymbolAddress((void**)&hW, g_hW);
    cudaGetSymbolAddress((void**)&lW, g_lW);

    cudaFuncSetAttribute(proj_all, cudaFuncAttributeMaxDynamicSharedMemorySize, 4 * TAB);
    cudaFuncSetAttribute(qk_rowsum_p, cudaFuncAttributeMaxDynamicSharedMemorySize, 3 * TAB);
    cudaFuncSetAttribute(attn_avg_p, cudaFuncAttributeMaxDynamicSharedMemorySize, ATT_SM);
    cudaFuncSetAttribute(hmma_bf16x3_nt, cudaFuncAttributeMaxDynamicSharedMemorySize, BUF4);

    const int M = B_ * S_;          // 8192
    const int NXH = B_ * S_ * H_;   // 8M

    zero_f<<<(B_ * S_ * HD) / 256, 256>>>(gAO, B_ * S_ * HD);
    zero_f<<<(16 * TAB / 4) / 256, 256>>>((float*)gWvpc, 16 * TAB / 4);

    // Pack all activations (value/query/key) and all weights
    cvt_pack3<<<dim3(NXH / 1024, 3), 256>>>((const float4*)value, (const float4*)query,
                                            (const float4*)key_in, gApc, NXH / 4);
    cvt_pack_w2<<<dim3((H_ * H_) / 1024, 2), 256>>>((const float4*)Wq, (const float4*)Wk,
                                                    gWpc, H_ * H_ / 4);
    cvt_pack_w64<<<(HD * H_) / 1024, 256>>>((const float4*)Wv, gWvpc, HD * H_ / 4);

    // All three projections in one launch (Q scaled by 0.125*log2e)
    proj_all<<<dim3(17, 64), 256, 4 * TAB>>>(gApc, gWpc, gWvpc, bq, bk, bv,
                                             gQpc, gKpc, gVTpc);

    // Pass A: softmax denominators
    qk_rowsum_p<<<dim3(S_ / 128, NH, B_), 256, 3 * TAB>>>(gQpc, gKpc, giL);

    // Pass B: head-averaged softmax + fused PV (occupancy 2)
    attn_avg_p<<<dim3(S_ / 128, S_ / 128, B_), 256, ATT_SM>>>(gQpc, gKpc, gVTpc, giL,
                                                              avg_out, gAO);

    // O projection (bf16x3)
    split_hl4<<<(B_ * S_ * HD) / 1024, 256>>>((const float4*)gAO, (uint2*)hA, (uint2*)lA,
                                              B_ * S_ * HD / 4);
    split_hl4<<<(H_ * HD) / 1024, 256>>>((const float4*)Wo, (uint2*)hW, (uint2*)lW, H_ * HD / 4);
    hmma_bf16x3_nt<<<dim3(H_ / 128, M / 128, 1), 256, BUF4>>>(hA, lA, hW, lW, bo,
        out, HD, HD, HD, H_);
}

// round 15
// speedup vs baseline: 11.9971x; 1.0464x over previous
#include <cuda_runtime.h>
#include <cuda_bf16.h>
#include <cuda_fp16.h>
#include <cstdint>

#define B_ 4
#define S_ 2048
#define H_ 1024
#define NH 16
#define HD 64

#define TAB 18432            // packed tile: 128 rows x 144B pitch (64 fp16 cols)
#define QHB 9216             // half tile: 64 rows x 144B
#define VTB 17408            // VT tile: 64 rows x 272B pitch (128 fp16 cols)
#define ASLICE ((size_t)64 * 16 * TAB)

// Q is pre-scaled by 0.125*log2(e) so softmax weight = exp2(score)
#define QSCALE 0.180336879f

// scratch
__device__ float g_AO[B_ * S_ * HD];
__device__ float g_iL[B_ * NH * S_];
__device__ __align__(16) char g_Ap[3 * 64 * 16 * TAB];   // slices: 0=value,1=query,2=key
__device__ __align__(16) char g_Wp[16 * 16 * TAB];       // slices 0-7: Wq, 8-15: Wk
__device__ __align__(16) char g_Wvp[16 * TAB];           // packed Wv (rows 64..127 stay zero)
__device__ __align__(16) char g_Qp[64 * 16 * TAB];
__device__ __align__(16) char g_Kp[64 * 16 * TAB];
__device__ __align__(16) char g_VTp[64 * VTB];
__device__ __nv_bfloat16 g_hA[B_ * S_ * HD], g_lA[B_ * S_ * HD];
__device__ __nv_bfloat16 g_hW[H_ * HD],      g_lW[H_ * HD];

// ---------------------------------------------------------------------------
// helpers
// ---------------------------------------------------------------------------
__device__ __forceinline__ uint32_t smem_u32(const void* p) {
    uint32_t a;
    asm("{ .reg .u64 t; cvta.to.shared.u64 t, %1; cvt.u32.u64 %0, t; }" : "=r"(a) : "l"(p));
    return a;
}
#define SWZ128(x) ((x) ^ (((x) >> 3) & 0x70))

__device__ __forceinline__ float ex2(float x) {
    float y; asm("ex2.approx.f32 %0, %1;" : "=f"(y) : "f"(x)); return y;
}

__device__ __forceinline__ void ldsm4(uint32_t& r0, uint32_t& r1, uint32_t& r2, uint32_t& r3,
                                      uint32_t addr) {
    asm volatile("ldmatrix.sync.aligned.m8n8.x4.shared.b16 {%0,%1,%2,%3}, [%4];"
                 : "=r"(r0), "=r"(r1), "=r"(r2), "=r"(r3) : "r"(addr));
}
__device__ __forceinline__ void mma_bf16(float* c, const uint32_t* a, const uint32_t* b) {
    asm volatile(
        "mma.sync.aligned.m16n8k16.row.col.f32.bf16.bf16.f32 "
        "{%0,%1,%2,%3}, {%4,%5,%6,%7}, {%8,%9}, {%0,%1,%2,%3};"
        : "+f"(c[0]), "+f"(c[1]), "+f"(c[2]), "+f"(c[3])
        : "r"(a[0]), "r"(a[1]), "r"(a[2]), "r"(a[3]), "r"(b[0]), "r"(b[1]));
}
__device__ __forceinline__ void mma_f16(float* c, const uint32_t* a, const uint32_t* b) {
    asm volatile(
        "mma.sync.aligned.m16n8k16.row.col.f32.f16.f16.f32 "
        "{%0,%1,%2,%3}, {%4,%5,%6,%7}, {%8,%9}, {%0,%1,%2,%3};"
        : "+f"(c[0]), "+f"(c[1]), "+f"(c[2]), "+f"(c[3])
        : "r"(a[0]), "r"(a[1]), "r"(a[2]), "r"(a[3]), "r"(b[0]), "r"(b[1]));
}
#define CP16(s, g) asm volatile("cp.async.cg.shared.global [%0], [%1], 16;" :: "r"(s), "l"(g))
#define CP_COMMIT() asm volatile("cp.async.commit_group;" ::: "memory")
#define CP_WAIT(n)  asm volatile("cp.async.wait_group %0;" :: "n"(n) : "memory")

// --- TMA bulk-copy + mbarrier (base sm_90 PTX) ---
__device__ __forceinline__ void bulk_cp(uint32_t sdst, const void* gsrc, uint32_t bytes,
                                        uint32_t mbar) {
    asm volatile(
        "cp.async.bulk.shared::cta.global.mbarrier::complete_tx::bytes [%0], [%1], %2, [%3];"
        :: "r"(sdst), "l"(gsrc), "r"(bytes), "r"(mbar) : "memory");
}
#define MBAR_INIT(a, n) \
    asm volatile("mbarrier.init.shared.b64 [%0], %1;" :: "r"(a), "r"((uint32_t)(n)) : "memory")
#define MBAR_EXPECT(a, bytes) \
    asm volatile("mbarrier.arrive.expect_tx.shared.b64 _, [%0], %1;" \
                 :: "r"(a), "r"((uint32_t)(bytes)) : "memory")
__device__ __forceinline__ void mbar_wait(uint32_t mbar, int parity) {
    asm volatile(
        "{\n\t.reg .pred P;\n\t"
        "LAB_%=:\n\t"
        "mbarrier.try_wait.parity.acquire.cta.shared::cta.b64 P, [%0], %1;\n\t"
        "@!P bra LAB_%=;\n\t}"
        :: "r"(mbar), "r"((uint32_t)parity) : "memory");
}

// LDGSTS staging (O-projection only)
__device__ __forceinline__ void cp_tile(const void* __restrict__ g, int ld_elems,
                                        uint32_t sdst, int tid)
{
    const __half* gh = (const __half*)g;
#pragma unroll
    for (int it = 0; it < 4; ++it) {
        int i = tid + it * 256;
        int row = i >> 3, c = i & 7;
        const void* gp = gh + (size_t)row * ld_elems + c * 8;
        uint32_t sp = sdst + SWZ128((uint32_t)(row * 128 + c * 16));
        CP16(sp, gp);
    }
}

// 128x128x64 fp16 MMA on two pitch-144 tiles (8 warps 4m x 2n)
__device__ __forceinline__ void mma_tile144(float acc[2][8][4], uint32_t aS, uint32_t bS,
                                            int a_row, uint32_t a_kext,
                                            int b_row, uint32_t b_kext)
{
#pragma unroll
    for (int ks = 0; ks < 4; ++ks) {
        uint32_t ah[2][4];
#pragma unroll
        for (int ma = 0; ma < 2; ++ma) {
            const uint32_t off = (uint32_t)((a_row + ma * 16) * 144 + ks * 32) + a_kext;
            ldsm4(ah[ma][0], ah[ma][1], ah[ma][2], ah[ma][3], aS + off);
        }
#pragma unroll
        for (int bg = 0; bg < 4; ++bg) {
            const uint32_t off = (uint32_t)((b_row + bg * 16) * 144 + ks * 32) + b_kext;
            uint32_t bh[4];
            ldsm4(bh[0], bh[1], bh[2], bh[3], bS + off);
#pragma unroll
            for (int na = 0; na < 2; ++na)
#pragma unroll
                for (int ma = 0; ma < 2; ++ma)
                    mma_f16(acc[ma][bg * 2 + na], ah[ma], &bh[na * 2]);
        }
    }
}

// 64x128x64: A half-tile (64 rows), warps 4m(16 rows) x 2n(64 cols)
__device__ __forceinline__ void mma_half144(float acc[8][4], uint32_t aS, uint32_t bS,
                                            int a_row, uint32_t a_kext,
                                            int b_row, uint32_t b_kext)
{
#pragma unroll
    for (int ks = 0; ks < 4; ++ks) {
        uint32_t ah[4];
        {
            const uint32_t off = (uint32_t)(a_row * 144 + ks * 32) + a_kext;
            ldsm4(ah[0], ah[1], ah[2], ah[3], aS + off);
        }
#pragma unroll
        for (int bg = 0; bg < 4; ++bg) {
            const uint32_t off = (uint32_t)((b_row + bg * 16) * 144 + ks * 32) + b_kext;
            uint32_t bh[4];
            ldsm4(bh[0], bh[1], bh[2], bh[3], bS + off);
#pragma unroll
            for (int na = 0; na < 2; ++na)
                mma_f16(acc[bg * 2 + na], ah, &bh[na * 2]);
        }
    }
}

// ---------------------------------------------------------------------------
// utility kernels
// ---------------------------------------------------------------------------
__global__ void cvt_pack3(const float4* __restrict__ x0, const float4* __restrict__ x1,
                          const float4* __restrict__ x2, char* __restrict__ out, int n4)
{
    int i = blockIdx.x * blockDim.x + threadIdx.x;
    if (i >= n4) return;
    const int z = blockIdx.y;
    const float4* x = (z == 0) ? x0 : ((z == 1) ? x1 : x2);
    float4 v = x[i];
    union { __half2 h2[2]; uint2 u; } p;
    p.h2[0] = __floats2half2_rn(v.x, v.y);
    p.h2[1] = __floats2half2_rn(v.z, v.w);
    int row = i >> 8;
    int col = (i & 255) << 2;
    int rt = row >> 7, r = row & 127, c = col >> 6, k = col & 63;
    *(uint2*)(out + (size_t)z * ASLICE + (size_t)(rt * 16 + c) * TAB + r * 144 + k * 2) = p.u;
}

__global__ void cvt_pack_w2(const float4* __restrict__ x0, const float4* __restrict__ x1,
                            char* __restrict__ out, int n4)
{
    int i = blockIdx.x * blockDim.x + threadIdx.x;
    if (i >= n4) return;
    const int z = blockIdx.y;
    const float4* x = z ? x1 : x0;
    float4 v = x[i];
    union { __half2 h2[2]; uint2 u; } p;
    p.h2[0] = __floats2half2_rn(v.x, v.y);
    p.h2[1] = __floats2half2_rn(v.z, v.w);
    int row = i >> 8;
    int col = (i & 255) << 2;
    int rt = row >> 7, r = row & 127, c = col >> 6, k = col & 63;
    *(uint2*)(out + (size_t)((z * 8 + rt) * 16 + c) * TAB + r * 144 + k * 2) = p.u;
}

__global__ void cvt_pack_w64(const float4* __restrict__ x, char* __restrict__ out, int n4)
{
    int i = blockIdx.x * blockDim.x + threadIdx.x;
    if (i >= n4) return;
    float4 v = x[i];
    union { __half2 h2[2]; uint2 u; } p;
    p.h2[0] = __floats2half2_rn(v.x, v.y);
    p.h2[1] = __floats2half2_rn(v.z, v.w);
    int row = i >> 8;
    int col = (i & 255) << 2;
    int c = col >> 6, k = col & 63;
    *(uint2*)(out + (size_t)c * TAB + row * 144 + k * 2) = p.u;
}

__global__ void split_hl4(const float4* __restrict__ x, uint2* __restrict__ hi,
                          uint2* __restrict__ lo, int n4)
{
    int i = blockIdx.x * blockDim.x + threadIdx.x;
    if (i < n4) {
        float4 v = x[i];
        __nv_bfloat16 h0 = __float2bfloat16(v.x), h1 = __float2bfloat16(v.y);
        __nv_bfloat16 h2 = __float2bfloat16(v.z), h3 = __float2bfloat16(v.w);
        __nv_bfloat16 l0 = __float2bfloat16(v.x - __bfloat162float(h0));
        __nv_bfloat16 l1 = __float2bfloat16(v.y - __bfloat162float(h1));
        __nv_bfloat16 l2 = __float2bfloat16(v.z - __bfloat162float(h2));
        __nv_bfloat16 l3 = __float2bfloat16(v.w - __bfloat162float(h3));
        union { __nv_bfloat162 b2[2]; uint2 u; } ph, pl;
        ph.b2[0].x = h0; ph.b2[0].y = h1; ph.b2[1].x = h2; ph.b2[1].y = h3;
        pl.b2[0].x = l0; pl.b2[0].y = l1; pl.b2[1].x = l2; pl.b2[1].y = l3;
        hi[i] = ph.u;
        lo[i] = pl.u;
    }
}

__global__ void zero_f(float* __restrict__ p, int n)
{
    int i = blockIdx.x * blockDim.x + threadIdx.x;
    if (i < n) p[i] = 0.f;
}

// ---------------------------------------------------------------------------
// Merged projection kernel: grid (17, 64).
// ---------------------------------------------------------------------------
__global__ void __launch_bounds__(256, 2)
proj_all(const char* __restrict__ Ap, const char* __restrict__ Wp,
         const char* __restrict__ Wvp,
         const float* __restrict__ bq, const float* __restrict__ bk,
         const float* __restrict__ bv,
         char* __restrict__ Qp, char* __restrict__ Kp, char* __restrict__ VTp)
{
    extern __shared__ char smem[];
    __shared__ uint64_t mb[2];
    const uint32_t sb = smem_u32(smem);
    const int tid = threadIdx.x, lane = tid & 31, w = tid >> 5;
    const int wm = w >> 1, wn = w & 1;
    const int nx = blockIdx.x, my = blockIdx.y;
    const bool isV = (nx == 16);

    const uint32_t mbar0 = smem_u32(&mb[0]), mbar1 = smem_u32(&mb[1]);
    if (tid == 0) { MBAR_INIT(mbar0, 1); MBAR_INIT(mbar1, 1); }
    __syncthreads();

    const int slice = isV ? 0 : (nx < 8 ? 1 : 2);
    const char* Asrc = Ap + (size_t)slice * ASLICE + (size_t)my * 16 * TAB;
    const char* Wsrc = isV ? Wvp : (Wp + (size_t)nx * 16 * TAB);

    if (tid == 0) {
        MBAR_EXPECT(mbar0, 2 * TAB);
        bulk_cp(sb, Asrc, TAB, mbar0);
        bulk_cp(sb + TAB, Wsrc, TAB, mbar0);
    }

    float acc[2][8][4] = {};
    const int a_row = wm * 32 + (lane & 15);
    const uint32_t a_kext = (lane & 16) ? 16u : 0u;
    const int b_row = wn * 64 + ((lane & 16) ? 8 : 0) + (lane & 7);
    const uint32_t b_kext = (lane & 8) ? 16u : 0u;
    int ph0 = 0, ph1 = 0;

    for (int c = 0; c < 16; ++c) {
        const int b = c & 1;
        if (c + 1 < 16 && tid == 0) {
            const uint32_t nb = sb + (1 - b) * 2 * TAB;
            const uint32_t m = b ? mbar0 : mbar1;
            MBAR_EXPECT(m, 2 * TAB);
            bulk_cp(nb, Asrc + (size_t)(c + 1) * TAB, TAB, m);
            bulk_cp(nb + TAB, Wsrc + (size_t)(c + 1) * TAB, TAB, m);
        }
        if (b == 0) { mbar_wait(mbar0, ph0); ph0 ^= 1; }
        else        { mbar_wait(mbar1, ph1); ph1 ^= 1; }
        const uint32_t aS = sb + b * 2 * TAB;
        mma_tile144(acc, aS, aS + TAB, a_row, a_kext, b_row, b_kext);
        __syncthreads();
    }

    const int gq = lane >> 2, tig = lane & 3;
    if (isV) {
        if (wn == 0) {
            char* Vt = VTp + (size_t)my * VTB;
#pragma unroll
            for (int ma = 0; ma < 2; ++ma) {
                const int rl = wm * 32 + ma * 16 + gq;
#pragma unroll
                for (int n = 0; n < 8; ++n) {
                    const int d = n * 8 + tig * 2;
                    const float b0 = bv[d], b1 = bv[d + 1];
                    *(__half*)(Vt + d * 272 + rl * 2)             = __float2half(acc[ma][n][0] + b0);
                    *(__half*)(Vt + (d + 1) * 272 + rl * 2)       = __float2half(acc[ma][n][1] + b1);
                    *(__half*)(Vt + d * 272 + (rl + 8) * 2)       = __float2half(acc[ma][n][2] + b0);
                    *(__half*)(Vt + (d + 1) * 272 + (rl + 8) * 2) = __float2half(acc[ma][n][3] + b1);
                }
            }
        }
    } else {
        const float* bias = (nx < 8) ? bq : bk;
        const float cs = (nx < 8) ? QSCALE : 1.0f;
        char* Cp = (nx < 8) ? Qp : Kp;
        const int nxl = nx & 7;
#pragma unroll
        for (int ma = 0; ma < 2; ++ma) {
            const int rl = wm * 32 + ma * 16 + gq;
#pragma unroll
            for (int n = 0; n < 8; ++n) {
                const int col = nxl * 128 + wn * 64 + n * 8 + tig * 2;
                const float b0 = bias[col], b1 = bias[col + 1];
                const size_t tb = (size_t)(my * 16 + (col >> 6)) * TAB + (col & 63) * 2;
                *(__half2*)(Cp + tb + rl * 144) =
                    __floats2half2_rn((acc[ma][n][0] + b0) * cs, (acc[ma][n][1] + b1) * cs);
                *(__half2*)(Cp + tb + (rl + 8) * 144) =
                    __floats2half2_rn((acc[ma][n][2] + b0) * cs, (acc[ma][n][3] + b1) * cs);
            }
        }
    }
}

// ---------------------------------------------------------------------------
// Pass A: per-(b,h,q) softmax denominators (128-row tile; no avgf -> no spill)
// ---------------------------------------------------------------------------
__global__ void __launch_bounds__(256, 2)
qk_rowsum_p(const char* __restrict__ Qp, const char* __restrict__ Kp, float* __restrict__ iL)
{
    extern __shared__ char smem[];
    __shared__ uint64_t mb[2];
    const uint32_t sb = smem_u32(smem);
    const int tid = threadIdx.x, lane = tid & 31, w = tid >> 5;
    const int wm = w >> 1, wn = w & 1;
    const int qt = blockIdx.x, h = blockIdx.y, b = blockIdx.z;

    const uint32_t mbar0 = smem_u32(&mb[0]), mbar1 = smem_u32(&mb[1]);
    if (tid == 0) { MBAR_INIT(mbar0, 1); MBAR_INIT(mbar1, 1); }
    __syncthreads();

    const char* Qsrc = Qp + ((size_t)(b * 16 + qt) * 16 + h) * TAB;
    if (tid == 0) {
        MBAR_EXPECT(mbar0, 2 * TAB);
        bulk_cp(sb, Qsrc, TAB, mbar0);
        bulk_cp(sb + TAB, Kp + ((size_t)(b * 16 + 0) * 16 + h) * TAB, TAB, mbar0);
    }

    const int a_row = wm * 32 + (lane & 15);
    const uint32_t a_kext = (lane & 16) ? 16u : 0u;
    const int b_row = wn * 64 + ((lane & 16) ? 8 : 0) + (lane & 7);
    const uint32_t b_kext = (lane & 8) ? 16u : 0u;

    float lsum[2][2] = {};
    int ph0 = 0, ph1 = 0;

    for (int kt = 0; kt < 16; ++kt) {
        const int bb = kt & 1;
        if (kt + 1 < 16 && tid == 0) {
            const uint32_t m = bb ? mbar0 : mbar1;
            MBAR_EXPECT(m, TAB);
            bulk_cp(sb + TAB + (1 - bb) * TAB,
                    Kp + ((size_t)(b * 16 + kt + 1) * 16 + h) * TAB, TAB, m);
        }
        if (bb == 0) { mbar_wait(mbar0, ph0); ph0 ^= 1; }
        else         { mbar_wait(mbar1, ph1); ph1 ^= 1; }

        float acc[2][8][4] = {};
        mma_tile144(acc, sb, sb + TAB + bb * TAB, a_row, a_kext, b_row, b_kext);

#pragma unroll
        for (int ma = 0; ma < 2; ++ma)
#pragma unroll
            for (int n = 0; n < 8; ++n) {
                lsum[ma][0] += ex2(acc[ma][n][0]) + ex2(acc[ma][n][1]);
                lsum[ma][1] += ex2(acc[ma][n][2]) + ex2(acc[ma][n][3]);
            }
        __syncthreads();
    }

#pragma unroll
    for (int o = 1; o <= 2; o <<= 1)
#pragma unroll
        for (int ma = 0; ma < 2; ++ma)
#pragma unroll
            for (int hh = 0; hh < 2; ++hh)
                lsum[ma][hh] += __shfl_xor_sync(0xffffffffu, lsum[ma][hh], o);

    __shared__ float Ls[128];
    if (tid < 128) Ls[tid] = 0.f;
    __syncthreads();
    if ((lane & 3) == 0) {
        const int gq = lane >> 2;
#pragma unroll
        for (int ma = 0; ma < 2; ++ma) {
            atomicAdd(&Ls[wm * 32 + ma * 16 + gq], lsum[ma][0]);
            atomicAdd(&Ls[wm * 32 + ma * 16 + gq + 8], lsum[ma][1]);
        }
    }
    __syncthreads();
    if (tid < 128)
        iL[((size_t)b * NH + h) * S_ + qt * 128 + tid] = 1.0f / (16.0f * Ls[tid]);
}

// ---------------------------------------------------------------------------
// Pass B: 64(q) x 128(k) tile — no register spills. grid (16 kt, 32 qh, 4 b).
// smem: stage = Q half (9216) + K (18432) = 27648, x2 buffers = 55296.
// Overlay after head loop: P (64x272=17408) at buf0, VT at buf1.
// ---------------------------------------------------------------------------
#define STG (QHB + TAB)          // 27648
#define ATT_SM (2 * STG)         // 55296

__global__ void __launch_bounds__(256, 2)
attn_avg_h(const char* __restrict__ Qp, const char* __restrict__ Kp,
           const char* __restrict__ VTp, const float* __restrict__ iL,
           float* __restrict__ avg, float* __restrict__ AO)
{
    extern __shared__ char smem[];
    __shared__ uint64_t mb[3];
    const uint32_t sb = smem_u32(smem);
    const int tid = threadIdx.x, lane = tid & 31, w = tid >> 5;
    const int wq = w >> 1, wn = w & 1;          // 4 m-warps x 2 n-warps
    const int kt = blockIdx.x, qh = blockIdx.y, b = blockIdx.z;
    const int qt = qh >> 1, half = qh & 1;

    const uint32_t mbar0 = smem_u32(&mb[0]), mbar1 = smem_u32(&mb[1]), mbar2 = smem_u32(&mb[2]);
    if (tid == 0) { MBAR_INIT(mbar0, 1); MBAR_INIT(mbar1, 1); MBAR_INIT(mbar2, 1); }
    __syncthreads();

    const char* Qsrc = Qp + (size_t)(b * 16 + qt) * 16 * TAB + half * QHB;
    const char* Ksrc = Kp + (size_t)(b * 16 + kt) * 16 * TAB;

    if (tid == 0) {
        MBAR_EXPECT(mbar0, STG);
        bulk_cp(sb, Qsrc, QHB, mbar0);
        bulk_cp(sb + QHB, Ksrc, TAB, mbar0);
    }

    const int a_row = wq * 16 + (lane & 15);
    const uint32_t a_kext = (lane & 16) ? 16u : 0u;
    const int b_row = wn * 64 + ((lane & 16) ? 8 : 0) + (lane & 7);
    const uint32_t b_kext = (lane & 8) ? 16u : 0u;
    const int gq = lane >> 2, tig = lane & 3;

    float avgf[8][4] = {};
    int ph0 = 0, ph1 = 0;

    for (int h = 0; h < NH; ++h) {
        const int bb = h & 1;
        if (h + 1 < NH && tid == 0) {
            const uint32_t nb = sb + (1 - bb) * STG;
            const uint32_t m = bb ? mbar0 : mbar1;
            MBAR_EXPECT(m, STG);
            bulk_cp(nb, Qsrc + (size_t)(h + 1) * TAB, QHB, m);
            bulk_cp(nb + QHB, Ksrc + (size_t)(h + 1) * TAB, TAB, m);
        }
        if (bb == 0) { mbar_wait(mbar0, ph0); ph0 ^= 1; }
        else         { mbar_wait(mbar1, ph1); ph1 ^= 1; }

        float acc[8][4] = {};
        const uint32_t aS = sb + bb * STG;
        mma_half144(acc, aS, aS + QHB, a_row, a_kext, b_row, b_kext);

        const float* Lh = iL + ((size_t)b * NH + h) * S_ + qh * 64;
        const float l0 = Lh[wq * 16 + gq];
        const float l1 = Lh[wq * 16 + gq + 8];
#pragma unroll
        for (int n = 0; n < 8; ++n) {
            avgf[n][0] += ex2(acc[n][0]) * l0;
            avgf[n][1] += ex2(acc[n][1]) * l0;
            avgf[n][2] += ex2(acc[n][2]) * l1;
            avgf[n][3] += ex2(acc[n][3]) * l1;
        }
        __syncthreads();
    }

    // Buffers dead: load VT into buf1 region; stage P into buf0 region.
    if (tid == 0) {
        MBAR_EXPECT(mbar2, VTB);
        bulk_cp(sb + STG, VTp + (size_t)(b * 16 + kt) * VTB, VTB, mbar2);
    }

    float* outp = avg + (size_t)b * S_ * S_;
#pragma unroll
    for (int n = 0; n < 8; ++n) {
        const int rl = wq * 16 + gq;
        const int r0 = qh * 64 + rl;
        const int col = wn * 64 + n * 8 + tig * 2;
        *(float2*)(outp + (size_t)r0 * S_ + kt * 128 + col) =
            make_float2(avgf[n][0], avgf[n][1]);
        *(float2*)(outp + (size_t)(r0 + 8) * S_ + kt * 128 + col) =
            make_float2(avgf[n][2], avgf[n][3]);
        *(__half2*)(smem + rl * 272 + col * 2) = __floats2half2_rn(avgf[n][0], avgf[n][1]);
        *(__half2*)(smem + (rl + 8) * 272 + col * 2) = __floats2half2_rn(avgf[n][2], avgf[n][3]);
    }
    mbar_wait(mbar2, 0);
    __syncthreads();

    // PV: [64q x 64d] += P[64q x 128k] @ VT[64d x 128k]^T
    float apv[4][4] = {};
    const int pv_brow = wn * 32 + ((lane & 16) ? 8 : 0) + (lane & 7);
    const uint32_t pS = sb, vS = sb + STG;
#pragma unroll
    for (int ks = 0; ks < 8; ++ks) {
        uint32_t ah[4];
        {
            const uint32_t off = (uint32_t)(a_row * 272 + ks * 32) + a_kext;
            ldsm4(ah[0], ah[1], ah[2], ah[3], pS + off);
        }
#pragma unroll
        for (int bg = 0; bg < 2; ++bg) {
            const uint32_t off = (uint32_t)((pv_brow + bg * 16) * 272 + ks * 32) + b_kext;
            uint32_t bh[4];
            ldsm4(bh[0], bh[1], bh[2], bh[3], vS + off);
#pragma unroll
            for (int na = 0; na < 2; ++na)
                mma_f16(apv[bg * 2 + na], ah, &bh[na * 2]);
        }
    }

    {
        const int r0 = qh * 64 + wq * 16 + gq;
#pragma unroll
        for (int nI = 0; nI < 4; ++nI) {
            const int d = wn * 32 + nI * 8 + tig * 2;
            float* a0 = AO + ((size_t)b * S_ + r0) * HD + d;
            float* a1 = AO + ((size_t)b * S_ + r0 + 8) * HD + d;
            atomicAdd(a0, apv[nI][0]);
            atomicAdd(a0 + 1, apv[nI][1]);
            atomicAdd(a1, apv[nI][2]);
            atomicAdd(a1 + 1, apv[nI][3]);
        }
    }
}

// ---------------------------------------------------------------------------
// bf16x3 split GEMM (O projection, K=64, LDGSTS path)
// ---------------------------------------------------------------------------
#define TILE_B 16384
#define BUF4 (4 * TILE_B)

__global__ void __launch_bounds__(256, 2)
hmma_bf16x3_nt(const __nv_bfloat16* __restrict__ hA, const __nv_bfloat16* __restrict__ lA,
               const __nv_bfloat16* __restrict__ hB, const __nv_bfloat16* __restrict__ lB,
               const float* __restrict__ bias, float* __restrict__ C,
               int K, int lda, int ldb, int ldc)
{
    extern __shared__ char smem[];
    const uint32_t sb = smem_u32(smem);
    const int tid = threadIdx.x, lane = tid & 31, w = tid >> 5;
    const int wm = w >> 1, wn = w & 1;
    const int m0 = blockIdx.y * 128, n0 = blockIdx.x * 128;

    hA += (size_t)m0 * lda; lA += (size_t)m0 * lda;
    hB += (size_t)n0 * ldb; lB += (size_t)n0 * ldb;

    cp_tile(hA, lda, sb + 0 * TILE_B, tid);
    cp_tile(lA, lda, sb + 1 * TILE_B, tid);
    cp_tile(hB, ldb, sb + 2 * TILE_B, tid);
    cp_tile(lB, ldb, sb + 3 * TILE_B, tid);
    CP_COMMIT();
    CP_WAIT(0);
    __syncthreads();

    float acc[2][8][4] = {};

    const int a_row = wm * 32 + (lane & 15);
    const uint32_t a_kext = (lane & 16) ? 16u : 0u;
    const int b_row = wn * 64 + ((lane & 16) ? 8 : 0) + (lane & 7);
    const uint32_t b_kext = (lane & 8) ? 16u : 0u;

    const uint32_t aH = sb, aL = sb + TILE_B, bH = sb + 2 * TILE_B, bL = sb + 3 * TILE_B;

#pragma unroll
    for (int ks = 0; ks < 4; ++ks) {
        uint32_t ah[2][4], al[2][4];
#pragma unroll
        for (int ma = 0; ma < 2; ++ma) {
            const uint32_t off =
                SWZ128((uint32_t)((a_row + ma * 16) * 128) + (uint32_t)(ks * 32) + a_kext);
            ldsm4(ah[ma][0], ah[ma][1], ah[ma][2], ah[ma][3], aH + off);
            ldsm4(al[ma][0], al[ma][1], al[ma][2], al[ma][3], aL + off);
        }
#pragma unroll
        for (int bg = 0; bg < 4; ++bg) {
            const uint32_t off =
                SWZ128((uint32_t)((b_row + bg * 16) * 128) + (uint32_t)(ks * 32) + b_kext);
            uint32_t bh[4], bl[4];
            ldsm4(bh[0], bh[1], bh[2], bh[3], bH + off);
            ldsm4(bl[0], bl[1], bl[2], bl[3], bL + off);
#pragma unroll
            for (int na = 0; na < 2; ++na) {
                const int n = bg * 2 + na;
#pragma unroll
                for (int ma = 0; ma < 2; ++ma) {
                    mma_bf16(acc[ma][n], ah[ma], &bh[na * 2]);
                    mma_bf16(acc[ma][n], ah[ma], &bl[na * 2]);
                    mma_bf16(acc[ma][n], al[ma], &bh[na * 2]);
                }
            }
        }
    }

    const int gq = lane >> 2, tig = lane & 3;
#pragma unroll
    for (int ma = 0; ma < 2; ++ma) {
        const int r0 = m0 + wm * 32 + ma * 16 + gq;
#pragma unroll
        for (int n = 0; n < 8; ++n) {
            const int col = n0 + wn * 64 + n * 8 + tig * 2;
            const float b0 = bias[col], b1 = bias[col + 1];
            *(float2*)(C + (size_t)r0 * ldc + col) =
                make_float2(acc[ma][n][0] + b0, acc[ma][n][1] + b1);
            *(float2*)(C + (size_t)(r0 + 8) * ldc + col) =
                make_float2(acc[ma][n][2] + b0, acc[ma][n][3] + b1);
        }
    }
}

extern "C" void kernel_launch(void* const* d_in, const int* in_sizes, int n_in,
                              void* d_out, int out_size)
{
    const float* query  = (const float*)d_in[0];
    const float* key_in = (const float*)d_in[1];
    const float* value  = (const float*)d_in[2];
    const float* Wq = (const float*)d_in[3];
    const float* bq = (const float*)d_in[4];
    const float* Wk = (const float*)d_in[5];
    const float* bk = (const float*)d_in[6];
    const float* Wv = (const float*)d_in[7];
    const float* bv = (const float*)d_in[8];
    const float* Wo = (const float*)d_in[9];
    const float* bo = (const float*)d_in[10];

    float* out = (float*)d_out;
    float* avg_out = out + (size_t)B_ * S_ * H_;

    float *gAO, *giL;
    char *gApc, *gWpc, *gWvpc, *gQpc, *gKpc, *gVTpc;
    __nv_bfloat16 *hA, *lA, *hW, *lW;
    cudaGetSymbolAddress((void**)&gAO, g_AO);
    cudaGetSymbolAddress((void**)&giL, g_iL);
    cudaGetSymbolAddress((void**)&gApc, g_Ap);
    cudaGetSymbolAddress((void**)&gWpc, g_Wp);
    cudaGetSymbolAddress((void**)&gWvpc, g_Wvp);
    cudaGetSymbolAddress((void**)&gQpc, g_Qp);
    cudaGetSymbolAddress((void**)&gKpc, g_Kp);
    cudaGetSymbolAddress((void**)&gVTpc, g_VTp);
    cudaGetSymbolAddress((void**)&hA, g_hA);
    cudaGetSymbolAddress((void**)&lA, g_lA);
    cudaGetSymbolAddress((void**)&hW, g_hW);
    cudaGetSymbolAddress((void**)&lW, g_lW);

    cudaFuncSetAttribute(proj_all, cudaFuncAttributeMaxDynamicSharedMemorySize, 4 * TAB);
    cudaFuncSetAttribute(qk_rowsum_p, cudaFuncAttributeMaxDynamicSharedMemorySize, 3 * TAB);
    cudaFuncSetAttribute(attn_avg_h, cudaFuncAttributeMaxDynamicSharedMemorySize, ATT_SM);
    cudaFuncSetAttribute(hmma_bf16x3_nt, cudaFuncAttributeMaxDynamicSharedMemorySize, BUF4);

    const int M = B_ * S_;          // 8192
    const int NXH = B_ * S_ * H_;   // 8M

    // zero attn_out accumulator (g_Wvp rows 64..127 stay zero from module load)
    zero_f<<<(B_ * S_ * HD) / 256, 256>>>(gAO, B_ * S_ * HD);

    // Pack all activations (value/query/key) and all weights
    cvt_pack3<<<dim3(NXH / 1024, 3), 256>>>((const float4*)value, (const float4*)query,
                                            (const float4*)key_in, gApc, NXH / 4);
    cvt_pack_w2<<<dim3((H_ * H_) / 1024, 2), 256>>>((const float4*)Wq, (const float4*)Wk,
                                                    gWpc, H_ * H_ / 4);
    cvt_pack_w64<<<(HD * H_) / 1024, 256>>>((const float4*)Wv, gWvpc, HD * H_ / 4);

    // All three projections in one launch (Q scaled by 0.125*log2e)
    proj_all<<<dim3(17, 64), 256, 4 * TAB>>>(gApc, gWpc, gWvpc, bq, bk, bv,
                                             gQpc, gKpc, gVTpc);

    // Pass A: softmax denominators
    qk_rowsum_p<<<dim3(S_ / 128, NH, B_), 256, 3 * TAB>>>(gQpc, gKpc, giL);

    // Pass B: head-averaged softmax + fused PV (64x128 tile, no spills, occ 2)
    attn_avg_h<<<dim3(S_ / 128, S_ / 64, B_), 256, ATT_SM>>>(gQpc, gKpc, gVTpc, giL,
                                                             avg_out, gAO);

    // O projection (bf16x3)
    split_hl4<<<(B_ * S_ * HD) / 1024, 256>>>((const float4*)gAO, (uint2*)hA, (uint2*)lA,
                                              B_ * S_ * HD / 4);
    split_hl4<<<(H_ * HD) / 1024, 256>>>((const float4*)Wo, (uint2*)hW, (uint2*)lW, H_ * HD / 4);
    hmma_bf16x3_nt<<<dim3(H_ / 128, M / 128, 1), 256, BUF4>>>(hA, lA, hW, lW, bo,
        out, HD, HD, HD, H_);
}

// round 16
// speedup vs baseline: 12.0674x; 1.0059x over previous
#include <cuda_runtime.h>
#include <cuda_bf16.h>
#include <cuda_fp16.h>
#include <cstdint>

#define B_ 4
#define S_ 2048
#define H_ 1024
#define NH 16
#define HD 64

#define TAB 18432            // packed tile: 128 rows x 144B pitch (64 fp16 cols)
#define QHB 9216             // half tile: 64 rows x 144B
#define VTB 17408            // VT tile: 64 rows x 272B pitch (128 fp16 cols)
#define ASLICE ((size_t)64 * 16 * TAB)

// Q is pre-scaled by 0.125*log2(e) so softmax weight = exp2(score)
#define QSCALE 0.180336879f

// scratch
__device__ float g_AO[B_ * S_ * HD];
__device__ float g_iL[B_ * NH * S_];
__device__ __align__(16) char g_Ap[3 * 64 * 16 * TAB];   // slices: 0=value,1=query,2=key
__device__ __align__(16) char g_Wp[16 * 16 * TAB];       // slices 0-7: Wq, 8-15: Wk
__device__ __align__(16) char g_Wvp[16 * TAB];           // packed Wv (rows 64..127 stay zero)
__device__ __align__(16) char g_Wop[8 * TAB];            // packed Wo (8 n-tiles, K=64)
__device__ __align__(16) char g_AOp[64 * TAB];           // packed AO fp16 (64 m-tiles, K=64)
__device__ __align__(16) char g_Qp[64 * 16 * TAB];
__device__ __align__(16) char g_Kp[64 * 16 * TAB];
__device__ __align__(16) char g_VTp[64 * VTB];

// ---------------------------------------------------------------------------
// helpers
// ---------------------------------------------------------------------------
__device__ __forceinline__ uint32_t smem_u32(const void* p) {
    uint32_t a;
    asm("{ .reg .u64 t; cvta.to.shared.u64 t, %1; cvt.u32.u64 %0, t; }" : "=r"(a) : "l"(p));
    return a;
}

__device__ __forceinline__ float ex2(float x) {
    float y; asm("ex2.approx.f32 %0, %1;" : "=f"(y) : "f"(x)); return y;
}

__device__ __forceinline__ void ldsm4(uint32_t& r0, uint32_t& r1, uint32_t& r2, uint32_t& r3,
                                      uint32_t addr) {
    asm volatile("ldmatrix.sync.aligned.m8n8.x4.shared.b16 {%0,%1,%2,%3}, [%4];"
                 : "=r"(r0), "=r"(r1), "=r"(r2), "=r"(r3) : "r"(addr));
}
__device__ __forceinline__ void mma_f16(float* c, const uint32_t* a, const uint32_t* b) {
    asm volatile(
        "mma.sync.aligned.m16n8k16.row.col.f32.f16.f16.f32 "
        "{%0,%1,%2,%3}, {%4,%5,%6,%7}, {%8,%9}, {%0,%1,%2,%3};"
        : "+f"(c[0]), "+f"(c[1]), "+f"(c[2]), "+f"(c[3])
        : "r"(a[0]), "r"(a[1]), "r"(a[2]), "r"(a[3]), "r"(b[0]), "r"(b[1]));
}

// --- TMA bulk-copy + mbarrier (base sm_90 PTX) ---
__device__ __forceinline__ void bulk_cp(uint32_t sdst, const void* gsrc, uint32_t bytes,
                                        uint32_t mbar) {
    asm volatile(
        "cp.async.bulk.shared::cta.global.mbarrier::complete_tx::bytes [%0], [%1], %2, [%3];"
        :: "r"(sdst), "l"(gsrc), "r"(bytes), "r"(mbar) : "memory");
}
#define MBAR_INIT(a, n) \
    asm volatile("mbarrier.init.shared.b64 [%0], %1;" :: "r"(a), "r"((uint32_t)(n)) : "memory")
#define MBAR_EXPECT(a, bytes) \
    asm volatile("mbarrier.arrive.expect_tx.shared.b64 _, [%0], %1;" \
                 :: "r"(a), "r"((uint32_t)(bytes)) : "memory")
__device__ __forceinline__ void mbar_wait(uint32_t mbar, int parity) {
    asm volatile(
        "{\n\t.reg .pred P;\n\t"
        "LAB_%=:\n\t"
        "mbarrier.try_wait.parity.acquire.cta.shared::cta.b64 P, [%0], %1;\n\t"
        "@!P bra LAB_%=;\n\t}"
        :: "r"(mbar), "r"((uint32_t)parity) : "memory");
}

// 128x128x64 fp16 MMA on two pitch-144 tiles (8 warps 4m x 2n)
__device__ __forceinline__ void mma_tile144(float acc[2][8][4], uint32_t aS, uint32_t bS,
                                            int a_row, uint32_t a_kext,
                                            int b_row, uint32_t b_kext)
{
#pragma unroll
    for (int ks = 0; ks < 4; ++ks) {
        uint32_t ah[2][4];
#pragma unroll
        for (int ma = 0; ma < 2; ++ma) {
            const uint32_t off = (uint32_t)((a_row + ma * 16) * 144 + ks * 32) + a_kext;
            ldsm4(ah[ma][0], ah[ma][1], ah[ma][2], ah[ma][3], aS + off);
        }
#pragma unroll
        for (int bg = 0; bg < 4; ++bg) {
            const uint32_t off = (uint32_t)((b_row + bg * 16) * 144 + ks * 32) + b_kext;
            uint32_t bh[4];
            ldsm4(bh[0], bh[1], bh[2], bh[3], bS + off);
#pragma unroll
            for (int na = 0; na < 2; ++na)
#pragma unroll
                for (int ma = 0; ma < 2; ++ma)
                    mma_f16(acc[ma][bg * 2 + na], ah[ma], &bh[na * 2]);
        }
    }
}

// 64x128x64: A half-tile (64 rows), warps 4m(16 rows) x 2n(64 cols)
__device__ __forceinline__ void mma_half144(float acc[8][4], uint32_t aS, uint32_t bS,
                                            int a_row, uint32_t a_kext,
                                            int b_row, uint32_t b_kext)
{
#pragma unroll
    for (int ks = 0; ks < 4; ++ks) {
        uint32_t ah[4];
        {
            const uint32_t off = (uint32_t)(a_row * 144 + ks * 32) + a_kext;
            ldsm4(ah[0], ah[1], ah[2], ah[3], aS + off);
        }
#pragma unroll
        for (int bg = 0; bg < 4; ++bg) {
            const uint32_t off = (uint32_t)((b_row + bg * 16) * 144 + ks * 32) + b_kext;
            uint32_t bh[4];
            ldsm4(bh[0], bh[1], bh[2], bh[3], bS + off);
#pragma unroll
            for (int na = 0; na < 2; ++na)
                mma_f16(acc[bg * 2 + na], ah, &bh[na * 2]);
        }
    }
}

// ---------------------------------------------------------------------------
// utility kernels
// ---------------------------------------------------------------------------
__global__ void cvt_pack3(const float4* __restrict__ x0, const float4* __restrict__ x1,
                          const float4* __restrict__ x2, char* __restrict__ out, int n4)
{
    int i = blockIdx.x * blockDim.x + threadIdx.x;
    if (i >= n4) return;
    const int z = blockIdx.y;
    const float4* x = (z == 0) ? x0 : ((z == 1) ? x1 : x2);
    float4 v = x[i];
    union { __half2 h2[2]; uint2 u; } p;
    p.h2[0] = __floats2half2_rn(v.x, v.y);
    p.h2[1] = __floats2half2_rn(v.z, v.w);
    int row = i >> 8;
    int col = (i & 255) << 2;
    int rt = row >> 7, r = row & 127, c = col >> 6, k = col & 63;
    *(uint2*)(out + (size_t)z * ASLICE + (size_t)(rt * 16 + c) * TAB + r * 144 + k * 2) = p.u;
}

__global__ void cvt_pack_w2(const float4* __restrict__ x0, const float4* __restrict__ x1,
                            char* __restrict__ out, int n4)
{
    int i = blockIdx.x * blockDim.x + threadIdx.x;
    if (i >= n4) return;
    const int z = blockIdx.y;
    const float4* x = z ? x1 : x0;
    float4 v = x[i];
    union { __half2 h2[2]; uint2 u; } p;
    p.h2[0] = __floats2half2_rn(v.x, v.y);
    p.h2[1] = __floats2half2_rn(v.z, v.w);
    int row = i >> 8;
    int col = (i & 255) << 2;
    int rt = row >> 7, r = row & 127, c = col >> 6, k = col & 63;
    *(uint2*)(out + (size_t)((z * 8 + rt) * 16 + c) * TAB + r * 144 + k * 2) = p.u;
}

// Wv [64 x 1024] -> packed rows 0..63 of 16 chunks
__global__ void cvt_pack_w64(const float4* __restrict__ x, char* __restrict__ out, int n4)
{
    int i = blockIdx.x * blockDim.x + threadIdx.x;
    if (i >= n4) return;
    float4 v = x[i];
    union { __half2 h2[2]; uint2 u; } p;
    p.h2[0] = __floats2half2_rn(v.x, v.y);
    p.h2[1] = __floats2half2_rn(v.z, v.w);
    int row = i >> 8;
    int col = (i & 255) << 2;
    int c = col >> 6, k = col & 63;
    *(uint2*)(out + (size_t)c * TAB + row * 144 + k * 2) = p.u;
}

// Wo [1024 rows x 64 cols] -> 8 n-tiles of 128 rows x 64 @ pitch 144
__global__ void cvt_pack_wo(const float4* __restrict__ x, char* __restrict__ out, int n4)
{
    int i = blockIdx.x * blockDim.x + threadIdx.x;
    if (i >= n4) return;
    float4 v = x[i];
    union { __half2 h2[2]; uint2 u; } p;
    p.h2[0] = __floats2half2_rn(v.x, v.y);
    p.h2[1] = __floats2half2_rn(v.z, v.w);
    int row = i >> 4;                 // 64 cols / 4 = 16 float4 per row
    int col = (i & 15) << 2;
    int rt = row >> 7, r = row & 127;
    *(uint2*)(out + (size_t)rt * TAB + r * 144 + col * 2) = p.u;
}

// AO fp32 [B*S rows x 64] -> 64 m-tiles of 128 rows x 64 fp16 @ pitch 144
__global__ void cvt_pack_ao(const float4* __restrict__ x, char* __restrict__ out, int n4)
{
    int i = blockIdx.x * blockDim.x + threadIdx.x;
    if (i >= n4) return;
    float4 v = x[i];
    union { __half2 h2[2]; uint2 u; } p;
    p.h2[0] = __floats2half2_rn(v.x, v.y);
    p.h2[1] = __floats2half2_rn(v.z, v.w);
    int row = i >> 4;
    int col = (i & 15) << 2;
    int rt = row >> 7, r = row & 127;
    *(uint2*)(out + (size_t)rt * TAB + r * 144 + col * 2) = p.u;
}

__global__ void zero_f(float* __restrict__ p, int n)
{
    int i = blockIdx.x * blockDim.x + threadIdx.x;
    if (i < n) p[i] = 0.f;
}

// ---------------------------------------------------------------------------
// Merged projection kernel: grid (17, 64).
// ---------------------------------------------------------------------------
__global__ void __launch_bounds__(256, 2)
proj_all(const char* __restrict__ Ap, const char* __restrict__ Wp,
         const char* __restrict__ Wvp,
         const float* __restrict__ bq, const float* __restrict__ bk,
         const float* __restrict__ bv,
         char* __restrict__ Qp, char* __restrict__ Kp, char* __restrict__ VTp)
{
    extern __shared__ char smem[];
    __shared__ uint64_t mb[2];
    const uint32_t sb = smem_u32(smem);
    const int tid = threadIdx.x, lane = tid & 31, w = tid >> 5;
    const int wm = w >> 1, wn = w & 1;
    const int nx = blockIdx.x, my = blockIdx.y;
    const bool isV = (nx == 16);

    const uint32_t mbar0 = smem_u32(&mb[0]), mbar1 = smem_u32(&mb[1]);
    if (tid == 0) { MBAR_INIT(mbar0, 1); MBAR_INIT(mbar1, 1); }
    __syncthreads();

    const int slice = isV ? 0 : (nx < 8 ? 1 : 2);
    const char* Asrc = Ap + (size_t)slice * ASLICE + (size_t)my * 16 * TAB;
    const char* Wsrc = isV ? Wvp : (Wp + (size_t)nx * 16 * TAB);

    if (tid == 0) {
        MBAR_EXPECT(mbar0, 2 * TAB);
        bulk_cp(sb, Asrc, TAB, mbar0);
        bulk_cp(sb + TAB, Wsrc, TAB, mbar0);
    }

    float acc[2][8][4] = {};
    const int a_row = wm * 32 + (lane & 15);
    const uint32_t a_kext = (lane & 16) ? 16u : 0u;
    const int b_row = wn * 64 + ((lane & 16) ? 8 : 0) + (lane & 7);
    const uint32_t b_kext = (lane & 8) ? 16u : 0u;
    int ph0 = 0, ph1 = 0;

    for (int c = 0; c < 16; ++c) {
        const int b = c & 1;
        if (c + 1 < 16 && tid == 0) {
            const uint32_t nb = sb + (1 - b) * 2 * TAB;
            const uint32_t m = b ? mbar0 : mbar1;
            MBAR_EXPECT(m, 2 * TAB);
            bulk_cp(nb, Asrc + (size_t)(c + 1) * TAB, TAB, m);
            bulk_cp(nb + TAB, Wsrc + (size_t)(c + 1) * TAB, TAB, m);
        }
        if (b == 0) { mbar_wait(mbar0, ph0); ph0 ^= 1; }
        else        { mbar_wait(mbar1, ph1); ph1 ^= 1; }
        const uint32_t aS = sb + b * 2 * TAB;
        mma_tile144(acc, aS, aS + TAB, a_row, a_kext, b_row, b_kext);
        __syncthreads();
    }

    const int gq = lane >> 2, tig = lane & 3;
    if (isV) {
        if (wn == 0) {
            char* Vt = VTp + (size_t)my * VTB;
#pragma unroll
            for (int ma = 0; ma < 2; ++ma) {
                const int rl = wm * 32 + ma * 16 + gq;
#pragma unroll
                for (int n = 0; n < 8; ++n) {
                    const int d = n * 8 + tig * 2;
                    const float b0 = bv[d], b1 = bv[d + 1];
                    *(__half*)(Vt + d * 272 + rl * 2)             = __float2half(acc[ma][n][0] + b0);
                    *(__half*)(Vt + (d + 1) * 272 + rl * 2)       = __float2half(acc[ma][n][1] + b1);
                    *(__half*)(Vt + d * 272 + (rl + 8) * 2)       = __float2half(acc[ma][n][2] + b0);
                    *(__half*)(Vt + (d + 1) * 272 + (rl + 8) * 2) = __float2half(acc[ma][n][3] + b1);
                }
            }
        }
    } else {
        const float* bias = (nx < 8) ? bq : bk;
        const float cs = (nx < 8) ? QSCALE : 1.0f;
        char* Cp = (nx < 8) ? Qp : Kp;
        const int nxl = nx & 7;
#pragma unroll
        for (int ma = 0; ma < 2; ++ma) {
            const int rl = wm * 32 + ma * 16 + gq;
#pragma unroll
            for (int n = 0; n < 8; ++n) {
                const int col = nxl * 128 + wn * 64 + n * 8 + tig * 2;
                const float b0 = bias[col], b1 = bias[col + 1];
                const size_t tb = (size_t)(my * 16 + (col >> 6)) * TAB + (col & 63) * 2;
                *(__half2*)(Cp + tb + rl * 144) =
                    __floats2half2_rn((acc[ma][n][0] + b0) * cs, (acc[ma][n][1] + b1) * cs);
                *(__half2*)(Cp + tb + (rl + 8) * 144) =
                    __floats2half2_rn((acc[ma][n][2] + b0) * cs, (acc[ma][n][3] + b1) * cs);
            }
        }
    }
}

// ---------------------------------------------------------------------------
// Pass A: per-(b,h,q) softmax denominators
// ---------------------------------------------------------------------------
__global__ void __launch_bounds__(256, 2)
qk_rowsum_p(const char* __restrict__ Qp, const char* __restrict__ Kp, float* __restrict__ iL)
{
    extern __shared__ char smem[];
    __shared__ uint64_t mb[2];
    const uint32_t sb = smem_u32(smem);
    const int tid = threadIdx.x, lane = tid & 31, w = tid >> 5;
    const int wm = w >> 1, wn = w & 1;
    const int qt = blockIdx.x, h = blockIdx.y, b = blockIdx.z;

    const uint32_t mbar0 = smem_u32(&mb[0]), mbar1 = smem_u32(&mb[1]);
    if (tid == 0) { MBAR_INIT(mbar0, 1); MBAR_INIT(mbar1, 1); }
    __syncthreads();

    const char* Qsrc = Qp + ((size_t)(b * 16 + qt) * 16 + h) * TAB;
    if (tid == 0) {
        MBAR_EXPECT(mbar0, 2 * TAB);
        bulk_cp(sb, Qsrc, TAB, mbar0);
        bulk_cp(sb + TAB, Kp + ((size_t)(b * 16 + 0) * 16 + h) * TAB, TAB, mbar0);
    }

    const int a_row = wm * 32 + (lane & 15);
    const uint32_t a_kext = (lane & 16) ? 16u : 0u;
    const int b_row = wn * 64 + ((lane & 16) ? 8 : 0) + (lane & 7);
    const uint32_t b_kext = (lane & 8) ? 16u : 0u;

    float lsum[2][2] = {};
    int ph0 = 0, ph1 = 0;

    for (int kt = 0; kt < 16; ++kt) {
        const int bb = kt & 1;
        if (kt + 1 < 16 && tid == 0) {
            const uint32_t m = bb ? mbar0 : mbar1;
            MBAR_EXPECT(m, TAB);
            bulk_cp(sb + TAB + (1 - bb) * TAB,
                    Kp + ((size_t)(b * 16 + kt + 1) * 16 + h) * TAB, TAB, m);
        }
        if (bb == 0) { mbar_wait(mbar0, ph0); ph0 ^= 1; }
        else         { mbar_wait(mbar1, ph1); ph1 ^= 1; }

        float acc[2][8][4] = {};
        mma_tile144(acc, sb, sb + TAB + bb * TAB, a_row, a_kext, b_row, b_kext);

#pragma unroll
        for (int ma = 0; ma < 2; ++ma)
#pragma unroll
            for (int n = 0; n < 8; ++n) {
                lsum[ma][0] += ex2(acc[ma][n][0]) + ex2(acc[ma][n][1]);
                lsum[ma][1] += ex2(acc[ma][n][2]) + ex2(acc[ma][n][3]);
            }
        __syncthreads();
    }

#pragma unroll
    for (int o = 1; o <= 2; o <<= 1)
#pragma unroll
        for (int ma = 0; ma < 2; ++ma)
#pragma unroll
            for (int hh = 0; hh < 2; ++hh)
                lsum[ma][hh] += __shfl_xor_sync(0xffffffffu, lsum[ma][hh], o);

    __shared__ float Ls[128];
    if (tid < 128) Ls[tid] = 0.f;
    __syncthreads();
    if ((lane & 3) == 0) {
        const int gq = lane >> 2;
#pragma unroll
        for (int ma = 0; ma < 2; ++ma) {
            atomicAdd(&Ls[wm * 32 + ma * 16 + gq], lsum[ma][0]);
            atomicAdd(&Ls[wm * 32 + ma * 16 + gq + 8], lsum[ma][1]);
        }
    }
    __syncthreads();
    if (tid < 128)
        iL[((size_t)b * NH + h) * S_ + qt * 128 + tid] = 1.0f / (16.0f * Ls[tid]);
}

// ---------------------------------------------------------------------------
// Pass B: 64(q) x 128(k) tile, no spills. grid (16 kt, 32 qh, 4 b).
// ---------------------------------------------------------------------------
#define STG (QHB + TAB)          // 27648
#define ATT_SM (2 * STG)         // 55296

__global__ void __launch_bounds__(256, 2)
attn_avg_h(const char* __restrict__ Qp, const char* __restrict__ Kp,
           const char* __restrict__ VTp, const float* __restrict__ iL,
           float* __restrict__ avg, float* __restrict__ AO)
{
    extern __shared__ char smem[];
    __shared__ uint64_t mb[3];
    const uint32_t sb = smem_u32(smem);
    const int tid = threadIdx.x, lane = tid & 31, w = tid >> 5;
    const int wq = w >> 1, wn = w & 1;
    const int kt = blockIdx.x, qh = blockIdx.y, b = blockIdx.z;
    const int qt = qh >> 1, half = qh & 1;

    const uint32_t mbar0 = smem_u32(&mb[0]), mbar1 = smem_u32(&mb[1]), mbar2 = smem_u32(&mb[2]);
    if (tid == 0) { MBAR_INIT(mbar0, 1); MBAR_INIT(mbar1, 1); MBAR_INIT(mbar2, 1); }
    __syncthreads();

    const char* Qsrc = Qp + (size_t)(b * 16 + qt) * 16 * TAB + half * QHB;
    const char* Ksrc = Kp + (size_t)(b * 16 + kt) * 16 * TAB;

    if (tid == 0) {
        MBAR_EXPECT(mbar0, STG);
        bulk_cp(sb, Qsrc, QHB, mbar0);
        bulk_cp(sb + QHB, Ksrc, TAB, mbar0);
    }

    const int a_row = wq * 16 + (lane & 15);
    const uint32_t a_kext = (lane & 16) ? 16u : 0u;
    const int b_row = wn * 64 + ((lane & 16) ? 8 : 0) + (lane & 7);
    const uint32_t b_kext = (lane & 8) ? 16u : 0u;
    const int gq = lane >> 2, tig = lane & 3;

    float avgf[8][4] = {};
    int ph0 = 0, ph1 = 0;

    for (int h = 0; h < NH; ++h) {
        const int bb = h & 1;
        if (h + 1 < NH && tid == 0) {
            const uint32_t nb = sb + (1 - bb) * STG;
            const uint32_t m = bb ? mbar0 : mbar1;
            MBAR_EXPECT(m, STG);
            bulk_cp(nb, Qsrc + (size_t)(h + 1) * TAB, QHB, m);
            bulk_cp(nb + QHB, Ksrc + (size_t)(h + 1) * TAB, TAB, m);
        }
        if (bb == 0) { mbar_wait(mbar0, ph0); ph0 ^= 1; }
        else         { mbar_wait(mbar1, ph1); ph1 ^= 1; }

        float acc[8][4] = {};
        const uint32_t aS = sb + bb * STG;
        mma_half144(acc, aS, aS + QHB, a_row, a_kext, b_row, b_kext);

        const float* Lh = iL + ((size_t)b * NH + h) * S_ + qh * 64;
        const float l0 = Lh[wq * 16 + gq];
        const float l1 = Lh[wq * 16 + gq + 8];
#pragma unroll
        for (int n = 0; n < 8; ++n) {
            avgf[n][0] += ex2(acc[n][0]) * l0;
            avgf[n][1] += ex2(acc[n][1]) * l0;
            avgf[n][2] += ex2(acc[n][2]) * l1;
            avgf[n][3] += ex2(acc[n][3]) * l1;
        }
        __syncthreads();
    }

    if (tid == 0) {
        MBAR_EXPECT(mbar2, VTB);
        bulk_cp(sb + STG, VTp + (size_t)(b * 16 + kt) * VTB, VTB, mbar2);
    }

    float* outp = avg + (size_t)b * S_ * S_;
#pragma unroll
    for (int n = 0; n < 8; ++n) {
        const int rl = wq * 16 + gq;
        const int r0 = qh * 64 + rl;
        const int col = wn * 64 + n * 8 + tig * 2;
        *(float2*)(outp + (size_t)r0 * S_ + kt * 128 + col) =
            make_float2(avgf[n][0], avgf[n][1]);
        *(float2*)(outp + (size_t)(r0 + 8) * S_ + kt * 128 + col) =
            make_float2(avgf[n][2], avgf[n][3]);
        *(__half2*)(smem + rl * 272 + col * 2) = __floats2half2_rn(avgf[n][0], avgf[n][1]);
        *(__half2*)(smem + (rl + 8) * 272 + col * 2) = __floats2half2_rn(avgf[n][2], avgf[n][3]);
    }
    mbar_wait(mbar2, 0);
    __syncthreads();

    float apv[4][4] = {};
    const int pv_brow = wn * 32 + ((lane & 16) ? 8 : 0) + (lane & 7);
    const uint32_t pS = sb, vS = sb + STG;
#pragma unroll
    for (int ks = 0; ks < 8; ++ks) {
        uint32_t ah[4];
        {
            const uint32_t off = (uint32_t)(a_row * 272 + ks * 32) + a_kext;
            ldsm4(ah[0], ah[1], ah[2], ah[3], pS + off);
        }
#pragma unroll
        for (int bg = 0; bg < 2; ++bg) {
            const uint32_t off = (uint32_t)((pv_brow + bg * 16) * 272 + ks * 32) + b_kext;
            uint32_t bh[4];
            ldsm4(bh[0], bh[1], bh[2], bh[3], vS + off);
#pragma unroll
            for (int na = 0; na < 2; ++na)
                mma_f16(apv[bg * 2 + na], ah, &bh[na * 2]);
        }
    }

    {
        const int r0 = qh * 64 + wq * 16 + gq;
#pragma unroll
        for (int nI = 0; nI < 4; ++nI) {
            const int d = wn * 32 + nI * 8 + tig * 2;
            float* a0 = AO + ((size_t)b * S_ + r0) * HD + d;
            float* a1 = AO + ((size_t)b * S_ + r0 + 8) * HD + d;
            atomicAdd(a0, apv[nI][0]);
            atomicAdd(a0 + 1, apv[nI][1]);
            atomicAdd(a1, apv[nI][2]);
            atomicAdd(a1 + 1, apv[nI][3]);
        }
    }
}

// ---------------------------------------------------------------------------
// O projection (fp16 single-term, K=64 single chunk, TMA staged)
// grid (8 nx, 64 my). out fp32 [8192 x 1024].
// ---------------------------------------------------------------------------
__global__ void __launch_bounds__(256, 2)
proj_o(const char* __restrict__ AOp, const char* __restrict__ Wop,
       const float* __restrict__ bo, float* __restrict__ out)
{
    extern __shared__ char smem[];
    __shared__ uint64_t mb[1];
    const uint32_t sb = smem_u32(smem);
    const int tid = threadIdx.x, lane = tid & 31, w = tid >> 5;
    const int wm = w >> 1, wn = w & 1;
    const int nx = blockIdx.x, my = blockIdx.y;

    const uint32_t mbar0 = smem_u32(&mb[0]);
    if (tid == 0) MBAR_INIT(mbar0, 1);
    __syncthreads();

    if (tid == 0) {
        MBAR_EXPECT(mbar0, 2 * TAB);
        bulk_cp(sb, AOp + (size_t)my * TAB, TAB, mbar0);
        bulk_cp(sb + TAB, Wop + (size_t)nx * TAB, TAB, mbar0);
    }

    const int a_row = wm * 32 + (lane & 15);
    const uint32_t a_kext = (lane & 16) ? 16u : 0u;
    const int b_row = wn * 64 + ((lane & 16) ? 8 : 0) + (lane & 7);
    const uint32_t b_kext = (lane & 8) ? 16u : 0u;

    mbar_wait(mbar0, 0);

    float acc[2][8][4] = {};
    mma_tile144(acc, sb, sb + TAB, a_row, a_kext, b_row, b_kext);

    const int gq = lane >> 2, tig = lane & 3;
#pragma unroll
    for (int ma = 0; ma < 2; ++ma) {
        const int r0 = my * 128 + wm * 32 + ma * 16 + gq;
#pragma unroll
        for (int n = 0; n < 8; ++n) {
            const int col = nx * 128 + wn * 64 + n * 8 + tig * 2;
            const float b0 = bo[col], b1 = bo[col + 1];
            *(float2*)(out + (size_t)r0 * H_ + col) =
                make_float2(acc[ma][n][0] + b0, acc[ma][n][1] + b1);
            *(float2*)(out + (size_t)(r0 + 8) * H_ + col) =
                make_float2(acc[ma][n][2] + b0, acc[ma][n][3] + b1);
        }
    }
}

extern "C" void kernel_launch(void* const* d_in, const int* in_sizes, int n_in,
                              void* d_out, int out_size)
{
    const float* query  = (const float*)d_in[0];
    const float* key_in = (const float*)d_in[1];
    const float* value  = (const float*)d_in[2];
    const float* Wq = (const float*)d_in[3];
    const float* bq = (const float*)d_in[4];
    const float* Wk = (const float*)d_in[5];
    const float* bk = (const float*)d_in[6];
    const float* Wv = (const float*)d_in[7];
    const float* bv = (const float*)d_in[8];
    const float* Wo = (const float*)d_in[9];
    const float* bo = (const float*)d_in[10];

    float* out = (float*)d_out;
    float* avg_out = out + (size_t)B_ * S_ * H_;

    float *gAO, *giL;
    char *gApc, *gWpc, *gWvpc, *gWopc, *gAOpc, *gQpc, *gKpc, *gVTpc;
    cudaGetSymbolAddress((void**)&gAO, g_AO);
    cudaGetSymbolAddress((void**)&giL, g_iL);
    cudaGetSymbolAddress((void**)&gApc, g_Ap);
    cudaGetSymbolAddress((void**)&gWpc, g_Wp);
    cudaGetSymbolAddress((void**)&gWvpc, g_Wvp);
    cudaGetSymbolAddress((void**)&gWopc, g_Wop);
    cudaGetSymbolAddress((void**)&gAOpc, g_AOp);
    cudaGetSymbolAddress((void**)&gQpc, g_Qp);
    cudaGetSymbolAddress((void**)&gKpc, g_Kp);
    cudaGetSymbolAddress((void**)&gVTpc, g_VTp);

    cudaFuncSetAttribute(proj_all, cudaFuncAttributeMaxDynamicSharedMemorySize, 4 * TAB);
    cudaFuncSetAttribute(qk_rowsum_p, cudaFuncAttributeMaxDynamicSharedMemorySize, 3 * TAB);
    cudaFuncSetAttribute(attn_avg_h, cudaFuncAttributeMaxDynamicSharedMemorySize, ATT_SM);
    cudaFuncSetAttribute(proj_o, cudaFuncAttributeMaxDynamicSharedMemorySize, 2 * TAB);

    const int NXH = B_ * S_ * H_;   // 8M

    // zero attn_out accumulator (g_Wvp rows 64..127 stay zero from module load)
    zero_f<<<(B_ * S_ * HD) / 256, 256>>>(gAO, B_ * S_ * HD);

    // Pack activations and all weights (Wo hoisted up front)
    cvt_pack3<<<dim3(NXH / 1024, 3), 256>>>((const float4*)value, (const float4*)query,
                                            (const float4*)key_in, gApc, NXH / 4);
    cvt_pack_w2<<<dim3((H_ * H_) / 1024, 2), 256>>>((const float4*)Wq, (const float4*)Wk,
                                                    gWpc, H_ * H_ / 4);
    cvt_pack_w64<<<(HD * H_) / 1024, 256>>>((const float4*)Wv, gWvpc, HD * H_ / 4);
    cvt_pack_wo<<<(H_ * HD) / 1024, 256>>>((const float4*)Wo, gWopc, H_ * HD / 4);

    // All three projections in one launch (Q scaled by 0.125*log2e)
    proj_all<<<dim3(17, 64), 256, 4 * TAB>>>(gApc, gWpc, gWvpc, bq, bk, bv,
                                             gQpc, gKpc, gVTpc);

    // Pass A: softmax denominators
    qk_rowsum_p<<<dim3(S_ / 128, NH, B_), 256, 3 * TAB>>>(gQpc, gKpc, giL);

    // Pass B: head-averaged softmax + fused PV (64x128 tile, occ 2)
    attn_avg_h<<<dim3(S_ / 128, S_ / 64, B_), 256, ATT_SM>>>(gQpc, gKpc, gVTpc, giL,
                                                             avg_out, gAO);

    // O projection: pack AO to fp16 tiles, then single-chunk fp16 GEMM
    cvt_pack_ao<<<(B_ * S_ * HD) / 1024, 256>>>((const float4*)gAO, gAOpc, B_ * S_ * HD / 4);
    proj_o<<<dim3(8, 64), 256, 2 * TAB>>>(gAOpc, gWopc, bo, out);
}

// round 17
// speedup vs baseline: 12.4588x; 1.0324x over previous
#include <cuda_runtime.h>
#include <cuda_bf16.h>
#include <cuda_fp16.h>
#include <cstdint>

#define B_ 4
#define S_ 2048
#define H_ 1024
#define NH 16
#define HD 64

#define TAB 18432            // packed tile: 128 rows x 144B pitch (64 fp16 cols)
#define QHB 9216             // half tile: 64 rows x 144B
#define VTB 17408            // VT tile: 64 rows x 272B pitch (128 fp16 cols)
#define ASLICE ((size_t)64 * 16 * TAB)

// Q is pre-scaled by 0.125*log2(e) so softmax weight = exp2(score)
#define QSCALE 0.180336879f

// scratch
__device__ float g_AO[B_ * S_ * HD];
__device__ float g_iL[B_ * NH * S_];
__device__ __align__(16) char g_Ap[3 * 64 * 16 * TAB];   // slices: 0=value,1=query,2=key
__device__ __align__(16) char g_Wp[16 * 16 * TAB];       // slices 0-7: Wq, 8-15: Wk
__device__ __align__(16) char g_Wvp[16 * TAB];           // packed Wv (rows 64..127 stay zero)
__device__ __align__(16) char g_Wop[8 * TAB];            // packed Wo
__device__ __align__(16) char g_AOp[64 * TAB];           // packed AO fp16
__device__ __align__(16) char g_Qp[64 * 16 * TAB];
__device__ __align__(16) char g_Kp[64 * 16 * TAB];
__device__ __align__(16) char g_VTp[64 * VTB];

// ---------------------------------------------------------------------------
// helpers
// ---------------------------------------------------------------------------
__device__ __forceinline__ uint32_t smem_u32(const void* p) {
    uint32_t a;
    asm("{ .reg .u64 t; cvta.to.shared.u64 t, %1; cvt.u32.u64 %0, t; }" : "=r"(a) : "l"(p));
    return a;
}

// exp2 of two fp32 via one f16x2 MUFU op (halves MUFU pressure)
__device__ __forceinline__ void ex2h2(float a0, float a1, float& e0, float& e1) {
    uint32_t hh, rr;
    asm("cvt.rn.f16x2.f32 %0, %1, %2;" : "=r"(hh) : "f"(a1), "f"(a0));   // hi=a1, lo=a0
    asm("ex2.approx.f16x2 %0, %1;" : "=r"(rr) : "r"(hh));
    asm("{\n\t.reg .b16 l, u;\n\tmov.b32 {l, u}, %2;\n\t"
        "cvt.f32.f16 %0, l;\n\tcvt.f32.f16 %1, u;\n\t}"
        : "=f"(e0), "=f"(e1) : "r"(rr));
}

__device__ __forceinline__ void ldsm4(uint32_t& r0, uint32_t& r1, uint32_t& r2, uint32_t& r3,
                                      uint32_t addr) {
    asm volatile("ldmatrix.sync.aligned.m8n8.x4.shared.b16 {%0,%1,%2,%3}, [%4];"
                 : "=r"(r0), "=r"(r1), "=r"(r2), "=r"(r3) : "r"(addr));
}
__device__ __forceinline__ void mma_f16(float* c, const uint32_t* a, const uint32_t* b) {
    asm volatile(
        "mma.sync.aligned.m16n8k16.row.col.f32.f16.f16.f32 "
        "{%0,%1,%2,%3}, {%4,%5,%6,%7}, {%8,%9}, {%0,%1,%2,%3};"
        : "+f"(c[0]), "+f"(c[1]), "+f"(c[2]), "+f"(c[3])
        : "r"(a[0]), "r"(a[1]), "r"(a[2]), "r"(a[3]), "r"(b[0]), "r"(b[1]));
}

// --- TMA bulk-copy + mbarrier (base sm_90 PTX) ---
__device__ __forceinline__ void bulk_cp(uint32_t sdst, const void* gsrc, uint32_t bytes,
                                        uint32_t mbar) {
    asm volatile(
        "cp.async.bulk.shared::cta.global.mbarrier::complete_tx::bytes [%0], [%1], %2, [%3];"
        :: "r"(sdst), "l"(gsrc), "r"(bytes), "r"(mbar) : "memory");
}
#define MBAR_INIT(a, n) \
    asm volatile("mbarrier.init.shared.b64 [%0], %1;" :: "r"(a), "r"((uint32_t)(n)) : "memory")
#define MBAR_EXPECT(a, bytes) \
    asm volatile("mbarrier.arrive.expect_tx.shared.b64 _, [%0], %1;" \
                 :: "r"(a), "r"((uint32_t)(bytes)) : "memory")
__device__ __forceinline__ void mbar_wait(uint32_t mbar, int parity) {
    asm volatile(
        "{\n\t.reg .pred P;\n\t"
        "LAB_%=:\n\t"
        "mbarrier.try_wait.parity.acquire.cta.shared::cta.b64 P, [%0], %1;\n\t"
        "@!P bra LAB_%=;\n\t}"
        :: "r"(mbar), "r"((uint32_t)parity) : "memory");
}

// 128x128x64 fp16 MMA on two pitch-144 tiles (8 warps 4m x 2n)
__device__ __forceinline__ void mma_tile144(float acc[2][8][4], uint32_t aS, uint32_t bS,
                                            int a_row, uint32_t a_kext,
                                            int b_row, uint32_t b_kext)
{
#pragma unroll
    for (int ks = 0; ks < 4; ++ks) {
        uint32_t ah[2][4];
#pragma unroll
        for (int ma = 0; ma < 2; ++ma) {
            const uint32_t off = (uint32_t)((a_row + ma * 16) * 144 + ks * 32) + a_kext;
            ldsm4(ah[ma][0], ah[ma][1], ah[ma][2], ah[ma][3], aS + off);
        }
#pragma unroll
        for (int bg = 0; bg < 4; ++bg) {
            const uint32_t off = (uint32_t)((b_row + bg * 16) * 144 + ks * 32) + b_kext;
            uint32_t bh[4];
            ldsm4(bh[0], bh[1], bh[2], bh[3], bS + off);
#pragma unroll
            for (int na = 0; na < 2; ++na)
#pragma unroll
                for (int ma = 0; ma < 2; ++ma)
                    mma_f16(acc[ma][bg * 2 + na], ah[ma], &bh[na * 2]);
        }
    }
}

// 64x128x64: A half-tile (64 rows), warps 4m(16 rows) x 2n(64 cols)
__device__ __forceinline__ void mma_half144(float acc[8][4], uint32_t aS, uint32_t bS,
                                            int a_row, uint32_t a_kext,
                                            int b_row, uint32_t b_kext)
{
#pragma unroll
    for (int ks = 0; ks < 4; ++ks) {
        uint32_t ah[4];
        {
            const uint32_t off = (uint32_t)(a_row * 144 + ks * 32) + a_kext;
            ldsm4(ah[0], ah[1], ah[2], ah[3], aS + off);
        }
#pragma unroll
        for (int bg = 0; bg < 4; ++bg) {
            const uint32_t off = (uint32_t)((b_row + bg * 16) * 144 + ks * 32) + b_kext;
            uint32_t bh[4];
            ldsm4(bh[0], bh[1], bh[2], bh[3], bS + off);
#pragma unroll
            for (int na = 0; na < 2; ++na)
                mma_f16(acc[bg * 2 + na], ah, &bh[na * 2]);
        }
    }
}

// ---------------------------------------------------------------------------
// utility kernels
// ---------------------------------------------------------------------------
__global__ void cvt_pack3(const float4* __restrict__ x0, const float4* __restrict__ x1,
                          const float4* __restrict__ x2, char* __restrict__ out, int n4)
{
    int i = blockIdx.x * blockDim.x + threadIdx.x;
    if (i >= n4) return;
    const int z = blockIdx.y;
    const float4* x = (z == 0) ? x0 : ((z == 1) ? x1 : x2);
    float4 v = x[i];
    union { __half2 h2[2]; uint2 u; } p;
    p.h2[0] = __floats2half2_rn(v.x, v.y);
    p.h2[1] = __floats2half2_rn(v.z, v.w);
    int row = i >> 8;
    int col = (i & 255) << 2;
    int rt = row >> 7, r = row & 127, c = col >> 6, k = col & 63;
    *(uint2*)(out + (size_t)z * ASLICE + (size_t)(rt * 16 + c) * TAB + r * 144 + k * 2) = p.u;
}

__global__ void cvt_pack_w2(const float4* __restrict__ x0, const float4* __restrict__ x1,
                            char* __restrict__ out, int n4)
{
    int i = blockIdx.x * blockDim.x + threadIdx.x;
    if (i >= n4) return;
    const int z = blockIdx.y;
    const float4* x = z ? x1 : x0;
    float4 v = x[i];
    union { __half2 h2[2]; uint2 u; } p;
    p.h2[0] = __floats2half2_rn(v.x, v.y);
    p.h2[1] = __floats2half2_rn(v.z, v.w);
    int row = i >> 8;
    int col = (i & 255) << 2;
    int rt = row >> 7, r = row & 127, c = col >> 6, k = col & 63;
    *(uint2*)(out + (size_t)((z * 8 + rt) * 16 + c) * TAB + r * 144 + k * 2) = p.u;
}

__global__ void cvt_pack_w64(const float4* __restrict__ x, char* __restrict__ out, int n4)
{
    int i = blockIdx.x * blockDim.x + threadIdx.x;
    if (i >= n4) return;
    float4 v = x[i];
    union { __half2 h2[2]; uint2 u; } p;
    p.h2[0] = __floats2half2_rn(v.x, v.y);
    p.h2[1] = __floats2half2_rn(v.z, v.w);
    int row = i >> 8;
    int col = (i & 255) << 2;
    int c = col >> 6, k = col & 63;
    *(uint2*)(out + (size_t)c * TAB + row * 144 + k * 2) = p.u;
}

__global__ void cvt_pack_wo(const float4* __restrict__ x, char* __restrict__ out, int n4)
{
    int i = blockIdx.x * blockDim.x + threadIdx.x;
    if (i >= n4) return;
    float4 v = x[i];
    union { __half2 h2[2]; uint2 u; } p;
    p.h2[0] = __floats2half2_rn(v.x, v.y);
    p.h2[1] = __floats2half2_rn(v.z, v.w);
    int row = i >> 4;
    int col = (i & 15) << 2;
    int rt = row >> 7, r = row & 127;
    *(uint2*)(out + (size_t)rt * TAB + r * 144 + col * 2) = p.u;
}

__global__ void cvt_pack_ao(const float4* __restrict__ x, char* __restrict__ out, int n4)
{
    int i = blockIdx.x * blockDim.x + threadIdx.x;
    if (i >= n4) return;
    float4 v = x[i];
    union { __half2 h2[2]; uint2 u; } p;
    p.h2[0] = __floats2half2_rn(v.x, v.y);
    p.h2[1] = __floats2half2_rn(v.z, v.w);
    int row = i >> 4;
    int col = (i & 15) << 2;
    int rt = row >> 7, r = row & 127;
    *(uint2*)(out + (size_t)rt * TAB + r * 144 + col * 2) = p.u;
}

__global__ void zero_f(float* __restrict__ p, int n)
{
    int i = blockIdx.x * blockDim.x + threadIdx.x;
    if (i < n) p[i] = 0.f;
}

// ---------------------------------------------------------------------------
// Merged projection kernel: grid (17, 64), 3-stage TMA pipeline.
// ---------------------------------------------------------------------------
__global__ void __launch_bounds__(256, 2)
proj_all(const char* __restrict__ Ap, const char* __restrict__ Wp,
         const char* __restrict__ Wvp,
         const float* __restrict__ bq, const float* __restrict__ bk,
         const float* __restrict__ bv,
         char* __restrict__ Qp, char* __restrict__ Kp, char* __restrict__ VTp)
{
    extern __shared__ char smem[];
    __shared__ uint64_t mb[3];
    const uint32_t sb = smem_u32(smem);
    const int tid = threadIdx.x, lane = tid & 31, w = tid >> 5;
    const int wm = w >> 1, wn = w & 1;
    const int nx = blockIdx.x, my = blockIdx.y;
    const bool isV = (nx == 16);

    uint32_t mbar[3];
    mbar[0] = smem_u32(&mb[0]); mbar[1] = smem_u32(&mb[1]); mbar[2] = smem_u32(&mb[2]);
    if (tid == 0) { MBAR_INIT(mbar[0], 1); MBAR_INIT(mbar[1], 1); MBAR_INIT(mbar[2], 1); }
    __syncthreads();

    const int slice = isV ? 0 : (nx < 8 ? 1 : 2);
    const char* Asrc = Ap + (size_t)slice * ASLICE + (size_t)my * 16 * TAB;
    const char* Wsrc = isV ? Wvp : (Wp + (size_t)nx * 16 * TAB);

    if (tid == 0) {
#pragma unroll
        for (int s = 0; s < 2; ++s) {
            MBAR_EXPECT(mbar[s], 2 * TAB);
            bulk_cp(sb + s * 2 * TAB, Asrc + (size_t)s * TAB, TAB, mbar[s]);
            bulk_cp(sb + s * 2 * TAB + TAB, Wsrc + (size_t)s * TAB, TAB, mbar[s]);
        }
    }

    float acc[2][8][4] = {};
    const int a_row = wm * 32 + (lane & 15);
    const uint32_t a_kext = (lane & 16) ? 16u : 0u;
    const int b_row = wn * 64 + ((lane & 16) ? 8 : 0) + (lane & 7);
    const uint32_t b_kext = (lane & 8) ? 16u : 0u;
    int ph[3] = {0, 0, 0};

#pragma unroll
    for (int c = 0; c < 16; ++c) {
        const int s = c % 3;
        if (c + 2 < 16 && tid == 0) {
            const int sn = (c + 2) % 3;
            MBAR_EXPECT(mbar[sn], 2 * TAB);
            bulk_cp(sb + sn * 2 * TAB, Asrc + (size_t)(c + 2) * TAB, TAB, mbar[sn]);
            bulk_cp(sb + sn * 2 * TAB + TAB, Wsrc + (size_t)(c + 2) * TAB, TAB, mbar[sn]);
        }
        mbar_wait(mbar[s], ph[s]); ph[s] ^= 1;
        const uint32_t aS = sb + s * 2 * TAB;
        mma_tile144(acc, aS, aS + TAB, a_row, a_kext, b_row, b_kext);
        __syncthreads();
    }

    const int gq = lane >> 2, tig = lane & 3;
    if (isV) {
        if (wn == 0) {
            char* Vt = VTp + (size_t)my * VTB;
#pragma unroll
            for (int ma = 0; ma < 2; ++ma) {
                const int rl = wm * 32 + ma * 16 + gq;
#pragma unroll
                for (int n = 0; n < 8; ++n) {
                    const int d = n * 8 + tig * 2;
                    const float b0 = bv[d], b1 = bv[d + 1];
                    *(__half*)(Vt + d * 272 + rl * 2)             = __float2half(acc[ma][n][0] + b0);
                    *(__half*)(Vt + (d + 1) * 272 + rl * 2)       = __float2half(acc[ma][n][1] + b1);
                    *(__half*)(Vt + d * 272 + (rl + 8) * 2)       = __float2half(acc[ma][n][2] + b0);
                    *(__half*)(Vt + (d + 1) * 272 + (rl + 8) * 2) = __float2half(acc[ma][n][3] + b1);
                }
            }
        }
    } else {
        const float* bias = (nx < 8) ? bq : bk;
        const float cs = (nx < 8) ? QSCALE : 1.0f;
        char* Cp = (nx < 8) ? Qp : Kp;
        const int nxl = nx & 7;
#pragma unroll
        for (int ma = 0; ma < 2; ++ma) {
            const int rl = wm * 32 + ma * 16 + gq;
#pragma unroll
            for (int n = 0; n < 8; ++n) {
                const int col = nxl * 128 + wn * 64 + n * 8 + tig * 2;
                const float b0 = bias[col], b1 = bias[col + 1];
                const size_t tb = (size_t)(my * 16 + (col >> 6)) * TAB + (col & 63) * 2;
                *(__half2*)(Cp + tb + rl * 144) =
                    __floats2half2_rn((acc[ma][n][0] + b0) * cs, (acc[ma][n][1] + b1) * cs);
                *(__half2*)(Cp + tb + (rl + 8) * 144) =
                    __floats2half2_rn((acc[ma][n][2] + b0) * cs, (acc[ma][n][3] + b1) * cs);
            }
        }
    }
}

// ---------------------------------------------------------------------------
// Pass A: per-(b,h,q) softmax denominators. Q resident + 3-stage K pipeline.
// smem: Q (TAB) + 3 x K (TAB) = 4*TAB.
// ---------------------------------------------------------------------------
__global__ void __launch_bounds__(256, 2)
qk_rowsum_p(const char* __restrict__ Qp, const char* __restrict__ Kp, float* __restrict__ iL)
{
    extern __shared__ char smem[];
    __shared__ uint64_t mb[3];
    const uint32_t sb = smem_u32(smem);
    const int tid = threadIdx.x, lane = tid & 31, w = tid >> 5;
    const int wm = w >> 1, wn = w & 1;
    const int qt = blockIdx.x, h = blockIdx.y, b = blockIdx.z;

    uint32_t mbar[3];
    mbar[0] = smem_u32(&mb[0]); mbar[1] = smem_u32(&mb[1]); mbar[2] = smem_u32(&mb[2]);
    if (tid == 0) { MBAR_INIT(mbar[0], 1); MBAR_INIT(mbar[1], 1); MBAR_INIT(mbar[2], 1); }
    __syncthreads();

    const char* Qsrc = Qp + ((size_t)(b * 16 + qt) * 16 + h) * TAB;
    const char* Kbase = Kp + (size_t)h * TAB + (size_t)b * 16 * 16 * TAB;

    if (tid == 0) {
        MBAR_EXPECT(mbar[0], 2 * TAB);
        bulk_cp(sb, Qsrc, TAB, mbar[0]);
        bulk_cp(sb + TAB, Kbase, TAB, mbar[0]);
        MBAR_EXPECT(mbar[1], TAB);
        bulk_cp(sb + 2 * TAB, Kbase + (size_t)16 * TAB, TAB, mbar[1]);
    }

    const int a_row = wm * 32 + (lane & 15);
    const uint32_t a_kext = (lane & 16) ? 16u : 0u;
    const int b_row = wn * 64 + ((lane & 16) ? 8 : 0) + (lane & 7);
    const uint32_t b_kext = (lane & 8) ? 16u : 0u;

    float lsum[2][2] = {};
    int ph[3] = {0, 0, 0};

#pragma unroll
    for (int kt = 0; kt < 16; ++kt) {
        const int s = kt % 3;
        if (kt + 2 < 16 && tid == 0) {
            const int sn = (kt + 2) % 3;
            MBAR_EXPECT(mbar[sn], TAB);
            bulk_cp(sb + TAB + sn * TAB, Kbase + (size_t)(kt + 2) * 16 * TAB, TAB, mbar[sn]);
        }
        mbar_wait(mbar[s], ph[s]); ph[s] ^= 1;

        float acc[2][8][4] = {};
        mma_tile144(acc, sb, sb + TAB + s * TAB, a_row, a_kext, b_row, b_kext);

#pragma unroll
        for (int ma = 0; ma < 2; ++ma)
#pragma unroll
            for (int n = 0; n < 8; ++n) {
                float e0, e1, e2, e3;
                ex2h2(acc[ma][n][0], acc[ma][n][1], e0, e1);
                ex2h2(acc[ma][n][2], acc[ma][n][3], e2, e3);
                lsum[ma][0] += e0 + e1;
                lsum[ma][1] += e2 + e3;
            }
        __syncthreads();
    }

#pragma unroll
    for (int o = 1; o <= 2; o <<= 1)
#pragma unroll
        for (int ma = 0; ma < 2; ++ma)
#pragma unroll
            for (int hh = 0; hh < 2; ++hh)
                lsum[ma][hh] += __shfl_xor_sync(0xffffffffu, lsum[ma][hh], o);

    __shared__ float Ls[128];
    if (tid < 128) Ls[tid] = 0.f;
    __syncthreads();
    if ((lane & 3) == 0) {
        const int gq = lane >> 2;
#pragma unroll
        for (int ma = 0; ma < 2; ++ma) {
            atomicAdd(&Ls[wm * 32 + ma * 16 + gq], lsum[ma][0]);
            atomicAdd(&Ls[wm * 32 + ma * 16 + gq + 8], lsum[ma][1]);
        }
    }
    __syncthreads();
    if (tid < 128)
        iL[((size_t)b * NH + h) * S_ + qt * 128 + tid] = 1.0f / (16.0f * Ls[tid]);
}

// ---------------------------------------------------------------------------
// Pass B: 64(q) x 128(k) tile, 3-stage pipeline, f16x2 exp.
// smem: 3 x (QHB + TAB) = 82944; overlay P at buf0, VT at buf1 after loop.
// ---------------------------------------------------------------------------
#define STG (QHB + TAB)          // 27648
#define ATT_SM (3 * STG)         // 82944

__global__ void __launch_bounds__(256, 2)
attn_avg_h(const char* __restrict__ Qp, const char* __restrict__ Kp,
           const char* __restrict__ VTp, const float* __restrict__ iL,
           float* __restrict__ avg, float* __restrict__ AO)
{
    extern __shared__ char smem[];
    __shared__ uint64_t mb[4];
    const uint32_t sb = smem_u32(smem);
    const int tid = threadIdx.x, lane = tid & 31, w = tid >> 5;
    const int wq = w >> 1, wn = w & 1;
    const int kt = blockIdx.x, qh = blockIdx.y, b = blockIdx.z;
    const int qt = qh >> 1, half = qh & 1;

    uint32_t mbar[4];
    mbar[0] = smem_u32(&mb[0]); mbar[1] = smem_u32(&mb[1]);
    mbar[2] = smem_u32(&mb[2]); mbar[3] = smem_u32(&mb[3]);
    if (tid == 0) {
        MBAR_INIT(mbar[0], 1); MBAR_INIT(mbar[1], 1);
        MBAR_INIT(mbar[2], 1); MBAR_INIT(mbar[3], 1);
    }
    __syncthreads();

    const char* Qsrc = Qp + (size_t)(b * 16 + qt) * 16 * TAB + half * QHB;
    const char* Ksrc = Kp + (size_t)(b * 16 + kt) * 16 * TAB;

    if (tid == 0) {
#pragma unroll
        for (int s = 0; s < 2; ++s) {
            MBAR_EXPECT(mbar[s], STG);
            bulk_cp(sb + s * STG, Qsrc + (size_t)s * TAB, QHB, mbar[s]);
            bulk_cp(sb + s * STG + QHB, Ksrc + (size_t)s * TAB, TAB, mbar[s]);
        }
    }

    const int a_row = wq * 16 + (lane & 15);
    const uint32_t a_kext = (lane & 16) ? 16u : 0u;
    const int b_row = wn * 64 + ((lane & 16) ? 8 : 0) + (lane & 7);
    const uint32_t b_kext = (lane & 8) ? 16u : 0u;
    const int gq = lane >> 2, tig = lane & 3;

    float avgf[8][4] = {};
    int ph[3] = {0, 0, 0};

#pragma unroll
    for (int h = 0; h < NH; ++h) {
        const int s = h % 3;
        if (h + 2 < NH && tid == 0) {
            const int sn = (h + 2) % 3;
            MBAR_EXPECT(mbar[sn], STG);
            bulk_cp(sb + sn * STG, Qsrc + (size_t)(h + 2) * TAB, QHB, mbar[sn]);
            bulk_cp(sb + sn * STG + QHB, Ksrc + (size_t)(h + 2) * TAB, TAB, mbar[sn]);
        }
        mbar_wait(mbar[s], ph[s]); ph[s] ^= 1;

        float acc[8][4] = {};
        const uint32_t aS = sb + s * STG;
        mma_half144(acc, aS, aS + QHB, a_row, a_kext, b_row, b_kext);

        const float* Lh = iL + ((size_t)b * NH + h) * S_ + qh * 64;
        const float l0 = Lh[wq * 16 + gq];
        const float l1 = Lh[wq * 16 + gq + 8];
#pragma unroll
        for (int n = 0; n < 8; ++n) {
            float e0, e1, e2, e3;
            ex2h2(acc[n][0], acc[n][1], e0, e1);
            ex2h2(acc[n][2], acc[n][3], e2, e3);
            avgf[n][0] += e0 * l0;
            avgf[n][1] += e1 * l0;
            avgf[n][2] += e2 * l1;
            avgf[n][3] += e3 * l1;
        }
        __syncthreads();
    }

    if (tid == 0) {
        MBAR_EXPECT(mbar[3], VTB);
        bulk_cp(sb + STG, VTp + (size_t)(b * 16 + kt) * VTB, VTB, mbar[3]);
    }

    float* outp = avg + (size_t)b * S_ * S_;
#pragma unroll
    for (int n = 0; n < 8; ++n) {
        const int rl = wq * 16 + gq;
        const int r0 = qh * 64 + rl;
        const int col = wn * 64 + n * 8 + tig * 2;
        *(float2*)(outp + (size_t)r0 * S_ + kt * 128 + col) =
            make_float2(avgf[n][0], avgf[n][1]);
        *(float2*)(outp + (size_t)(r0 + 8) * S_ + kt * 128 + col) =
            make_float2(avgf[n][2], avgf[n][3]);
        *(__half2*)(smem + rl * 272 + col * 2) = __floats2half2_rn(avgf[n][0], avgf[n][1]);
        *(__half2*)(smem + (rl + 8) * 272 + col * 2) = __floats2half2_rn(avgf[n][2], avgf[n][3]);
    }
    mbar_wait(mbar[3], 0);
    __syncthreads();

    float apv[4][4] = {};
    const int pv_brow = wn * 32 + ((lane & 16) ? 8 : 0) + (lane & 7);
    const uint32_t pS = sb, vS = sb + STG;
#pragma unroll
    for (int ks = 0; ks < 8; ++ks) {
        uint32_t ah[4];
        {
            const uint32_t off = (uint32_t)(a_row * 272 + ks * 32) + a_kext;
            ldsm4(ah[0], ah[1], ah[2], ah[3], pS + off);
        }
#pragma unroll
        for (int bg = 0; bg < 2; ++bg) {
            const uint32_t off = (uint32_t)((pv_brow + bg * 16) * 272 + ks * 32) + b_kext;
            uint32_t bh[4];
            ldsm4(bh[0], bh[1], bh[2], bh[3], vS + off);
#pragma unroll
            for (int na = 0; na < 2; ++na)
                mma_f16(apv[bg * 2 + na], ah, &bh[na * 2]);
        }
    }

    {
        const int r0 = qh * 64 + wq * 16 + gq;
#pragma unroll
        for (int nI = 0; nI < 4; ++nI) {
            const int d = wn * 32 + nI * 8 + tig * 2;
            float* a0 = AO + ((size_t)b * S_ + r0) * HD + d;
            float* a1 = AO + ((size_t)b * S_ + r0 + 8) * HD + d;
            atomicAdd(a0, apv[nI][0]);
            atomicAdd(a0 + 1, apv[nI][1]);
            atomicAdd(a1, apv[nI][2]);
            atomicAdd(a1 + 1, apv[nI][3]);
        }
    }
}

// ---------------------------------------------------------------------------
// O projection (fp16 single-term, K=64 single chunk, TMA staged)
// ---------------------------------------------------------------------------
__global__ void __launch_bounds__(256, 2)
proj_o(const char* __restrict__ AOp, const char* __restrict__ Wop,
       const float* __restrict__ bo, float* __restrict__ out)
{
    extern __shared__ char smem[];
    __shared__ uint64_t mb[1];
    const uint32_t sb = smem_u32(smem);
    const int tid = threadIdx.x, lane = tid & 31, w = tid >> 5;
    const int wm = w >> 1, wn = w & 1;
    const int nx = blockIdx.x, my = blockIdx.y;

    const uint32_t mbar0 = smem_u32(&mb[0]);
    if (tid == 0) MBAR_INIT(mbar0, 1);
    __syncthreads();

    if (tid == 0) {
        MBAR_EXPECT(mbar0, 2 * TAB);
        bulk_cp(sb, AOp + (size_t)my * TAB, TAB, mbar0);
        bulk_cp(sb + TAB, Wop + (size_t)nx * TAB, TAB, mbar0);
    }

    const int a_row = wm * 32 + (lane & 15);
    const uint32_t a_kext = (lane & 16) ? 16u : 0u;
    const int b_row = wn * 64 + ((lane & 16) ? 8 : 0) + (lane & 7);
    const uint32_t b_kext = (lane & 8) ? 16u : 0u;

    mbar_wait(mbar0, 0);

    float acc[2][8][4] = {};
    mma_tile144(acc, sb, sb + TAB, a_row, a_kext, b_row, b_kext);

    const int gq = lane >> 2, tig = lane & 3;
#pragma unroll
    for (int ma = 0; ma < 2; ++ma) {
        const int r0 = my * 128 + wm * 32 + ma * 16 + gq;
#pragma unroll
        for (int n = 0; n < 8; ++n) {
            const int col = nx * 128 + wn * 64 + n * 8 + tig * 2;
            const float b0 = bo[col], b1 = bo[col + 1];
            *(float2*)(out + (size_t)r0 * H_ + col) =
                make_float2(acc[ma][n][0] + b0, acc[ma][n][1] + b1);
            *(float2*)(out + (size_t)(r0 + 8) * H_ + col) =
                make_float2(acc[ma][n][2] + b0, acc[ma][n][3] + b1);
        }
    }
}

extern "C" void kernel_launch(void* const* d_in, const int* in_sizes, int n_in,
                              void* d_out, int out_size)
{
    const float* query  = (const float*)d_in[0];
    const float* key_in = (const float*)d_in[1];
    const float* value  = (const float*)d_in[2];
    const float* Wq = (const float*)d_in[3];
    const float* bq = (const float*)d_in[4];
    const float* Wk = (const float*)d_in[5];
    const float* bk = (const float*)d_in[6];
    const float* Wv = (const float*)d_in[7];
    const float* bv = (const float*)d_in[8];
    const float* Wo = (const float*)d_in[9];
    const float* bo = (const float*)d_in[10];

    float* out = (float*)d_out;
    float* avg_out = out + (size_t)B_ * S_ * H_;

    float *gAO, *giL;
    char *gApc, *gWpc, *gWvpc, *gWopc, *gAOpc, *gQpc, *gKpc, *gVTpc;
    cudaGetSymbolAddress((void**)&gAO, g_AO);
    cudaGetSymbolAddress((void**)&giL, g_iL);
    cudaGetSymbolAddress((void**)&gApc, g_Ap);
    cudaGetSymbolAddress((void**)&gWpc, g_Wp);
    cudaGetSymbolAddress((void**)&gWvpc, g_Wvp);
    cudaGetSymbolAddress((void**)&gWopc, g_Wop);
    cudaGetSymbolAddress((void**)&gAOpc, g_AOp);
    cudaGetSymbolAddress((void**)&gQpc, g_Qp);
    cudaGetSymbolAddress((void**)&gKpc, g_Kp);
    cudaGetSymbolAddress((void**)&gVTpc, g_VTp);

    cudaFuncSetAttribute(proj_all, cudaFuncAttributeMaxDynamicSharedMemorySize, 6 * TAB);
    cudaFuncSetAttribute(qk_rowsum_p, cudaFuncAttributeMaxDynamicSharedMemorySize, 4 * TAB);
    cudaFuncSetAttribute(attn_avg_h, cudaFuncAttributeMaxDynamicSharedMemorySize, ATT_SM);
    cudaFuncSetAttribute(proj_o, cudaFuncAttributeMaxDynamicSharedMemorySize, 2 * TAB);

    const int NXH = B_ * S_ * H_;   // 8M

    zero_f<<<(B_ * S_ * HD) / 256, 256>>>(gAO, B_ * S_ * HD);

    // Pack activations and all weights
    cvt_pack3<<<dim3(NXH / 1024, 3), 256>>>((const float4*)value, (const float4*)query,
                                            (const float4*)key_in, gApc, NXH / 4);
    cvt_pack_w2<<<dim3((H_ * H_) / 1024, 2), 256>>>((const float4*)Wq, (const float4*)Wk,
                                                    gWpc, H_ * H_ / 4);
    cvt_pack_w64<<<(HD * H_) / 1024, 256>>>((const float4*)Wv, gWvpc, HD * H_ / 4);
    cvt_pack_wo<<<(H_ * HD) / 1024, 256>>>((const float4*)Wo, gWopc, H_ * HD / 4);

    // All three projections in one launch (Q scaled by 0.125*log2e)
    proj_all<<<dim3(17, 64), 256, 6 * TAB>>>(gApc, gWpc, gWvpc, bq, bk, bv,
                                             gQpc, gKpc, gVTpc);

    // Pass A: softmax denominators
    qk_rowsum_p<<<dim3(S_ / 128, NH, B_), 256, 4 * TAB>>>(gQpc, gKpc, giL);

    // Pass B: head-averaged softmax + fused PV
    attn_avg_h<<<dim3(S_ / 128, S_ / 64, B_), 256, ATT_SM>>>(gQpc, gKpc, gVTpc, giL,
                                                             avg_out, gAO);

    // O projection
    cvt_pack_ao<<<(B_ * S_ * HD) / 1024, 256>>>((const float4*)gAO, gAOpc, B_ * S_ * HD / 4);
    proj_o<<<dim3(8, 64), 256, 2 * TAB>>>(gAOpc, gWopc, bo, out);
}